// round 1
// baseline (speedup 1.0000x reference)
#include <cuda_runtime.h>
#include <math.h>

// ---------------- problem constants ----------------
#define DD     768
#define NTOK   171
#define BATCH  64
#define MROWS  (BATCH*NTOK)      // 10944
#define NPATCH 170
#define CROWS  (BATCH*NPATCH)    // 10880
#define KCONV  600               // 6*10*10
#define NHEAD  12
#define HDIM   64
#define DEPTH  12
#define EPS    1e-5f

// ---------------- scratch (device globals; no cudaMalloc allowed) ----------------
__device__ float g_col[CROWS * KCONV];     // im2col        (~26 MB)
__device__ float g_wt [KCONV * DD];        // conv_w^T      (~1.8 MB)
__device__ float g_h  [MROWS * DD];        // residual stream (~33.6 MB)
__device__ float g_y  [MROWS * DD];        // LN out / attn out
__device__ float g_big[MROWS * 4 * DD];    // qkv / fc1 out (~134 MB)
__device__ float g_cls[BATCH * DD];        // final LN of cls rows

// ---------------- im2col ----------------
__global__ void im2col_kernel(const float* __restrict__ x, float* __restrict__ col) {
    int idx = blockIdx.x * blockDim.x + threadIdx.x;
    if (idx >= CROWS * KCONV) return;
    int r = idx / KCONV, c = idx % KCONV;
    int b = r / NPATCH, p = r % NPATCH;
    int ch = c / 100, rem = c % 100;
    int kh = rem / 10, kw = rem % 10;
    int ph = p / 34, pw = p % 34;
    col[idx] = x[((b * 6 + ch) * 50 + ph * 10 + kh) * 345 + pw * 10 + kw];
}

// ---------------- transpose conv weights [768,600] -> [600,768] ----------------
__global__ void transw_kernel(const float* __restrict__ w, float* __restrict__ wt) {
    int idx = blockIdx.x * blockDim.x + threadIdx.x;
    if (idx >= KCONV * DD) return;
    int k = idx / DD, d = idx % DD;
    wt[idx] = w[d * KCONV + k];
}

// ---------------- assemble tokens: cls + patches + pos_embed ----------------
__global__ void assemble_kernel(const float* __restrict__ conv_out,
                                const float* __restrict__ cls,
                                const float* __restrict__ pos,
                                float* __restrict__ h) {
    int idx = blockIdx.x * blockDim.x + threadIdx.x;
    if (idx >= MROWS * DD) return;
    int row = idx / DD, d = idx % DD;
    int b = row / NTOK, t = row % NTOK;
    float v = (t == 0) ? cls[d] : conv_out[(b * NPATCH + t - 1) * DD + d];
    h[idx] = v + pos[t * DD + d];
}

// ---------------- tiled SGEMM: C[M,N] = A[M,K] @ B[K,N] (+bias) (opt GELU) (+res) ----------------
#define BM 64
#define BN 64
#define BK 16

template <bool GELU>
__global__ void sgemm_kernel(const float* __restrict__ A, const float* __restrict__ B,
                             const float* __restrict__ bias, const float* res,
                             float* C, int M, int N, int K) {
    __shared__ float As[BK][BM + 4];
    __shared__ float Bs[BK][BN];
    int tid = threadIdx.x;
    int m0 = blockIdx.y * BM;
    int n0 = blockIdx.x * BN;
    int tx = tid & 15, ty = tid >> 4;

    float acc[4][4];
#pragma unroll
    for (int i = 0; i < 4; i++)
#pragma unroll
        for (int j = 0; j < 4; j++) acc[i][j] = 0.f;

    for (int k0 = 0; k0 < K; k0 += BK) {
#pragma unroll
        for (int i = 0; i < 4; i++) {
            int idx = tid + i * 256;
            int ar = idx >> 4, ac = idx & 15;     // [64][16] tile of A
            int gr = m0 + ar, gc = k0 + ac;
            float v = 0.f;
            if (gr < M && gc < K) v = A[(size_t)gr * K + gc];
            As[ac][ar] = v;
        }
#pragma unroll
        for (int i = 0; i < 4; i++) {
            int idx = tid + i * 256;
            int br = idx >> 6, bc = idx & 63;     // [16][64] tile of B
            int gr = k0 + br, gc = n0 + bc;
            float v = 0.f;
            if (gr < K && gc < N) v = B[(size_t)gr * N + gc];
            Bs[br][bc] = v;
        }
        __syncthreads();
#pragma unroll
        for (int kk = 0; kk < BK; kk++) {
            float4 a4 = *reinterpret_cast<const float4*>(&As[kk][ty * 4]);
            float4 b4 = *reinterpret_cast<const float4*>(&Bs[kk][tx * 4]);
            float a[4] = {a4.x, a4.y, a4.z, a4.w};
            float bb[4] = {b4.x, b4.y, b4.z, b4.w};
#pragma unroll
            for (int i = 0; i < 4; i++)
#pragma unroll
                for (int j = 0; j < 4; j++) acc[i][j] += a[i] * bb[j];
        }
        __syncthreads();
    }

#pragma unroll
    for (int i = 0; i < 4; i++) {
        int m = m0 + ty * 4 + i;
        if (m >= M) continue;
#pragma unroll
        for (int j = 0; j < 4; j++) {
            int n = n0 + tx * 4 + j;
            if (n >= N) continue;
            float v = acc[i][j];
            if (bias) v += bias[n];
            if (GELU) v = 0.5f * v * (1.f + erff(v * 0.70710678118654752f));
            if (res) v += res[(size_t)m * N + n];
            C[(size_t)m * N + n] = v;
        }
    }
}

// ---------------- LayerNorm: one block per row (768 = 3*256) ----------------
__global__ void ln_kernel(const float* __restrict__ X, const float* __restrict__ w,
                          const float* __restrict__ b, float* __restrict__ Y,
                          int row_mul) {
    int row_in = blockIdx.x * row_mul;
    int row_out = blockIdx.x;
    int tid = threadIdx.x;
    const float* xr = X + (size_t)row_in * DD;

    float v0 = xr[tid], v1 = xr[tid + 256], v2 = xr[tid + 512];
    float s = v0 + v1 + v2;
    float q = v0 * v0 + v1 * v1 + v2 * v2;

    int lane = tid & 31, warp = tid >> 5;
#pragma unroll
    for (int off = 16; off; off >>= 1) {
        s += __shfl_down_sync(0xffffffffu, s, off);
        q += __shfl_down_sync(0xffffffffu, q, off);
    }
    __shared__ float sa[8], sb[8];
    if (lane == 0) { sa[warp] = s; sb[warp] = q; }
    __syncthreads();
    if (warp == 0) {
        s = (lane < 8) ? sa[lane] : 0.f;
        q = (lane < 8) ? sb[lane] : 0.f;
#pragma unroll
        for (int off = 4; off; off >>= 1) {
            s += __shfl_down_sync(0xffffffffu, s, off);
            q += __shfl_down_sync(0xffffffffu, q, off);
        }
        if (lane == 0) { sa[0] = s; sb[0] = q; }
    }
    __syncthreads();
    float mean = sa[0] * (1.f / DD);
    float var = sb[0] * (1.f / DD) - mean * mean;
    float inv = rsqrtf(var + EPS);

    float* yr = Y + (size_t)row_out * DD;
    yr[tid]       = (v0 - mean) * inv * w[tid]       + b[tid];
    yr[tid + 256] = (v1 - mean) * inv * w[tid + 256] + b[tid + 256];
    yr[tid + 512] = (v2 - mean) * inv * w[tid + 512] + b[tid + 512];
}

// ---------------- fused attention: one block per (b, head) ----------------
// qkv row layout per token: [3][12][64]; q off 0, k off 768, v off 1536
#define KVPAD 65
__global__ void attn_kernel(const float* __restrict__ qkv, float* __restrict__ out) {
    extern __shared__ float dynsm[];
    float* Ks = dynsm;                 // [171][65]
    float* Vs = dynsm + NTOK * KVPAD;  // [171][65]
    __shared__ float Qs[8][64];

    int bh = blockIdx.x;
    int b = bh / NHEAD, hh = bh % NHEAD;
    int tid = threadIdx.x;
    int lane = tid & 31, warp = tid >> 5;

    size_t base = (size_t)b * NTOK * (3 * DD) + hh * HDIM;
    for (int idx = tid; idx < NTOK * HDIM; idx += 256) {
        int t = idx >> 6, d = idx & 63;
        size_t roff = base + (size_t)t * (3 * DD) + d;
        Ks[t * KVPAD + d] = qkv[roff + DD];
        Vs[t * KVPAD + d] = qkv[roff + 2 * DD];
    }
    __syncthreads();

    for (int qrow = warp; qrow < NTOK; qrow += 8) {
        size_t qoff = base + (size_t)qrow * (3 * DD);
        __syncwarp();
        Qs[warp][lane] = qkv[qoff + lane];
        Qs[warp][lane + 32] = qkv[qoff + lane + 32];
        __syncwarp();

        // scores for keys lane + 32*i
        float sc[6];
        const float* kp[6];
#pragma unroll
        for (int i = 0; i < 6; i++) {
            int k = lane + 32 * i;
            kp[i] = Ks + (k < NTOK ? k : NTOK - 1) * KVPAD;
            sc[i] = 0.f;
        }
#pragma unroll 8
        for (int d = 0; d < HDIM; d++) {
            float qd = Qs[warp][d];
#pragma unroll
            for (int i = 0; i < 6; i++) sc[i] += qd * kp[i][d];
        }
        float mx = -INFINITY;
#pragma unroll
        for (int i = 0; i < 6; i++) {
            sc[i] = (lane + 32 * i < NTOK) ? sc[i] * 0.125f : -INFINITY;
            mx = fmaxf(mx, sc[i]);
        }
#pragma unroll
        for (int off = 16; off; off >>= 1)
            mx = fmaxf(mx, __shfl_xor_sync(0xffffffffu, mx, off));

        float p[6], sum = 0.f;
#pragma unroll
        for (int i = 0; i < 6; i++) {
            p[i] = (lane + 32 * i < NTOK) ? __expf(sc[i] - mx) : 0.f;
            sum += p[i];
        }
#pragma unroll
        for (int off = 16; off; off >>= 1)
            sum += __shfl_xor_sync(0xffffffffu, sum, off);
        float invs = 1.f / sum;

        float o0 = 0.f, o1 = 0.f;
#pragma unroll
        for (int i = 0; i < 6; i++) {
            int kb = 32 * i;
#pragma unroll
            for (int src = 0; src < 32; src++) {
                int k = kb + src;
                if (k >= NTOK) break;
                float pk = __shfl_sync(0xffffffffu, p[i], src);
                o0 += pk * Vs[k * KVPAD + lane];
                o1 += pk * Vs[k * KVPAD + lane + 32];
            }
        }
        size_t ooff = ((size_t)(b * NTOK + qrow)) * DD + hh * HDIM;
        out[ooff + lane] = o0 * invs;
        out[ooff + lane + 32] = o1 * invs;
    }
}

// ---------------- head: [64,768] @ [768,3] + b ----------------
__global__ void head_kernel(const float* __restrict__ cls, const float* __restrict__ hw,
                            const float* __restrict__ hb, float* __restrict__ out) {
    int b = blockIdx.x;
    int tid = threadIdx.x;
    float a0 = 0.f, a1 = 0.f, a2 = 0.f;
    for (int d = tid; d < DD; d += 256) {
        float v = cls[b * DD + d];
        a0 += v * hw[d * 3 + 0];
        a1 += v * hw[d * 3 + 1];
        a2 += v * hw[d * 3 + 2];
    }
    int lane = tid & 31, warp = tid >> 5;
#pragma unroll
    for (int off = 16; off; off >>= 1) {
        a0 += __shfl_down_sync(0xffffffffu, a0, off);
        a1 += __shfl_down_sync(0xffffffffu, a1, off);
        a2 += __shfl_down_sync(0xffffffffu, a2, off);
    }
    __shared__ float s0[8], s1[8], s2[8];
    if (lane == 0) { s0[warp] = a0; s1[warp] = a1; s2[warp] = a2; }
    __syncthreads();
    if (warp == 0 && lane < 8) {
        a0 = s0[lane]; a1 = s1[lane]; a2 = s2[lane];
#pragma unroll
        for (int off = 4; off; off >>= 1) {
            a0 += __shfl_down_sync(0x000000ffu, a0, off);
            a1 += __shfl_down_sync(0x000000ffu, a1, off);
            a2 += __shfl_down_sync(0x000000ffu, a2, off);
        }
        if (lane == 0) {
            out[b * 3 + 0] = a0 + hb[0];
            out[b * 3 + 1] = a1 + hb[1];
            out[b * 3 + 2] = a2 + hb[2];
        }
    }
}

// ---------------- launcher ----------------
extern "C" void kernel_launch(void* const* d_in, const int* in_sizes, int n_in,
                              void* d_out, int out_size) {
    const float* x        = (const float*)d_in[0];
    const float* conv_w   = (const float*)d_in[1];
    const float* conv_b   = (const float*)d_in[2];
    const float* cls_tok  = (const float*)d_in[3];
    const float* pos      = (const float*)d_in[4];
    const float* ln1_w    = (const float*)d_in[5];
    const float* ln1_b    = (const float*)d_in[6];
    const float* qkv_w    = (const float*)d_in[7];
    const float* qkv_b    = (const float*)d_in[8];
    const float* proj_w   = (const float*)d_in[9];
    const float* proj_b   = (const float*)d_in[10];
    const float* ln2_w    = (const float*)d_in[11];
    const float* ln2_b    = (const float*)d_in[12];
    const float* fc1_w    = (const float*)d_in[13];
    const float* fc1_b    = (const float*)d_in[14];
    const float* fc2_w    = (const float*)d_in[15];
    const float* fc2_b    = (const float*)d_in[16];
    const float* norm_w   = (const float*)d_in[17];
    const float* norm_b   = (const float*)d_in[18];
    const float* head_w   = (const float*)d_in[19];
    const float* head_b   = (const float*)d_in[20];
    float* out = (float*)d_out;

    float *col, *wt, *h, *y, *big, *clsb;
    cudaGetSymbolAddress((void**)&col, g_col);
    cudaGetSymbolAddress((void**)&wt, g_wt);
    cudaGetSymbolAddress((void**)&h, g_h);
    cudaGetSymbolAddress((void**)&y, g_y);
    cudaGetSymbolAddress((void**)&big, g_big);
    cudaGetSymbolAddress((void**)&clsb, g_cls);

    int attn_smem = 2 * NTOK * KVPAD * (int)sizeof(float);
    cudaFuncSetAttribute(attn_kernel, cudaFuncAttributeMaxDynamicSharedMemorySize, attn_smem);

    // patch embed
    im2col_kernel<<<(CROWS * KCONV + 255) / 256, 256>>>(x, col);
    transw_kernel<<<(KCONV * DD + 255) / 256, 256>>>(conv_w, wt);
    sgemm_kernel<false><<<dim3(DD / BN, CROWS / BM), 256>>>(col, wt, conv_b, nullptr, big,
                                                            CROWS, DD, KCONV);
    assemble_kernel<<<(MROWS * DD + 255) / 256, 256>>>(big, cls_tok, pos, h);

    for (int i = 0; i < DEPTH; i++) {
        const float* l_ln1w = ln1_w + (size_t)i * DD;
        const float* l_ln1b = ln1_b + (size_t)i * DD;
        const float* l_qkvw = qkv_w + (size_t)i * DD * 3 * DD;
        const float* l_qkvb = qkv_b + (size_t)i * 3 * DD;
        const float* l_projw = proj_w + (size_t)i * DD * DD;
        const float* l_projb = proj_b + (size_t)i * DD;
        const float* l_ln2w = ln2_w + (size_t)i * DD;
        const float* l_ln2b = ln2_b + (size_t)i * DD;
        const float* l_fc1w = fc1_w + (size_t)i * DD * 4 * DD;
        const float* l_fc1b = fc1_b + (size_t)i * 4 * DD;
        const float* l_fc2w = fc2_w + (size_t)i * 4 * DD * DD;
        const float* l_fc2b = fc2_b + (size_t)i * DD;

        ln_kernel<<<MROWS, 256>>>(h, l_ln1w, l_ln1b, y, 1);
        sgemm_kernel<false><<<dim3(3 * DD / BN, MROWS / BM), 256>>>(y, l_qkvw, l_qkvb, nullptr,
                                                                    big, MROWS, 3 * DD, DD);
        attn_kernel<<<BATCH * NHEAD, 256, attn_smem>>>(big, y);
        sgemm_kernel<false><<<dim3(DD / BN, MROWS / BM), 256>>>(y, l_projw, l_projb, h, h,
                                                                MROWS, DD, DD);
        ln_kernel<<<MROWS, 256>>>(h, l_ln2w, l_ln2b, y, 1);
        sgemm_kernel<true><<<dim3(4 * DD / BN, MROWS / BM), 256>>>(y, l_fc1w, l_fc1b, nullptr,
                                                                   big, MROWS, 4 * DD, DD);
        sgemm_kernel<false><<<dim3(DD / BN, MROWS / BM), 256>>>(big, l_fc2w, l_fc2b, h, h,
                                                                MROWS, DD, 4 * DD);
    }

    ln_kernel<<<BATCH, 256>>>(h, norm_w, norm_b, clsb, NTOK);
    head_kernel<<<BATCH, 256>>>(clsb, head_w, head_b, out);
}

// round 4
// speedup vs baseline: 2.0968x; 2.0968x over previous
#include <cuda_runtime.h>
#include <cuda_bf16.h>
#include <math.h>
#include <stdint.h>

// ---------------- problem constants ----------------
#define DD     768
#define NTOK   171
#define BATCH  64
#define MROWS  (BATCH*NTOK)      // 10944
#define MPAD   11008             // 86*128
#define NPATCH 170
#define CROWS  (BATCH*NPATCH)    // 10880
#define KCONV  600
#define NHEAD  12
#define HDIM   64
#define DEPTH  12
#define EPS    1e-5f

typedef __nv_bfloat16 bf16;

// ---------------- scratch (device globals) ----------------
__device__ float g_col [CROWS * KCONV];
__device__ float g_wt  [KCONV * DD];
__device__ float g_conv[CROWS * DD];
__device__ float g_h   [MROWS * DD];
__device__ float g_cls [BATCH * DD];
__device__ float g_qkvf[MPAD * 3 * DD];
__device__ bf16 g_yhi  [MPAD * DD];
__device__ bf16 g_ylo  [MPAD * DD];
__device__ bf16 g_ahi  [MPAD * DD];
__device__ bf16 g_alo  [MPAD * DD];
__device__ bf16 g_bighi[MPAD * 4 * DD];
__device__ bf16 g_biglo[MPAD * 4 * DD];
__device__ bf16 g_qkvThi[DEPTH * 3 * DD * DD];
__device__ bf16 g_qkvTlo[DEPTH * 3 * DD * DD];
__device__ bf16 g_projThi[DEPTH * DD * DD];
__device__ bf16 g_projTlo[DEPTH * DD * DD];
__device__ bf16 g_fc1Thi[DEPTH * 4 * DD * DD];
__device__ bf16 g_fc1Tlo[DEPTH * 4 * DD * DD];
__device__ bf16 g_fc2Thi[DEPTH * 4 * DD * DD];
__device__ bf16 g_fc2Tlo[DEPTH * 4 * DD * DD];

// ---------------- helpers ----------------
__device__ __forceinline__ uint32_t smem_u32(const void* p) {
    uint32_t a;
    asm("{ .reg .u64 t; cvta.to.shared.u64 t, %1; cvt.u32.u64 %0, t; }" : "=r"(a) : "l"(p));
    return a;
}
__device__ __forceinline__ void cp_async16(void* dst, const void* src) {
    asm volatile("cp.async.cg.shared.global [%0], [%1], 16;"
                 :: "r"(smem_u32(dst)), "l"(src) : "memory");
}
__device__ __forceinline__ void cp_commit() {
    asm volatile("cp.async.commit_group;" ::: "memory");
}
template <int N>
__device__ __forceinline__ void cp_wait() {
    asm volatile("cp.async.wait_group %0;" :: "n"(N) : "memory");
}
__device__ __forceinline__ void mma_bf16(float* c, const uint32_t* a, const uint32_t* b) {
    asm volatile(
        "mma.sync.aligned.m16n8k16.row.col.f32.bf16.bf16.f32 "
        "{%0,%1,%2,%3}, {%4,%5,%6,%7}, {%8,%9}, {%0,%1,%2,%3};"
        : "+f"(c[0]), "+f"(c[1]), "+f"(c[2]), "+f"(c[3])
        : "r"(a[0]), "r"(a[1]), "r"(a[2]), "r"(a[3]), "r"(b[0]), "r"(b[1]));
}
__device__ __forceinline__ void split2(float v, bf16& hi, bf16& lo) {
    hi = __float2bfloat16(v);
    lo = __float2bfloat16(v - __bfloat162float(hi));
}

// ---------------- split-bf16 HMMA GEMM: C = A @ Wt^T (~fp32 accurate) ----------------
// A = Ahi+Alo [MPAD,K], Wt = Whi+Wlo [N,K]. Tile 128x128, BK=32, 8 warps (2m x 4n).
#define GSTR 40          // smem row stride (bf16 elems) = 80B
#define TILEB (128 * GSTR * 2)      // 10240 B per tile
#define STAGEB (4 * TILEB)          // 40960 B per stage
#define SMTOT (2 * STAGEB)          // 81920 B

template <bool SPLIT_OUT, bool GELU_, bool RES>
__global__ void __launch_bounds__(256)
hmma3_gemm(const bf16* __restrict__ Ahi, const bf16* __restrict__ Alo,
           const bf16* __restrict__ Whi, const bf16* __restrict__ Wlo,
           const float* __restrict__ bias, const float* __restrict__ res,
           float* __restrict__ Cf, bf16* __restrict__ Chi, bf16* __restrict__ Clo,
           int Mvalid, int Ntot, int K) {
    extern __shared__ char dsm[];

    const int tid = threadIdx.x;
    const int lane = tid & 31, wid = tid >> 5;
    const int wm = wid & 1, wn = wid >> 1;
    const int group = lane >> 2, tq = lane & 3;
    const int m0 = blockIdx.y * 128;
    const int n0 = blockIdx.x * 128;
    const int KT = K >> 5;

    const bf16* gAh = Ahi + (size_t)m0 * K;
    const bf16* gAl = Alo + (size_t)m0 * K;
    const bf16* gBh = Whi + (size_t)n0 * K;
    const bf16* gBl = Wlo + (size_t)n0 * K;

    float acc[4][4][4];
#pragma unroll
    for (int mi = 0; mi < 4; mi++)
#pragma unroll
        for (int ni = 0; ni < 4; ni++)
#pragma unroll
            for (int q = 0; q < 4; q++) acc[mi][ni][q] = 0.f;

    const int lr = tid >> 2;      // 0..63
    const int lc = tid & 3;       // 16B chunk

    auto load_stage = [&](int kt, int st) {
        const size_t koff = (size_t)kt * 32;
        char* base = dsm + st * STAGEB;
#pragma unroll
        for (int i = 0; i < 2; i++) {
            int r = lr + i * 64;
            uint32_t so = (r * GSTR + lc * 8) * 2;
            size_t go = (size_t)r * K + koff + lc * 8;
            cp_async16(base + 0 * TILEB + so, gAh + go);
            cp_async16(base + 1 * TILEB + so, gAl + go);
            cp_async16(base + 2 * TILEB + so, gBh + go);
            cp_async16(base + 3 * TILEB + so, gBl + go);
        }
        cp_commit();
    };

    load_stage(0, 0);

    for (int kt = 0; kt < KT; kt++) {
        if (kt + 1 < KT) {
            load_stage(kt + 1, (kt + 1) & 1);
            cp_wait<1>();
        } else {
            cp_wait<0>();
        }
        __syncthreads();

        const char* base = dsm + (kt & 1) * STAGEB;
        const bf16* pAh = (const bf16*)(base + 0 * TILEB);
        const bf16* pAl = (const bf16*)(base + 1 * TILEB);
        const bf16* pBh = (const bf16*)(base + 2 * TILEB);
        const bf16* pBl = (const bf16*)(base + 3 * TILEB);

#pragma unroll
        for (int ks = 0; ks < 2; ks++) {
            const int k = ks * 16 + tq * 2;
#pragma unroll
            for (int pr = 0; pr < 3; pr++) {
                const bf16* pa = (pr == 2) ? pAl : pAh;
                const bf16* pb = (pr == 1) ? pBl : pBh;
                uint32_t af[4][4], bfr[4][2];
#pragma unroll
                for (int mi = 0; mi < 4; mi++) {
                    int r = wm * 64 + mi * 16 + group;
                    af[mi][0] = *(const uint32_t*)&pa[r * GSTR + k];
                    af[mi][1] = *(const uint32_t*)&pa[(r + 8) * GSTR + k];
                    af[mi][2] = *(const uint32_t*)&pa[r * GSTR + k + 8];
                    af[mi][3] = *(const uint32_t*)&pa[(r + 8) * GSTR + k + 8];
                }
#pragma unroll
                for (int ni = 0; ni < 4; ni++) {
                    int r = wn * 32 + ni * 8 + group;
                    bfr[ni][0] = *(const uint32_t*)&pb[r * GSTR + k];
                    bfr[ni][1] = *(const uint32_t*)&pb[r * GSTR + k + 8];
                }
#pragma unroll
                for (int mi = 0; mi < 4; mi++)
#pragma unroll
                    for (int ni = 0; ni < 4; ni++)
                        mma_bf16(acc[mi][ni], af[mi], bfr[ni]);
            }
        }
        __syncthreads();
    }

    // ---- epilogue ----
#pragma unroll
    for (int mi = 0; mi < 4; mi++) {
#pragma unroll
        for (int rr = 0; rr < 2; rr++) {
            int m = m0 + wm * 64 + mi * 16 + group + rr * 8;
            if (m >= Mvalid) continue;
#pragma unroll
            for (int ni = 0; ni < 4; ni++) {
                int n = n0 + wn * 32 + ni * 8 + tq * 2;
                float v0 = acc[mi][ni][rr * 2 + 0] + bias[n];
                float v1 = acc[mi][ni][rr * 2 + 1] + bias[n + 1];
                if (GELU_) {
                    v0 = 0.5f * v0 * (1.f + erff(v0 * 0.70710678118654752f));
                    v1 = 0.5f * v1 * (1.f + erff(v1 * 0.70710678118654752f));
                }
                if (RES) {
                    float2 rv = *(const float2*)(res + (size_t)m * Ntot + n);
                    v0 += rv.x; v1 += rv.y;
                }
                if (SPLIT_OUT) {
                    bf16 h0, l0, h1, l1;
                    split2(v0, h0, l0);
                    split2(v1, h1, l1);
                    __nv_bfloat162 hh; hh.x = h0; hh.y = h1;
                    __nv_bfloat162 ll; ll.x = l0; ll.y = l1;
                    *(__nv_bfloat162*)(Chi + (size_t)m * Ntot + n) = hh;
                    *(__nv_bfloat162*)(Clo + (size_t)m * Ntot + n) = ll;
                } else {
                    *(float2*)(Cf + (size_t)m * Ntot + n) = make_float2(v0, v1);
                }
            }
        }
    }
}

// ---------------- weight transpose + split: W[R,C] f32 -> Whi/Wlo[C,R] bf16 ----------------
__global__ void transpose_split(const float* __restrict__ W, bf16* __restrict__ Whi,
                                bf16* __restrict__ Wlo, int R, int C) {
    __shared__ float t[32][33];
    int z = blockIdx.z;
    const float* Wl = W + (size_t)z * R * C;
    bf16* Whl = Whi + (size_t)z * R * C;
    bf16* Wll = Wlo + (size_t)z * R * C;
    int c0 = blockIdx.x * 32, r0 = blockIdx.y * 32;
    int x = threadIdx.x, y = threadIdx.y;
#pragma unroll
    for (int i = 0; i < 32; i += 8)
        t[y + i][x] = Wl[(size_t)(r0 + y + i) * C + c0 + x];
    __syncthreads();
#pragma unroll
    for (int i = 0; i < 32; i += 8) {
        float v = t[x][y + i];
        bf16 hi, lo;
        split2(v, hi, lo);
        size_t o = (size_t)(c0 + y + i) * R + r0 + x;
        Whl[o] = hi;
        Wll[o] = lo;
    }
}

// ---------------- im2col / conv / assemble ----------------
__global__ void im2col_kernel(const float* __restrict__ x, float* __restrict__ col) {
    int idx = blockIdx.x * blockDim.x + threadIdx.x;
    if (idx >= CROWS * KCONV) return;
    int r = idx / KCONV, c = idx % KCONV;
    int b = r / NPATCH, p = r % NPATCH;
    int chn = c / 100, rem = c % 100;
    int kh = rem / 10, kw = rem % 10;
    int phh = p / 34, pw = p % 34;
    col[idx] = x[((b * 6 + chn) * 50 + phh * 10 + kh) * 345 + pw * 10 + kw];
}

__global__ void transw_kernel(const float* __restrict__ w, float* __restrict__ wt) {
    int idx = blockIdx.x * blockDim.x + threadIdx.x;
    if (idx >= KCONV * DD) return;
    int k = idx / DD, d = idx % DD;
    wt[idx] = w[d * KCONV + k];
}

__global__ void assemble_kernel(const float* __restrict__ conv_out,
                                const float* __restrict__ cls,
                                const float* __restrict__ pos,
                                float* __restrict__ h) {
    int idx = blockIdx.x * blockDim.x + threadIdx.x;
    if (idx >= MROWS * DD) return;
    int row = idx / DD, d = idx % DD;
    int b = row / NTOK, t = row % NTOK;
    float v = (t == 0) ? cls[d] : conv_out[(b * NPATCH + t - 1) * DD + d];
    h[idx] = v + pos[t * DD + d];
}

// ---------------- fp32 SGEMM (conv patch-embed only) ----------------
#define BM 64
#define BN 64
#define BK 16
__global__ void sgemm_kernel(const float* __restrict__ A, const float* __restrict__ B,
                             const float* __restrict__ bias, float* C, int M, int N, int K) {
    __shared__ float As[BK][BM + 4];
    __shared__ float Bs[BK][BN];
    int tid = threadIdx.x;
    int m0 = blockIdx.y * BM, n0 = blockIdx.x * BN;
    int tx = tid & 15, ty = tid >> 4;
    float acc[4][4];
#pragma unroll
    for (int i = 0; i < 4; i++)
#pragma unroll
        for (int j = 0; j < 4; j++) acc[i][j] = 0.f;
    for (int k0 = 0; k0 < K; k0 += BK) {
#pragma unroll
        for (int i = 0; i < 4; i++) {
            int idx = tid + i * 256;
            int ar = idx >> 4, ac = idx & 15;
            int gr = m0 + ar, gc = k0 + ac;
            float v = 0.f;
            if (gr < M && gc < K) v = A[(size_t)gr * K + gc];
            As[ac][ar] = v;
        }
#pragma unroll
        for (int i = 0; i < 4; i++) {
            int idx = tid + i * 256;
            int br = idx >> 6, bc = idx & 63;
            int gr = k0 + br, gc = n0 + bc;
            float v = 0.f;
            if (gr < K && gc < N) v = B[(size_t)gr * N + gc];
            Bs[br][bc] = v;
        }
        __syncthreads();
#pragma unroll
        for (int kk = 0; kk < BK; kk++) {
            float4 a4 = *reinterpret_cast<const float4*>(&As[kk][ty * 4]);
            float4 b4 = *reinterpret_cast<const float4*>(&Bs[kk][tx * 4]);
            float a[4] = {a4.x, a4.y, a4.z, a4.w};
            float bb[4] = {b4.x, b4.y, b4.z, b4.w};
#pragma unroll
            for (int i = 0; i < 4; i++)
#pragma unroll
                for (int j = 0; j < 4; j++) acc[i][j] += a[i] * bb[j];
        }
        __syncthreads();
    }
#pragma unroll
    for (int i = 0; i < 4; i++) {
        int m = m0 + ty * 4 + i;
        if (m >= M) continue;
#pragma unroll
        for (int j = 0; j < 4; j++) {
            int n = n0 + tx * 4 + j;
            if (n >= N) continue;
            C[(size_t)m * N + n] = acc[i][j] + bias[n];
        }
    }
}

// ---------------- LayerNorm fp32 -> split hi/lo bf16 ----------------
__global__ void ln_split_kernel(const float* __restrict__ X, const float* __restrict__ w,
                                const float* __restrict__ b,
                                bf16* __restrict__ Yhi, bf16* __restrict__ Ylo) {
    int row = blockIdx.x;
    int tid = threadIdx.x;
    const float* xr = X + (size_t)row * DD;
    float v0 = xr[tid], v1 = xr[tid + 256], v2 = xr[tid + 512];
    float s = v0 + v1 + v2;
    float q = v0 * v0 + v1 * v1 + v2 * v2;
    int lane = tid & 31, warp = tid >> 5;
#pragma unroll
    for (int off = 16; off; off >>= 1) {
        s += __shfl_down_sync(0xffffffffu, s, off);
        q += __shfl_down_sync(0xffffffffu, q, off);
    }
    __shared__ float sa[8], sbm[8];
    if (lane == 0) { sa[warp] = s; sbm[warp] = q; }
    __syncthreads();
    if (warp == 0) {
        s = (lane < 8) ? sa[lane] : 0.f;
        q = (lane < 8) ? sbm[lane] : 0.f;
#pragma unroll
        for (int off = 4; off; off >>= 1) {
            s += __shfl_down_sync(0xffffffffu, s, off);
            q += __shfl_down_sync(0xffffffffu, q, off);
        }
        if (lane == 0) { sa[0] = s; sbm[0] = q; }
    }
    __syncthreads();
    float mean = sa[0] * (1.f / DD);
    float var = sbm[0] * (1.f / DD) - mean * mean;
    float inv = rsqrtf(var + EPS);
#pragma unroll
    for (int i = 0; i < 3; i++) {
        int d = tid + i * 256;
        float v = (i == 0 ? v0 : (i == 1 ? v1 : v2));
        float y = (v - mean) * inv * w[d] + b[d];
        bf16 hi, lo;
        split2(y, hi, lo);
        Yhi[(size_t)row * DD + d] = hi;
        Ylo[(size_t)row * DD + d] = lo;
    }
}

// ---------------- LayerNorm fp32 -> fp32 (final, cls rows) ----------------
__global__ void ln_kernel(const float* __restrict__ X, const float* __restrict__ w,
                          const float* __restrict__ b, float* __restrict__ Y, int row_mul) {
    int row_in = blockIdx.x * row_mul;
    int row_out = blockIdx.x;
    int tid = threadIdx.x;
    const float* xr = X + (size_t)row_in * DD;
    float v0 = xr[tid], v1 = xr[tid + 256], v2 = xr[tid + 512];
    float s = v0 + v1 + v2;
    float q = v0 * v0 + v1 * v1 + v2 * v2;
    int lane = tid & 31, warp = tid >> 5;
#pragma unroll
    for (int off = 16; off; off >>= 1) {
        s += __shfl_down_sync(0xffffffffu, s, off);
        q += __shfl_down_sync(0xffffffffu, q, off);
    }
    __shared__ float sa[8], sbm[8];
    if (lane == 0) { sa[warp] = s; sbm[warp] = q; }
    __syncthreads();
    if (warp == 0) {
        s = (lane < 8) ? sa[lane] : 0.f;
        q = (lane < 8) ? sbm[lane] : 0.f;
#pragma unroll
        for (int off = 4; off; off >>= 1) {
            s += __shfl_down_sync(0xffffffffu, s, off);
            q += __shfl_down_sync(0xffffffffu, q, off);
        }
        if (lane == 0) { sa[0] = s; sbm[0] = q; }
    }
    __syncthreads();
    float mean = sa[0] * (1.f / DD);
    float var = sbm[0] * (1.f / DD) - mean * mean;
    float inv = rsqrtf(var + EPS);
    float* yr = Y + (size_t)row_out * DD;
    yr[tid]       = (v0 - mean) * inv * w[tid]       + b[tid];
    yr[tid + 256] = (v1 - mean) * inv * w[tid + 256] + b[tid + 256];
    yr[tid + 512] = (v2 - mean) * inv * w[tid + 512] + b[tid + 512];
}

// ---------------- fused attention (fp32 in, split bf16 out) ----------------
#define KVPAD 65
__global__ void attn_kernel(const float* __restrict__ qkv,
                            bf16* __restrict__ ohi, bf16* __restrict__ olo) {
    extern __shared__ float dynsm[];
    float* Ks = dynsm;
    float* Vs = Ks + NTOK * KVPAD;
    __shared__ float Qs[8][64];

    int bh = blockIdx.x;
    int b = bh / NHEAD, hh = bh % NHEAD;
    int tid = threadIdx.x;
    int lane = tid & 31, warp = tid >> 5;

    size_t base = (size_t)b * NTOK * (3 * DD) + hh * HDIM;
    for (int idx = tid; idx < NTOK * HDIM; idx += 256) {
        int t = idx >> 6, d = idx & 63;
        size_t roff = base + (size_t)t * (3 * DD) + d;
        Ks[t * KVPAD + d] = qkv[roff + DD];
        Vs[t * KVPAD + d] = qkv[roff + 2 * DD];
    }
    __syncthreads();

    for (int qrow = warp; qrow < NTOK; qrow += 8) {
        size_t qoff = base + (size_t)qrow * (3 * DD);
        __syncwarp();
        Qs[warp][lane] = qkv[qoff + lane];
        Qs[warp][lane + 32] = qkv[qoff + lane + 32];
        __syncwarp();

        float sc[6];
        const float* kp[6];
#pragma unroll
        for (int i = 0; i < 6; i++) {
            int k = lane + 32 * i;
            kp[i] = Ks + (k < NTOK ? k : NTOK - 1) * KVPAD;
            sc[i] = 0.f;
        }
#pragma unroll 8
        for (int d = 0; d < HDIM; d++) {
            float qd = Qs[warp][d];
#pragma unroll
            for (int i = 0; i < 6; i++) sc[i] += qd * kp[i][d];
        }
        float mx = -INFINITY;
#pragma unroll
        for (int i = 0; i < 6; i++) {
            sc[i] = (lane + 32 * i < NTOK) ? sc[i] * 0.125f : -INFINITY;
            mx = fmaxf(mx, sc[i]);
        }
#pragma unroll
        for (int off = 16; off; off >>= 1)
            mx = fmaxf(mx, __shfl_xor_sync(0xffffffffu, mx, off));
        float p[6], sum = 0.f;
#pragma unroll
        for (int i = 0; i < 6; i++) {
            p[i] = (lane + 32 * i < NTOK) ? __expf(sc[i] - mx) : 0.f;
            sum += p[i];
        }
#pragma unroll
        for (int off = 16; off; off >>= 1)
            sum += __shfl_xor_sync(0xffffffffu, sum, off);
        float invs = 1.f / sum;

        float o0 = 0.f, o1 = 0.f;
#pragma unroll
        for (int i = 0; i < 6; i++) {
            int kb = 32 * i;
#pragma unroll
            for (int src = 0; src < 32; src++) {
                int k = kb + src;
                if (k >= NTOK) break;
                float pk = __shfl_sync(0xffffffffu, p[i], src);
                o0 += pk * Vs[k * KVPAD + lane];
                o1 += pk * Vs[k * KVPAD + lane + 32];
            }
        }
        size_t ooff = ((size_t)(b * NTOK + qrow)) * DD + hh * HDIM;
        bf16 h0, l0, h1, l1;
        split2(o0 * invs, h0, l0);
        split2(o1 * invs, h1, l1);
        ohi[ooff + lane] = h0;
        olo[ooff + lane] = l0;
        ohi[ooff + lane + 32] = h1;
        olo[ooff + lane + 32] = l1;
    }
}

// ---------------- head ----------------
__global__ void head_kernel(const float* __restrict__ cls, const float* __restrict__ hw,
                            const float* __restrict__ hb, float* __restrict__ out) {
    int b = blockIdx.x;
    int tid = threadIdx.x;
    float a0 = 0.f, a1 = 0.f, a2 = 0.f;
    for (int d = tid; d < DD; d += 256) {
        float v = cls[b * DD + d];
        a0 += v * hw[d * 3 + 0];
        a1 += v * hw[d * 3 + 1];
        a2 += v * hw[d * 3 + 2];
    }
    int lane = tid & 31, warp = tid >> 5;
#pragma unroll
    for (int off = 16; off; off >>= 1) {
        a0 += __shfl_down_sync(0xffffffffu, a0, off);
        a1 += __shfl_down_sync(0xffffffffu, a1, off);
        a2 += __shfl_down_sync(0xffffffffu, a2, off);
    }
    __shared__ float s0[8], s1[8], s2[8];
    if (lane == 0) { s0[warp] = a0; s1[warp] = a1; s2[warp] = a2; }
    __syncthreads();
    if (warp == 0 && lane < 8) {
        a0 = s0[lane]; a1 = s1[lane]; a2 = s2[lane];
#pragma unroll
        for (int off = 4; off; off >>= 1) {
            a0 += __shfl_down_sync(0x000000ffu, a0, off);
            a1 += __shfl_down_sync(0x000000ffu, a1, off);
            a2 += __shfl_down_sync(0x000000ffu, a2, off);
        }
        if (lane == 0) {
            out[b * 3 + 0] = a0 + hb[0];
            out[b * 3 + 1] = a1 + hb[1];
            out[b * 3 + 2] = a2 + hb[2];
        }
    }
}

// ---------------- launcher ----------------
extern "C" void kernel_launch(void* const* d_in, const int* in_sizes, int n_in,
                              void* d_out, int out_size) {
    const float* x        = (const float*)d_in[0];
    const float* conv_w   = (const float*)d_in[1];
    const float* conv_b   = (const float*)d_in[2];
    const float* cls_tok  = (const float*)d_in[3];
    const float* pos      = (const float*)d_in[4];
    const float* ln1_w    = (const float*)d_in[5];
    const float* ln1_b    = (const float*)d_in[6];
    const float* qkv_w    = (const float*)d_in[7];
    const float* qkv_b    = (const float*)d_in[8];
    const float* proj_w   = (const float*)d_in[9];
    const float* proj_b   = (const float*)d_in[10];
    const float* ln2_w    = (const float*)d_in[11];
    const float* ln2_b    = (const float*)d_in[12];
    const float* fc1_w    = (const float*)d_in[13];
    const float* fc1_b    = (const float*)d_in[14];
    const float* fc2_w    = (const float*)d_in[15];
    const float* fc2_b    = (const float*)d_in[16];
    const float* norm_w   = (const float*)d_in[17];
    const float* norm_b   = (const float*)d_in[18];
    const float* head_w   = (const float*)d_in[19];
    const float* head_b   = (const float*)d_in[20];
    float* out = (float*)d_out;

    float *col, *wt, *conv, *h, *clsb, *qkvf;
    bf16 *yhi, *ylo, *ahi, *alo, *bighi, *biglo;
    bf16 *qkvThi, *qkvTlo, *projThi, *projTlo, *fc1Thi, *fc1Tlo, *fc2Thi, *fc2Tlo;
    cudaGetSymbolAddress((void**)&col, g_col);
    cudaGetSymbolAddress((void**)&wt, g_wt);
    cudaGetSymbolAddress((void**)&conv, g_conv);
    cudaGetSymbolAddress((void**)&h, g_h);
    cudaGetSymbolAddress((void**)&clsb, g_cls);
    cudaGetSymbolAddress((void**)&qkvf, g_qkvf);
    cudaGetSymbolAddress((void**)&yhi, g_yhi);
    cudaGetSymbolAddress((void**)&ylo, g_ylo);
    cudaGetSymbolAddress((void**)&ahi, g_ahi);
    cudaGetSymbolAddress((void**)&alo, g_alo);
    cudaGetSymbolAddress((void**)&bighi, g_bighi);
    cudaGetSymbolAddress((void**)&biglo, g_biglo);
    cudaGetSymbolAddress((void**)&qkvThi, g_qkvThi);
    cudaGetSymbolAddress((void**)&qkvTlo, g_qkvTlo);
    cudaGetSymbolAddress((void**)&projThi, g_projThi);
    cudaGetSymbolAddress((void**)&projTlo, g_projTlo);
    cudaGetSymbolAddress((void**)&fc1Thi, g_fc1Thi);
    cudaGetSymbolAddress((void**)&fc1Tlo, g_fc1Tlo);
    cudaGetSymbolAddress((void**)&fc2Thi, g_fc2Thi);
    cudaGetSymbolAddress((void**)&fc2Tlo, g_fc2Tlo);

    int attn_smem = 2 * NTOK * KVPAD * (int)sizeof(float);
    cudaFuncSetAttribute(attn_kernel, cudaFuncAttributeMaxDynamicSharedMemorySize, attn_smem);
    cudaFuncSetAttribute(hmma3_gemm<false, false, false>, cudaFuncAttributeMaxDynamicSharedMemorySize, SMTOT);
    cudaFuncSetAttribute(hmma3_gemm<false, false, true>, cudaFuncAttributeMaxDynamicSharedMemorySize, SMTOT);
    cudaFuncSetAttribute(hmma3_gemm<true, true, false>, cudaFuncAttributeMaxDynamicSharedMemorySize, SMTOT);

    // weight transpose + split (all layers)
    transpose_split<<<dim3(3 * DD / 32, DD / 32, DEPTH), dim3(32, 8)>>>(qkv_w, qkvThi, qkvTlo, DD, 3 * DD);
    transpose_split<<<dim3(DD / 32, DD / 32, DEPTH), dim3(32, 8)>>>(proj_w, projThi, projTlo, DD, DD);
    transpose_split<<<dim3(4 * DD / 32, DD / 32, DEPTH), dim3(32, 8)>>>(fc1_w, fc1Thi, fc1Tlo, DD, 4 * DD);
    transpose_split<<<dim3(DD / 32, 4 * DD / 32, DEPTH), dim3(32, 8)>>>(fc2_w, fc2Thi, fc2Tlo, 4 * DD, DD);

    // patch embed (fp32 exact)
    im2col_kernel<<<(CROWS * KCONV + 255) / 256, 256>>>(x, col);
    transw_kernel<<<(KCONV * DD + 255) / 256, 256>>>(conv_w, wt);
    sgemm_kernel<<<dim3(DD / BN, CROWS / BM), 256>>>(col, wt, conv_b, conv, CROWS, DD, KCONV);
    assemble_kernel<<<(MROWS * DD + 255) / 256, 256>>>(conv, cls_tok, pos, h);

    const int MT = MPAD / 128;  // 86
    for (int i = 0; i < DEPTH; i++) {
        ln_split_kernel<<<MROWS, 256>>>(h, ln1_w + (size_t)i * DD, ln1_b + (size_t)i * DD, yhi, ylo);
        hmma3_gemm<false, false, false><<<dim3(3 * DD / 128, MT), 256, SMTOT>>>(
            yhi, ylo, qkvThi + (size_t)i * 3 * DD * DD, qkvTlo + (size_t)i * 3 * DD * DD,
            qkv_b + (size_t)i * 3 * DD, nullptr, qkvf, nullptr, nullptr, MROWS, 3 * DD, DD);
        attn_kernel<<<BATCH * NHEAD, 256, attn_smem>>>(qkvf, ahi, alo);
        hmma3_gemm<false, false, true><<<dim3(DD / 128, MT), 256, SMTOT>>>(
            ahi, alo, projThi + (size_t)i * DD * DD, projTlo + (size_t)i * DD * DD,
            proj_b + (size_t)i * DD, h, h, nullptr, nullptr, MROWS, DD, DD);
        ln_split_kernel<<<MROWS, 256>>>(h, ln2_w + (size_t)i * DD, ln2_b + (size_t)i * DD, yhi, ylo);
        hmma3_gemm<true, true, false><<<dim3(4 * DD / 128, MT), 256, SMTOT>>>(
            yhi, ylo, fc1Thi + (size_t)i * 4 * DD * DD, fc1Tlo + (size_t)i * 4 * DD * DD,
            fc1_b + (size_t)i * 4 * DD, nullptr, nullptr, bighi, biglo, MROWS, 4 * DD, DD);
        hmma3_gemm<false, false, true><<<dim3(DD / 128, MT), 256, SMTOT>>>(
            bighi, biglo, fc2Thi + (size_t)i * 4 * DD * DD, fc2Tlo + (size_t)i * 4 * DD * DD,
            fc2_b + (size_t)i * DD, h, h, nullptr, nullptr, MROWS, DD, 4 * DD);
    }

    ln_kernel<<<BATCH, 256>>>(h, norm_w, norm_b, clsb, NTOK);
    head_kernel<<<BATCH, 256>>>(clsb, head_w, head_b, out);
}

// round 5
// speedup vs baseline: 2.1636x; 1.0319x over previous
#include <cuda_runtime.h>
#include <cuda_bf16.h>
#include <math.h>
#include <stdint.h>

// ---------------- problem constants ----------------
#define DD     768
#define NTOK   171
#define BATCH  64
#define MROWS  (BATCH*NTOK)      // 10944
#define MPAD   11008             // 86*128
#define NPATCH 170
#define CROWS  (BATCH*NPATCH)    // 10880
#define KCONV  600
#define NHEAD  12
#define HDIM   64
#define DEPTH  12
#define EPS    1e-5f

typedef __nv_bfloat16 bf16;

// ---------------- scratch (device globals) ----------------
__device__ float g_col [CROWS * KCONV];
__device__ float g_wt  [KCONV * DD];
__device__ float g_conv[CROWS * DD];
__device__ float g_h   [MROWS * DD];
__device__ float g_cls [BATCH * DD];
__device__ float g_qkvf[MPAD * 3 * DD];
__device__ bf16 g_yhi  [MPAD * DD];
__device__ bf16 g_ylo  [MPAD * DD];
__device__ bf16 g_ahi  [MPAD * DD];
__device__ bf16 g_alo  [MPAD * DD];
__device__ bf16 g_bighi[MPAD * 4 * DD];
__device__ bf16 g_biglo[MPAD * 4 * DD];
__device__ bf16 g_qkvThi[DEPTH * 3 * DD * DD];
__device__ bf16 g_qkvTlo[DEPTH * 3 * DD * DD];
__device__ bf16 g_projThi[DEPTH * DD * DD];
__device__ bf16 g_projTlo[DEPTH * DD * DD];
__device__ bf16 g_fc1Thi[DEPTH * 4 * DD * DD];
__device__ bf16 g_fc1Tlo[DEPTH * 4 * DD * DD];
__device__ bf16 g_fc2Thi[DEPTH * 4 * DD * DD];
__device__ bf16 g_fc2Tlo[DEPTH * 4 * DD * DD];

// ---------------- helpers ----------------
__device__ __forceinline__ uint32_t smem_u32(const void* p) {
    uint32_t a;
    asm("{ .reg .u64 t; cvta.to.shared.u64 t, %1; cvt.u32.u64 %0, t; }" : "=r"(a) : "l"(p));
    return a;
}
__device__ __forceinline__ void cp_async16(uint32_t dst, const void* src) {
    asm volatile("cp.async.cg.shared.global [%0], [%1], 16;"
                 :: "r"(dst), "l"(src) : "memory");
}
__device__ __forceinline__ void cp_commit() {
    asm volatile("cp.async.commit_group;" ::: "memory");
}
template <int N>
__device__ __forceinline__ void cp_wait() {
    asm volatile("cp.async.wait_group %0;" :: "n"(N) : "memory");
}
__device__ __forceinline__ void ldsm4(uint32_t* r, uint32_t addr) {
    asm volatile("ldmatrix.sync.aligned.m8n8.x4.shared.b16 {%0,%1,%2,%3}, [%4];"
                 : "=r"(r[0]), "=r"(r[1]), "=r"(r[2]), "=r"(r[3]) : "r"(addr));
}
__device__ __forceinline__ void mma_bf16(float* c, const uint32_t* a, const uint32_t* b) {
    asm volatile(
        "mma.sync.aligned.m16n8k16.row.col.f32.bf16.bf16.f32 "
        "{%0,%1,%2,%3}, {%4,%5,%6,%7}, {%8,%9}, {%0,%1,%2,%3};"
        : "+f"(c[0]), "+f"(c[1]), "+f"(c[2]), "+f"(c[3])
        : "r"(a[0]), "r"(a[1]), "r"(a[2]), "r"(a[3]), "r"(b[0]), "r"(b[1]));
}
__device__ __forceinline__ void split2(float v, bf16& hi, bf16& lo) {
    hi = __float2bfloat16(v);
    lo = __float2bfloat16(v - __bfloat162float(hi));
}

// ---------------- split-bf16 HMMA GEMM: C = A @ Wt^T (~fp32 accurate) ----------------
// Tile 128x128, BK=32, 8 warps (2m x 4n), 3-stage cp.async, ldmatrix fragments.
#define GSTR 40                       // smem row stride (bf16) = 80B; LDSM conflict-free
#define TILEB (128 * GSTR * 2)        // 10240 B per tile
#define STAGEB (4 * TILEB)            // 40960 B per stage (Ahi,Alo,Bhi,Blo)
#define NSTAGE 3
#define SMTOT (NSTAGE * STAGEB)       // 122880 B

template <bool SPLIT_OUT, bool GELU_, bool RES>
__global__ void __launch_bounds__(256, 1)
hmma3_gemm(const bf16* __restrict__ Ahi, const bf16* __restrict__ Alo,
           const bf16* __restrict__ Whi, const bf16* __restrict__ Wlo,
           const float* __restrict__ bias, const float* __restrict__ res,
           float* __restrict__ Cf, bf16* __restrict__ Chi, bf16* __restrict__ Clo,
           int Mvalid, int Ntot, int K) {
    extern __shared__ char dsm[];
    const uint32_t sb = smem_u32(dsm);

    const int tid = threadIdx.x;
    const int lane = tid & 31, wid = tid >> 5;
    const int wm = wid & 1, wn = wid >> 1;
    const int group = lane >> 2, tq = lane & 3;
    const int m0 = blockIdx.y * 128;
    const int n0 = blockIdx.x * 128;
    const int KT = K >> 5;

    const bf16* gAh = Ahi + (size_t)m0 * K;
    const bf16* gAl = Alo + (size_t)m0 * K;
    const bf16* gBh = Whi + (size_t)n0 * K;
    const bf16* gBl = Wlo + (size_t)n0 * K;

    float acc[4][4][4];
#pragma unroll
    for (int mi = 0; mi < 4; mi++)
#pragma unroll
        for (int ni = 0; ni < 4; ni++)
#pragma unroll
            for (int q = 0; q < 4; q++) acc[mi][ni][q] = 0.f;

    // cp.async thread mapping: 64 rows x 4 chunks, two row-halves
    const int lr = tid >> 2;
    const int lc = tid & 3;

    auto load_stage = [&](int kt, int st) {
        const size_t koff = (size_t)kt * 32;
        uint32_t base = sb + st * STAGEB;
#pragma unroll
        for (int i = 0; i < 2; i++) {
            int r = lr + i * 64;
            uint32_t so = (r * GSTR + lc * 8) * 2;
            size_t go = (size_t)r * K + koff + lc * 8;
            cp_async16(base + 0 * TILEB + so, gAh + go);
            cp_async16(base + 1 * TILEB + so, gAl + go);
            cp_async16(base + 2 * TILEB + so, gBh + go);
            cp_async16(base + 3 * TILEB + so, gBl + go);
        }
        cp_commit();
    };

    // ldmatrix per-thread base offsets (bytes, within a tile)
    const uint32_t arow = wm * 64 + (lane & 7) + ((lane >> 3) & 1) * 8;
    const uint32_t acol = (lane >> 4) * 8;
    const uint32_t aoff = (arow * GSTR + acol) * 2;
    const uint32_t brow = wn * 32 + (lane & 7) + (lane >> 4) * 8;
    const uint32_t bcol = ((lane >> 3) & 1) * 8;
    const uint32_t boff = (brow * GSTR + bcol) * 2;

    load_stage(0, 0);
    if (KT > 1) load_stage(1, 1);

    for (int kt = 0; kt < KT; kt++) {
        if (kt + 2 < KT) { load_stage(kt + 2, (kt + 2) % NSTAGE); cp_wait<2>(); }
        else if (kt + 1 < KT) { cp_wait<1>(); }
        else { cp_wait<0>(); }
        __syncthreads();

        const uint32_t stbase = sb + (kt % NSTAGE) * STAGEB;
        const uint32_t aHi = stbase + aoff;
        const uint32_t aLo = stbase + TILEB + aoff;
        const uint32_t bHi = stbase + 2 * TILEB + boff;
        const uint32_t bLo = stbase + 3 * TILEB + boff;

#pragma unroll
        for (int ks = 0; ks < 2; ks++) {
            const uint32_t kadd = ks * 32;   // 16 bf16
            uint32_t ah[16], al[16], bh[8], bl[8];
#pragma unroll
            for (int mi = 0; mi < 4; mi++) {
                ldsm4(ah + mi * 4, aHi + mi * (16 * GSTR * 2) + kadd);
                ldsm4(al + mi * 4, aLo + mi * (16 * GSTR * 2) + kadd);
            }
#pragma unroll
            for (int nj = 0; nj < 2; nj++) {
                ldsm4(bh + nj * 4, bHi + nj * (16 * GSTR * 2) + kadd);
                ldsm4(bl + nj * 4, bLo + nj * (16 * GSTR * 2) + kadd);
            }
            // pass 1: hi*hi
#pragma unroll
            for (int mi = 0; mi < 4; mi++)
#pragma unroll
                for (int ni = 0; ni < 4; ni++)
                    mma_bf16(acc[mi][ni], ah + mi * 4, bh + ni * 2);
            // pass 2: hi*lo
#pragma unroll
            for (int mi = 0; mi < 4; mi++)
#pragma unroll
                for (int ni = 0; ni < 4; ni++)
                    mma_bf16(acc[mi][ni], ah + mi * 4, bl + ni * 2);
            // pass 3: lo*hi
#pragma unroll
            for (int mi = 0; mi < 4; mi++)
#pragma unroll
                for (int ni = 0; ni < 4; ni++)
                    mma_bf16(acc[mi][ni], al + mi * 4, bh + ni * 2);
        }
        __syncthreads();
    }

    // ---- epilogue ----
#pragma unroll
    for (int mi = 0; mi < 4; mi++) {
#pragma unroll
        for (int rr = 0; rr < 2; rr++) {
            int m = m0 + wm * 64 + mi * 16 + group + rr * 8;
            if (m >= Mvalid) continue;
#pragma unroll
            for (int ni = 0; ni < 4; ni++) {
                int n = n0 + wn * 32 + ni * 8 + tq * 2;
                float v0 = acc[mi][ni][rr * 2 + 0] + bias[n];
                float v1 = acc[mi][ni][rr * 2 + 1] + bias[n + 1];
                if (GELU_) {
                    v0 = 0.5f * v0 * (1.f + erff(v0 * 0.70710678118654752f));
                    v1 = 0.5f * v1 * (1.f + erff(v1 * 0.70710678118654752f));
                }
                if (RES) {
                    float2 rv = *(const float2*)(res + (size_t)m * Ntot + n);
                    v0 += rv.x; v1 += rv.y;
                }
                if (SPLIT_OUT) {
                    bf16 h0, l0, h1, l1;
                    split2(v0, h0, l0);
                    split2(v1, h1, l1);
                    __nv_bfloat162 hh; hh.x = h0; hh.y = h1;
                    __nv_bfloat162 ll; ll.x = l0; ll.y = l1;
                    *(__nv_bfloat162*)(Chi + (size_t)m * Ntot + n) = hh;
                    *(__nv_bfloat162*)(Clo + (size_t)m * Ntot + n) = ll;
                } else {
                    *(float2*)(Cf + (size_t)m * Ntot + n) = make_float2(v0, v1);
                }
            }
        }
    }
}

// ---------------- weight transpose + split ----------------
__global__ void transpose_split(const float* __restrict__ W, bf16* __restrict__ Whi,
                                bf16* __restrict__ Wlo, int R, int C) {
    __shared__ float t[32][33];
    int z = blockIdx.z;
    const float* Wl = W + (size_t)z * R * C;
    bf16* Whl = Whi + (size_t)z * R * C;
    bf16* Wll = Wlo + (size_t)z * R * C;
    int c0 = blockIdx.x * 32, r0 = blockIdx.y * 32;
    int x = threadIdx.x, y = threadIdx.y;
#pragma unroll
    for (int i = 0; i < 32; i += 8)
        t[y + i][x] = Wl[(size_t)(r0 + y + i) * C + c0 + x];
    __syncthreads();
#pragma unroll
    for (int i = 0; i < 32; i += 8) {
        float v = t[x][y + i];
        bf16 hi, lo;
        split2(v, hi, lo);
        size_t o = (size_t)(c0 + y + i) * R + r0 + x;
        Whl[o] = hi;
        Wll[o] = lo;
    }
}

// ---------------- im2col / conv / assemble ----------------
__global__ void im2col_kernel(const float* __restrict__ x, float* __restrict__ col) {
    int idx = blockIdx.x * blockDim.x + threadIdx.x;
    if (idx >= CROWS * KCONV) return;
    int r = idx / KCONV, c = idx % KCONV;
    int b = r / NPATCH, p = r % NPATCH;
    int chn = c / 100, rem = c % 100;
    int kh = rem / 10, kw = rem % 10;
    int phh = p / 34, pw = p % 34;
    col[idx] = x[((b * 6 + chn) * 50 + phh * 10 + kh) * 345 + pw * 10 + kw];
}

__global__ void transw_kernel(const float* __restrict__ w, float* __restrict__ wt) {
    int idx = blockIdx.x * blockDim.x + threadIdx.x;
    if (idx >= KCONV * DD) return;
    int k = idx / DD, d = idx % DD;
    wt[idx] = w[d * KCONV + k];
}

__global__ void assemble_kernel(const float* __restrict__ conv_out,
                                const float* __restrict__ cls,
                                const float* __restrict__ pos,
                                float* __restrict__ h) {
    int idx = blockIdx.x * blockDim.x + threadIdx.x;
    if (idx >= MROWS * DD) return;
    int row = idx / DD, d = idx % DD;
    int b = row / NTOK, t = row % NTOK;
    float v = (t == 0) ? cls[d] : conv_out[(b * NPATCH + t - 1) * DD + d];
    h[idx] = v + pos[t * DD + d];
}

// ---------------- fp32 SGEMM (conv patch-embed only) ----------------
#define BM 64
#define BN 64
#define BK 16
__global__ void sgemm_kernel(const float* __restrict__ A, const float* __restrict__ B,
                             const float* __restrict__ bias, float* C, int M, int N, int K) {
    __shared__ float As[BK][BM + 4];
    __shared__ float Bs[BK][BN];
    int tid = threadIdx.x;
    int m0 = blockIdx.y * BM, n0 = blockIdx.x * BN;
    int tx = tid & 15, ty = tid >> 4;
    float acc[4][4];
#pragma unroll
    for (int i = 0; i < 4; i++)
#pragma unroll
        for (int j = 0; j < 4; j++) acc[i][j] = 0.f;
    for (int k0 = 0; k0 < K; k0 += BK) {
#pragma unroll
        for (int i = 0; i < 4; i++) {
            int idx = tid + i * 256;
            int ar = idx >> 4, ac = idx & 15;
            int gr = m0 + ar, gc = k0 + ac;
            float v = 0.f;
            if (gr < M && gc < K) v = A[(size_t)gr * K + gc];
            As[ac][ar] = v;
        }
#pragma unroll
        for (int i = 0; i < 4; i++) {
            int idx = tid + i * 256;
            int br = idx >> 6, bc = idx & 63;
            int gr = k0 + br, gc = n0 + bc;
            float v = 0.f;
            if (gr < K && gc < N) v = B[(size_t)gr * N + gc];
            Bs[br][bc] = v;
        }
        __syncthreads();
#pragma unroll
        for (int kk = 0; kk < BK; kk++) {
            float4 a4 = *reinterpret_cast<const float4*>(&As[kk][ty * 4]);
            float4 b4 = *reinterpret_cast<const float4*>(&Bs[kk][tx * 4]);
            float a[4] = {a4.x, a4.y, a4.z, a4.w};
            float bb[4] = {b4.x, b4.y, b4.z, b4.w};
#pragma unroll
            for (int i = 0; i < 4; i++)
#pragma unroll
                for (int j = 0; j < 4; j++) acc[i][j] += a[i] * bb[j];
        }
        __syncthreads();
    }
#pragma unroll
    for (int i = 0; i < 4; i++) {
        int m = m0 + ty * 4 + i;
        if (m >= M) continue;
#pragma unroll
        for (int j = 0; j < 4; j++) {
            int n = n0 + tx * 4 + j;
            if (n >= N) continue;
            C[(size_t)m * N + n] = acc[i][j] + bias[n];
        }
    }
}

// ---------------- LayerNorm fp32 -> split hi/lo bf16 ----------------
__global__ void ln_split_kernel(const float* __restrict__ X, const float* __restrict__ w,
                                const float* __restrict__ b,
                                bf16* __restrict__ Yhi, bf16* __restrict__ Ylo) {
    int row = blockIdx.x;
    int tid = threadIdx.x;
    const float* xr = X + (size_t)row * DD;
    float v0 = xr[tid], v1 = xr[tid + 256], v2 = xr[tid + 512];
    float s = v0 + v1 + v2;
    float q = v0 * v0 + v1 * v1 + v2 * v2;
    int lane = tid & 31, warp = tid >> 5;
#pragma unroll
    for (int off = 16; off; off >>= 1) {
        s += __shfl_down_sync(0xffffffffu, s, off);
        q += __shfl_down_sync(0xffffffffu, q, off);
    }
    __shared__ float sa[8], sbm[8];
    if (lane == 0) { sa[warp] = s; sbm[warp] = q; }
    __syncthreads();
    if (warp == 0) {
        s = (lane < 8) ? sa[lane] : 0.f;
        q = (lane < 8) ? sbm[lane] : 0.f;
#pragma unroll
        for (int off = 4; off; off >>= 1) {
            s += __shfl_down_sync(0xffffffffu, s, off);
            q += __shfl_down_sync(0xffffffffu, q, off);
        }
        if (lane == 0) { sa[0] = s; sbm[0] = q; }
    }
    __syncthreads();
    float mean = sa[0] * (1.f / DD);
    float var = sbm[0] * (1.f / DD) - mean * mean;
    float inv = rsqrtf(var + EPS);
#pragma unroll
    for (int i = 0; i < 3; i++) {
        int d = tid + i * 256;
        float v = (i == 0 ? v0 : (i == 1 ? v1 : v2));
        float y = (v - mean) * inv * w[d] + b[d];
        bf16 hi, lo;
        split2(y, hi, lo);
        Yhi[(size_t)row * DD + d] = hi;
        Ylo[(size_t)row * DD + d] = lo;
    }
}

// ---------------- LayerNorm fp32 -> fp32 (final, cls rows) ----------------
__global__ void ln_kernel(const float* __restrict__ X, const float* __restrict__ w,
                          const float* __restrict__ b, float* __restrict__ Y, int row_mul) {
    int row_in = blockIdx.x * row_mul;
    int row_out = blockIdx.x;
    int tid = threadIdx.x;
    const float* xr = X + (size_t)row_in * DD;
    float v0 = xr[tid], v1 = xr[tid + 256], v2 = xr[tid + 512];
    float s = v0 + v1 + v2;
    float q = v0 * v0 + v1 * v1 + v2 * v2;
    int lane = tid & 31, warp = tid >> 5;
#pragma unroll
    for (int off = 16; off; off >>= 1) {
        s += __shfl_down_sync(0xffffffffu, s, off);
        q += __shfl_down_sync(0xffffffffu, q, off);
    }
    __shared__ float sa[8], sbm[8];
    if (lane == 0) { sa[warp] = s; sbm[warp] = q; }
    __syncthreads();
    if (warp == 0) {
        s = (lane < 8) ? sa[lane] : 0.f;
        q = (lane < 8) ? sbm[lane] : 0.f;
#pragma unroll
        for (int off = 4; off; off >>= 1) {
            s += __shfl_down_sync(0xffffffffu, s, off);
            q += __shfl_down_sync(0xffffffffu, q, off);
        }
        if (lane == 0) { sa[0] = s; sbm[0] = q; }
    }
    __syncthreads();
    float mean = sa[0] * (1.f / DD);
    float var = sbm[0] * (1.f / DD) - mean * mean;
    float inv = rsqrtf(var + EPS);
    float* yr = Y + (size_t)row_out * DD;
    yr[tid]       = (v0 - mean) * inv * w[tid]       + b[tid];
    yr[tid + 256] = (v1 - mean) * inv * w[tid + 256] + b[tid + 256];
    yr[tid + 512] = (v2 - mean) * inv * w[tid + 512] + b[tid + 512];
}

// ---------------- fused attention (fp32 in, split bf16 out) ----------------
#define KVPAD 65
__global__ void attn_kernel(const float* __restrict__ qkv,
                            bf16* __restrict__ ohi, bf16* __restrict__ olo) {
    extern __shared__ float dynsm[];
    float* Ks = dynsm;
    float* Vs = Ks + NTOK * KVPAD;
    __shared__ float Qs[8][64];

    int bh = blockIdx.x;
    int b = bh / NHEAD, hh = bh % NHEAD;
    int tid = threadIdx.x;
    int lane = tid & 31, warp = tid >> 5;

    size_t base = (size_t)b * NTOK * (3 * DD) + hh * HDIM;
    for (int idx = tid; idx < NTOK * HDIM; idx += 256) {
        int t = idx >> 6, d = idx & 63;
        size_t roff = base + (size_t)t * (3 * DD) + d;
        Ks[t * KVPAD + d] = qkv[roff + DD];
        Vs[t * KVPAD + d] = qkv[roff + 2 * DD];
    }
    __syncthreads();

    for (int qrow = warp; qrow < NTOK; qrow += 8) {
        size_t qoff = base + (size_t)qrow * (3 * DD);
        __syncwarp();
        Qs[warp][lane] = qkv[qoff + lane];
        Qs[warp][lane + 32] = qkv[qoff + lane + 32];
        __syncwarp();

        float sc[6];
        const float* kp[6];
#pragma unroll
        for (int i = 0; i < 6; i++) {
            int k = lane + 32 * i;
            kp[i] = Ks + (k < NTOK ? k : NTOK - 1) * KVPAD;
            sc[i] = 0.f;
        }
#pragma unroll 8
        for (int d = 0; d < HDIM; d++) {
            float qd = Qs[warp][d];
#pragma unroll
            for (int i = 0; i < 6; i++) sc[i] += qd * kp[i][d];
        }
        float mx = -INFINITY;
#pragma unroll
        for (int i = 0; i < 6; i++) {
            sc[i] = (lane + 32 * i < NTOK) ? sc[i] * 0.125f : -INFINITY;
            mx = fmaxf(mx, sc[i]);
        }
#pragma unroll
        for (int off = 16; off; off >>= 1)
            mx = fmaxf(mx, __shfl_xor_sync(0xffffffffu, mx, off));
        float p[6], sum = 0.f;
#pragma unroll
        for (int i = 0; i < 6; i++) {
            p[i] = (lane + 32 * i < NTOK) ? __expf(sc[i] - mx) : 0.f;
            sum += p[i];
        }
#pragma unroll
        for (int off = 16; off; off >>= 1)
            sum += __shfl_xor_sync(0xffffffffu, sum, off);
        float invs = 1.f / sum;

        float o0 = 0.f, o1 = 0.f;
#pragma unroll
        for (int i = 0; i < 6; i++) {
            int kb = 32 * i;
#pragma unroll
            for (int src = 0; src < 32; src++) {
                int k = kb + src;
                if (k >= NTOK) break;
                float pk = __shfl_sync(0xffffffffu, p[i], src);
                o0 += pk * Vs[k * KVPAD + lane];
                o1 += pk * Vs[k * KVPAD + lane + 32];
            }
        }
        size_t ooff = ((size_t)(b * NTOK + qrow)) * DD + hh * HDIM;
        bf16 h0, l0, h1, l1;
        split2(o0 * invs, h0, l0);
        split2(o1 * invs, h1, l1);
        ohi[ooff + lane] = h0;
        olo[ooff + lane] = l0;
        ohi[ooff + lane + 32] = h1;
        olo[ooff + lane + 32] = l1;
    }
}

// ---------------- head ----------------
__global__ void head_kernel(const float* __restrict__ cls, const float* __restrict__ hw,
                            const float* __restrict__ hb, float* __restrict__ out) {
    int b = blockIdx.x;
    int tid = threadIdx.x;
    float a0 = 0.f, a1 = 0.f, a2 = 0.f;
    for (int d = tid; d < DD; d += 256) {
        float v = cls[b * DD + d];
        a0 += v * hw[d * 3 + 0];
        a1 += v * hw[d * 3 + 1];
        a2 += v * hw[d * 3 + 2];
    }
    int lane = tid & 31, warp = tid >> 5;
#pragma unroll
    for (int off = 16; off; off >>= 1) {
        a0 += __shfl_down_sync(0xffffffffu, a0, off);
        a1 += __shfl_down_sync(0xffffffffu, a1, off);
        a2 += __shfl_down_sync(0xffffffffu, a2, off);
    }
    __shared__ float s0[8], s1[8], s2[8];
    if (lane == 0) { s0[warp] = a0; s1[warp] = a1; s2[warp] = a2; }
    __syncthreads();
    if (warp == 0 && lane < 8) {
        a0 = s0[lane]; a1 = s1[lane]; a2 = s2[lane];
#pragma unroll
        for (int off = 4; off; off >>= 1) {
            a0 += __shfl_down_sync(0x000000ffu, a0, off);
            a1 += __shfl_down_sync(0x000000ffu, a1, off);
            a2 += __shfl_down_sync(0x000000ffu, a2, off);
        }
        if (lane == 0) {
            out[b * 3 + 0] = a0 + hb[0];
            out[b * 3 + 1] = a1 + hb[1];
            out[b * 3 + 2] = a2 + hb[2];
        }
    }
}

// ---------------- launcher ----------------
extern "C" void kernel_launch(void* const* d_in, const int* in_sizes, int n_in,
                              void* d_out, int out_size) {
    const float* x        = (const float*)d_in[0];
    const float* conv_w   = (const float*)d_in[1];
    const float* conv_b   = (const float*)d_in[2];
    const float* cls_tok  = (const float*)d_in[3];
    const float* pos      = (const float*)d_in[4];
    const float* ln1_w    = (const float*)d_in[5];
    const float* ln1_b    = (const float*)d_in[6];
    const float* qkv_w    = (const float*)d_in[7];
    const float* qkv_b    = (const float*)d_in[8];
    const float* proj_w   = (const float*)d_in[9];
    const float* proj_b   = (const float*)d_in[10];
    const float* ln2_w    = (const float*)d_in[11];
    const float* ln2_b    = (const float*)d_in[12];
    const float* fc1_w    = (const float*)d_in[13];
    const float* fc1_b    = (const float*)d_in[14];
    const float* fc2_w    = (const float*)d_in[15];
    const float* fc2_b    = (const float*)d_in[16];
    const float* norm_w   = (const float*)d_in[17];
    const float* norm_b   = (const float*)d_in[18];
    const float* head_w   = (const float*)d_in[19];
    const float* head_b   = (const float*)d_in[20];
    float* out = (float*)d_out;

    float *col, *wt, *conv, *h, *clsb, *qkvf;
    bf16 *yhi, *ylo, *ahi, *alo, *bighi, *biglo;
    bf16 *qkvThi, *qkvTlo, *projThi, *projTlo, *fc1Thi, *fc1Tlo, *fc2Thi, *fc2Tlo;
    cudaGetSymbolAddress((void**)&col, g_col);
    cudaGetSymbolAddress((void**)&wt, g_wt);
    cudaGetSymbolAddress((void**)&conv, g_conv);
    cudaGetSymbolAddress((void**)&h, g_h);
    cudaGetSymbolAddress((void**)&clsb, g_cls);
    cudaGetSymbolAddress((void**)&qkvf, g_qkvf);
    cudaGetSymbolAddress((void**)&yhi, g_yhi);
    cudaGetSymbolAddress((void**)&ylo, g_ylo);
    cudaGetSymbolAddress((void**)&ahi, g_ahi);
    cudaGetSymbolAddress((void**)&alo, g_alo);
    cudaGetSymbolAddress((void**)&bighi, g_bighi);
    cudaGetSymbolAddress((void**)&biglo, g_biglo);
    cudaGetSymbolAddress((void**)&qkvThi, g_qkvThi);
    cudaGetSymbolAddress((void**)&qkvTlo, g_qkvTlo);
    cudaGetSymbolAddress((void**)&projThi, g_projThi);
    cudaGetSymbolAddress((void**)&projTlo, g_projTlo);
    cudaGetSymbolAddress((void**)&fc1Thi, g_fc1Thi);
    cudaGetSymbolAddress((void**)&fc1Tlo, g_fc1Tlo);
    cudaGetSymbolAddress((void**)&fc2Thi, g_fc2Thi);
    cudaGetSymbolAddress((void**)&fc2Tlo, g_fc2Tlo);

    int attn_smem = 2 * NTOK * KVPAD * (int)sizeof(float);
    cudaFuncSetAttribute(attn_kernel, cudaFuncAttributeMaxDynamicSharedMemorySize, attn_smem);
    cudaFuncSetAttribute(hmma3_gemm<false, false, false>, cudaFuncAttributeMaxDynamicSharedMemorySize, SMTOT);
    cudaFuncSetAttribute(hmma3_gemm<false, false, true>, cudaFuncAttributeMaxDynamicSharedMemorySize, SMTOT);
    cudaFuncSetAttribute(hmma3_gemm<true, true, false>, cudaFuncAttributeMaxDynamicSharedMemorySize, SMTOT);

    // weight transpose + split (all layers)
    transpose_split<<<dim3(3 * DD / 32, DD / 32, DEPTH), dim3(32, 8)>>>(qkv_w, qkvThi, qkvTlo, DD, 3 * DD);
    transpose_split<<<dim3(DD / 32, DD / 32, DEPTH), dim3(32, 8)>>>(proj_w, projThi, projTlo, DD, DD);
    transpose_split<<<dim3(4 * DD / 32, DD / 32, DEPTH), dim3(32, 8)>>>(fc1_w, fc1Thi, fc1Tlo, DD, 4 * DD);
    transpose_split<<<dim3(DD / 32, 4 * DD / 32, DEPTH), dim3(32, 8)>>>(fc2_w, fc2Thi, fc2Tlo, 4 * DD, DD);

    // patch embed (fp32 exact)
    im2col_kernel<<<(CROWS * KCONV + 255) / 256, 256>>>(x, col);
    transw_kernel<<<(KCONV * DD + 255) / 256, 256>>>(conv_w, wt);
    sgemm_kernel<<<dim3(DD / BN, CROWS / BM), 256>>>(col, wt, conv_b, conv, CROWS, DD, KCONV);
    assemble_kernel<<<(MROWS * DD + 255) / 256, 256>>>(conv, cls_tok, pos, h);

    const int MT = MPAD / 128;  // 86
    for (int i = 0; i < DEPTH; i++) {
        ln_split_kernel<<<MROWS, 256>>>(h, ln1_w + (size_t)i * DD, ln1_b + (size_t)i * DD, yhi, ylo);
        hmma3_gemm<false, false, false><<<dim3(3 * DD / 128, MT), 256, SMTOT>>>(
            yhi, ylo, qkvThi + (size_t)i * 3 * DD * DD, qkvTlo + (size_t)i * 3 * DD * DD,
            qkv_b + (size_t)i * 3 * DD, nullptr, qkvf, nullptr, nullptr, MROWS, 3 * DD, DD);
        attn_kernel<<<BATCH * NHEAD, 256, attn_smem>>>(qkvf, ahi, alo);
        hmma3_gemm<false, false, true><<<dim3(DD / 128, MT), 256, SMTOT>>>(
            ahi, alo, projThi + (size_t)i * DD * DD, projTlo + (size_t)i * DD * DD,
            proj_b + (size_t)i * DD, h, h, nullptr, nullptr, MROWS, DD, DD);
        ln_split_kernel<<<MROWS, 256>>>(h, ln2_w + (size_t)i * DD, ln2_b + (size_t)i * DD, yhi, ylo);
        hmma3_gemm<true, true, false><<<dim3(4 * DD / 128, MT), 256, SMTOT>>>(
            yhi, ylo, fc1Thi + (size_t)i * 4 * DD * DD, fc1Tlo + (size_t)i * 4 * DD * DD,
            fc1_b + (size_t)i * 4 * DD, nullptr, nullptr, bighi, biglo, MROWS, 4 * DD, DD);
        hmma3_gemm<false, false, true><<<dim3(DD / 128, MT), 256, SMTOT>>>(
            bighi, biglo, fc2Thi + (size_t)i * 4 * DD * DD, fc2Tlo + (size_t)i * 4 * DD * DD,
            fc2_b + (size_t)i * DD, h, h, nullptr, nullptr, MROWS, DD, 4 * DD);
    }

    ln_kernel<<<BATCH, 256>>>(h, norm_w, norm_b, clsb, NTOK);
    head_kernel<<<BATCH, 256>>>(clsb, head_w, head_b, out);
}

// round 6
// speedup vs baseline: 3.0793x; 1.4232x over previous
#include <cuda_runtime.h>
#include <cuda_fp16.h>
#include <math.h>
#include <stdint.h>

// ---------------- problem constants ----------------
#define DD     768
#define NTOK   171
#define BATCH  64
#define MROWS  (BATCH*NTOK)      // 10944
#define MPAD   11008             // 86*128
#define NPATCH 170
#define CROWS  (BATCH*NPATCH)    // 10880
#define KCONV  600
#define NHEAD  12
#define HDIM   64
#define DEPTH  12
#define EPS    1e-5f

// ---------------- scratch (device globals) ----------------
__device__ float g_col [CROWS * KCONV];
__device__ float g_wt  [KCONV * DD];
__device__ float g_conv[CROWS * DD];
__device__ float g_h   [MROWS * DD];
__device__ float g_cls [BATCH * DD];
__device__ float g_qkvf[MPAD * 3 * DD];
__device__ __half g_yf   [MPAD * DD];        // LN out (fp16)
__device__ __half g_af   [MPAD * DD];        // attn out (fp16)
__device__ __half g_bigf [MPAD * 4 * DD];    // fc1 out (fp16)
__device__ __half g_qkvWh[DEPTH * 3 * DD * DD];
__device__ __half g_qkvWl[DEPTH * 3 * DD * DD];
__device__ __half g_projWh[DEPTH * DD * DD];
__device__ __half g_projWl[DEPTH * DD * DD];
__device__ __half g_fc1Wh[DEPTH * 4 * DD * DD];
__device__ __half g_fc1Wl[DEPTH * 4 * DD * DD];
__device__ __half g_fc2Wh[DEPTH * 4 * DD * DD];
__device__ __half g_fc2Wl[DEPTH * 4 * DD * DD];

// ---------------- helpers ----------------
__device__ __forceinline__ uint32_t smem_u32(const void* p) {
    uint32_t a;
    asm("{ .reg .u64 t; cvta.to.shared.u64 t, %1; cvt.u32.u64 %0, t; }" : "=r"(a) : "l"(p));
    return a;
}
__device__ __forceinline__ void cp_async16(uint32_t dst, const void* src) {
    asm volatile("cp.async.cg.shared.global [%0], [%1], 16;"
                 :: "r"(dst), "l"(src) : "memory");
}
__device__ __forceinline__ void cp_commit() {
    asm volatile("cp.async.commit_group;" ::: "memory");
}
template <int N>
__device__ __forceinline__ void cp_wait() {
    asm volatile("cp.async.wait_group %0;" :: "n"(N) : "memory");
}
__device__ __forceinline__ void ldsm4(uint32_t* r, uint32_t addr) {
    asm volatile("ldmatrix.sync.aligned.m8n8.x4.shared.b16 {%0,%1,%2,%3}, [%4];"
                 : "=r"(r[0]), "=r"(r[1]), "=r"(r[2]), "=r"(r[3]) : "r"(addr));
}
__device__ __forceinline__ void mma_f16(float* c, const uint32_t* a, const uint32_t* b) {
    asm volatile(
        "mma.sync.aligned.m16n8k16.row.col.f32.f16.f16.f32 "
        "{%0,%1,%2,%3}, {%4,%5,%6,%7}, {%8,%9}, {%0,%1,%2,%3};"
        : "+f"(c[0]), "+f"(c[1]), "+f"(c[2]), "+f"(c[3])
        : "r"(a[0]), "r"(a[1]), "r"(a[2]), "r"(a[3]), "r"(b[0]), "r"(b[1]));
}
__device__ __forceinline__ void splith(float v, __half& hi, __half& lo) {
    hi = __float2half(v);
    lo = __float2half(v - __half2float(hi));
}

// ---------------- 2-product fp16 GEMM: C = A @ (Wh+Wl)^T ----------------
// A[MPAD,K] fp16; Wh/Wl[N,K] fp16. Tile 128x128, BK=32, 8 warps (2m x 4n).
#define GSTR 40                       // smem row stride (fp16) = 80B; LDSM conflict-free
#define TILEB (128 * GSTR * 2)        // 10240 B per tile
#define STAGEB (3 * TILEB)            // 30720 B per stage (A, Wh, Wl)
#define NSTAGE 3
#define SMTOT (NSTAGE * STAGEB)       // 92160 B

template <bool OUTF16, bool GELU_, bool RES>
__global__ void __launch_bounds__(256, 1)
hmma2_gemm(const __half* __restrict__ A,
           const __half* __restrict__ Wh, const __half* __restrict__ Wl,
           const float* __restrict__ bias, const float* __restrict__ res,
           float* __restrict__ Cf, __half* __restrict__ Ch,
           int Mvalid, int Ntot, int K) {
    extern __shared__ char dsm[];
    const uint32_t sb = smem_u32(dsm);

    const int tid = threadIdx.x;
    const int lane = tid & 31, wid = tid >> 5;
    const int wm = wid & 1, wn = wid >> 1;
    const int group = lane >> 2, tq = lane & 3;
    const int m0 = blockIdx.y * 128;
    const int n0 = blockIdx.x * 128;
    const int KT = K >> 5;

    const __half* gA = A + (size_t)m0 * K;
    const __half* gWh = Wh + (size_t)n0 * K;
    const __half* gWl = Wl + (size_t)n0 * K;

    float acc[4][4][4];
#pragma unroll
    for (int mi = 0; mi < 4; mi++)
#pragma unroll
        for (int ni = 0; ni < 4; ni++)
#pragma unroll
            for (int q = 0; q < 4; q++) acc[mi][ni][q] = 0.f;

    const int lr = tid >> 2;
    const int lc = tid & 3;

    auto load_stage = [&](int kt, int st) {
        const size_t koff = (size_t)kt * 32;
        uint32_t base = sb + st * STAGEB;
#pragma unroll
        for (int i = 0; i < 2; i++) {
            int r = lr + i * 64;
            uint32_t so = (r * GSTR + lc * 8) * 2;
            size_t go = (size_t)r * K + koff + lc * 8;
            cp_async16(base + 0 * TILEB + so, gA + go);
            cp_async16(base + 1 * TILEB + so, gWh + go);
            cp_async16(base + 2 * TILEB + so, gWl + go);
        }
        cp_commit();
    };

    // ldmatrix per-thread base offsets (bytes within a tile)
    const uint32_t arow = wm * 64 + (lane & 7) + ((lane >> 3) & 1) * 8;
    const uint32_t acol = (lane >> 4) * 8;
    const uint32_t aoff = (arow * GSTR + acol) * 2;
    const uint32_t brow = wn * 32 + (lane & 7) + (lane >> 4) * 8;
    const uint32_t bcol = ((lane >> 3) & 1) * 8;
    const uint32_t boff = (brow * GSTR + bcol) * 2;

    load_stage(0, 0);
    if (KT > 1) load_stage(1, 1);

    for (int kt = 0; kt < KT; kt++) {
        if (kt + 2 < KT) { load_stage(kt + 2, (kt + 2) % NSTAGE); cp_wait<2>(); }
        else if (kt + 1 < KT) { cp_wait<1>(); }
        else { cp_wait<0>(); }
        __syncthreads();

        const uint32_t stbase = sb + (kt % NSTAGE) * STAGEB;
        const uint32_t aA = stbase + aoff;
        const uint32_t bH = stbase + 1 * TILEB + boff;
        const uint32_t bL = stbase + 2 * TILEB + boff;

#pragma unroll
        for (int ks = 0; ks < 2; ks++) {
            const uint32_t kadd = ks * 32;   // 16 fp16
            uint32_t af[16], bh[8], bl[8];
#pragma unroll
            for (int mi = 0; mi < 4; mi++)
                ldsm4(af + mi * 4, aA + mi * (16 * GSTR * 2) + kadd);
#pragma unroll
            for (int nj = 0; nj < 2; nj++) {
                ldsm4(bh + nj * 4, bH + nj * (16 * GSTR * 2) + kadd);
                ldsm4(bl + nj * 4, bL + nj * (16 * GSTR * 2) + kadd);
            }
            // pass 1: A * Wh
#pragma unroll
            for (int mi = 0; mi < 4; mi++)
#pragma unroll
                for (int ni = 0; ni < 4; ni++)
                    mma_f16(acc[mi][ni], af + mi * 4, bh + ni * 2);
            // pass 2: A * Wl
#pragma unroll
            for (int mi = 0; mi < 4; mi++)
#pragma unroll
                for (int ni = 0; ni < 4; ni++)
                    mma_f16(acc[mi][ni], af + mi * 4, bl + ni * 2);
        }
        __syncthreads();
    }

    // ---- epilogue ----
#pragma unroll
    for (int mi = 0; mi < 4; mi++) {
#pragma unroll
        for (int rr = 0; rr < 2; rr++) {
            int m = m0 + wm * 64 + mi * 16 + group + rr * 8;
            if (m >= Mvalid) continue;
#pragma unroll
            for (int ni = 0; ni < 4; ni++) {
                int n = n0 + wn * 32 + ni * 8 + tq * 2;
                float v0 = acc[mi][ni][rr * 2 + 0] + bias[n];
                float v1 = acc[mi][ni][rr * 2 + 1] + bias[n + 1];
                if (GELU_) {
                    v0 = 0.5f * v0 * (1.f + erff(v0 * 0.70710678118654752f));
                    v1 = 0.5f * v1 * (1.f + erff(v1 * 0.70710678118654752f));
                }
                if (RES) {
                    float2 rv = *(const float2*)(res + (size_t)m * Ntot + n);
                    v0 += rv.x; v1 += rv.y;
                }
                if (OUTF16) {
                    __half2 h2 = __floats2half2_rn(v0, v1);
                    *(__half2*)(Ch + (size_t)m * Ntot + n) = h2;
                } else {
                    *(float2*)(Cf + (size_t)m * Ntot + n) = make_float2(v0, v1);
                }
            }
        }
    }
}

// ---------------- weight transpose + fp16 split: W[R,C] f32 -> Wh/Wl[C,R] ----------------
__global__ void transpose_split(const float* __restrict__ W, __half* __restrict__ Wh,
                                __half* __restrict__ Wl, int R, int C) {
    __shared__ float t[32][33];
    int z = blockIdx.z;
    const float* Wz = W + (size_t)z * R * C;
    __half* Whz = Wh + (size_t)z * R * C;
    __half* Wlz = Wl + (size_t)z * R * C;
    int c0 = blockIdx.x * 32, r0 = blockIdx.y * 32;
    int x = threadIdx.x, y = threadIdx.y;
#pragma unroll
    for (int i = 0; i < 32; i += 8)
        t[y + i][x] = Wz[(size_t)(r0 + y + i) * C + c0 + x];
    __syncthreads();
#pragma unroll
    for (int i = 0; i < 32; i += 8) {
        float v = t[x][y + i];
        __half hi, lo;
        splith(v, hi, lo);
        size_t o = (size_t)(c0 + y + i) * R + r0 + x;
        Whz[o] = hi;
        Wlz[o] = lo;
    }
}

// ---------------- im2col / conv / assemble ----------------
__global__ void im2col_kernel(const float* __restrict__ x, float* __restrict__ col) {
    int idx = blockIdx.x * blockDim.x + threadIdx.x;
    if (idx >= CROWS * KCONV) return;
    int r = idx / KCONV, c = idx % KCONV;
    int b = r / NPATCH, p = r % NPATCH;
    int chn = c / 100, rem = c % 100;
    int kh = rem / 10, kw = rem % 10;
    int phh = p / 34, pw = p % 34;
    col[idx] = x[((b * 6 + chn) * 50 + phh * 10 + kh) * 345 + pw * 10 + kw];
}

__global__ void transw_kernel(const float* __restrict__ w, float* __restrict__ wt) {
    int idx = blockIdx.x * blockDim.x + threadIdx.x;
    if (idx >= KCONV * DD) return;
    int k = idx / DD, d = idx % DD;
    wt[idx] = w[d * KCONV + k];
}

__global__ void assemble_kernel(const float* __restrict__ conv_out,
                                const float* __restrict__ cls,
                                const float* __restrict__ pos,
                                float* __restrict__ h) {
    int idx = blockIdx.x * blockDim.x + threadIdx.x;
    if (idx >= MROWS * DD) return;
    int row = idx / DD, d = idx % DD;
    int b = row / NTOK, t = row % NTOK;
    float v = (t == 0) ? cls[d] : conv_out[(b * NPATCH + t - 1) * DD + d];
    h[idx] = v + pos[t * DD + d];
}

// ---------------- fp32 SGEMM (conv patch-embed only) ----------------
#define BM 64
#define BN 64
#define BK 16
__global__ void sgemm_kernel(const float* __restrict__ A, const float* __restrict__ B,
                             const float* __restrict__ bias, float* C, int M, int N, int K) {
    __shared__ float As[BK][BM + 4];
    __shared__ float Bs[BK][BN];
    int tid = threadIdx.x;
    int m0 = blockIdx.y * BM, n0 = blockIdx.x * BN;
    int tx = tid & 15, ty = tid >> 4;
    float acc[4][4];
#pragma unroll
    for (int i = 0; i < 4; i++)
#pragma unroll
        for (int j = 0; j < 4; j++) acc[i][j] = 0.f;
    for (int k0 = 0; k0 < K; k0 += BK) {
#pragma unroll
        for (int i = 0; i < 4; i++) {
            int idx = tid + i * 256;
            int ar = idx >> 4, ac = idx & 15;
            int gr = m0 + ar, gc = k0 + ac;
            float v = 0.f;
            if (gr < M && gc < K) v = A[(size_t)gr * K + gc];
            As[ac][ar] = v;
        }
#pragma unroll
        for (int i = 0; i < 4; i++) {
            int idx = tid + i * 256;
            int br = idx >> 6, bc = idx & 63;
            int gr = k0 + br, gc = n0 + bc;
            float v = 0.f;
            if (gr < K && gc < N) v = B[(size_t)gr * N + gc];
            Bs[br][bc] = v;
        }
        __syncthreads();
#pragma unroll
        for (int kk = 0; kk < BK; kk++) {
            float4 a4 = *reinterpret_cast<const float4*>(&As[kk][ty * 4]);
            float4 b4 = *reinterpret_cast<const float4*>(&Bs[kk][tx * 4]);
            float a[4] = {a4.x, a4.y, a4.z, a4.w};
            float bb[4] = {b4.x, b4.y, b4.z, b4.w};
#pragma unroll
            for (int i = 0; i < 4; i++)
#pragma unroll
                for (int j = 0; j < 4; j++) acc[i][j] += a[i] * bb[j];
        }
        __syncthreads();
    }
#pragma unroll
    for (int i = 0; i < 4; i++) {
        int m = m0 + ty * 4 + i;
        if (m >= M) continue;
#pragma unroll
        for (int j = 0; j < 4; j++) {
            int n = n0 + tx * 4 + j;
            if (n >= N) continue;
            C[(size_t)m * N + n] = acc[i][j] + bias[n];
        }
    }
}

// ---------------- LayerNorm fp32 -> fp16 ----------------
__global__ void ln_f16_kernel(const float* __restrict__ X, const float* __restrict__ w,
                              const float* __restrict__ b, __half* __restrict__ Y) {
    int row = blockIdx.x;
    int tid = threadIdx.x;
    const float* xr = X + (size_t)row * DD;
    float v0 = xr[tid], v1 = xr[tid + 256], v2 = xr[tid + 512];
    float s = v0 + v1 + v2;
    float q = v0 * v0 + v1 * v1 + v2 * v2;
    int lane = tid & 31, warp = tid >> 5;
#pragma unroll
    for (int off = 16; off; off >>= 1) {
        s += __shfl_down_sync(0xffffffffu, s, off);
        q += __shfl_down_sync(0xffffffffu, q, off);
    }
    __shared__ float sa[8], sbm[8];
    if (lane == 0) { sa[warp] = s; sbm[warp] = q; }
    __syncthreads();
    if (warp == 0) {
        s = (lane < 8) ? sa[lane] : 0.f;
        q = (lane < 8) ? sbm[lane] : 0.f;
#pragma unroll
        for (int off = 4; off; off >>= 1) {
            s += __shfl_down_sync(0xffffffffu, s, off);
            q += __shfl_down_sync(0xffffffffu, q, off);
        }
        if (lane == 0) { sa[0] = s; sbm[0] = q; }
    }
    __syncthreads();
    float mean = sa[0] * (1.f / DD);
    float var = sbm[0] * (1.f / DD) - mean * mean;
    float inv = rsqrtf(var + EPS);
    __half* yr = Y + (size_t)row * DD;
    yr[tid]       = __float2half((v0 - mean) * inv * w[tid]       + b[tid]);
    yr[tid + 256] = __float2half((v1 - mean) * inv * w[tid + 256] + b[tid + 256]);
    yr[tid + 512] = __float2half((v2 - mean) * inv * w[tid + 512] + b[tid + 512]);
}

// ---------------- LayerNorm fp32 -> fp32 (final, cls rows) ----------------
__global__ void ln_kernel(const float* __restrict__ X, const float* __restrict__ w,
                          const float* __restrict__ b, float* __restrict__ Y, int row_mul) {
    int row_in = blockIdx.x * row_mul;
    int row_out = blockIdx.x;
    int tid = threadIdx.x;
    const float* xr = X + (size_t)row_in * DD;
    float v0 = xr[tid], v1 = xr[tid + 256], v2 = xr[tid + 512];
    float s = v0 + v1 + v2;
    float q = v0 * v0 + v1 * v1 + v2 * v2;
    int lane = tid & 31, warp = tid >> 5;
#pragma unroll
    for (int off = 16; off; off >>= 1) {
        s += __shfl_down_sync(0xffffffffu, s, off);
        q += __shfl_down_sync(0xffffffffu, q, off);
    }
    __shared__ float sa[8], sbm[8];
    if (lane == 0) { sa[warp] = s; sbm[warp] = q; }
    __syncthreads();
    if (warp == 0) {
        s = (lane < 8) ? sa[lane] : 0.f;
        q = (lane < 8) ? sbm[lane] : 0.f;
#pragma unroll
        for (int off = 4; off; off >>= 1) {
            s += __shfl_down_sync(0xffffffffu, s, off);
            q += __shfl_down_sync(0xffffffffu, q, off);
        }
        if (lane == 0) { sa[0] = s; sbm[0] = q; }
    }
    __syncthreads();
    float mean = sa[0] * (1.f / DD);
    float var = sbm[0] * (1.f / DD) - mean * mean;
    float inv = rsqrtf(var + EPS);
    float* yr = Y + (size_t)row_out * DD;
    yr[tid]       = (v0 - mean) * inv * w[tid]       + b[tid];
    yr[tid + 256] = (v1 - mean) * inv * w[tid + 256] + b[tid + 256];
    yr[tid + 512] = (v2 - mean) * inv * w[tid + 512] + b[tid + 512];
}

// ---------------- fused attention (fp32 in, fp16 out) ----------------
#define KVPAD 65
__global__ void attn_kernel(const float* __restrict__ qkv, __half* __restrict__ out) {
    extern __shared__ float dynsm[];
    float* Ks = dynsm;
    float* Vs = Ks + NTOK * KVPAD;
    __shared__ float Qs[8][64];

    int bh = blockIdx.x;
    int b = bh / NHEAD, hh = bh % NHEAD;
    int tid = threadIdx.x;
    int lane = tid & 31, warp = tid >> 5;

    size_t base = (size_t)b * NTOK * (3 * DD) + hh * HDIM;
    for (int idx = tid; idx < NTOK * HDIM; idx += 256) {
        int t = idx >> 6, d = idx & 63;
        size_t roff = base + (size_t)t * (3 * DD) + d;
        Ks[t * KVPAD + d] = qkv[roff + DD];
        Vs[t * KVPAD + d] = qkv[roff + 2 * DD];
    }
    __syncthreads();

    for (int qrow = warp; qrow < NTOK; qrow += 8) {
        size_t qoff = base + (size_t)qrow * (3 * DD);
        __syncwarp();
        Qs[warp][lane] = qkv[qoff + lane];
        Qs[warp][lane + 32] = qkv[qoff + lane + 32];
        __syncwarp();

        float sc[6];
        const float* kp[6];
#pragma unroll
        for (int i = 0; i < 6; i++) {
            int k = lane + 32 * i;
            kp[i] = Ks + (k < NTOK ? k : NTOK - 1) * KVPAD;
            sc[i] = 0.f;
        }
#pragma unroll 8
        for (int d = 0; d < HDIM; d++) {
            float qd = Qs[warp][d];
#pragma unroll
            for (int i = 0; i < 6; i++) sc[i] += qd * kp[i][d];
        }
        float mx = -INFINITY;
#pragma unroll
        for (int i = 0; i < 6; i++) {
            sc[i] = (lane + 32 * i < NTOK) ? sc[i] * 0.125f : -INFINITY;
            mx = fmaxf(mx, sc[i]);
        }
#pragma unroll
        for (int off = 16; off; off >>= 1)
            mx = fmaxf(mx, __shfl_xor_sync(0xffffffffu, mx, off));
        float p[6], sum = 0.f;
#pragma unroll
        for (int i = 0; i < 6; i++) {
            p[i] = (lane + 32 * i < NTOK) ? __expf(sc[i] - mx) : 0.f;
            sum += p[i];
        }
#pragma unroll
        for (int off = 16; off; off >>= 1)
            sum += __shfl_xor_sync(0xffffffffu, sum, off);
        float invs = 1.f / sum;

        float o0 = 0.f, o1 = 0.f;
#pragma unroll
        for (int i = 0; i < 6; i++) {
            int kb = 32 * i;
#pragma unroll
            for (int src = 0; src < 32; src++) {
                int k = kb + src;
                if (k >= NTOK) break;
                float pk = __shfl_sync(0xffffffffu, p[i], src);
                o0 += pk * Vs[k * KVPAD + lane];
                o1 += pk * Vs[k * KVPAD + lane + 32];
            }
        }
        size_t ooff = ((size_t)(b * NTOK + qrow)) * DD + hh * HDIM;
        out[ooff + lane] = __float2half(o0 * invs);
        out[ooff + lane + 32] = __float2half(o1 * invs);
    }
}

// ---------------- head ----------------
__global__ void head_kernel(const float* __restrict__ cls, const float* __restrict__ hw,
                            const float* __restrict__ hb, float* __restrict__ out) {
    int b = blockIdx.x;
    int tid = threadIdx.x;
    float a0 = 0.f, a1 = 0.f, a2 = 0.f;
    for (int d = tid; d < DD; d += 256) {
        float v = cls[b * DD + d];
        a0 += v * hw[d * 3 + 0];
        a1 += v * hw[d * 3 + 1];
        a2 += v * hw[d * 3 + 2];
    }
    int lane = tid & 31, warp = tid >> 5;
#pragma unroll
    for (int off = 16; off; off >>= 1) {
        a0 += __shfl_down_sync(0xffffffffu, a0, off);
        a1 += __shfl_down_sync(0xffffffffu, a1, off);
        a2 += __shfl_down_sync(0xffffffffu, a2, off);
    }
    __shared__ float s0[8], s1[8], s2[8];
    if (lane == 0) { s0[warp] = a0; s1[warp] = a1; s2[warp] = a2; }
    __syncthreads();
    if (warp == 0 && lane < 8) {
        a0 = s0[lane]; a1 = s1[lane]; a2 = s2[lane];
#pragma unroll
        for (int off = 4; off; off >>= 1) {
            a0 += __shfl_down_sync(0x000000ffu, a0, off);
            a1 += __shfl_down_sync(0x000000ffu, a1, off);
            a2 += __shfl_down_sync(0x000000ffu, a2, off);
        }
        if (lane == 0) {
            out[b * 3 + 0] = a0 + hb[0];
            out[b * 3 + 1] = a1 + hb[1];
            out[b * 3 + 2] = a2 + hb[2];
        }
    }
}

// ---------------- launcher ----------------
extern "C" void kernel_launch(void* const* d_in, const int* in_sizes, int n_in,
                              void* d_out, int out_size) {
    const float* x        = (const float*)d_in[0];
    const float* conv_w   = (const float*)d_in[1];
    const float* conv_b   = (const float*)d_in[2];
    const float* cls_tok  = (const float*)d_in[3];
    const float* pos      = (const float*)d_in[4];
    const float* ln1_w    = (const float*)d_in[5];
    const float* ln1_b    = (const float*)d_in[6];
    const float* qkv_w    = (const float*)d_in[7];
    const float* qkv_b    = (const float*)d_in[8];
    const float* proj_w   = (const float*)d_in[9];
    const float* proj_b   = (const float*)d_in[10];
    const float* ln2_w    = (const float*)d_in[11];
    const float* ln2_b    = (const float*)d_in[12];
    const float* fc1_w    = (const float*)d_in[13];
    const float* fc1_b    = (const float*)d_in[14];
    const float* fc2_w    = (const float*)d_in[15];
    const float* fc2_b    = (const float*)d_in[16];
    const float* norm_w   = (const float*)d_in[17];
    const float* norm_b   = (const float*)d_in[18];
    const float* head_w   = (const float*)d_in[19];
    const float* head_b   = (const float*)d_in[20];
    float* out = (float*)d_out;

    float *col, *wt, *conv, *h, *clsb, *qkvf;
    __half *yf, *af, *bigf;
    __half *qkvWh, *qkvWl, *projWh, *projWl, *fc1Wh, *fc1Wl, *fc2Wh, *fc2Wl;
    cudaGetSymbolAddress((void**)&col, g_col);
    cudaGetSymbolAddress((void**)&wt, g_wt);
    cudaGetSymbolAddress((void**)&conv, g_conv);
    cudaGetSymbolAddress((void**)&h, g_h);
    cudaGetSymbolAddress((void**)&clsb, g_cls);
    cudaGetSymbolAddress((void**)&qkvf, g_qkvf);
    cudaGetSymbolAddress((void**)&yf, g_yf);
    cudaGetSymbolAddress((void**)&af, g_af);
    cudaGetSymbolAddress((void**)&bigf, g_bigf);
    cudaGetSymbolAddress((void**)&qkvWh, g_qkvWh);
    cudaGetSymbolAddress((void**)&qkvWl, g_qkvWl);
    cudaGetSymbolAddress((void**)&projWh, g_projWh);
    cudaGetSymbolAddress((void**)&projWl, g_projWl);
    cudaGetSymbolAddress((void**)&fc1Wh, g_fc1Wh);
    cudaGetSymbolAddress((void**)&fc1Wl, g_fc1Wl);
    cudaGetSymbolAddress((void**)&fc2Wh, g_fc2Wh);
    cudaGetSymbolAddress((void**)&fc2Wl, g_fc2Wl);

    int attn_smem = 2 * NTOK * KVPAD * (int)sizeof(float);
    cudaFuncSetAttribute(attn_kernel, cudaFuncAttributeMaxDynamicSharedMemorySize, attn_smem);
    cudaFuncSetAttribute(hmma2_gemm<false, false, false>, cudaFuncAttributeMaxDynamicSharedMemorySize, SMTOT);
    cudaFuncSetAttribute(hmma2_gemm<false, false, true>, cudaFuncAttributeMaxDynamicSharedMemorySize, SMTOT);
    cudaFuncSetAttribute(hmma2_gemm<true, true, false>, cudaFuncAttributeMaxDynamicSharedMemorySize, SMTOT);

    // weight transpose + fp16 split (all layers)
    transpose_split<<<dim3(3 * DD / 32, DD / 32, DEPTH), dim3(32, 8)>>>(qkv_w, qkvWh, qkvWl, DD, 3 * DD);
    transpose_split<<<dim3(DD / 32, DD / 32, DEPTH), dim3(32, 8)>>>(proj_w, projWh, projWl, DD, DD);
    transpose_split<<<dim3(4 * DD / 32, DD / 32, DEPTH), dim3(32, 8)>>>(fc1_w, fc1Wh, fc1Wl, DD, 4 * DD);
    transpose_split<<<dim3(DD / 32, 4 * DD / 32, DEPTH), dim3(32, 8)>>>(fc2_w, fc2Wh, fc2Wl, 4 * DD, DD);

    // patch embed (fp32 exact)
    im2col_kernel<<<(CROWS * KCONV + 255) / 256, 256>>>(x, col);
    transw_kernel<<<(KCONV * DD + 255) / 256, 256>>>(conv_w, wt);
    sgemm_kernel<<<dim3(DD / BN, CROWS / BM), 256>>>(col, wt, conv_b, conv, CROWS, DD, KCONV);
    assemble_kernel<<<(MROWS * DD + 255) / 256, 256>>>(conv, cls_tok, pos, h);

    const int MT = MPAD / 128;  // 86
    for (int i = 0; i < DEPTH; i++) {
        ln_f16_kernel<<<MROWS, 256>>>(h, ln1_w + (size_t)i * DD, ln1_b + (size_t)i * DD, yf);
        hmma2_gemm<false, false, false><<<dim3(3 * DD / 128, MT), 256, SMTOT>>>(
            yf, qkvWh + (size_t)i * 3 * DD * DD, qkvWl + (size_t)i * 3 * DD * DD,
            qkv_b + (size_t)i * 3 * DD, nullptr, qkvf, nullptr, MROWS, 3 * DD, DD);
        attn_kernel<<<BATCH * NHEAD, 256, attn_smem>>>(qkvf, af);
        hmma2_gemm<false, false, true><<<dim3(DD / 128, MT), 256, SMTOT>>>(
            af, projWh + (size_t)i * DD * DD, projWl + (size_t)i * DD * DD,
            proj_b + (size_t)i * DD, h, h, nullptr, MROWS, DD, DD);
        ln_f16_kernel<<<MROWS, 256>>>(h, ln2_w + (size_t)i * DD, ln2_b + (size_t)i * DD, yf);
        hmma2_gemm<true, true, false><<<dim3(4 * DD / 128, MT), 256, SMTOT>>>(
            yf, fc1Wh + (size_t)i * 4 * DD * DD, fc1Wl + (size_t)i * 4 * DD * DD,
            fc1_b + (size_t)i * 4 * DD, nullptr, nullptr, bigf, MROWS, 4 * DD, DD);
        hmma2_gemm<false, false, true><<<dim3(DD / 128, MT), 256, SMTOT>>>(
            bigf, fc2Wh + (size_t)i * 4 * DD * DD, fc2Wl + (size_t)i * 4 * DD * DD,
            fc2_b + (size_t)i * DD, h, h, nullptr, MROWS, DD, 4 * DD);
    }

    ln_kernel<<<BATCH, 256>>>(h, norm_w, norm_b, clsb, NTOK);
    head_kernel<<<BATCH, 256>>>(clsb, head_w, head_b, out);
}

// round 7
// speedup vs baseline: 4.1638x; 1.3522x over previous
#include <cuda_runtime.h>
#include <cuda_fp16.h>
#include <math.h>
#include <stdint.h>

// ---------------- problem constants ----------------
#define DD     768
#define NTOK   171
#define BATCH  64
#define MROWS  (BATCH*NTOK)      // 10944
#define MPAD   11008             // 86*128
#define NPATCH 170
#define CROWS  (BATCH*NPATCH)    // 10880
#define KCONV  600
#define NHEAD  12
#define HDIM   64
#define DEPTH  12
#define EPS    1e-5f

// ---------------- scratch (device globals) ----------------
__device__ float g_col [CROWS * KCONV];
__device__ float g_wt  [KCONV * DD];
__device__ float g_conv[CROWS * DD];
__device__ float g_h   [MROWS * DD];
__device__ float g_cls [BATCH * DD];
__device__ float g_qkvf[MPAD * 3 * DD];
__device__ __half g_yf   [MPAD * DD];        // LN out (fp16)
__device__ __half g_af   [MPAD * DD];        // attn out (fp16)
__device__ __half g_bigf [MPAD * 4 * DD];    // fc1 out (fp16)
__device__ __half g_qkvWh[DEPTH * 3 * DD * DD];
__device__ __half g_qkvWl[DEPTH * 3 * DD * DD];
__device__ __half g_projWh[DEPTH * DD * DD];
__device__ __half g_projWl[DEPTH * DD * DD];
__device__ __half g_fc1Wh[DEPTH * 4 * DD * DD];
__device__ __half g_fc1Wl[DEPTH * 4 * DD * DD];
__device__ __half g_fc2Wh[DEPTH * 4 * DD * DD];
__device__ __half g_fc2Wl[DEPTH * 4 * DD * DD];

// ---------------- helpers ----------------
__device__ __forceinline__ uint32_t smem_u32(const void* p) {
    uint32_t a;
    asm("{ .reg .u64 t; cvta.to.shared.u64 t, %1; cvt.u32.u64 %0, t; }" : "=r"(a) : "l"(p));
    return a;
}
__device__ __forceinline__ void cp_async16(uint32_t dst, const void* src) {
    asm volatile("cp.async.cg.shared.global [%0], [%1], 16;"
                 :: "r"(dst), "l"(src) : "memory");
}
__device__ __forceinline__ void cp_commit() {
    asm volatile("cp.async.commit_group;" ::: "memory");
}
template <int N>
__device__ __forceinline__ void cp_wait() {
    asm volatile("cp.async.wait_group %0;" :: "n"(N) : "memory");
}
__device__ __forceinline__ void ldsm4(uint32_t* r, uint32_t addr) {
    asm volatile("ldmatrix.sync.aligned.m8n8.x4.shared.b16 {%0,%1,%2,%3}, [%4];"
                 : "=r"(r[0]), "=r"(r[1]), "=r"(r[2]), "=r"(r[3]) : "r"(addr));
}
__device__ __forceinline__ void mma_f16(float* c, const uint32_t* a, const uint32_t* b) {
    asm volatile(
        "mma.sync.aligned.m16n8k16.row.col.f32.f16.f16.f32 "
        "{%0,%1,%2,%3}, {%4,%5,%6,%7}, {%8,%9}, {%0,%1,%2,%3};"
        : "+f"(c[0]), "+f"(c[1]), "+f"(c[2]), "+f"(c[3])
        : "r"(a[0]), "r"(a[1]), "r"(a[2]), "r"(a[3]), "r"(b[0]), "r"(b[1]));
}
__device__ __forceinline__ void splith(float v, __half& hi, __half& lo) {
    hi = __float2half(v);
    lo = __float2half(v - __half2float(hi));
}
__device__ __forceinline__ uint32_t pack_h2(float a, float b) {
    __half2 h = __floats2half2_rn(a, b);
    return *(uint32_t*)&h;
}

// ---------------- 2-product fp16 GEMM: C = A @ (Wh+Wl)^T ----------------
#define GSTR 40
#define TILEB (128 * GSTR * 2)
#define STAGEB (3 * TILEB)
#define NSTAGE 3
#define SMTOT (NSTAGE * STAGEB)

template <bool OUTF16, bool GELU_, bool RES>
__global__ void __launch_bounds__(256, 1)
hmma2_gemm(const __half* __restrict__ A,
           const __half* __restrict__ Wh, const __half* __restrict__ Wl,
           const float* __restrict__ bias, const float* __restrict__ res,
           float* __restrict__ Cf, __half* __restrict__ Ch,
           int Mvalid, int Ntot, int K) {
    extern __shared__ char dsm[];
    const uint32_t sb = smem_u32(dsm);

    const int tid = threadIdx.x;
    const int lane = tid & 31, wid = tid >> 5;
    const int wm = wid & 1, wn = wid >> 1;
    const int group = lane >> 2, tq = lane & 3;
    const int m0 = blockIdx.y * 128;
    const int n0 = blockIdx.x * 128;
    const int KT = K >> 5;

    const __half* gA = A + (size_t)m0 * K;
    const __half* gWh = Wh + (size_t)n0 * K;
    const __half* gWl = Wl + (size_t)n0 * K;

    float acc[4][4][4];
#pragma unroll
    for (int mi = 0; mi < 4; mi++)
#pragma unroll
        for (int ni = 0; ni < 4; ni++)
#pragma unroll
            for (int q = 0; q < 4; q++) acc[mi][ni][q] = 0.f;

    const int lr = tid >> 2;
    const int lc = tid & 3;

    auto load_stage = [&](int kt, int st) {
        const size_t koff = (size_t)kt * 32;
        uint32_t base = sb + st * STAGEB;
#pragma unroll
        for (int i = 0; i < 2; i++) {
            int r = lr + i * 64;
            uint32_t so = (r * GSTR + lc * 8) * 2;
            size_t go = (size_t)r * K + koff + lc * 8;
            cp_async16(base + 0 * TILEB + so, gA + go);
            cp_async16(base + 1 * TILEB + so, gWh + go);
            cp_async16(base + 2 * TILEB + so, gWl + go);
        }
        cp_commit();
    };

    const uint32_t arow = wm * 64 + (lane & 7) + ((lane >> 3) & 1) * 8;
    const uint32_t acol = (lane >> 4) * 8;
    const uint32_t aoff = (arow * GSTR + acol) * 2;
    const uint32_t brow = wn * 32 + (lane & 7) + (lane >> 4) * 8;
    const uint32_t bcol = ((lane >> 3) & 1) * 8;
    const uint32_t boff = (brow * GSTR + bcol) * 2;

    load_stage(0, 0);
    if (KT > 1) load_stage(1, 1);

    for (int kt = 0; kt < KT; kt++) {
        if (kt + 2 < KT) { load_stage(kt + 2, (kt + 2) % NSTAGE); cp_wait<2>(); }
        else if (kt + 1 < KT) { cp_wait<1>(); }
        else { cp_wait<0>(); }
        __syncthreads();

        const uint32_t stbase = sb + (kt % NSTAGE) * STAGEB;
        const uint32_t aA = stbase + aoff;
        const uint32_t bH = stbase + 1 * TILEB + boff;
        const uint32_t bL = stbase + 2 * TILEB + boff;

#pragma unroll
        for (int ks = 0; ks < 2; ks++) {
            const uint32_t kadd = ks * 32;
            uint32_t af[16], bh[8], bl[8];
#pragma unroll
            for (int mi = 0; mi < 4; mi++)
                ldsm4(af + mi * 4, aA + mi * (16 * GSTR * 2) + kadd);
#pragma unroll
            for (int nj = 0; nj < 2; nj++) {
                ldsm4(bh + nj * 4, bH + nj * (16 * GSTR * 2) + kadd);
                ldsm4(bl + nj * 4, bL + nj * (16 * GSTR * 2) + kadd);
            }
#pragma unroll
            for (int mi = 0; mi < 4; mi++)
#pragma unroll
                for (int ni = 0; ni < 4; ni++)
                    mma_f16(acc[mi][ni], af + mi * 4, bh + ni * 2);
#pragma unroll
            for (int mi = 0; mi < 4; mi++)
#pragma unroll
                for (int ni = 0; ni < 4; ni++)
                    mma_f16(acc[mi][ni], af + mi * 4, bl + ni * 2);
        }
        __syncthreads();
    }

#pragma unroll
    for (int mi = 0; mi < 4; mi++) {
#pragma unroll
        for (int rr = 0; rr < 2; rr++) {
            int m = m0 + wm * 64 + mi * 16 + group + rr * 8;
            if (m >= Mvalid) continue;
#pragma unroll
            for (int ni = 0; ni < 4; ni++) {
                int n = n0 + wn * 32 + ni * 8 + tq * 2;
                float v0 = acc[mi][ni][rr * 2 + 0] + bias[n];
                float v1 = acc[mi][ni][rr * 2 + 1] + bias[n + 1];
                if (GELU_) {
                    v0 = 0.5f * v0 * (1.f + erff(v0 * 0.70710678118654752f));
                    v1 = 0.5f * v1 * (1.f + erff(v1 * 0.70710678118654752f));
                }
                if (RES) {
                    float2 rv = *(const float2*)(res + (size_t)m * Ntot + n);
                    v0 += rv.x; v1 += rv.y;
                }
                if (OUTF16) {
                    __half2 h2 = __floats2half2_rn(v0, v1);
                    *(__half2*)(Ch + (size_t)m * Ntot + n) = h2;
                } else {
                    *(float2*)(Cf + (size_t)m * Ntot + n) = make_float2(v0, v1);
                }
            }
        }
    }
}

// ---------------- weight transpose + fp16 split ----------------
__global__ void transpose_split(const float* __restrict__ W, __half* __restrict__ Wh,
                                __half* __restrict__ Wl, int R, int C) {
    __shared__ float t[32][33];
    int z = blockIdx.z;
    const float* Wz = W + (size_t)z * R * C;
    __half* Whz = Wh + (size_t)z * R * C;
    __half* Wlz = Wl + (size_t)z * R * C;
    int c0 = blockIdx.x * 32, r0 = blockIdx.y * 32;
    int x = threadIdx.x, y = threadIdx.y;
#pragma unroll
    for (int i = 0; i < 32; i += 8)
        t[y + i][x] = Wz[(size_t)(r0 + y + i) * C + c0 + x];
    __syncthreads();
#pragma unroll
    for (int i = 0; i < 32; i += 8) {
        float v = t[x][y + i];
        __half hi, lo;
        splith(v, hi, lo);
        size_t o = (size_t)(c0 + y + i) * R + r0 + x;
        Whz[o] = hi;
        Wlz[o] = lo;
    }
}

// ---------------- im2col / conv / assemble ----------------
__global__ void im2col_kernel(const float* __restrict__ x, float* __restrict__ col) {
    int idx = blockIdx.x * blockDim.x + threadIdx.x;
    if (idx >= CROWS * KCONV) return;
    int r = idx / KCONV, c = idx % KCONV;
    int b = r / NPATCH, p = r % NPATCH;
    int chn = c / 100, rem = c % 100;
    int kh = rem / 10, kw = rem % 10;
    int phh = p / 34, pw = p % 34;
    col[idx] = x[((b * 6 + chn) * 50 + phh * 10 + kh) * 345 + pw * 10 + kw];
}

__global__ void transw_kernel(const float* __restrict__ w, float* __restrict__ wt) {
    int idx = blockIdx.x * blockDim.x + threadIdx.x;
    if (idx >= KCONV * DD) return;
    int k = idx / DD, d = idx % DD;
    wt[idx] = w[d * KCONV + k];
}

__global__ void assemble_kernel(const float* __restrict__ conv_out,
                                const float* __restrict__ cls,
                                const float* __restrict__ pos,
                                float* __restrict__ h) {
    int idx = blockIdx.x * blockDim.x + threadIdx.x;
    if (idx >= MROWS * DD) return;
    int row = idx / DD, d = idx % DD;
    int b = row / NTOK, t = row % NTOK;
    float v = (t == 0) ? cls[d] : conv_out[(b * NPATCH + t - 1) * DD + d];
    h[idx] = v + pos[t * DD + d];
}

// ---------------- fp32 SGEMM (conv patch-embed only) ----------------
#define BM 64
#define BN 64
#define BK 16
__global__ void sgemm_kernel(const float* __restrict__ A, const float* __restrict__ B,
                             const float* __restrict__ bias, float* C, int M, int N, int K) {
    __shared__ float As[BK][BM + 4];
    __shared__ float Bs[BK][BN];
    int tid = threadIdx.x;
    int m0 = blockIdx.y * BM, n0 = blockIdx.x * BN;
    int tx = tid & 15, ty = tid >> 4;
    float acc[4][4];
#pragma unroll
    for (int i = 0; i < 4; i++)
#pragma unroll
        for (int j = 0; j < 4; j++) acc[i][j] = 0.f;
    for (int k0 = 0; k0 < K; k0 += BK) {
#pragma unroll
        for (int i = 0; i < 4; i++) {
            int idx = tid + i * 256;
            int ar = idx >> 4, ac = idx & 15;
            int gr = m0 + ar, gc = k0 + ac;
            float v = 0.f;
            if (gr < M && gc < K) v = A[(size_t)gr * K + gc];
            As[ac][ar] = v;
        }
#pragma unroll
        for (int i = 0; i < 4; i++) {
            int idx = tid + i * 256;
            int br = idx >> 6, bc = idx & 63;
            int gr = k0 + br, gc = n0 + bc;
            float v = 0.f;
            if (gr < K && gc < N) v = B[(size_t)gr * N + gc];
            Bs[br][bc] = v;
        }
        __syncthreads();
#pragma unroll
        for (int kk = 0; kk < BK; kk++) {
            float4 a4 = *reinterpret_cast<const float4*>(&As[kk][ty * 4]);
            float4 b4 = *reinterpret_cast<const float4*>(&Bs[kk][tx * 4]);
            float a[4] = {a4.x, a4.y, a4.z, a4.w};
            float bb[4] = {b4.x, b4.y, b4.z, b4.w};
#pragma unroll
            for (int i = 0; i < 4; i++)
#pragma unroll
                for (int j = 0; j < 4; j++) acc[i][j] += a[i] * bb[j];
        }
        __syncthreads();
    }
#pragma unroll
    for (int i = 0; i < 4; i++) {
        int m = m0 + ty * 4 + i;
        if (m >= M) continue;
#pragma unroll
        for (int j = 0; j < 4; j++) {
            int n = n0 + tx * 4 + j;
            if (n >= N) continue;
            C[(size_t)m * N + n] = acc[i][j] + bias[n];
        }
    }
}

// ---------------- LayerNorm fp32 -> fp16 ----------------
__global__ void ln_f16_kernel(const float* __restrict__ X, const float* __restrict__ w,
                              const float* __restrict__ b, __half* __restrict__ Y) {
    int row = blockIdx.x;
    int tid = threadIdx.x;
    const float* xr = X + (size_t)row * DD;
    float v0 = xr[tid], v1 = xr[tid + 256], v2 = xr[tid + 512];
    float s = v0 + v1 + v2;
    float q = v0 * v0 + v1 * v1 + v2 * v2;
    int lane = tid & 31, warp = tid >> 5;
#pragma unroll
    for (int off = 16; off; off >>= 1) {
        s += __shfl_down_sync(0xffffffffu, s, off);
        q += __shfl_down_sync(0xffffffffu, q, off);
    }
    __shared__ float sa[8], sbm[8];
    if (lane == 0) { sa[warp] = s; sbm[warp] = q; }
    __syncthreads();
    if (warp == 0) {
        s = (lane < 8) ? sa[lane] : 0.f;
        q = (lane < 8) ? sbm[lane] : 0.f;
#pragma unroll
        for (int off = 4; off; off >>= 1) {
            s += __shfl_down_sync(0xffffffffu, s, off);
            q += __shfl_down_sync(0xffffffffu, q, off);
        }
        if (lane == 0) { sa[0] = s; sbm[0] = q; }
    }
    __syncthreads();
    float mean = sa[0] * (1.f / DD);
    float var = sbm[0] * (1.f / DD) - mean * mean;
    float inv = rsqrtf(var + EPS);
    __half* yr = Y + (size_t)row * DD;
    yr[tid]       = __float2half((v0 - mean) * inv * w[tid]       + b[tid]);
    yr[tid + 256] = __float2half((v1 - mean) * inv * w[tid + 256] + b[tid + 256]);
    yr[tid + 512] = __float2half((v2 - mean) * inv * w[tid + 512] + b[tid + 512]);
}

// ---------------- LayerNorm fp32 -> fp32 (final, cls rows) ----------------
__global__ void ln_kernel(const float* __restrict__ X, const float* __restrict__ w,
                          const float* __restrict__ b, float* __restrict__ Y, int row_mul) {
    int row_in = blockIdx.x * row_mul;
    int row_out = blockIdx.x;
    int tid = threadIdx.x;
    const float* xr = X + (size_t)row_in * DD;
    float v0 = xr[tid], v1 = xr[tid + 256], v2 = xr[tid + 512];
    float s = v0 + v1 + v2;
    float q = v0 * v0 + v1 * v1 + v2 * v2;
    int lane = tid & 31, warp = tid >> 5;
#pragma unroll
    for (int off = 16; off; off >>= 1) {
        s += __shfl_down_sync(0xffffffffu, s, off);
        q += __shfl_down_sync(0xffffffffu, q, off);
    }
    __shared__ float sa[8], sbm[8];
    if (lane == 0) { sa[warp] = s; sbm[warp] = q; }
    __syncthreads();
    if (warp == 0) {
        s = (lane < 8) ? sa[lane] : 0.f;
        q = (lane < 8) ? sbm[lane] : 0.f;
#pragma unroll
        for (int off = 4; off; off >>= 1) {
            s += __shfl_down_sync(0xffffffffu, s, off);
            q += __shfl_down_sync(0xffffffffu, q, off);
        }
        if (lane == 0) { sa[0] = s; sbm[0] = q; }
    }
    __syncthreads();
    float mean = sa[0] * (1.f / DD);
    float var = sbm[0] * (1.f / DD) - mean * mean;
    float inv = rsqrtf(var + EPS);
    float* yr = Y + (size_t)row_out * DD;
    yr[tid]       = (v0 - mean) * inv * w[tid]       + b[tid];
    yr[tid + 256] = (v1 - mean) * inv * w[tid + 256] + b[tid + 256];
    yr[tid + 512] = (v2 - mean) * inv * w[tid + 512] + b[tid + 512];
}

// ---------------- MMA attention: one block per (b, head) ----------------
// Q=Qh+Ql, K=Kh+Kl, V=Vh+Vl (fp16 splits of fp32), P=Ph+Pl in regs.
// S = QhKh+QlKh+QhKl; O = PhVh+PlVh+PhVl. Effectively fp32-exact.
#define NTOKP 176
#define ASTR 72          // Q/K row stride (fp16 elems), 144B: ldsm conflict-free
#define VSTR 184         // Vt row stride, 368B: ldsm conflict-free
#define SA_QH 0
#define SA_QL (SA_QH + NTOKP*ASTR*2)
#define SA_KH (SA_QL + NTOKP*ASTR*2)
#define SA_KL (SA_KH + NTOKP*ASTR*2)
#define SA_VH (SA_KL + NTOKP*ASTR*2)
#define SA_VL (SA_VH + 64*VSTR*2)
#define ATTN_SMEM (SA_VL + 64*VSTR*2)   // 148480 B

__global__ void __launch_bounds__(256, 1)
attn_mma_kernel(const float* __restrict__ qkv, __half* __restrict__ out) {
    extern __shared__ char asmem[];
    const uint32_t sb = smem_u32(asmem);
    __half* QH = (__half*)(asmem + SA_QH);
    __half* QL = (__half*)(asmem + SA_QL);
    __half* KH = (__half*)(asmem + SA_KH);
    __half* KL = (__half*)(asmem + SA_KL);
    __half* VH = (__half*)(asmem + SA_VH);
    __half* VL = (__half*)(asmem + SA_VL);

    const int bh = blockIdx.x;
    const int b = bh / NHEAD, hh = bh % NHEAD;
    const int tid = threadIdx.x;
    const int lane = tid & 31, wid = tid >> 5;
    const int group = lane >> 2, tq = lane & 3;
    const size_t base = (size_t)b * NTOK * (3 * DD) + hh * HDIM;

    // ---- fill smem (split fp16) ----
    for (int idx = tid; idx < NTOKP * 64; idx += 256) {
        int row = idx >> 6, d = idx & 63;
        float qv = 0.f, kv = 0.f, vv = 0.f;
        if (row < NTOK) {
            size_t o = base + (size_t)row * (3 * DD) + d;
            qv = qkv[o]; kv = qkv[o + DD]; vv = qkv[o + 2 * DD];
        }
        __half h, l;
        splith(qv, h, l); QH[row * ASTR + d] = h; QL[row * ASTR + d] = l;
        splith(kv, h, l); KH[row * ASTR + d] = h; KL[row * ASTR + d] = l;
        splith(vv, h, l); VH[d * VSTR + row] = h; VL[d * VSTR + row] = l;
    }
    __syncthreads();

    // fragment addressing lanes
    const uint32_t a_r = (lane & 7) + ((lane >> 3) & 1) * 8;  // A: row in m16
    const uint32_t a_c = (lane >> 4) * 8;                     // A: col in k16
    const uint32_t b_r = (lane & 7) + (lane >> 4) * 8;        // B: row in n16
    const uint32_t b_c = ((lane >> 3) & 1) * 8;               // B: col in k16

    // 11 m16 tiles (176 rows); warp w handles tiles w, w+8
    for (int t = wid; t < 11; t += 8) {
        const int m0 = t * 16;

        // Q fragments for 4 k16 steps
        uint32_t aq[4][4], aql[4][4];
#pragma unroll
        for (int k = 0; k < 4; k++) {
            uint32_t off = ((m0 + a_r) * ASTR + a_c + k * 16) * 2;
            ldsm4(aq[k], sb + SA_QH + off);
            ldsm4(aql[k], sb + SA_QL + off);
        }

        // ---- S = Q K^T (3-product) ----
        float s[22][4];
#pragma unroll
        for (int j = 0; j < 22; j++)
#pragma unroll
            for (int q = 0; q < 4; q++) s[j][q] = 0.f;

#pragma unroll
        for (int nj = 0; nj < 11; nj++) {
            const int n0 = nj * 16;
#pragma unroll
            for (int k = 0; k < 4; k++) {
                uint32_t bkh[4], bkl[4];
                uint32_t off = ((n0 + b_r) * ASTR + b_c + k * 16) * 2;
                ldsm4(bkh, sb + SA_KH + off);
                ldsm4(bkl, sb + SA_KL + off);
                mma_f16(s[2 * nj],     aq[k],  bkh);
                mma_f16(s[2 * nj + 1], aq[k],  bkh + 2);
                mma_f16(s[2 * nj],     aql[k], bkh);
                mma_f16(s[2 * nj + 1], aql[k], bkh + 2);
                mma_f16(s[2 * nj],     aq[k],  bkl);
                mma_f16(s[2 * nj + 1], aq[k],  bkl + 2);
            }
        }

        // mask cols >= NTOK (tile 21 covers cols 168..175)
        {
            int c0 = 168 + tq * 2;
            if (c0 >= NTOK)     { s[21][0] = -1e30f; s[21][2] = -1e30f; }
            if (c0 + 1 >= NTOK) { s[21][1] = -1e30f; s[21][3] = -1e30f; }
        }

        // ---- softmax (rows group, group+8) ----
        float mx0 = -1e30f, mx1 = -1e30f;
#pragma unroll
        for (int j = 0; j < 22; j++) {
            mx0 = fmaxf(mx0, fmaxf(s[j][0], s[j][1]));
            mx1 = fmaxf(mx1, fmaxf(s[j][2], s[j][3]));
        }
        mx0 = fmaxf(mx0, __shfl_xor_sync(0xffffffffu, mx0, 1));
        mx0 = fmaxf(mx0, __shfl_xor_sync(0xffffffffu, mx0, 2));
        mx1 = fmaxf(mx1, __shfl_xor_sync(0xffffffffu, mx1, 1));
        mx1 = fmaxf(mx1, __shfl_xor_sync(0xffffffffu, mx1, 2));

        float rs0 = 0.f, rs1 = 0.f;
#pragma unroll
        for (int j = 0; j < 22; j++) {
            s[j][0] = __expf((s[j][0] - mx0) * 0.125f);
            s[j][1] = __expf((s[j][1] - mx0) * 0.125f);
            s[j][2] = __expf((s[j][2] - mx1) * 0.125f);
            s[j][3] = __expf((s[j][3] - mx1) * 0.125f);
            rs0 += s[j][0] + s[j][1];
            rs1 += s[j][2] + s[j][3];
        }
        rs0 += __shfl_xor_sync(0xffffffffu, rs0, 1);
        rs0 += __shfl_xor_sync(0xffffffffu, rs0, 2);
        rs1 += __shfl_xor_sync(0xffffffffu, rs1, 1);
        rs1 += __shfl_xor_sync(0xffffffffu, rs1, 2);

        // ---- O = P V (3-product, P split in regs) ----
        float o[8][4];
#pragma unroll
        for (int j = 0; j < 8; j++)
#pragma unroll
            for (int q = 0; q < 4; q++) o[j][q] = 0.f;

#pragma unroll
        for (int kt = 0; kt < 11; kt++) {
            uint32_t ap[4], apl[4];
#pragma unroll
            for (int half = 0; half < 2; half++) {
                const float* sv = s[2 * kt + half];
                __half h0 = __float2half(sv[0]), h1 = __float2half(sv[1]);
                __half h2v = __float2half(sv[2]), h3 = __float2half(sv[3]);
                ap[2 * half]     = pack_h2(__half2float(h0), __half2float(h1));
                ap[2 * half + 1] = pack_h2(__half2float(h2v), __half2float(h3));
                // rebuild exact hi then residual
                apl[2 * half]     = pack_h2(sv[0] - __half2float(h0), sv[1] - __half2float(h1));
                apl[2 * half + 1] = pack_h2(sv[2] - __half2float(h2v), sv[3] - __half2float(h3));
            }
#pragma unroll
            for (int dj = 0; dj < 4; dj++) {
                const int d0 = dj * 16;
                uint32_t bvh[4], bvl[4];
                uint32_t off = ((d0 + b_r) * VSTR + b_c + kt * 16) * 2;
                ldsm4(bvh, sb + SA_VH + off);
                ldsm4(bvl, sb + SA_VL + off);
                mma_f16(o[2 * dj],     ap,  bvh);
                mma_f16(o[2 * dj + 1], ap,  bvh + 2);
                mma_f16(o[2 * dj],     apl, bvh);
                mma_f16(o[2 * dj + 1], apl, bvh + 2);
                mma_f16(o[2 * dj],     ap,  bvl);
                mma_f16(o[2 * dj + 1], ap,  bvl + 2);
            }
        }

        // ---- store ----
        const float i0 = 1.f / rs0, i1 = 1.f / rs1;
        const int r0 = m0 + group, r1 = r0 + 8;
#pragma unroll
        for (int j = 0; j < 8; j++) {
            int d = 8 * j + tq * 2;
            if (r0 < NTOK) {
                __half2 hv = __floats2half2_rn(o[j][0] * i0, o[j][1] * i0);
                *(__half2*)(out + (size_t)(b * NTOK + r0) * DD + hh * HDIM + d) = hv;
            }
            if (r1 < NTOK) {
                __half2 hv = __floats2half2_rn(o[j][2] * i1, o[j][3] * i1);
                *(__half2*)(out + (size_t)(b * NTOK + r1) * DD + hh * HDIM + d) = hv;
            }
        }
    }
}

// ---------------- head ----------------
__global__ void head_kernel(const float* __restrict__ cls, const float* __restrict__ hw,
                            const float* __restrict__ hb, float* __restrict__ out) {
    int b = blockIdx.x;
    int tid = threadIdx.x;
    float a0 = 0.f, a1 = 0.f, a2 = 0.f;
    for (int d = tid; d < DD; d += 256) {
        float v = cls[b * DD + d];
        a0 += v * hw[d * 3 + 0];
        a1 += v * hw[d * 3 + 1];
        a2 += v * hw[d * 3 + 2];
    }
    int lane = tid & 31, warp = tid >> 5;
#pragma unroll
    for (int off = 16; off; off >>= 1) {
        a0 += __shfl_down_sync(0xffffffffu, a0, off);
        a1 += __shfl_down_sync(0xffffffffu, a1, off);
        a2 += __shfl_down_sync(0xffffffffu, a2, off);
    }
    __shared__ float s0[8], s1[8], s2[8];
    if (lane == 0) { s0[warp] = a0; s1[warp] = a1; s2[warp] = a2; }
    __syncthreads();
    if (warp == 0 && lane < 8) {
        a0 = s0[lane]; a1 = s1[lane]; a2 = s2[lane];
#pragma unroll
        for (int off = 4; off; off >>= 1) {
            a0 += __shfl_down_sync(0x000000ffu, a0, off);
            a1 += __shfl_down_sync(0x000000ffu, a1, off);
            a2 += __shfl_down_sync(0x000000ffu, a2, off);
        }
        if (lane == 0) {
            out[b * 3 + 0] = a0 + hb[0];
            out[b * 3 + 1] = a1 + hb[1];
            out[b * 3 + 2] = a2 + hb[2];
        }
    }
}

// ---------------- launcher ----------------
extern "C" void kernel_launch(void* const* d_in, const int* in_sizes, int n_in,
                              void* d_out, int out_size) {
    const float* x        = (const float*)d_in[0];
    const float* conv_w   = (const float*)d_in[1];
    const float* conv_b   = (const float*)d_in[2];
    const float* cls_tok  = (const float*)d_in[3];
    const float* pos      = (const float*)d_in[4];
    const float* ln1_w    = (const float*)d_in[5];
    const float* ln1_b    = (const float*)d_in[6];
    const float* qkv_w    = (const float*)d_in[7];
    const float* qkv_b    = (const float*)d_in[8];
    const float* proj_w   = (const float*)d_in[9];
    const float* proj_b   = (const float*)d_in[10];
    const float* ln2_w    = (const float*)d_in[11];
    const float* ln2_b    = (const float*)d_in[12];
    const float* fc1_w    = (const float*)d_in[13];
    const float* fc1_b    = (const float*)d_in[14];
    const float* fc2_w    = (const float*)d_in[15];
    const float* fc2_b    = (const float*)d_in[16];
    const float* norm_w   = (const float*)d_in[17];
    const float* norm_b   = (const float*)d_in[18];
    const float* head_w   = (const float*)d_in[19];
    const float* head_b   = (const float*)d_in[20];
    float* out = (float*)d_out;

    float *col, *wt, *conv, *h, *clsb, *qkvf;
    __half *yf, *af, *bigf;
    __half *qkvWh, *qkvWl, *projWh, *projWl, *fc1Wh, *fc1Wl, *fc2Wh, *fc2Wl;
    cudaGetSymbolAddress((void**)&col, g_col);
    cudaGetSymbolAddress((void**)&wt, g_wt);
    cudaGetSymbolAddress((void**)&conv, g_conv);
    cudaGetSymbolAddress((void**)&h, g_h);
    cudaGetSymbolAddress((void**)&clsb, g_cls);
    cudaGetSymbolAddress((void**)&qkvf, g_qkvf);
    cudaGetSymbolAddress((void**)&yf, g_yf);
    cudaGetSymbolAddress((void**)&af, g_af);
    cudaGetSymbolAddress((void**)&bigf, g_bigf);
    cudaGetSymbolAddress((void**)&qkvWh, g_qkvWh);
    cudaGetSymbolAddress((void**)&qkvWl, g_qkvWl);
    cudaGetSymbolAddress((void**)&projWh, g_projWh);
    cudaGetSymbolAddress((void**)&projWl, g_projWl);
    cudaGetSymbolAddress((void**)&fc1Wh, g_fc1Wh);
    cudaGetSymbolAddress((void**)&fc1Wl, g_fc1Wl);
    cudaGetSymbolAddress((void**)&fc2Wh, g_fc2Wh);
    cudaGetSymbolAddress((void**)&fc2Wl, g_fc2Wl);

    cudaFuncSetAttribute(attn_mma_kernel, cudaFuncAttributeMaxDynamicSharedMemorySize, ATTN_SMEM);
    cudaFuncSetAttribute(hmma2_gemm<false, false, false>, cudaFuncAttributeMaxDynamicSharedMemorySize, SMTOT);
    cudaFuncSetAttribute(hmma2_gemm<false, false, true>, cudaFuncAttributeMaxDynamicSharedMemorySize, SMTOT);
    cudaFuncSetAttribute(hmma2_gemm<true, true, false>, cudaFuncAttributeMaxDynamicSharedMemorySize, SMTOT);

    // weight transpose + fp16 split (all layers)
    transpose_split<<<dim3(3 * DD / 32, DD / 32, DEPTH), dim3(32, 8)>>>(qkv_w, qkvWh, qkvWl, DD, 3 * DD);
    transpose_split<<<dim3(DD / 32, DD / 32, DEPTH), dim3(32, 8)>>>(proj_w, projWh, projWl, DD, DD);
    transpose_split<<<dim3(4 * DD / 32, DD / 32, DEPTH), dim3(32, 8)>>>(fc1_w, fc1Wh, fc1Wl, DD, 4 * DD);
    transpose_split<<<dim3(DD / 32, 4 * DD / 32, DEPTH), dim3(32, 8)>>>(fc2_w, fc2Wh, fc2Wl, 4 * DD, DD);

    // patch embed (fp32 exact)
    im2col_kernel<<<(CROWS * KCONV + 255) / 256, 256>>>(x, col);
    transw_kernel<<<(KCONV * DD + 255) / 256, 256>>>(conv_w, wt);
    sgemm_kernel<<<dim3(DD / BN, CROWS / BM), 256>>>(col, wt, conv_b, conv, CROWS, DD, KCONV);
    assemble_kernel<<<(MROWS * DD + 255) / 256, 256>>>(conv, cls_tok, pos, h);

    const int MT = MPAD / 128;  // 86
    for (int i = 0; i < DEPTH; i++) {
        ln_f16_kernel<<<MROWS, 256>>>(h, ln1_w + (size_t)i * DD, ln1_b + (size_t)i * DD, yf);
        hmma2_gemm<false, false, false><<<dim3(3 * DD / 128, MT), 256, SMTOT>>>(
            yf, qkvWh + (size_t)i * 3 * DD * DD, qkvWl + (size_t)i * 3 * DD * DD,
            qkv_b + (size_t)i * 3 * DD, nullptr, qkvf, nullptr, MROWS, 3 * DD, DD);
        attn_mma_kernel<<<BATCH * NHEAD, 256, ATTN_SMEM>>>(qkvf, af);
        hmma2_gemm<false, false, true><<<dim3(DD / 128, MT), 256, SMTOT>>>(
            af, projWh + (size_t)i * DD * DD, projWl + (size_t)i * DD * DD,
            proj_b + (size_t)i * DD, h, h, nullptr, MROWS, DD, DD);
        ln_f16_kernel<<<MROWS, 256>>>(h, ln2_w + (size_t)i * DD, ln2_b + (size_t)i * DD, yf);
        hmma2_gemm<true, true, false><<<dim3(4 * DD / 128, MT), 256, SMTOT>>>(
            yf, fc1Wh + (size_t)i * 4 * DD * DD, fc1Wl + (size_t)i * 4 * DD * DD,
            fc1_b + (size_t)i * 4 * DD, nullptr, nullptr, bigf, MROWS, 4 * DD, DD);
        hmma2_gemm<false, false, true><<<dim3(DD / 128, MT), 256, SMTOT>>>(
            bigf, fc2Wh + (size_t)i * 4 * DD * DD, fc2Wl + (size_t)i * 4 * DD * DD,
            fc2_b + (size_t)i * DD, h, h, nullptr, MROWS, DD, 4 * DD);
    }

    ln_kernel<<<BATCH, 256>>>(h, norm_w, norm_b, clsb, NTOK);
    head_kernel<<<BATCH, 256>>>(clsb, head_w, head_b, out);
}

// round 8
// speedup vs baseline: 4.8742x; 1.1706x over previous
#include <cuda_runtime.h>
#include <cuda_fp16.h>
#include <math.h>
#include <stdint.h>

// ---------------- problem constants ----------------
#define DD     768
#define NTOK   171
#define BATCH  64
#define MROWS  (BATCH*NTOK)      // 10944
#define MPAD   11008             // 86*128
#define NPATCH 170
#define CROWS  (BATCH*NPATCH)    // 10880
#define KCONV  600
#define NHEAD  12
#define HDIM   64
#define DEPTH  12
#define EPS    1e-5f

// ---------------- scratch (device globals) ----------------
__device__ float g_col [CROWS * KCONV];
__device__ float g_wt  [KCONV * DD];
__device__ float g_conv[CROWS * DD];
__device__ float g_h   [MROWS * DD];
__device__ float g_cls [BATCH * DD];
__device__ float g_qkvf[MPAD * 3 * DD];
__device__ __half g_yf   [MPAD * DD];
__device__ __half g_af   [MPAD * DD];
__device__ __half g_bigf [MPAD * 4 * DD];
__device__ __half g_qkvWh[DEPTH * 3 * DD * DD];
__device__ __half g_qkvWl[DEPTH * 3 * DD * DD];
__device__ __half g_projWh[DEPTH * DD * DD];
__device__ __half g_projWl[DEPTH * DD * DD];
__device__ __half g_fc1Wh[DEPTH * 4 * DD * DD];
__device__ __half g_fc1Wl[DEPTH * 4 * DD * DD];
__device__ __half g_fc2Wh[DEPTH * 4 * DD * DD];
__device__ __half g_fc2Wl[DEPTH * 4 * DD * DD];

// ---------------- helpers ----------------
__device__ __forceinline__ uint32_t smem_u32(const void* p) {
    uint32_t a;
    asm("{ .reg .u64 t; cvta.to.shared.u64 t, %1; cvt.u32.u64 %0, t; }" : "=r"(a) : "l"(p));
    return a;
}
__device__ __forceinline__ void cp_async16(uint32_t dst, const void* src) {
    asm volatile("cp.async.cg.shared.global [%0], [%1], 16;"
                 :: "r"(dst), "l"(src) : "memory");
}
__device__ __forceinline__ void cp_commit() {
    asm volatile("cp.async.commit_group;" ::: "memory");
}
template <int N>
__device__ __forceinline__ void cp_wait() {
    asm volatile("cp.async.wait_group %0;" :: "n"(N) : "memory");
}
__device__ __forceinline__ void ldsm4(uint32_t* r, uint32_t addr) {
    asm volatile("ldmatrix.sync.aligned.m8n8.x4.shared.b16 {%0,%1,%2,%3}, [%4];"
                 : "=r"(r[0]), "=r"(r[1]), "=r"(r[2]), "=r"(r[3]) : "r"(addr));
}
__device__ __forceinline__ void mma_f16(float* c, const uint32_t* a, const uint32_t* b) {
    asm volatile(
        "mma.sync.aligned.m16n8k16.row.col.f32.f16.f16.f32 "
        "{%0,%1,%2,%3}, {%4,%5,%6,%7}, {%8,%9}, {%0,%1,%2,%3};"
        : "+f"(c[0]), "+f"(c[1]), "+f"(c[2]), "+f"(c[3])
        : "r"(a[0]), "r"(a[1]), "r"(a[2]), "r"(a[3]), "r"(b[0]), "r"(b[1]));
}
__device__ __forceinline__ void splith(float v, __half& hi, __half& lo) {
    hi = __float2half(v);
    lo = __float2half(v - __half2float(hi));
}
__device__ __forceinline__ uint32_t pack_h2(float a, float b) {
    __half2 h = __floats2half2_rn(a, b);
    return *(uint32_t*)&h;
}

// ---------------- fp16 GEMM: C = A @ W^T (TWO: W = Wh + Wl, 2 products) ----------------
#define GSTR 40
#define TILEB (128 * GSTR * 2)
#define SMTOT1 (4 * 2 * TILEB)   // single product: 4 stages x 2 tiles = 81920
#define SMTOT2 (3 * 3 * TILEB)   // two products:  3 stages x 3 tiles = 92160

template <bool TWO, bool OUTF16, bool GELU_, bool RES>
__global__ void __launch_bounds__(256, 1)
hmma_gemm(const __half* __restrict__ A,
          const __half* __restrict__ Wh, const __half* __restrict__ Wl,
          const float* __restrict__ bias, const float* __restrict__ res,
          float* __restrict__ Cf, __half* __restrict__ Ch,
          int Mvalid, int Ntot, int K) {
    extern __shared__ char dsm[];
    const uint32_t sb = smem_u32(dsm);
    constexpr int TILES = TWO ? 3 : 2;
    constexpr int STG = TILES * TILEB;
    constexpr int NST = TWO ? 3 : 4;

    const int tid = threadIdx.x;
    const int lane = tid & 31, wid = tid >> 5;
    const int wm = wid & 1, wn = wid >> 1;
    const int group = lane >> 2, tq = lane & 3;
    const int m0 = blockIdx.y * 128;
    const int n0 = blockIdx.x * 128;
    const int KT = K >> 5;

    const __half* gA = A + (size_t)m0 * K;
    const __half* gWh = Wh + (size_t)n0 * K;
    const __half* gWl = TWO ? (Wl + (size_t)n0 * K) : nullptr;

    float acc[4][4][4];
#pragma unroll
    for (int mi = 0; mi < 4; mi++)
#pragma unroll
        for (int ni = 0; ni < 4; ni++)
#pragma unroll
            for (int q = 0; q < 4; q++) acc[mi][ni][q] = 0.f;

    const int lr = tid >> 2;
    const int lc = tid & 3;

    auto load_stage = [&](int kt, int st) {
        const size_t koff = (size_t)kt * 32;
        uint32_t base = sb + st * STG;
#pragma unroll
        for (int i = 0; i < 2; i++) {
            int r = lr + i * 64;
            uint32_t so = (r * GSTR + lc * 8) * 2;
            size_t go = (size_t)r * K + koff + lc * 8;
            cp_async16(base + 0 * TILEB + so, gA + go);
            cp_async16(base + 1 * TILEB + so, gWh + go);
            if (TWO) cp_async16(base + 2 * TILEB + so, gWl + go);
        }
        cp_commit();
    };

    const uint32_t arow = wm * 64 + (lane & 7) + ((lane >> 3) & 1) * 8;
    const uint32_t acol = (lane >> 4) * 8;
    const uint32_t aoff = (arow * GSTR + acol) * 2;
    const uint32_t brow = wn * 32 + (lane & 7) + (lane >> 4) * 8;
    const uint32_t bcol = ((lane >> 3) & 1) * 8;
    const uint32_t boff = (brow * GSTR + bcol) * 2;

#pragma unroll
    for (int p = 0; p < NST - 1; p++)
        if (p < KT) load_stage(p, p);

    for (int kt = 0; kt < KT; kt++) {
        if (kt + NST - 1 < KT) { load_stage(kt + NST - 1, (kt + NST - 1) % NST); cp_wait<NST - 1>(); }
        else if (NST > 3 && kt + 3 < KT) { cp_wait<3>(); }
        else if (kt + 2 < KT) { cp_wait<2>(); }
        else if (kt + 1 < KT) { cp_wait<1>(); }
        else { cp_wait<0>(); }
        __syncthreads();

        const uint32_t stbase = sb + (kt % NST) * STG;
        const uint32_t aA = stbase + aoff;
        const uint32_t bH = stbase + 1 * TILEB + boff;
        const uint32_t bL = stbase + 2 * TILEB + boff;

#pragma unroll
        for (int ks = 0; ks < 2; ks++) {
            const uint32_t kadd = ks * 32;
            uint32_t af[16], bh[8];
#pragma unroll
            for (int mi = 0; mi < 4; mi++)
                ldsm4(af + mi * 4, aA + mi * (16 * GSTR * 2) + kadd);
#pragma unroll
            for (int nj = 0; nj < 2; nj++)
                ldsm4(bh + nj * 4, bH + nj * (16 * GSTR * 2) + kadd);
#pragma unroll
            for (int mi = 0; mi < 4; mi++)
#pragma unroll
                for (int ni = 0; ni < 4; ni++)
                    mma_f16(acc[mi][ni], af + mi * 4, bh + ni * 2);
            if (TWO) {
                uint32_t bl[8];
#pragma unroll
                for (int nj = 0; nj < 2; nj++)
                    ldsm4(bl + nj * 4, bL + nj * (16 * GSTR * 2) + kadd);
#pragma unroll
                for (int mi = 0; mi < 4; mi++)
#pragma unroll
                    for (int ni = 0; ni < 4; ni++)
                        mma_f16(acc[mi][ni], af + mi * 4, bl + ni * 2);
            }
        }
        __syncthreads();
    }

#pragma unroll
    for (int mi = 0; mi < 4; mi++) {
#pragma unroll
        for (int rr = 0; rr < 2; rr++) {
            int m = m0 + wm * 64 + mi * 16 + group + rr * 8;
            if (m >= Mvalid) continue;
#pragma unroll
            for (int ni = 0; ni < 4; ni++) {
                int n = n0 + wn * 32 + ni * 8 + tq * 2;
                float v0 = acc[mi][ni][rr * 2 + 0] + bias[n];
                float v1 = acc[mi][ni][rr * 2 + 1] + bias[n + 1];
                if (GELU_) {
                    v0 = 0.5f * v0 * (1.f + erff(v0 * 0.70710678118654752f));
                    v1 = 0.5f * v1 * (1.f + erff(v1 * 0.70710678118654752f));
                }
                if (RES) {
                    float2 rv = *(const float2*)(res + (size_t)m * Ntot + n);
                    v0 += rv.x; v1 += rv.y;
                }
                if (OUTF16) {
                    __half2 h2 = __floats2half2_rn(v0, v1);
                    *(__half2*)(Ch + (size_t)m * Ntot + n) = h2;
                } else {
                    *(float2*)(Cf + (size_t)m * Ntot + n) = make_float2(v0, v1);
                }
            }
        }
    }
}

// ---------------- weight transpose + fp16 split ----------------
__global__ void transpose_split(const float* __restrict__ W, __half* __restrict__ Wh,
                                __half* __restrict__ Wl, int R, int C) {
    __shared__ float t[32][33];
    int z = blockIdx.z;
    const float* Wz = W + (size_t)z * R * C;
    __half* Whz = Wh + (size_t)z * R * C;
    __half* Wlz = Wl + (size_t)z * R * C;
    int c0 = blockIdx.x * 32, r0 = blockIdx.y * 32;
    int x = threadIdx.x, y = threadIdx.y;
#pragma unroll
    for (int i = 0; i < 32; i += 8)
        t[y + i][x] = Wz[(size_t)(r0 + y + i) * C + c0 + x];
    __syncthreads();
#pragma unroll
    for (int i = 0; i < 32; i += 8) {
        float v = t[x][y + i];
        __half hi, lo;
        splith(v, hi, lo);
        size_t o = (size_t)(c0 + y + i) * R + r0 + x;
        Whz[o] = hi;
        Wlz[o] = lo;
    }
}

// ---------------- im2col / conv / assemble ----------------
__global__ void im2col_kernel(const float* __restrict__ x, float* __restrict__ col) {
    int idx = blockIdx.x * blockDim.x + threadIdx.x;
    if (idx >= CROWS * KCONV) return;
    int r = idx / KCONV, c = idx % KCONV;
    int b = r / NPATCH, p = r % NPATCH;
    int chn = c / 100, rem = c % 100;
    int kh = rem / 10, kw = rem % 10;
    int phh = p / 34, pw = p % 34;
    col[idx] = x[((b * 6 + chn) * 50 + phh * 10 + kh) * 345 + pw * 10 + kw];
}

__global__ void transw_kernel(const float* __restrict__ w, float* __restrict__ wt) {
    int idx = blockIdx.x * blockDim.x + threadIdx.x;
    if (idx >= KCONV * DD) return;
    int k = idx / DD, d = idx % DD;
    wt[idx] = w[d * KCONV + k];
}

__global__ void assemble_kernel(const float* __restrict__ conv_out,
                                const float* __restrict__ cls,
                                const float* __restrict__ pos,
                                float* __restrict__ h) {
    int idx = blockIdx.x * blockDim.x + threadIdx.x;
    if (idx >= MROWS * DD) return;
    int row = idx / DD, d = idx % DD;
    int b = row / NTOK, t = row % NTOK;
    float v = (t == 0) ? cls[d] : conv_out[(b * NPATCH + t - 1) * DD + d];
    h[idx] = v + pos[t * DD + d];
}

// ---------------- fp32 SGEMM (conv patch-embed only) ----------------
#define BM 64
#define BN 64
#define BK 16
__global__ void sgemm_kernel(const float* __restrict__ A, const float* __restrict__ B,
                             const float* __restrict__ bias, float* C, int M, int N, int K) {
    __shared__ float As[BK][BM + 4];
    __shared__ float Bs[BK][BN];
    int tid = threadIdx.x;
    int m0 = blockIdx.y * BM, n0 = blockIdx.x * BN;
    int tx = tid & 15, ty = tid >> 4;
    float acc[4][4];
#pragma unroll
    for (int i = 0; i < 4; i++)
#pragma unroll
        for (int j = 0; j < 4; j++) acc[i][j] = 0.f;
    for (int k0 = 0; k0 < K; k0 += BK) {
#pragma unroll
        for (int i = 0; i < 4; i++) {
            int idx = tid + i * 256;
            int ar = idx >> 4, ac = idx & 15;
            int gr = m0 + ar, gc = k0 + ac;
            float v = 0.f;
            if (gr < M && gc < K) v = A[(size_t)gr * K + gc];
            As[ac][ar] = v;
        }
#pragma unroll
        for (int i = 0; i < 4; i++) {
            int idx = tid + i * 256;
            int br = idx >> 6, bc = idx & 63;
            int gr = k0 + br, gc = n0 + bc;
            float v = 0.f;
            if (gr < K && gc < N) v = B[(size_t)gr * N + gc];
            Bs[br][bc] = v;
        }
        __syncthreads();
#pragma unroll
        for (int kk = 0; kk < BK; kk++) {
            float4 a4 = *reinterpret_cast<const float4*>(&As[kk][ty * 4]);
            float4 b4 = *reinterpret_cast<const float4*>(&Bs[kk][tx * 4]);
            float a[4] = {a4.x, a4.y, a4.z, a4.w};
            float bb[4] = {b4.x, b4.y, b4.z, b4.w};
#pragma unroll
            for (int i = 0; i < 4; i++)
#pragma unroll
                for (int j = 0; j < 4; j++) acc[i][j] += a[i] * bb[j];
        }
        __syncthreads();
    }
#pragma unroll
    for (int i = 0; i < 4; i++) {
        int m = m0 + ty * 4 + i;
        if (m >= M) continue;
#pragma unroll
        for (int j = 0; j < 4; j++) {
            int n = n0 + tx * 4 + j;
            if (n >= N) continue;
            C[(size_t)m * N + n] = acc[i][j] + bias[n];
        }
    }
}

// ---------------- LayerNorm fp32 -> fp16 ----------------
__global__ void ln_f16_kernel(const float* __restrict__ X, const float* __restrict__ w,
                              const float* __restrict__ b, __half* __restrict__ Y) {
    int row = blockIdx.x;
    int tid = threadIdx.x;
    const float* xr = X + (size_t)row * DD;
    float v0 = xr[tid], v1 = xr[tid + 256], v2 = xr[tid + 512];
    float s = v0 + v1 + v2;
    float q = v0 * v0 + v1 * v1 + v2 * v2;
    int lane = tid & 31, warp = tid >> 5;
#pragma unroll
    for (int off = 16; off; off >>= 1) {
        s += __shfl_down_sync(0xffffffffu, s, off);
        q += __shfl_down_sync(0xffffffffu, q, off);
    }
    __shared__ float sa[8], sbm[8];
    if (lane == 0) { sa[warp] = s; sbm[warp] = q; }
    __syncthreads();
    if (warp == 0) {
        s = (lane < 8) ? sa[lane] : 0.f;
        q = (lane < 8) ? sbm[lane] : 0.f;
#pragma unroll
        for (int off = 4; off; off >>= 1) {
            s += __shfl_down_sync(0xffffffffu, s, off);
            q += __shfl_down_sync(0xffffffffu, q, off);
        }
        if (lane == 0) { sa[0] = s; sbm[0] = q; }
    }
    __syncthreads();
    float mean = sa[0] * (1.f / DD);
    float var = sbm[0] * (1.f / DD) - mean * mean;
    float inv = rsqrtf(var + EPS);
    __half* yr = Y + (size_t)row * DD;
    yr[tid]       = __float2half((v0 - mean) * inv * w[tid]       + b[tid]);
    yr[tid + 256] = __float2half((v1 - mean) * inv * w[tid + 256] + b[tid + 256]);
    yr[tid + 512] = __float2half((v2 - mean) * inv * w[tid + 512] + b[tid + 512]);
}

// ---------------- LayerNorm fp32 -> fp32 (final, cls rows) ----------------
__global__ void ln_kernel(const float* __restrict__ X, const float* __restrict__ w,
                          const float* __restrict__ b, float* __restrict__ Y, int row_mul) {
    int row_in = blockIdx.x * row_mul;
    int row_out = blockIdx.x;
    int tid = threadIdx.x;
    const float* xr = X + (size_t)row_in * DD;
    float v0 = xr[tid], v1 = xr[tid + 256], v2 = xr[tid + 512];
    float s = v0 + v1 + v2;
    float q = v0 * v0 + v1 * v1 + v2 * v2;
    int lane = tid & 31, warp = tid >> 5;
#pragma unroll
    for (int off = 16; off; off >>= 1) {
        s += __shfl_down_sync(0xffffffffu, s, off);
        q += __shfl_down_sync(0xffffffffu, q, off);
    }
    __shared__ float sa[8], sbm[8];
    if (lane == 0) { sa[warp] = s; sbm[warp] = q; }
    __syncthreads();
    if (warp == 0) {
        s = (lane < 8) ? sa[lane] : 0.f;
        q = (lane < 8) ? sbm[lane] : 0.f;
#pragma unroll
        for (int off = 4; off; off >>= 1) {
            s += __shfl_down_sync(0xffffffffu, s, off);
            q += __shfl_down_sync(0xffffffffu, q, off);
        }
        if (lane == 0) { sa[0] = s; sbm[0] = q; }
    }
    __syncthreads();
    float mean = sa[0] * (1.f / DD);
    float var = sbm[0] * (1.f / DD) - mean * mean;
    float inv = rsqrtf(var + EPS);
    float* yr = Y + (size_t)row_out * DD;
    yr[tid]       = (v0 - mean) * inv * w[tid]       + b[tid];
    yr[tid + 256] = (v1 - mean) * inv * w[tid + 256] + b[tid + 256];
    yr[tid + 512] = (v2 - mean) * inv * w[tid + 512] + b[tid + 512];
}

// ---------------- MMA attention (split fp16, ~fp32 exact) ----------------
#define NTOKP 176
#define ASTR 72
#define VSTR 184
#define SA_QH 0
#define SA_QL (SA_QH + NTOKP*ASTR*2)
#define SA_KH (SA_QL + NTOKP*ASTR*2)
#define SA_KL (SA_KH + NTOKP*ASTR*2)
#define SA_VH (SA_KL + NTOKP*ASTR*2)
#define SA_VL (SA_VH + 64*VSTR*2)
#define ATTN_SMEM (SA_VL + 64*VSTR*2)

__global__ void __launch_bounds__(256, 1)
attn_mma_kernel(const float* __restrict__ qkv, __half* __restrict__ out) {
    extern __shared__ char asmem[];
    const uint32_t sb = smem_u32(asmem);
    __half* QH = (__half*)(asmem + SA_QH);
    __half* QL = (__half*)(asmem + SA_QL);
    __half* KH = (__half*)(asmem + SA_KH);
    __half* KL = (__half*)(asmem + SA_KL);
    __half* VH = (__half*)(asmem + SA_VH);
    __half* VL = (__half*)(asmem + SA_VL);

    const int bh = blockIdx.x;
    const int b = bh / NHEAD, hh = bh % NHEAD;
    const int tid = threadIdx.x;
    const int lane = tid & 31, wid = tid >> 5;
    const int group = lane >> 2, tq = lane & 3;
    const size_t base = (size_t)b * NTOK * (3 * DD) + hh * HDIM;

    for (int idx = tid; idx < NTOKP * 64; idx += 256) {
        int row = idx >> 6, d = idx & 63;
        float qv = 0.f, kv = 0.f, vv = 0.f;
        if (row < NTOK) {
            size_t o = base + (size_t)row * (3 * DD) + d;
            qv = qkv[o]; kv = qkv[o + DD]; vv = qkv[o + 2 * DD];
        }
        __half h, l;
        splith(qv, h, l); QH[row * ASTR + d] = h; QL[row * ASTR + d] = l;
        splith(kv, h, l); KH[row * ASTR + d] = h; KL[row * ASTR + d] = l;
        splith(vv, h, l); VH[d * VSTR + row] = h; VL[d * VSTR + row] = l;
    }
    __syncthreads();

    const uint32_t a_r = (lane & 7) + ((lane >> 3) & 1) * 8;
    const uint32_t a_c = (lane >> 4) * 8;
    const uint32_t b_r = (lane & 7) + (lane >> 4) * 8;
    const uint32_t b_c = ((lane >> 3) & 1) * 8;

    for (int t = wid; t < 11; t += 8) {
        const int m0 = t * 16;

        uint32_t aq[4][4], aql[4][4];
#pragma unroll
        for (int k = 0; k < 4; k++) {
            uint32_t off = ((m0 + a_r) * ASTR + a_c + k * 16) * 2;
            ldsm4(aq[k], sb + SA_QH + off);
            ldsm4(aql[k], sb + SA_QL + off);
        }

        float s[22][4];
#pragma unroll
        for (int j = 0; j < 22; j++)
#pragma unroll
            for (int q = 0; q < 4; q++) s[j][q] = 0.f;

#pragma unroll
        for (int nj = 0; nj < 11; nj++) {
            const int n0 = nj * 16;
#pragma unroll
            for (int k = 0; k < 4; k++) {
                uint32_t bkh[4], bkl[4];
                uint32_t off = ((n0 + b_r) * ASTR + b_c + k * 16) * 2;
                ldsm4(bkh, sb + SA_KH + off);
                ldsm4(bkl, sb + SA_KL + off);
                mma_f16(s[2 * nj],     aq[k],  bkh);
                mma_f16(s[2 * nj + 1], aq[k],  bkh + 2);
                mma_f16(s[2 * nj],     aql[k], bkh);
                mma_f16(s[2 * nj + 1], aql[k], bkh + 2);
                mma_f16(s[2 * nj],     aq[k],  bkl);
                mma_f16(s[2 * nj + 1], aq[k],  bkl + 2);
            }
        }

        {
            int c0 = 168 + tq * 2;
            if (c0 >= NTOK)     { s[21][0] = -1e30f; s[21][2] = -1e30f; }
            if (c0 + 1 >= NTOK) { s[21][1] = -1e30f; s[21][3] = -1e30f; }
        }

        float mx0 = -1e30f, mx1 = -1e30f;
#pragma unroll
        for (int j = 0; j < 22; j++) {
            mx0 = fmaxf(mx0, fmaxf(s[j][0], s[j][1]));
            mx1 = fmaxf(mx1, fmaxf(s[j][2], s[j][3]));
        }
        mx0 = fmaxf(mx0, __shfl_xor_sync(0xffffffffu, mx0, 1));
        mx0 = fmaxf(mx0, __shfl_xor_sync(0xffffffffu, mx0, 2));
        mx1 = fmaxf(mx1, __shfl_xor_sync(0xffffffffu, mx1, 1));
        mx1 = fmaxf(mx1, __shfl_xor_sync(0xffffffffu, mx1, 2));

        float rs0 = 0.f, rs1 = 0.f;
#pragma unroll
        for (int j = 0; j < 22; j++) {
            s[j][0] = __expf((s[j][0] - mx0) * 0.125f);
            s[j][1] = __expf((s[j][1] - mx0) * 0.125f);
            s[j][2] = __expf((s[j][2] - mx1) * 0.125f);
            s[j][3] = __expf((s[j][3] - mx1) * 0.125f);
            rs0 += s[j][0] + s[j][1];
            rs1 += s[j][2] + s[j][3];
        }
        rs0 += __shfl_xor_sync(0xffffffffu, rs0, 1);
        rs0 += __shfl_xor_sync(0xffffffffu, rs0, 2);
        rs1 += __shfl_xor_sync(0xffffffffu, rs1, 1);
        rs1 += __shfl_xor_sync(0xffffffffu, rs1, 2);

        float o[8][4];
#pragma unroll
        for (int j = 0; j < 8; j++)
#pragma unroll
            for (int q = 0; q < 4; q++) o[j][q] = 0.f;

#pragma unroll
        for (int kt = 0; kt < 11; kt++) {
            uint32_t ap[4], apl[4];
#pragma unroll
            for (int half = 0; half < 2; half++) {
                const float* sv = s[2 * kt + half];
                __half h0 = __float2half(sv[0]), h1 = __float2half(sv[1]);
                __half h2v = __float2half(sv[2]), h3 = __float2half(sv[3]);
                ap[2 * half]     = pack_h2(__half2float(h0), __half2float(h1));
                ap[2 * half + 1] = pack_h2(__half2float(h2v), __half2float(h3));
                apl[2 * half]     = pack_h2(sv[0] - __half2float(h0), sv[1] - __half2float(h1));
                apl[2 * half + 1] = pack_h2(sv[2] - __half2float(h2v), sv[3] - __half2float(h3));
            }
#pragma unroll
            for (int dj = 0; dj < 4; dj++) {
                const int d0 = dj * 16;
                uint32_t bvh[4], bvl[4];
                uint32_t off = ((d0 + b_r) * VSTR + b_c + kt * 16) * 2;
                ldsm4(bvh, sb + SA_VH + off);
                ldsm4(bvl, sb + SA_VL + off);
                mma_f16(o[2 * dj],     ap,  bvh);
                mma_f16(o[2 * dj + 1], ap,  bvh + 2);
                mma_f16(o[2 * dj],     apl, bvh);
                mma_f16(o[2 * dj + 1], apl, bvh + 2);
                mma_f16(o[2 * dj],     ap,  bvl);
                mma_f16(o[2 * dj + 1], ap,  bvl + 2);
            }
        }

        const float i0 = 1.f / rs0, i1 = 1.f / rs1;
        const int r0 = m0 + group, r1 = r0 + 8;
#pragma unroll
        for (int j = 0; j < 8; j++) {
            int d = 8 * j + tq * 2;
            if (r0 < NTOK) {
                __half2 hv = __floats2half2_rn(o[j][0] * i0, o[j][1] * i0);
                *(__half2*)(out + (size_t)(b * NTOK + r0) * DD + hh * HDIM + d) = hv;
            }
            if (r1 < NTOK) {
                __half2 hv = __floats2half2_rn(o[j][2] * i1, o[j][3] * i1);
                *(__half2*)(out + (size_t)(b * NTOK + r1) * DD + hh * HDIM + d) = hv;
            }
        }
    }
}

// ---------------- head ----------------
__global__ void head_kernel(const float* __restrict__ cls, const float* __restrict__ hw,
                            const float* __restrict__ hb, float* __restrict__ out) {
    int b = blockIdx.x;
    int tid = threadIdx.x;
    float a0 = 0.f, a1 = 0.f, a2 = 0.f;
    for (int d = tid; d < DD; d += 256) {
        float v = cls[b * DD + d];
        a0 += v * hw[d * 3 + 0];
        a1 += v * hw[d * 3 + 1];
        a2 += v * hw[d * 3 + 2];
    }
    int lane = tid & 31, warp = tid >> 5;
#pragma unroll
    for (int off = 16; off; off >>= 1) {
        a0 += __shfl_down_sync(0xffffffffu, a0, off);
        a1 += __shfl_down_sync(0xffffffffu, a1, off);
        a2 += __shfl_down_sync(0xffffffffu, a2, off);
    }
    __shared__ float s0[8], s1[8], s2[8];
    if (lane == 0) { s0[warp] = a0; s1[warp] = a1; s2[warp] = a2; }
    __syncthreads();
    if (warp == 0 && lane < 8) {
        a0 = s0[lane]; a1 = s1[lane]; a2 = s2[lane];
#pragma unroll
        for (int off = 4; off; off >>= 1) {
            a0 += __shfl_down_sync(0x000000ffu, a0, off);
            a1 += __shfl_down_sync(0x000000ffu, a1, off);
            a2 += __shfl_down_sync(0x000000ffu, a2, off);
        }
        if (lane == 0) {
            out[b * 3 + 0] = a0 + hb[0];
            out[b * 3 + 1] = a1 + hb[1];
            out[b * 3 + 2] = a2 + hb[2];
        }
    }
}

// ---------------- launcher ----------------
extern "C" void kernel_launch(void* const* d_in, const int* in_sizes, int n_in,
                              void* d_out, int out_size) {
    const float* x        = (const float*)d_in[0];
    const float* conv_w   = (const float*)d_in[1];
    const float* conv_b   = (const float*)d_in[2];
    const float* cls_tok  = (const float*)d_in[3];
    const float* pos      = (const float*)d_in[4];
    const float* ln1_w    = (const float*)d_in[5];
    const float* ln1_b    = (const float*)d_in[6];
    const float* qkv_w    = (const float*)d_in[7];
    const float* qkv_b    = (const float*)d_in[8];
    const float* proj_w   = (const float*)d_in[9];
    const float* proj_b   = (const float*)d_in[10];
    const float* ln2_w    = (const float*)d_in[11];
    const float* ln2_b    = (const float*)d_in[12];
    const float* fc1_w    = (const float*)d_in[13];
    const float* fc1_b    = (const float*)d_in[14];
    const float* fc2_w    = (const float*)d_in[15];
    const float* fc2_b    = (const float*)d_in[16];
    const float* norm_w   = (const float*)d_in[17];
    const float* norm_b   = (const float*)d_in[18];
    const float* head_w   = (const float*)d_in[19];
    const float* head_b   = (const float*)d_in[20];
    float* out = (float*)d_out;

    float *col, *wt, *conv, *h, *clsb, *qkvf;
    __half *yf, *af, *bigf;
    __half *qkvWh, *qkvWl, *projWh, *projWl, *fc1Wh, *fc1Wl, *fc2Wh, *fc2Wl;
    cudaGetSymbolAddress((void**)&col, g_col);
    cudaGetSymbolAddress((void**)&wt, g_wt);
    cudaGetSymbolAddress((void**)&conv, g_conv);
    cudaGetSymbolAddress((void**)&h, g_h);
    cudaGetSymbolAddress((void**)&clsb, g_cls);
    cudaGetSymbolAddress((void**)&qkvf, g_qkvf);
    cudaGetSymbolAddress((void**)&yf, g_yf);
    cudaGetSymbolAddress((void**)&af, g_af);
    cudaGetSymbolAddress((void**)&bigf, g_bigf);
    cudaGetSymbolAddress((void**)&qkvWh, g_qkvWh);
    cudaGetSymbolAddress((void**)&qkvWl, g_qkvWl);
    cudaGetSymbolAddress((void**)&projWh, g_projWh);
    cudaGetSymbolAddress((void**)&projWl, g_projWl);
    cudaGetSymbolAddress((void**)&fc1Wh, g_fc1Wh);
    cudaGetSymbolAddress((void**)&fc1Wl, g_fc1Wl);
    cudaGetSymbolAddress((void**)&fc2Wh, g_fc2Wh);
    cudaGetSymbolAddress((void**)&fc2Wl, g_fc2Wl);

    cudaFuncSetAttribute(attn_mma_kernel, cudaFuncAttributeMaxDynamicSharedMemorySize, ATTN_SMEM);
    cudaFuncSetAttribute(hmma_gemm<false, false, false, false>, cudaFuncAttributeMaxDynamicSharedMemorySize, SMTOT1);
    cudaFuncSetAttribute(hmma_gemm<false, false, false, true>, cudaFuncAttributeMaxDynamicSharedMemorySize, SMTOT1);
    cudaFuncSetAttribute(hmma_gemm<false, true, true, false>, cudaFuncAttributeMaxDynamicSharedMemorySize, SMTOT1);

    // weight transpose + fp16 split (Wl kept for per-GEMM accuracy fallback)
    transpose_split<<<dim3(3 * DD / 32, DD / 32, DEPTH), dim3(32, 8)>>>(qkv_w, qkvWh, qkvWl, DD, 3 * DD);
    transpose_split<<<dim3(DD / 32, DD / 32, DEPTH), dim3(32, 8)>>>(proj_w, projWh, projWl, DD, DD);
    transpose_split<<<dim3(4 * DD / 32, DD / 32, DEPTH), dim3(32, 8)>>>(fc1_w, fc1Wh, fc1Wl, DD, 4 * DD);
    transpose_split<<<dim3(DD / 32, 4 * DD / 32, DEPTH), dim3(32, 8)>>>(fc2_w, fc2Wh, fc2Wl, 4 * DD, DD);

    // patch embed (fp32 exact)
    im2col_kernel<<<(CROWS * KCONV + 255) / 256, 256>>>(x, col);
    transw_kernel<<<(KCONV * DD + 255) / 256, 256>>>(conv_w, wt);
    sgemm_kernel<<<dim3(DD / BN, CROWS / BM), 256>>>(col, wt, conv_b, conv, CROWS, DD, KCONV);
    assemble_kernel<<<(MROWS * DD + 255) / 256, 256>>>(conv, cls_tok, pos, h);

    const int MT = MPAD / 128;  // 86
    for (int i = 0; i < DEPTH; i++) {
        ln_f16_kernel<<<MROWS, 256>>>(h, ln1_w + (size_t)i * DD, ln1_b + (size_t)i * DD, yf);
        hmma_gemm<false, false, false, false><<<dim3(3 * DD / 128, MT), 256, SMTOT1>>>(
            yf, qkvWh + (size_t)i * 3 * DD * DD, qkvWl + (size_t)i * 3 * DD * DD,
            qkv_b + (size_t)i * 3 * DD, nullptr, qkvf, nullptr, MROWS, 3 * DD, DD);
        attn_mma_kernel<<<BATCH * NHEAD, 256, ATTN_SMEM>>>(qkvf, af);
        hmma_gemm<false, false, false, true><<<dim3(DD / 128, MT), 256, SMTOT1>>>(
            af, projWh + (size_t)i * DD * DD, projWl + (size_t)i * DD * DD,
            proj_b + (size_t)i * DD, h, h, nullptr, MROWS, DD, DD);
        ln_f16_kernel<<<MROWS, 256>>>(h, ln2_w + (size_t)i * DD, ln2_b + (size_t)i * DD, yf);
        hmma_gemm<false, true, true, false><<<dim3(4 * DD / 128, MT), 256, SMTOT1>>>(
            yf, fc1Wh + (size_t)i * 4 * DD * DD, fc1Wl + (size_t)i * 4 * DD * DD,
            fc1_b + (size_t)i * 4 * DD, nullptr, nullptr, bigf, MROWS, 4 * DD, DD);
        hmma_gemm<false, false, false, true><<<dim3(DD / 128, MT), 256, SMTOT1>>>(
            bigf, fc2Wh + (size_t)i * 4 * DD * DD, fc2Wl + (size_t)i * 4 * DD * DD,
            fc2_b + (size_t)i * DD, h, h, nullptr, MROWS, DD, 4 * DD);
    }

    ln_kernel<<<BATCH, 256>>>(h, norm_w, norm_b, clsb, NTOK);
    head_kernel<<<BATCH, 256>>>(clsb, head_w, head_b, out);
}

// round 9
// speedup vs baseline: 5.9045x; 1.2114x over previous
#include <cuda_runtime.h>
#include <cuda_fp16.h>
#include <math.h>
#include <stdint.h>

// ---------------- problem constants ----------------
#define DD     768
#define NTOK   171
#define BATCH  64
#define MROWS  (BATCH*NTOK)      // 10944
#define MPAD   11008             // 86*128
#define NPATCH 170
#define CROWS  (BATCH*NPATCH)    // 10880
#define KCONV  600
#define NHEAD  12
#define HDIM   64
#define DEPTH  12
#define EPS    1e-5f

// ---------------- scratch (device globals) ----------------
__device__ float g_col [CROWS * KCONV];
__device__ float g_wt  [KCONV * DD];
__device__ float g_conv[CROWS * DD];
__device__ float g_h   [MROWS * DD];
__device__ float g_cls [BATCH * DD];
__device__ float g_qkvf[MPAD * 3 * DD];
__device__ __half g_yf   [MPAD * DD];
__device__ __half g_af   [MPAD * DD];
__device__ __half g_bigf [MPAD * 4 * DD];
__device__ __half g_qkvWh[DEPTH * 3 * DD * DD];
__device__ __half g_qkvWl[DEPTH * 3 * DD * DD];
__device__ __half g_projWh[DEPTH * DD * DD];
__device__ __half g_projWl[DEPTH * DD * DD];
__device__ __half g_fc1Wh[DEPTH * 4 * DD * DD];
__device__ __half g_fc1Wl[DEPTH * 4 * DD * DD];
__device__ __half g_fc2Wh[DEPTH * 4 * DD * DD];
__device__ __half g_fc2Wl[DEPTH * 4 * DD * DD];

// ---------------- helpers ----------------
__device__ __forceinline__ uint32_t smem_u32(const void* p) {
    uint32_t a;
    asm("{ .reg .u64 t; cvta.to.shared.u64 t, %1; cvt.u32.u64 %0, t; }" : "=r"(a) : "l"(p));
    return a;
}
__device__ __forceinline__ void cp_async16(uint32_t dst, const void* src) {
    asm volatile("cp.async.cg.shared.global [%0], [%1], 16;"
                 :: "r"(dst), "l"(src) : "memory");
}
__device__ __forceinline__ void cp_commit() {
    asm volatile("cp.async.commit_group;" ::: "memory");
}
template <int N>
__device__ __forceinline__ void cp_wait() {
    asm volatile("cp.async.wait_group %0;" :: "n"(N) : "memory");
}
__device__ __forceinline__ void ldsm4(uint32_t* r, uint32_t addr) {
    asm volatile("ldmatrix.sync.aligned.m8n8.x4.shared.b16 {%0,%1,%2,%3}, [%4];"
                 : "=r"(r[0]), "=r"(r[1]), "=r"(r[2]), "=r"(r[3]) : "r"(addr));
}
__device__ __forceinline__ void mma_f16(float* c, const uint32_t* a, const uint32_t* b) {
    asm volatile(
        "mma.sync.aligned.m16n8k16.row.col.f32.f16.f16.f32 "
        "{%0,%1,%2,%3}, {%4,%5,%6,%7}, {%8,%9}, {%0,%1,%2,%3};"
        : "+f"(c[0]), "+f"(c[1]), "+f"(c[2]), "+f"(c[3])
        : "r"(a[0]), "r"(a[1]), "r"(a[2]), "r"(a[3]), "r"(b[0]), "r"(b[1]));
}
__device__ __forceinline__ void splith(float v, __half& hi, __half& lo) {
    hi = __float2half(v);
    lo = __float2half(v - __half2float(hi));
}
__device__ __forceinline__ uint32_t pack_h2(float a, float b) {
    __half2 h = __floats2half2_rn(a, b);
    return *(uint32_t*)&h;
}

// ---------------- fp16 GEMM: C = A @ W^T (single product, 2 CTAs/SM) ----------------
#define GSTR 40
#define TILEB (128 * GSTR * 2)
#define SMTOT1 (4 * 2 * TILEB)   // 4 stages x 2 tiles = 81920 B/CTA (2 CTAs = 160 KB/SM)

template <bool TWO, bool OUTF16, bool GELU_, bool RES>
__global__ void __launch_bounds__(256, 2)
hmma_gemm(const __half* __restrict__ A,
          const __half* __restrict__ Wh, const __half* __restrict__ Wl,
          const float* __restrict__ bias, const float* __restrict__ res,
          float* __restrict__ Cf, __half* __restrict__ Ch,
          int Mvalid, int Ntot, int K) {
    extern __shared__ char dsm[];
    const uint32_t sb = smem_u32(dsm);
    constexpr int TILES = TWO ? 3 : 2;
    constexpr int STG = TILES * TILEB;
    constexpr int NST = TWO ? 3 : 4;

    const int tid = threadIdx.x;
    const int lane = tid & 31, wid = tid >> 5;
    const int wm = wid & 1, wn = wid >> 1;
    const int group = lane >> 2, tq = lane & 3;
    const int m0 = blockIdx.y * 128;
    const int n0 = blockIdx.x * 128;
    const int KT = K >> 5;

    const __half* gA = A + (size_t)m0 * K;
    const __half* gWh = Wh + (size_t)n0 * K;
    const __half* gWl = TWO ? (Wl + (size_t)n0 * K) : nullptr;

    float acc[4][4][4];
#pragma unroll
    for (int mi = 0; mi < 4; mi++)
#pragma unroll
        for (int ni = 0; ni < 4; ni++)
#pragma unroll
            for (int q = 0; q < 4; q++) acc[mi][ni][q] = 0.f;

    const int lr = tid >> 2;
    const int lc = tid & 3;

    auto load_stage = [&](int kt, int st) {
        const size_t koff = (size_t)kt * 32;
        uint32_t base = sb + st * STG;
#pragma unroll
        for (int i = 0; i < 2; i++) {
            int r = lr + i * 64;
            uint32_t so = (r * GSTR + lc * 8) * 2;
            size_t go = (size_t)r * K + koff + lc * 8;
            cp_async16(base + 0 * TILEB + so, gA + go);
            cp_async16(base + 1 * TILEB + so, gWh + go);
            if (TWO) cp_async16(base + 2 * TILEB + so, gWl + go);
        }
        cp_commit();
    };

    const uint32_t arow = wm * 64 + (lane & 7) + ((lane >> 3) & 1) * 8;
    const uint32_t acol = (lane >> 4) * 8;
    const uint32_t aoff = (arow * GSTR + acol) * 2;
    const uint32_t brow = wn * 32 + (lane & 7) + (lane >> 4) * 8;
    const uint32_t bcol = ((lane >> 3) & 1) * 8;
    const uint32_t boff = (brow * GSTR + bcol) * 2;

#pragma unroll
    for (int p = 0; p < NST - 1; p++)
        if (p < KT) load_stage(p, p);

    for (int kt = 0; kt < KT; kt++) {
        if (kt + NST - 1 < KT) { load_stage(kt + NST - 1, (kt + NST - 1) % NST); cp_wait<NST - 1>(); }
        else if (NST > 3 && kt + 3 < KT) { cp_wait<3>(); }
        else if (kt + 2 < KT) { cp_wait<2>(); }
        else if (kt + 1 < KT) { cp_wait<1>(); }
        else { cp_wait<0>(); }
        __syncthreads();

        const uint32_t stbase = sb + (kt % NST) * STG;
        const uint32_t aA = stbase + aoff;
        const uint32_t bH = stbase + 1 * TILEB + boff;
        const uint32_t bL = stbase + 2 * TILEB + boff;

#pragma unroll
        for (int ks = 0; ks < 2; ks++) {
            const uint32_t kadd = ks * 32;
            uint32_t af[16], bh[8];
#pragma unroll
            for (int mi = 0; mi < 4; mi++)
                ldsm4(af + mi * 4, aA + mi * (16 * GSTR * 2) + kadd);
#pragma unroll
            for (int nj = 0; nj < 2; nj++)
                ldsm4(bh + nj * 4, bH + nj * (16 * GSTR * 2) + kadd);
#pragma unroll
            for (int mi = 0; mi < 4; mi++)
#pragma unroll
                for (int ni = 0; ni < 4; ni++)
                    mma_f16(acc[mi][ni], af + mi * 4, bh + ni * 2);
            if (TWO) {
                uint32_t bl[8];
#pragma unroll
                for (int nj = 0; nj < 2; nj++)
                    ldsm4(bl + nj * 4, bL + nj * (16 * GSTR * 2) + kadd);
#pragma unroll
                for (int mi = 0; mi < 4; mi++)
#pragma unroll
                    for (int ni = 0; ni < 4; ni++)
                        mma_f16(acc[mi][ni], af + mi * 4, bl + ni * 2);
            }
        }
        __syncthreads();
    }

#pragma unroll
    for (int mi = 0; mi < 4; mi++) {
#pragma unroll
        for (int rr = 0; rr < 2; rr++) {
            int m = m0 + wm * 64 + mi * 16 + group + rr * 8;
            if (m >= Mvalid) continue;
#pragma unroll
            for (int ni = 0; ni < 4; ni++) {
                int n = n0 + wn * 32 + ni * 8 + tq * 2;
                float v0 = acc[mi][ni][rr * 2 + 0] + bias[n];
                float v1 = acc[mi][ni][rr * 2 + 1] + bias[n + 1];
                if (GELU_) {
                    v0 = 0.5f * v0 * (1.f + erff(v0 * 0.70710678118654752f));
                    v1 = 0.5f * v1 * (1.f + erff(v1 * 0.70710678118654752f));
                }
                if (RES) {
                    float2 rv = *(const float2*)(res + (size_t)m * Ntot + n);
                    v0 += rv.x; v1 += rv.y;
                }
                if (OUTF16) {
                    __half2 h2 = __floats2half2_rn(v0, v1);
                    *(__half2*)(Ch + (size_t)m * Ntot + n) = h2;
                } else {
                    *(float2*)(Cf + (size_t)m * Ntot + n) = make_float2(v0, v1);
                }
            }
        }
    }
}

// ---------------- weight transpose + fp16 split ----------------
__global__ void transpose_split(const float* __restrict__ W, __half* __restrict__ Wh,
                                __half* __restrict__ Wl, int R, int C) {
    __shared__ float t[32][33];
    int z = blockIdx.z;
    const float* Wz = W + (size_t)z * R * C;
    __half* Whz = Wh + (size_t)z * R * C;
    __half* Wlz = Wl + (size_t)z * R * C;
    int c0 = blockIdx.x * 32, r0 = blockIdx.y * 32;
    int x = threadIdx.x, y = threadIdx.y;
#pragma unroll
    for (int i = 0; i < 32; i += 8)
        t[y + i][x] = Wz[(size_t)(r0 + y + i) * C + c0 + x];
    __syncthreads();
#pragma unroll
    for (int i = 0; i < 32; i += 8) {
        float v = t[x][y + i];
        __half hi, lo;
        splith(v, hi, lo);
        size_t o = (size_t)(c0 + y + i) * R + r0 + x;
        Whz[o] = hi;
        Wlz[o] = lo;
    }
}

// ---------------- im2col / conv / assemble ----------------
__global__ void im2col_kernel(const float* __restrict__ x, float* __restrict__ col) {
    int idx = blockIdx.x * blockDim.x + threadIdx.x;
    if (idx >= CROWS * KCONV) return;
    int r = idx / KCONV, c = idx % KCONV;
    int b = r / NPATCH, p = r % NPATCH;
    int chn = c / 100, rem = c % 100;
    int kh = rem / 10, kw = rem % 10;
    int phh = p / 34, pw = p % 34;
    col[idx] = x[((b * 6 + chn) * 50 + phh * 10 + kh) * 345 + pw * 10 + kw];
}

__global__ void transw_kernel(const float* __restrict__ w, float* __restrict__ wt) {
    int idx = blockIdx.x * blockDim.x + threadIdx.x;
    if (idx >= KCONV * DD) return;
    int k = idx / DD, d = idx % DD;
    wt[idx] = w[d * KCONV + k];
}

__global__ void assemble_kernel(const float* __restrict__ conv_out,
                                const float* __restrict__ cls,
                                const float* __restrict__ pos,
                                float* __restrict__ h) {
    int idx = blockIdx.x * blockDim.x + threadIdx.x;
    if (idx >= MROWS * DD) return;
    int row = idx / DD, d = idx % DD;
    int b = row / NTOK, t = row % NTOK;
    float v = (t == 0) ? cls[d] : conv_out[(b * NPATCH + t - 1) * DD + d];
    h[idx] = v + pos[t * DD + d];
}

// ---------------- fp32 SGEMM (conv patch-embed only) ----------------
#define BM 64
#define BN 64
#define BK 16
__global__ void sgemm_kernel(const float* __restrict__ A, const float* __restrict__ B,
                             const float* __restrict__ bias, float* C, int M, int N, int K) {
    __shared__ float As[BK][BM + 4];
    __shared__ float Bs[BK][BN];
    int tid = threadIdx.x;
    int m0 = blockIdx.y * BM, n0 = blockIdx.x * BN;
    int tx = tid & 15, ty = tid >> 4;
    float acc[4][4];
#pragma unroll
    for (int i = 0; i < 4; i++)
#pragma unroll
        for (int j = 0; j < 4; j++) acc[i][j] = 0.f;
    for (int k0 = 0; k0 < K; k0 += BK) {
#pragma unroll
        for (int i = 0; i < 4; i++) {
            int idx = tid + i * 256;
            int ar = idx >> 4, ac = idx & 15;
            int gr = m0 + ar, gc = k0 + ac;
            float v = 0.f;
            if (gr < M && gc < K) v = A[(size_t)gr * K + gc];
            As[ac][ar] = v;
        }
#pragma unroll
        for (int i = 0; i < 4; i++) {
            int idx = tid + i * 256;
            int br = idx >> 6, bc = idx & 63;
            int gr = k0 + br, gc = n0 + bc;
            float v = 0.f;
            if (gr < K && gc < N) v = B[(size_t)gr * N + gc];
            Bs[br][bc] = v;
        }
        __syncthreads();
#pragma unroll
        for (int kk = 0; kk < BK; kk++) {
            float4 a4 = *reinterpret_cast<const float4*>(&As[kk][ty * 4]);
            float4 b4 = *reinterpret_cast<const float4*>(&Bs[kk][tx * 4]);
            float a[4] = {a4.x, a4.y, a4.z, a4.w};
            float bb[4] = {b4.x, b4.y, b4.z, b4.w};
#pragma unroll
            for (int i = 0; i < 4; i++)
#pragma unroll
                for (int j = 0; j < 4; j++) acc[i][j] += a[i] * bb[j];
        }
        __syncthreads();
    }
#pragma unroll
    for (int i = 0; i < 4; i++) {
        int m = m0 + ty * 4 + i;
        if (m >= M) continue;
#pragma unroll
        for (int j = 0; j < 4; j++) {
            int n = n0 + tx * 4 + j;
            if (n >= N) continue;
            C[(size_t)m * N + n] = acc[i][j] + bias[n];
        }
    }
}

// ---------------- LayerNorm fp32 -> fp16 ----------------
__global__ void ln_f16_kernel(const float* __restrict__ X, const float* __restrict__ w,
                              const float* __restrict__ b, __half* __restrict__ Y) {
    int row = blockIdx.x;
    int tid = threadIdx.x;
    const float* xr = X + (size_t)row * DD;
    float v0 = xr[tid], v1 = xr[tid + 256], v2 = xr[tid + 512];
    float s = v0 + v1 + v2;
    float q = v0 * v0 + v1 * v1 + v2 * v2;
    int lane = tid & 31, warp = tid >> 5;
#pragma unroll
    for (int off = 16; off; off >>= 1) {
        s += __shfl_down_sync(0xffffffffu, s, off);
        q += __shfl_down_sync(0xffffffffu, q, off);
    }
    __shared__ float sa[8], sbm[8];
    if (lane == 0) { sa[warp] = s; sbm[warp] = q; }
    __syncthreads();
    if (warp == 0) {
        s = (lane < 8) ? sa[lane] : 0.f;
        q = (lane < 8) ? sbm[lane] : 0.f;
#pragma unroll
        for (int off = 4; off; off >>= 1) {
            s += __shfl_down_sync(0xffffffffu, s, off);
            q += __shfl_down_sync(0xffffffffu, q, off);
        }
        if (lane == 0) { sa[0] = s; sbm[0] = q; }
    }
    __syncthreads();
    float mean = sa[0] * (1.f / DD);
    float var = sbm[0] * (1.f / DD) - mean * mean;
    float inv = rsqrtf(var + EPS);
    __half* yr = Y + (size_t)row * DD;
    yr[tid]       = __float2half((v0 - mean) * inv * w[tid]       + b[tid]);
    yr[tid + 256] = __float2half((v1 - mean) * inv * w[tid + 256] + b[tid + 256]);
    yr[tid + 512] = __float2half((v2 - mean) * inv * w[tid + 512] + b[tid + 512]);
}

// ---------------- LayerNorm fp32 -> fp32 (final, cls rows) ----------------
__global__ void ln_kernel(const float* __restrict__ X, const float* __restrict__ w,
                          const float* __restrict__ b, float* __restrict__ Y, int row_mul) {
    int row_in = blockIdx.x * row_mul;
    int row_out = blockIdx.x;
    int tid = threadIdx.x;
    const float* xr = X + (size_t)row_in * DD;
    float v0 = xr[tid], v1 = xr[tid + 256], v2 = xr[tid + 512];
    float s = v0 + v1 + v2;
    float q = v0 * v0 + v1 * v1 + v2 * v2;
    int lane = tid & 31, warp = tid >> 5;
#pragma unroll
    for (int off = 16; off; off >>= 1) {
        s += __shfl_down_sync(0xffffffffu, s, off);
        q += __shfl_down_sync(0xffffffffu, q, off);
    }
    __shared__ float sa[8], sbm[8];
    if (lane == 0) { sa[warp] = s; sbm[warp] = q; }
    __syncthreads();
    if (warp == 0) {
        s = (lane < 8) ? sa[lane] : 0.f;
        q = (lane < 8) ? sbm[lane] : 0.f;
#pragma unroll
        for (int off = 4; off; off >>= 1) {
            s += __shfl_down_sync(0xffffffffu, s, off);
            q += __shfl_down_sync(0xffffffffu, q, off);
        }
        if (lane == 0) { sa[0] = s; sbm[0] = q; }
    }
    __syncthreads();
    float mean = sa[0] * (1.f / DD);
    float var = sbm[0] * (1.f / DD) - mean * mean;
    float inv = rsqrtf(var + EPS);
    float* yr = Y + (size_t)row_out * DD;
    yr[tid]       = (v0 - mean) * inv * w[tid]       + b[tid];
    yr[tid + 256] = (v1 - mean) * inv * w[tid + 256] + b[tid + 256];
    yr[tid + 512] = (v2 - mean) * inv * w[tid + 512] + b[tid + 512];
}

// ---------------- MMA attention (split fp16, ~fp32 exact) ----------------
#define NTOKP 176
#define ASTR 72
#define VSTR 184
#define SA_QH 0
#define SA_QL (SA_QH + NTOKP*ASTR*2)
#define SA_KH (SA_QL + NTOKP*ASTR*2)
#define SA_KL (SA_KH + NTOKP*ASTR*2)
#define SA_VH (SA_KL + NTOKP*ASTR*2)
#define SA_VL (SA_VH + 64*VSTR*2)
#define ATTN_SMEM (SA_VL + 64*VSTR*2)

__global__ void __launch_bounds__(256, 1)
attn_mma_kernel(const float* __restrict__ qkv, __half* __restrict__ out) {
    extern __shared__ char asmem[];
    const uint32_t sb = smem_u32(asmem);
    __half* QH = (__half*)(asmem + SA_QH);
    __half* QL = (__half*)(asmem + SA_QL);
    __half* KH = (__half*)(asmem + SA_KH);
    __half* KL = (__half*)(asmem + SA_KL);
    __half* VH = (__half*)(asmem + SA_VH);
    __half* VL = (__half*)(asmem + SA_VL);

    const int bh = blockIdx.x;
    const int b = bh / NHEAD, hh = bh % NHEAD;
    const int tid = threadIdx.x;
    const int lane = tid & 31, wid = tid >> 5;
    const int group = lane >> 2, tq = lane & 3;
    const size_t base = (size_t)b * NTOK * (3 * DD) + hh * HDIM;

    for (int idx = tid; idx < NTOKP * 64; idx += 256) {
        int row = idx >> 6, d = idx & 63;
        float qv = 0.f, kv = 0.f, vv = 0.f;
        if (row < NTOK) {
            size_t o = base + (size_t)row * (3 * DD) + d;
            qv = qkv[o]; kv = qkv[o + DD]; vv = qkv[o + 2 * DD];
        }
        __half h, l;
        splith(qv, h, l); QH[row * ASTR + d] = h; QL[row * ASTR + d] = l;
        splith(kv, h, l); KH[row * ASTR + d] = h; KL[row * ASTR + d] = l;
        splith(vv, h, l); VH[d * VSTR + row] = h; VL[d * VSTR + row] = l;
    }
    __syncthreads();

    const uint32_t a_r = (lane & 7) + ((lane >> 3) & 1) * 8;
    const uint32_t a_c = (lane >> 4) * 8;
    const uint32_t b_r = (lane & 7) + (lane >> 4) * 8;
    const uint32_t b_c = ((lane >> 3) & 1) * 8;

    for (int t = wid; t < 11; t += 8) {
        const int m0 = t * 16;

        uint32_t aq[4][4], aql[4][4];
#pragma unroll
        for (int k = 0; k < 4; k++) {
            uint32_t off = ((m0 + a_r) * ASTR + a_c + k * 16) * 2;
            ldsm4(aq[k], sb + SA_QH + off);
            ldsm4(aql[k], sb + SA_QL + off);
        }

        float s[22][4];
#pragma unroll
        for (int j = 0; j < 22; j++)
#pragma unroll
            for (int q = 0; q < 4; q++) s[j][q] = 0.f;

#pragma unroll
        for (int nj = 0; nj < 11; nj++) {
            const int n0 = nj * 16;
#pragma unroll
            for (int k = 0; k < 4; k++) {
                uint32_t bkh[4], bkl[4];
                uint32_t off = ((n0 + b_r) * ASTR + b_c + k * 16) * 2;
                ldsm4(bkh, sb + SA_KH + off);
                ldsm4(bkl, sb + SA_KL + off);
                mma_f16(s[2 * nj],     aq[k],  bkh);
                mma_f16(s[2 * nj + 1], aq[k],  bkh + 2);
                mma_f16(s[2 * nj],     aql[k], bkh);
                mma_f16(s[2 * nj + 1], aql[k], bkh + 2);
                mma_f16(s[2 * nj],     aq[k],  bkl);
                mma_f16(s[2 * nj + 1], aq[k],  bkl + 2);
            }
        }

        {
            int c0 = 168 + tq * 2;
            if (c0 >= NTOK)     { s[21][0] = -1e30f; s[21][2] = -1e30f; }
            if (c0 + 1 >= NTOK) { s[21][1] = -1e30f; s[21][3] = -1e30f; }
        }

        float mx0 = -1e30f, mx1 = -1e30f;
#pragma unroll
        for (int j = 0; j < 22; j++) {
            mx0 = fmaxf(mx0, fmaxf(s[j][0], s[j][1]));
            mx1 = fmaxf(mx1, fmaxf(s[j][2], s[j][3]));
        }
        mx0 = fmaxf(mx0, __shfl_xor_sync(0xffffffffu, mx0, 1));
        mx0 = fmaxf(mx0, __shfl_xor_sync(0xffffffffu, mx0, 2));
        mx1 = fmaxf(mx1, __shfl_xor_sync(0xffffffffu, mx1, 1));
        mx1 = fmaxf(mx1, __shfl_xor_sync(0xffffffffu, mx1, 2));

        float rs0 = 0.f, rs1 = 0.f;
#pragma unroll
        for (int j = 0; j < 22; j++) {
            s[j][0] = __expf((s[j][0] - mx0) * 0.125f);
            s[j][1] = __expf((s[j][1] - mx0) * 0.125f);
            s[j][2] = __expf((s[j][2] - mx1) * 0.125f);
            s[j][3] = __expf((s[j][3] - mx1) * 0.125f);
            rs0 += s[j][0] + s[j][1];
            rs1 += s[j][2] + s[j][3];
        }
        rs0 += __shfl_xor_sync(0xffffffffu, rs0, 1);
        rs0 += __shfl_xor_sync(0xffffffffu, rs0, 2);
        rs1 += __shfl_xor_sync(0xffffffffu, rs1, 1);
        rs1 += __shfl_xor_sync(0xffffffffu, rs1, 2);

        float o[8][4];
#pragma unroll
        for (int j = 0; j < 8; j++)
#pragma unroll
            for (int q = 0; q < 4; q++) o[j][q] = 0.f;

#pragma unroll
        for (int kt = 0; kt < 11; kt++) {
            uint32_t ap[4], apl[4];
#pragma unroll
            for (int half = 0; half < 2; half++) {
                const float* sv = s[2 * kt + half];
                __half h0 = __float2half(sv[0]), h1 = __float2half(sv[1]);
                __half h2v = __float2half(sv[2]), h3 = __float2half(sv[3]);
                ap[2 * half]     = pack_h2(__half2float(h0), __half2float(h1));
                ap[2 * half + 1] = pack_h2(__half2float(h2v), __half2float(h3));
                apl[2 * half]     = pack_h2(sv[0] - __half2float(h0), sv[1] - __half2float(h1));
                apl[2 * half + 1] = pack_h2(sv[2] - __half2float(h2v), sv[3] - __half2float(h3));
            }
#pragma unroll
            for (int dj = 0; dj < 4; dj++) {
                const int d0 = dj * 16;
                uint32_t bvh[4], bvl[4];
                uint32_t off = ((d0 + b_r) * VSTR + b_c + kt * 16) * 2;
                ldsm4(bvh, sb + SA_VH + off);
                ldsm4(bvl, sb + SA_VL + off);
                mma_f16(o[2 * dj],     ap,  bvh);
                mma_f16(o[2 * dj + 1], ap,  bvh + 2);
                mma_f16(o[2 * dj],     apl, bvh);
                mma_f16(o[2 * dj + 1], apl, bvh + 2);
                mma_f16(o[2 * dj],     ap,  bvl);
                mma_f16(o[2 * dj + 1], ap,  bvl + 2);
            }
        }

        const float i0 = 1.f / rs0, i1 = 1.f / rs1;
        const int r0 = m0 + group, r1 = r0 + 8;
#pragma unroll
        for (int j = 0; j < 8; j++) {
            int d = 8 * j + tq * 2;
            if (r0 < NTOK) {
                __half2 hv = __floats2half2_rn(o[j][0] * i0, o[j][1] * i0);
                *(__half2*)(out + (size_t)(b * NTOK + r0) * DD + hh * HDIM + d) = hv;
            }
            if (r1 < NTOK) {
                __half2 hv = __floats2half2_rn(o[j][2] * i1, o[j][3] * i1);
                *(__half2*)(out + (size_t)(b * NTOK + r1) * DD + hh * HDIM + d) = hv;
            }
        }
    }
}

// ---------------- head ----------------
__global__ void head_kernel(const float* __restrict__ cls, const float* __restrict__ hw,
                            const float* __restrict__ hb, float* __restrict__ out) {
    int b = blockIdx.x;
    int tid = threadIdx.x;
    float a0 = 0.f, a1 = 0.f, a2 = 0.f;
    for (int d = tid; d < DD; d += 256) {
        float v = cls[b * DD + d];
        a0 += v * hw[d * 3 + 0];
        a1 += v * hw[d * 3 + 1];
        a2 += v * hw[d * 3 + 2];
    }
    int lane = tid & 31, warp = tid >> 5;
#pragma unroll
    for (int off = 16; off; off >>= 1) {
        a0 += __shfl_down_sync(0xffffffffu, a0, off);
        a1 += __shfl_down_sync(0xffffffffu, a1, off);
        a2 += __shfl_down_sync(0xffffffffu, a2, off);
    }
    __shared__ float s0[8], s1[8], s2[8];
    if (lane == 0) { s0[warp] = a0; s1[warp] = a1; s2[warp] = a2; }
    __syncthreads();
    if (warp == 0 && lane < 8) {
        a0 = s0[lane]; a1 = s1[lane]; a2 = s2[lane];
#pragma unroll
        for (int off = 4; off; off >>= 1) {
            a0 += __shfl_down_sync(0x000000ffu, a0, off);
            a1 += __shfl_down_sync(0x000000ffu, a1, off);
            a2 += __shfl_down_sync(0x000000ffu, a2, off);
        }
        if (lane == 0) {
            out[b * 3 + 0] = a0 + hb[0];
            out[b * 3 + 1] = a1 + hb[1];
            out[b * 3 + 2] = a2 + hb[2];
        }
    }
}

// ---------------- launcher ----------------
extern "C" void kernel_launch(void* const* d_in, const int* in_sizes, int n_in,
                              void* d_out, int out_size) {
    const float* x        = (const float*)d_in[0];
    const float* conv_w   = (const float*)d_in[1];
    const float* conv_b   = (const float*)d_in[2];
    const float* cls_tok  = (const float*)d_in[3];
    const float* pos      = (const float*)d_in[4];
    const float* ln1_w    = (const float*)d_in[5];
    const float* ln1_b    = (const float*)d_in[6];
    const float* qkv_w    = (const float*)d_in[7];
    const float* qkv_b    = (const float*)d_in[8];
    const float* proj_w   = (const float*)d_in[9];
    const float* proj_b   = (const float*)d_in[10];
    const float* ln2_w    = (const float*)d_in[11];
    const float* ln2_b    = (const float*)d_in[12];
    const float* fc1_w    = (const float*)d_in[13];
    const float* fc1_b    = (const float*)d_in[14];
    const float* fc2_w    = (const float*)d_in[15];
    const float* fc2_b    = (const float*)d_in[16];
    const float* norm_w   = (const float*)d_in[17];
    const float* norm_b   = (const float*)d_in[18];
    const float* head_w   = (const float*)d_in[19];
    const float* head_b   = (const float*)d_in[20];
    float* out = (float*)d_out;

    float *col, *wt, *conv, *h, *clsb, *qkvf;
    __half *yf, *af, *bigf;
    __half *qkvWh, *qkvWl, *projWh, *projWl, *fc1Wh, *fc1Wl, *fc2Wh, *fc2Wl;
    cudaGetSymbolAddress((void**)&col, g_col);
    cudaGetSymbolAddress((void**)&wt, g_wt);
    cudaGetSymbolAddress((void**)&conv, g_conv);
    cudaGetSymbolAddress((void**)&h, g_h);
    cudaGetSymbolAddress((void**)&clsb, g_cls);
    cudaGetSymbolAddress((void**)&qkvf, g_qkvf);
    cudaGetSymbolAddress((void**)&yf, g_yf);
    cudaGetSymbolAddress((void**)&af, g_af);
    cudaGetSymbolAddress((void**)&bigf, g_bigf);
    cudaGetSymbolAddress((void**)&qkvWh, g_qkvWh);
    cudaGetSymbolAddress((void**)&qkvWl, g_qkvWl);
    cudaGetSymbolAddress((void**)&projWh, g_projWh);
    cudaGetSymbolAddress((void**)&projWl, g_projWl);
    cudaGetSymbolAddress((void**)&fc1Wh, g_fc1Wh);
    cudaGetSymbolAddress((void**)&fc1Wl, g_fc1Wl);
    cudaGetSymbolAddress((void**)&fc2Wh, g_fc2Wh);
    cudaGetSymbolAddress((void**)&fc2Wl, g_fc2Wl);

    cudaFuncSetAttribute(attn_mma_kernel, cudaFuncAttributeMaxDynamicSharedMemorySize, ATTN_SMEM);
    cudaFuncSetAttribute(hmma_gemm<false, false, false, false>, cudaFuncAttributeMaxDynamicSharedMemorySize, SMTOT1);
    cudaFuncSetAttribute(hmma_gemm<false, false, false, true>, cudaFuncAttributeMaxDynamicSharedMemorySize, SMTOT1);
    cudaFuncSetAttribute(hmma_gemm<false, true, true, false>, cudaFuncAttributeMaxDynamicSharedMemorySize, SMTOT1);

    // weight transpose + fp16 split (Wl kept for per-GEMM accuracy fallback)
    transpose_split<<<dim3(3 * DD / 32, DD / 32, DEPTH), dim3(32, 8)>>>(qkv_w, qkvWh, qkvWl, DD, 3 * DD);
    transpose_split<<<dim3(DD / 32, DD / 32, DEPTH), dim3(32, 8)>>>(proj_w, projWh, projWl, DD, DD);
    transpose_split<<<dim3(4 * DD / 32, DD / 32, DEPTH), dim3(32, 8)>>>(fc1_w, fc1Wh, fc1Wl, DD, 4 * DD);
    transpose_split<<<dim3(DD / 32, 4 * DD / 32, DEPTH), dim3(32, 8)>>>(fc2_w, fc2Wh, fc2Wl, 4 * DD, DD);

    // patch embed (fp32 exact)
    im2col_kernel<<<(CROWS * KCONV + 255) / 256, 256>>>(x, col);
    transw_kernel<<<(KCONV * DD + 255) / 256, 256>>>(conv_w, wt);
    sgemm_kernel<<<dim3(DD / BN, CROWS / BM), 256>>>(col, wt, conv_b, conv, CROWS, DD, KCONV);
    assemble_kernel<<<(MROWS * DD + 255) / 256, 256>>>(conv, cls_tok, pos, h);

    const int MT = MPAD / 128;  // 86
    for (int i = 0; i < DEPTH; i++) {
        ln_f16_kernel<<<MROWS, 256>>>(h, ln1_w + (size_t)i * DD, ln1_b + (size_t)i * DD, yf);
        hmma_gemm<false, false, false, false><<<dim3(3 * DD / 128, MT), 256, SMTOT1>>>(
            yf, qkvWh + (size_t)i * 3 * DD * DD, qkvWl + (size_t)i * 3 * DD * DD,
            qkv_b + (size_t)i * 3 * DD, nullptr, qkvf, nullptr, MROWS, 3 * DD, DD);
        attn_mma_kernel<<<BATCH * NHEAD, 256, ATTN_SMEM>>>(qkvf, af);
        hmma_gemm<false, false, false, true><<<dim3(DD / 128, MT), 256, SMTOT1>>>(
            af, projWh + (size_t)i * DD * DD, projWl + (size_t)i * DD * DD,
            proj_b + (size_t)i * DD, h, h, nullptr, MROWS, DD, DD);
        ln_f16_kernel<<<MROWS, 256>>>(h, ln2_w + (size_t)i * DD, ln2_b + (size_t)i * DD, yf);
        hmma_gemm<false, true, true, false><<<dim3(4 * DD / 128, MT), 256, SMTOT1>>>(
            yf, fc1Wh + (size_t)i * 4 * DD * DD, fc1Wl + (size_t)i * 4 * DD * DD,
            fc1_b + (size_t)i * 4 * DD, nullptr, nullptr, bigf, MROWS, 4 * DD, DD);
        hmma_gemm<false, false, false, true><<<dim3(DD / 128, MT), 256, SMTOT1>>>(
            bigf, fc2Wh + (size_t)i * 4 * DD * DD, fc2Wl + (size_t)i * 4 * DD * DD,
            fc2_b + (size_t)i * DD, h, h, nullptr, MROWS, DD, 4 * DD);
    }

    ln_kernel<<<BATCH, 256>>>(h, norm_w, norm_b, clsb, NTOK);
    head_kernel<<<BATCH, 256>>>(clsb, head_w, head_b, out);
}

// round 10
// speedup vs baseline: 6.4370x; 1.0902x over previous
#include <cuda_runtime.h>
#include <cuda_fp16.h>
#include <math.h>
#include <stdint.h>

// ---------------- problem constants ----------------
#define DD     768
#define NTOK   171
#define BATCH  64
#define MROWS  (BATCH*NTOK)      // 10944
#define MPAD   11008             // 86*128
#define NPATCH 170
#define CROWS  (BATCH*NPATCH)    // 10880
#define KCONV  600
#define NHEAD  12
#define HDIM   64
#define DEPTH  12
#define EPS    1e-5f

// ---------------- scratch (device globals) ----------------
__device__ float g_col [CROWS * KCONV];
__device__ float g_wt  [KCONV * DD];
__device__ float g_conv[CROWS * DD];
__device__ float g_h   [MROWS * DD];
__device__ float g_cls [BATCH * DD];
__device__ float g_qkvf[MPAD * 3 * DD];
__device__ __half g_yf   [MPAD * DD];
__device__ __half g_af   [MPAD * DD];
__device__ __half g_bigf [MPAD * 4 * DD];
__device__ __half g_qkvWh[DEPTH * 3 * DD * DD];
__device__ __half g_projWh[DEPTH * DD * DD];
__device__ __half g_fc1Wh[DEPTH * 4 * DD * DD];
__device__ __half g_fc2Wh[DEPTH * 4 * DD * DD];

// ---------------- helpers ----------------
__device__ __forceinline__ uint32_t smem_u32(const void* p) {
    uint32_t a;
    asm("{ .reg .u64 t; cvta.to.shared.u64 t, %1; cvt.u32.u64 %0, t; }" : "=r"(a) : "l"(p));
    return a;
}
__device__ __forceinline__ void cp_async16(uint32_t dst, const void* src) {
    asm volatile("cp.async.cg.shared.global [%0], [%1], 16;"
                 :: "r"(dst), "l"(src) : "memory");
}
__device__ __forceinline__ void cp_commit() {
    asm volatile("cp.async.commit_group;" ::: "memory");
}
template <int N>
__device__ __forceinline__ void cp_wait() {
    asm volatile("cp.async.wait_group %0;" :: "n"(N) : "memory");
}
__device__ __forceinline__ void ldsm4(uint32_t* r, uint32_t addr) {
    asm volatile("ldmatrix.sync.aligned.m8n8.x4.shared.b16 {%0,%1,%2,%3}, [%4];"
                 : "=r"(r[0]), "=r"(r[1]), "=r"(r[2]), "=r"(r[3]) : "r"(addr));
}
__device__ __forceinline__ void mma_f16(float* c, const uint32_t* a, const uint32_t* b) {
    asm volatile(
        "mma.sync.aligned.m16n8k16.row.col.f32.f16.f16.f32 "
        "{%0,%1,%2,%3}, {%4,%5,%6,%7}, {%8,%9}, {%0,%1,%2,%3};"
        : "+f"(c[0]), "+f"(c[1]), "+f"(c[2]), "+f"(c[3])
        : "r"(a[0]), "r"(a[1]), "r"(a[2]), "r"(a[3]), "r"(b[0]), "r"(b[1]));
}
__device__ __forceinline__ void splith(float v, __half& hi, __half& lo) {
    hi = __float2half(v);
    lo = __float2half(v - __half2float(hi));
}
__device__ __forceinline__ uint32_t pack_h2(float a, float b) {
    __half2 h = __floats2half2_rn(a, b);
    return *(uint32_t*)&h;
}

// ---------------- fp16 GEMM: C = A @ Wh^T (single product, 2 CTAs/SM, 1 sync/kt) ----------------
#define GSTR 40
#define TILEB (128 * GSTR * 2)
#define STG (2 * TILEB)          // A + Wh per stage
#define NST 4
#define SMTOT1 (NST * STG)       // 81920 B/CTA

template <bool OUTF16, bool GELU_, bool RES>
__global__ void __launch_bounds__(256, 2)
hmma_gemm(const __half* __restrict__ A, const __half* __restrict__ Wh,
          const float* __restrict__ bias, const float* __restrict__ res,
          float* __restrict__ Cf, __half* __restrict__ Ch,
          int Mvalid, int Ntot, int K) {
    extern __shared__ char dsm[];
    const uint32_t sb = smem_u32(dsm);

    const int tid = threadIdx.x;
    const int lane = tid & 31, wid = tid >> 5;
    const int wm = wid & 1, wn = wid >> 1;
    const int group = lane >> 2, tq = lane & 3;
    const int m0 = blockIdx.y * 128;
    const int n0 = blockIdx.x * 128;
    const int KT = K >> 5;

    const __half* gA = A + (size_t)m0 * K;
    const __half* gWh = Wh + (size_t)n0 * K;

    float acc[4][4][4];
#pragma unroll
    for (int mi = 0; mi < 4; mi++)
#pragma unroll
        for (int ni = 0; ni < 4; ni++)
#pragma unroll
            for (int q = 0; q < 4; q++) acc[mi][ni][q] = 0.f;

    const int lr = tid >> 2;
    const int lc = tid & 3;

    auto load_stage = [&](int kt, int st) {
        const size_t koff = (size_t)kt * 32;
        uint32_t base = sb + st * STG;
#pragma unroll
        for (int i = 0; i < 2; i++) {
            int r = lr + i * 64;
            uint32_t so = (r * GSTR + lc * 8) * 2;
            size_t go = (size_t)r * K + koff + lc * 8;
            cp_async16(base + 0 * TILEB + so, gA + go);
            cp_async16(base + 1 * TILEB + so, gWh + go);
        }
        cp_commit();
    };

    const uint32_t arow = wm * 64 + (lane & 7) + ((lane >> 3) & 1) * 8;
    const uint32_t acol = (lane >> 4) * 8;
    const uint32_t aoff = (arow * GSTR + acol) * 2;
    const uint32_t brow = wn * 32 + (lane & 7) + (lane >> 4) * 8;
    const uint32_t bcol = ((lane >> 3) & 1) * 8;
    const uint32_t boff = (brow * GSTR + bcol) * 2;

    // prologue: 3 stages in flight (KT >= 24 always here)
    load_stage(0, 0);
    load_stage(1, 1);
    load_stage(2, 2);

#pragma unroll 1
    for (int kt = 0; kt < KT; kt++) {
        // wait for stage kt (allow later groups outstanding), then make visible
        if (kt + 2 < KT)      cp_wait<2>();
        else if (kt + 1 < KT) cp_wait<1>();
        else                  cp_wait<0>();
        __syncthreads();   // visibility of stage kt to all warps; also proves
                           // all warps finished compute(kt-1) -> safe to overwrite
                           // buf (kt+3)%4 == (kt-1)%4 after this point.

        const uint32_t stbase = sb + (kt & 3) * STG;
        const uint32_t aA = stbase + aoff;
        const uint32_t bH = stbase + TILEB + boff;

#pragma unroll
        for (int ks = 0; ks < 2; ks++) {
            const uint32_t kadd = ks * 32;
            uint32_t af[16], bh[8];
#pragma unroll
            for (int mi = 0; mi < 4; mi++)
                ldsm4(af + mi * 4, aA + mi * (16 * GSTR * 2) + kadd);
#pragma unroll
            for (int nj = 0; nj < 2; nj++)
                ldsm4(bh + nj * 4, bH + nj * (16 * GSTR * 2) + kadd);
#pragma unroll
            for (int mi = 0; mi < 4; mi++)
#pragma unroll
                for (int ni = 0; ni < 4; ni++)
                    mma_f16(acc[mi][ni], af + mi * 4, bh + ni * 2);
        }

        if (kt + 3 < KT) load_stage(kt + 3, (kt + 3) & 3);
    }

#pragma unroll
    for (int mi = 0; mi < 4; mi++) {
#pragma unroll
        for (int rr = 0; rr < 2; rr++) {
            int m = m0 + wm * 64 + mi * 16 + group + rr * 8;
            if (m >= Mvalid) continue;
#pragma unroll
            for (int ni = 0; ni < 4; ni++) {
                int n = n0 + wn * 32 + ni * 8 + tq * 2;
                float v0 = acc[mi][ni][rr * 2 + 0] + bias[n];
                float v1 = acc[mi][ni][rr * 2 + 1] + bias[n + 1];
                if (GELU_) {
                    v0 = 0.5f * v0 * (1.f + erff(v0 * 0.70710678118654752f));
                    v1 = 0.5f * v1 * (1.f + erff(v1 * 0.70710678118654752f));
                }
                if (RES) {
                    float2 rv = *(const float2*)(res + (size_t)m * Ntot + n);
                    v0 += rv.x; v1 += rv.y;
                }
                if (OUTF16) {
                    __half2 h2 = __floats2half2_rn(v0, v1);
                    *(__half2*)(Ch + (size_t)m * Ntot + n) = h2;
                } else {
                    *(float2*)(Cf + (size_t)m * Ntot + n) = make_float2(v0, v1);
                }
            }
        }
    }
}

// ---------------- weight transpose -> fp16 (hi only) ----------------
__global__ void transpose_hi(const float* __restrict__ W, __half* __restrict__ Wh,
                             int R, int C) {
    __shared__ float t[32][33];
    int z = blockIdx.z;
    const float* Wz = W + (size_t)z * R * C;
    __half* Whz = Wh + (size_t)z * R * C;
    int c0 = blockIdx.x * 32, r0 = blockIdx.y * 32;
    int x = threadIdx.x, y = threadIdx.y;
#pragma unroll
    for (int i = 0; i < 32; i += 8)
        t[y + i][x] = Wz[(size_t)(r0 + y + i) * C + c0 + x];
    __syncthreads();
#pragma unroll
    for (int i = 0; i < 32; i += 8)
        Whz[(size_t)(c0 + y + i) * R + r0 + x] = __float2half(t[x][y + i]);
}

// ---------------- im2col / conv / assemble ----------------
__global__ void im2col_kernel(const float* __restrict__ x, float* __restrict__ col) {
    int idx = blockIdx.x * blockDim.x + threadIdx.x;
    if (idx >= CROWS * KCONV) return;
    int r = idx / KCONV, c = idx % KCONV;
    int b = r / NPATCH, p = r % NPATCH;
    int chn = c / 100, rem = c % 100;
    int kh = rem / 10, kw = rem % 10;
    int phh = p / 34, pw = p % 34;
    col[idx] = x[((b * 6 + chn) * 50 + phh * 10 + kh) * 345 + pw * 10 + kw];
}

__global__ void transw_kernel(const float* __restrict__ w, float* __restrict__ wt) {
    int idx = blockIdx.x * blockDim.x + threadIdx.x;
    if (idx >= KCONV * DD) return;
    int k = idx / DD, d = idx % DD;
    wt[idx] = w[d * KCONV + k];
}

__global__ void assemble_kernel(const float* __restrict__ conv_out,
                                const float* __restrict__ cls,
                                const float* __restrict__ pos,
                                float* __restrict__ h) {
    int idx = blockIdx.x * blockDim.x + threadIdx.x;
    if (idx >= MROWS * DD) return;
    int row = idx / DD, d = idx % DD;
    int b = row / NTOK, t = row % NTOK;
    float v = (t == 0) ? cls[d] : conv_out[(b * NPATCH + t - 1) * DD + d];
    h[idx] = v + pos[t * DD + d];
}

// ---------------- fp32 SGEMM (conv patch-embed only) ----------------
#define BM 64
#define BN 64
#define BK 16
__global__ void sgemm_kernel(const float* __restrict__ A, const float* __restrict__ B,
                             const float* __restrict__ bias, float* C, int M, int N, int K) {
    __shared__ float As[BK][BM + 4];
    __shared__ float Bs[BK][BN];
    int tid = threadIdx.x;
    int m0 = blockIdx.y * BM, n0 = blockIdx.x * BN;
    int tx = tid & 15, ty = tid >> 4;
    float acc[4][4];
#pragma unroll
    for (int i = 0; i < 4; i++)
#pragma unroll
        for (int j = 0; j < 4; j++) acc[i][j] = 0.f;
    for (int k0 = 0; k0 < K; k0 += BK) {
#pragma unroll
        for (int i = 0; i < 4; i++) {
            int idx = tid + i * 256;
            int ar = idx >> 4, ac = idx & 15;
            int gr = m0 + ar, gc = k0 + ac;
            float v = 0.f;
            if (gr < M && gc < K) v = A[(size_t)gr * K + gc];
            As[ac][ar] = v;
        }
#pragma unroll
        for (int i = 0; i < 4; i++) {
            int idx = tid + i * 256;
            int br = idx >> 6, bc = idx & 63;
            int gr = k0 + br, gc = n0 + bc;
            float v = 0.f;
            if (gr < K && gc < N) v = B[(size_t)gr * N + gc];
            Bs[br][bc] = v;
        }
        __syncthreads();
#pragma unroll
        for (int kk = 0; kk < BK; kk++) {
            float4 a4 = *reinterpret_cast<const float4*>(&As[kk][ty * 4]);
            float4 b4 = *reinterpret_cast<const float4*>(&Bs[kk][tx * 4]);
            float a[4] = {a4.x, a4.y, a4.z, a4.w};
            float bb[4] = {b4.x, b4.y, b4.z, b4.w};
#pragma unroll
            for (int i = 0; i < 4; i++)
#pragma unroll
                for (int j = 0; j < 4; j++) acc[i][j] += a[i] * bb[j];
        }
        __syncthreads();
    }
#pragma unroll
    for (int i = 0; i < 4; i++) {
        int m = m0 + ty * 4 + i;
        if (m >= M) continue;
#pragma unroll
        for (int j = 0; j < 4; j++) {
            int n = n0 + tx * 4 + j;
            if (n >= N) continue;
            C[(size_t)m * N + n] = acc[i][j] + bias[n];
        }
    }
}

// ---------------- LayerNorm fp32 -> fp16 ----------------
__global__ void ln_f16_kernel(const float* __restrict__ X, const float* __restrict__ w,
                              const float* __restrict__ b, __half* __restrict__ Y) {
    int row = blockIdx.x;
    int tid = threadIdx.x;
    const float* xr = X + (size_t)row * DD;
    float v0 = xr[tid], v1 = xr[tid + 256], v2 = xr[tid + 512];
    float s = v0 + v1 + v2;
    float q = v0 * v0 + v1 * v1 + v2 * v2;
    int lane = tid & 31, warp = tid >> 5;
#pragma unroll
    for (int off = 16; off; off >>= 1) {
        s += __shfl_down_sync(0xffffffffu, s, off);
        q += __shfl_down_sync(0xffffffffu, q, off);
    }
    __shared__ float sa[8], sbm[8];
    if (lane == 0) { sa[warp] = s; sbm[warp] = q; }
    __syncthreads();
    if (warp == 0) {
        s = (lane < 8) ? sa[lane] : 0.f;
        q = (lane < 8) ? sbm[lane] : 0.f;
#pragma unroll
        for (int off = 4; off; off >>= 1) {
            s += __shfl_down_sync(0xffffffffu, s, off);
            q += __shfl_down_sync(0xffffffffu, q, off);
        }
        if (lane == 0) { sa[0] = s; sbm[0] = q; }
    }
    __syncthreads();
    float mean = sa[0] * (1.f / DD);
    float var = sbm[0] * (1.f / DD) - mean * mean;
    float inv = rsqrtf(var + EPS);
    __half* yr = Y + (size_t)row * DD;
    yr[tid]       = __float2half((v0 - mean) * inv * w[tid]       + b[tid]);
    yr[tid + 256] = __float2half((v1 - mean) * inv * w[tid + 256] + b[tid + 256]);
    yr[tid + 512] = __float2half((v2 - mean) * inv * w[tid + 512] + b[tid + 512]);
}

// ---------------- LayerNorm fp32 -> fp32 (final, cls rows) ----------------
__global__ void ln_kernel(const float* __restrict__ X, const float* __restrict__ w,
                          const float* __restrict__ b, float* __restrict__ Y, int row_mul) {
    int row_in = blockIdx.x * row_mul;
    int row_out = blockIdx.x;
    int tid = threadIdx.x;
    const float* xr = X + (size_t)row_in * DD;
    float v0 = xr[tid], v1 = xr[tid + 256], v2 = xr[tid + 512];
    float s = v0 + v1 + v2;
    float q = v0 * v0 + v1 * v1 + v2 * v2;
    int lane = tid & 31, warp = tid >> 5;
#pragma unroll
    for (int off = 16; off; off >>= 1) {
        s += __shfl_down_sync(0xffffffffu, s, off);
        q += __shfl_down_sync(0xffffffffu, q, off);
    }
    __shared__ float sa[8], sbm[8];
    if (lane == 0) { sa[warp] = s; sbm[warp] = q; }
    __syncthreads();
    if (warp == 0) {
        s = (lane < 8) ? sa[lane] : 0.f;
        q = (lane < 8) ? sbm[lane] : 0.f;
#pragma unroll
        for (int off = 4; off; off >>= 1) {
            s += __shfl_down_sync(0xffffffffu, s, off);
            q += __shfl_down_sync(0xffffffffu, q, off);
        }
        if (lane == 0) { sa[0] = s; sbm[0] = q; }
    }
    __syncthreads();
    float mean = sa[0] * (1.f / DD);
    float var = sbm[0] * (1.f / DD) - mean * mean;
    float inv = rsqrtf(var + EPS);
    float* yr = Y + (size_t)row_out * DD;
    yr[tid]       = (v0 - mean) * inv * w[tid]       + b[tid];
    yr[tid + 256] = (v1 - mean) * inv * w[tid + 256] + b[tid + 256];
    yr[tid + 512] = (v2 - mean) * inv * w[tid + 512] + b[tid + 512];
}

// ---------------- MMA attention (split fp16, ~fp32 exact) ----------------
#define NTOKP 176
#define ASTR 72
#define VSTR 184
#define SA_QH 0
#define SA_QL (SA_QH + NTOKP*ASTR*2)
#define SA_KH (SA_QL + NTOKP*ASTR*2)
#define SA_KL (SA_KH + NTOKP*ASTR*2)
#define SA_VH (SA_KL + NTOKP*ASTR*2)
#define SA_VL (SA_VH + 64*VSTR*2)
#define ATTN_SMEM (SA_VL + 64*VSTR*2)

__global__ void __launch_bounds__(256, 1)
attn_mma_kernel(const float* __restrict__ qkv, __half* __restrict__ out) {
    extern __shared__ char asmem[];
    const uint32_t sb = smem_u32(asmem);
    __half* QH = (__half*)(asmem + SA_QH);
    __half* QL = (__half*)(asmem + SA_QL);
    __half* KH = (__half*)(asmem + SA_KH);
    __half* KL = (__half*)(asmem + SA_KL);
    __half* VH = (__half*)(asmem + SA_VH);
    __half* VL = (__half*)(asmem + SA_VL);

    const int bh = blockIdx.x;
    const int b = bh / NHEAD, hh = bh % NHEAD;
    const int tid = threadIdx.x;
    const int lane = tid & 31, wid = tid >> 5;
    const int group = lane >> 2, tq = lane & 3;
    const size_t base = (size_t)b * NTOK * (3 * DD) + hh * HDIM;

    for (int idx = tid; idx < NTOKP * 64; idx += 256) {
        int row = idx >> 6, d = idx & 63;
        float qv = 0.f, kv = 0.f, vv = 0.f;
        if (row < NTOK) {
            size_t o = base + (size_t)row * (3 * DD) + d;
            qv = qkv[o]; kv = qkv[o + DD]; vv = qkv[o + 2 * DD];
        }
        __half h, l;
        splith(qv, h, l); QH[row * ASTR + d] = h; QL[row * ASTR + d] = l;
        splith(kv, h, l); KH[row * ASTR + d] = h; KL[row * ASTR + d] = l;
        splith(vv, h, l); VH[d * VSTR + row] = h; VL[d * VSTR + row] = l;
    }
    __syncthreads();

    const uint32_t a_r = (lane & 7) + ((lane >> 3) & 1) * 8;
    const uint32_t a_c = (lane >> 4) * 8;
    const uint32_t b_r = (lane & 7) + (lane >> 4) * 8;
    const uint32_t b_c = ((lane >> 3) & 1) * 8;

    for (int t = wid; t < 11; t += 8) {
        const int m0 = t * 16;

        uint32_t aq[4][4], aql[4][4];
#pragma unroll
        for (int k = 0; k < 4; k++) {
            uint32_t off = ((m0 + a_r) * ASTR + a_c + k * 16) * 2;
            ldsm4(aq[k], sb + SA_QH + off);
            ldsm4(aql[k], sb + SA_QL + off);
        }

        float s[22][4];
#pragma unroll
        for (int j = 0; j < 22; j++)
#pragma unroll
            for (int q = 0; q < 4; q++) s[j][q] = 0.f;

#pragma unroll
        for (int nj = 0; nj < 11; nj++) {
            const int n0 = nj * 16;
#pragma unroll
            for (int k = 0; k < 4; k++) {
                uint32_t bkh[4], bkl[4];
                uint32_t off = ((n0 + b_r) * ASTR + b_c + k * 16) * 2;
                ldsm4(bkh, sb + SA_KH + off);
                ldsm4(bkl, sb + SA_KL + off);
                mma_f16(s[2 * nj],     aq[k],  bkh);
                mma_f16(s[2 * nj + 1], aq[k],  bkh + 2);
                mma_f16(s[2 * nj],     aql[k], bkh);
                mma_f16(s[2 * nj + 1], aql[k], bkh + 2);
                mma_f16(s[2 * nj],     aq[k],  bkl);
                mma_f16(s[2 * nj + 1], aq[k],  bkl + 2);
            }
        }

        {
            int c0 = 168 + tq * 2;
            if (c0 >= NTOK)     { s[21][0] = -1e30f; s[21][2] = -1e30f; }
            if (c0 + 1 >= NTOK) { s[21][1] = -1e30f; s[21][3] = -1e30f; }
        }

        float mx0 = -1e30f, mx1 = -1e30f;
#pragma unroll
        for (int j = 0; j < 22; j++) {
            mx0 = fmaxf(mx0, fmaxf(s[j][0], s[j][1]));
            mx1 = fmaxf(mx1, fmaxf(s[j][2], s[j][3]));
        }
        mx0 = fmaxf(mx0, __shfl_xor_sync(0xffffffffu, mx0, 1));
        mx0 = fmaxf(mx0, __shfl_xor_sync(0xffffffffu, mx0, 2));
        mx1 = fmaxf(mx1, __shfl_xor_sync(0xffffffffu, mx1, 1));
        mx1 = fmaxf(mx1, __shfl_xor_sync(0xffffffffu, mx1, 2));

        float rs0 = 0.f, rs1 = 0.f;
#pragma unroll
        for (int j = 0; j < 22; j++) {
            s[j][0] = __expf((s[j][0] - mx0) * 0.125f);
            s[j][1] = __expf((s[j][1] - mx0) * 0.125f);
            s[j][2] = __expf((s[j][2] - mx1) * 0.125f);
            s[j][3] = __expf((s[j][3] - mx1) * 0.125f);
            rs0 += s[j][0] + s[j][1];
            rs1 += s[j][2] + s[j][3];
        }
        rs0 += __shfl_xor_sync(0xffffffffu, rs0, 1);
        rs0 += __shfl_xor_sync(0xffffffffu, rs0, 2);
        rs1 += __shfl_xor_sync(0xffffffffu, rs1, 1);
        rs1 += __shfl_xor_sync(0xffffffffu, rs1, 2);

        float o[8][4];
#pragma unroll
        for (int j = 0; j < 8; j++)
#pragma unroll
            for (int q = 0; q < 4; q++) o[j][q] = 0.f;

#pragma unroll
        for (int kt = 0; kt < 11; kt++) {
            uint32_t ap[4], apl[4];
#pragma unroll
            for (int half = 0; half < 2; half++) {
                const float* sv = s[2 * kt + half];
                __half h0 = __float2half(sv[0]), h1 = __float2half(sv[1]);
                __half h2v = __float2half(sv[2]), h3 = __float2half(sv[3]);
                ap[2 * half]     = pack_h2(__half2float(h0), __half2float(h1));
                ap[2 * half + 1] = pack_h2(__half2float(h2v), __half2float(h3));
                apl[2 * half]     = pack_h2(sv[0] - __half2float(h0), sv[1] - __half2float(h1));
                apl[2 * half + 1] = pack_h2(sv[2] - __half2float(h2v), sv[3] - __half2float(h3));
            }
#pragma unroll
            for (int dj = 0; dj < 4; dj++) {
                const int d0 = dj * 16;
                uint32_t bvh[4], bvl[4];
                uint32_t off = ((d0 + b_r) * VSTR + b_c + kt * 16) * 2;
                ldsm4(bvh, sb + SA_VH + off);
                ldsm4(bvl, sb + SA_VL + off);
                mma_f16(o[2 * dj],     ap,  bvh);
                mma_f16(o[2 * dj + 1], ap,  bvh + 2);
                mma_f16(o[2 * dj],     apl, bvh);
                mma_f16(o[2 * dj + 1], apl, bvh + 2);
                mma_f16(o[2 * dj],     ap,  bvl);
                mma_f16(o[2 * dj + 1], ap,  bvl + 2);
            }
        }

        const float i0 = 1.f / rs0, i1 = 1.f / rs1;
        const int r0 = m0 + group, r1 = r0 + 8;
#pragma unroll
        for (int j = 0; j < 8; j++) {
            int d = 8 * j + tq * 2;
            if (r0 < NTOK) {
                __half2 hv = __floats2half2_rn(o[j][0] * i0, o[j][1] * i0);
                *(__half2*)(out + (size_t)(b * NTOK + r0) * DD + hh * HDIM + d) = hv;
            }
            if (r1 < NTOK) {
                __half2 hv = __floats2half2_rn(o[j][2] * i1, o[j][3] * i1);
                *(__half2*)(out + (size_t)(b * NTOK + r1) * DD + hh * HDIM + d) = hv;
            }
        }
    }
}

// ---------------- head ----------------
__global__ void head_kernel(const float* __restrict__ cls, const float* __restrict__ hw,
                            const float* __restrict__ hb, float* __restrict__ out) {
    int b = blockIdx.x;
    int tid = threadIdx.x;
    float a0 = 0.f, a1 = 0.f, a2 = 0.f;
    for (int d = tid; d < DD; d += 256) {
        float v = cls[b * DD + d];
        a0 += v * hw[d * 3 + 0];
        a1 += v * hw[d * 3 + 1];
        a2 += v * hw[d * 3 + 2];
    }
    int lane = tid & 31, warp = tid >> 5;
#pragma unroll
    for (int off = 16; off; off >>= 1) {
        a0 += __shfl_down_sync(0xffffffffu, a0, off);
        a1 += __shfl_down_sync(0xffffffffu, a1, off);
        a2 += __shfl_down_sync(0xffffffffu, a2, off);
    }
    __shared__ float s0[8], s1[8], s2[8];
    if (lane == 0) { s0[warp] = a0; s1[warp] = a1; s2[warp] = a2; }
    __syncthreads();
    if (warp == 0 && lane < 8) {
        a0 = s0[lane]; a1 = s1[lane]; a2 = s2[lane];
#pragma unroll
        for (int off = 4; off; off >>= 1) {
            a0 += __shfl_down_sync(0x000000ffu, a0, off);
            a1 += __shfl_down_sync(0x000000ffu, a1, off);
            a2 += __shfl_down_sync(0x000000ffu, a2, off);
        }
        if (lane == 0) {
            out[b * 3 + 0] = a0 + hb[0];
            out[b * 3 + 1] = a1 + hb[1];
            out[b * 3 + 2] = a2 + hb[2];
        }
    }
}

// ---------------- launcher ----------------
extern "C" void kernel_launch(void* const* d_in, const int* in_sizes, int n_in,
                              void* d_out, int out_size) {
    const float* x        = (const float*)d_in[0];
    const float* conv_w   = (const float*)d_in[1];
    const float* conv_b   = (const float*)d_in[2];
    const float* cls_tok  = (const float*)d_in[3];
    const float* pos      = (const float*)d_in[4];
    const float* ln1_w    = (const float*)d_in[5];
    const float* ln1_b    = (const float*)d_in[6];
    const float* qkv_w    = (const float*)d_in[7];
    const float* qkv_b    = (const float*)d_in[8];
    const float* proj_w   = (const float*)d_in[9];
    const float* proj_b   = (const float*)d_in[10];
    const float* ln2_w    = (const float*)d_in[11];
    const float* ln2_b    = (const float*)d_in[12];
    const float* fc1_w    = (const float*)d_in[13];
    const float* fc1_b    = (const float*)d_in[14];
    const float* fc2_w    = (const float*)d_in[15];
    const float* fc2_b    = (const float*)d_in[16];
    const float* norm_w   = (const float*)d_in[17];
    const float* norm_b   = (const float*)d_in[18];
    const float* head_w   = (const float*)d_in[19];
    const float* head_b   = (const float*)d_in[20];
    float* out = (float*)d_out;

    float *col, *wt, *conv, *h, *clsb, *qkvf;
    __half *yf, *af, *bigf;
    __half *qkvWh, *projWh, *fc1Wh, *fc2Wh;
    cudaGetSymbolAddress((void**)&col, g_col);
    cudaGetSymbolAddress((void**)&wt, g_wt);
    cudaGetSymbolAddress((void**)&conv, g_conv);
    cudaGetSymbolAddress((void**)&h, g_h);
    cudaGetSymbolAddress((void**)&clsb, g_cls);
    cudaGetSymbolAddress((void**)&qkvf, g_qkvf);
    cudaGetSymbolAddress((void**)&yf, g_yf);
    cudaGetSymbolAddress((void**)&af, g_af);
    cudaGetSymbolAddress((void**)&bigf, g_bigf);
    cudaGetSymbolAddress((void**)&qkvWh, g_qkvWh);
    cudaGetSymbolAddress((void**)&projWh, g_projWh);
    cudaGetSymbolAddress((void**)&fc1Wh, g_fc1Wh);
    cudaGetSymbolAddress((void**)&fc2Wh, g_fc2Wh);

    cudaFuncSetAttribute(attn_mma_kernel, cudaFuncAttributeMaxDynamicSharedMemorySize, ATTN_SMEM);
    cudaFuncSetAttribute(hmma_gemm<false, false, false>, cudaFuncAttributeMaxDynamicSharedMemorySize, SMTOT1);
    cudaFuncSetAttribute(hmma_gemm<false, false, true>, cudaFuncAttributeMaxDynamicSharedMemorySize, SMTOT1);
    cudaFuncSetAttribute(hmma_gemm<true, true, false>, cudaFuncAttributeMaxDynamicSharedMemorySize, SMTOT1);

    // weight transpose -> fp16 (hi only; lo products no longer used)
    transpose_hi<<<dim3(3 * DD / 32, DD / 32, DEPTH), dim3(32, 8)>>>(qkv_w, qkvWh, DD, 3 * DD);
    transpose_hi<<<dim3(DD / 32, DD / 32, DEPTH), dim3(32, 8)>>>(proj_w, projWh, DD, DD);
    transpose_hi<<<dim3(4 * DD / 32, DD / 32, DEPTH), dim3(32, 8)>>>(fc1_w, fc1Wh, DD, 4 * DD);
    transpose_hi<<<dim3(DD / 32, 4 * DD / 32, DEPTH), dim3(32, 8)>>>(fc2_w, fc2Wh, 4 * DD, DD);

    // patch embed (fp32 exact)
    im2col_kernel<<<(CROWS * KCONV + 255) / 256, 256>>>(x, col);
    transw_kernel<<<(KCONV * DD + 255) / 256, 256>>>(conv_w, wt);
    sgemm_kernel<<<dim3(DD / BN, CROWS / BM), 256>>>(col, wt, conv_b, conv, CROWS, DD, KCONV);
    assemble_kernel<<<(MROWS * DD + 255) / 256, 256>>>(conv, cls_tok, pos, h);

    const int MT = MPAD / 128;  // 86
    for (int i = 0; i < DEPTH; i++) {
        ln_f16_kernel<<<MROWS, 256>>>(h, ln1_w + (size_t)i * DD, ln1_b + (size_t)i * DD, yf);
        hmma_gemm<false, false, false><<<dim3(3 * DD / 128, MT), 256, SMTOT1>>>(
            yf, qkvWh + (size_t)i * 3 * DD * DD,
            qkv_b + (size_t)i * 3 * DD, nullptr, qkvf, nullptr, MROWS, 3 * DD, DD);
        attn_mma_kernel<<<BATCH * NHEAD, 256, ATTN_SMEM>>>(qkvf, af);
        hmma_gemm<false, false, true><<<dim3(DD / 128, MT), 256, SMTOT1>>>(
            af, projWh + (size_t)i * DD * DD,
            proj_b + (size_t)i * DD, h, h, nullptr, MROWS, DD, DD);
        ln_f16_kernel<<<MROWS, 256>>>(h, ln2_w + (size_t)i * DD, ln2_b + (size_t)i * DD, yf);
        hmma_gemm<true, true, false><<<dim3(4 * DD / 128, MT), 256, SMTOT1>>>(
            yf, fc1Wh + (size_t)i * 4 * DD * DD,
            fc1_b + (size_t)i * 4 * DD, nullptr, nullptr, bigf, MROWS, 4 * DD, DD);
        hmma_gemm<false, false, true><<<dim3(DD / 128, MT), 256, SMTOT1>>>(
            bigf, fc2Wh + (size_t)i * 4 * DD * DD,
            fc2_b + (size_t)i * DD, h, h, nullptr, MROWS, DD, 4 * DD);
    }

    ln_kernel<<<BATCH, 256>>>(h, norm_w, norm_b, clsb, NTOK);
    head_kernel<<<BATCH, 256>>>(clsb, head_w, head_b, out);
}

// round 11
// speedup vs baseline: 6.6525x; 1.0335x over previous
#include <cuda_runtime.h>
#include <cuda_fp16.h>
#include <math.h>
#include <stdint.h>

// ---------------- problem constants ----------------
#define DD     768
#define NTOK   171
#define BATCH  64
#define MROWS  (BATCH*NTOK)      // 10944
#define MPAD   11008             // 86*128
#define NPATCH 170
#define CROWS  (BATCH*NPATCH)    // 10880 = 85*128
#define KCONV  600
#define KCPAD  640
#define NHEAD  12
#define HDIM   64
#define DEPTH  12
#define EPS    1e-5f

// ---------------- scratch (device globals) ----------------
__device__ __half g_colh[CROWS * KCPAD];
__device__ __half g_coll[CROWS * KCPAD];
__device__ __half g_convWh[DD * KCPAD];
__device__ float g_h   [MROWS * DD];
__device__ float g_cls [BATCH * DD];
__device__ float g_qkvf[MPAD * 3 * DD];
__device__ __half g_yf   [MPAD * DD];
__device__ __half g_af   [MPAD * DD];
__device__ __half g_bigf [MPAD * 4 * DD];
__device__ __half g_qkvWh[DEPTH * 3 * DD * DD];
__device__ __half g_projWh[DEPTH * DD * DD];
__device__ __half g_fc1Wh[DEPTH * 4 * DD * DD];
__device__ __half g_fc2Wh[DEPTH * 4 * DD * DD];

// ---------------- helpers ----------------
__device__ __forceinline__ uint32_t smem_u32(const void* p) {
    uint32_t a;
    asm("{ .reg .u64 t; cvta.to.shared.u64 t, %1; cvt.u32.u64 %0, t; }" : "=r"(a) : "l"(p));
    return a;
}
__device__ __forceinline__ void cp_async16(uint32_t dst, const void* src) {
    asm volatile("cp.async.cg.shared.global [%0], [%1], 16;"
                 :: "r"(dst), "l"(src) : "memory");
}
__device__ __forceinline__ void cp_commit() {
    asm volatile("cp.async.commit_group;" ::: "memory");
}
template <int N>
__device__ __forceinline__ void cp_wait() {
    asm volatile("cp.async.wait_group %0;" :: "n"(N) : "memory");
}
__device__ __forceinline__ void ldsm4(uint32_t* r, uint32_t addr) {
    asm volatile("ldmatrix.sync.aligned.m8n8.x4.shared.b16 {%0,%1,%2,%3}, [%4];"
                 : "=r"(r[0]), "=r"(r[1]), "=r"(r[2]), "=r"(r[3]) : "r"(addr));
}
__device__ __forceinline__ void mma_f16(float* c, const uint32_t* a, const uint32_t* b) {
    asm volatile(
        "mma.sync.aligned.m16n8k16.row.col.f32.f16.f16.f32 "
        "{%0,%1,%2,%3}, {%4,%5,%6,%7}, {%8,%9}, {%0,%1,%2,%3};"
        : "+f"(c[0]), "+f"(c[1]), "+f"(c[2]), "+f"(c[3])
        : "r"(a[0]), "r"(a[1]), "r"(a[2]), "r"(a[3]), "r"(b[0]), "r"(b[1]));
}
__device__ __forceinline__ void splith(float v, __half& hi, __half& lo) {
    hi = __float2half(v);
    lo = __float2half(v - __half2float(hi));
}
__device__ __forceinline__ uint32_t pack_h2(float a, float b) {
    __half2 h = __floats2half2_rn(a, b);
    return *(uint32_t*)&h;
}

// ---------------- fp16 GEMM: C = A @ Wh^T (single product, 2 CTAs/SM, 1 sync/kt) ----------------
#define GSTR 40
#define TILEB (128 * GSTR * 2)
#define STG (2 * TILEB)
#define NST 4
#define SMTOT1 (NST * STG)       // 81920 B/CTA

template <bool OUTF16, bool GELU_, bool RES>
__global__ void __launch_bounds__(256, 2)
hmma_gemm(const __half* __restrict__ A, const __half* __restrict__ Wh,
          const float* __restrict__ bias, const float* __restrict__ res,
          float* __restrict__ Cf, __half* __restrict__ Ch,
          int Mvalid, int Ntot, int K) {
    extern __shared__ char dsm[];
    const uint32_t sb = smem_u32(dsm);

    const int tid = threadIdx.x;
    const int lane = tid & 31, wid = tid >> 5;
    const int wm = wid & 1, wn = wid >> 1;
    const int group = lane >> 2, tq = lane & 3;
    const int m0 = blockIdx.y * 128;
    const int n0 = blockIdx.x * 128;
    const int KT = K >> 5;

    const __half* gA = A + (size_t)m0 * K;
    const __half* gWh = Wh + (size_t)n0 * K;

    float acc[4][4][4];
#pragma unroll
    for (int mi = 0; mi < 4; mi++)
#pragma unroll
        for (int ni = 0; ni < 4; ni++)
#pragma unroll
            for (int q = 0; q < 4; q++) acc[mi][ni][q] = 0.f;

    const int lr = tid >> 2;
    const int lc = tid & 3;

    auto load_stage = [&](int kt, int st) {
        const size_t koff = (size_t)kt * 32;
        uint32_t base = sb + st * STG;
#pragma unroll
        for (int i = 0; i < 2; i++) {
            int r = lr + i * 64;
            uint32_t so = (r * GSTR + lc * 8) * 2;
            size_t go = (size_t)r * K + koff + lc * 8;
            cp_async16(base + 0 * TILEB + so, gA + go);
            cp_async16(base + 1 * TILEB + so, gWh + go);
        }
        cp_commit();
    };

    const uint32_t arow = wm * 64 + (lane & 7) + ((lane >> 3) & 1) * 8;
    const uint32_t acol = (lane >> 4) * 8;
    const uint32_t aoff = (arow * GSTR + acol) * 2;
    const uint32_t brow = wn * 32 + (lane & 7) + (lane >> 4) * 8;
    const uint32_t bcol = ((lane >> 3) & 1) * 8;
    const uint32_t boff = (brow * GSTR + bcol) * 2;

    load_stage(0, 0);
    load_stage(1, 1);
    load_stage(2, 2);

#pragma unroll 1
    for (int kt = 0; kt < KT; kt++) {
        if (kt + 2 < KT)      cp_wait<2>();
        else if (kt + 1 < KT) cp_wait<1>();
        else                  cp_wait<0>();
        __syncthreads();

        const uint32_t stbase = sb + (kt & 3) * STG;
        const uint32_t aA = stbase + aoff;
        const uint32_t bH = stbase + TILEB + boff;

#pragma unroll
        for (int ks = 0; ks < 2; ks++) {
            const uint32_t kadd = ks * 32;
            uint32_t af[16], bh[8];
#pragma unroll
            for (int mi = 0; mi < 4; mi++)
                ldsm4(af + mi * 4, aA + mi * (16 * GSTR * 2) + kadd);
#pragma unroll
            for (int nj = 0; nj < 2; nj++)
                ldsm4(bh + nj * 4, bH + nj * (16 * GSTR * 2) + kadd);
#pragma unroll
            for (int mi = 0; mi < 4; mi++)
#pragma unroll
                for (int ni = 0; ni < 4; ni++)
                    mma_f16(acc[mi][ni], af + mi * 4, bh + ni * 2);
        }

        if (kt + 3 < KT) load_stage(kt + 3, (kt + 3) & 3);
    }

#pragma unroll
    for (int mi = 0; mi < 4; mi++) {
#pragma unroll
        for (int rr = 0; rr < 2; rr++) {
            int m = m0 + wm * 64 + mi * 16 + group + rr * 8;
            if (m >= Mvalid) continue;
#pragma unroll
            for (int ni = 0; ni < 4; ni++) {
                int n = n0 + wn * 32 + ni * 8 + tq * 2;
                float v0 = acc[mi][ni][rr * 2 + 0] + bias[n];
                float v1 = acc[mi][ni][rr * 2 + 1] + bias[n + 1];
                if (GELU_) {
                    v0 = 0.5f * v0 * (1.f + erff(v0 * 0.70710678118654752f));
                    v1 = 0.5f * v1 * (1.f + erff(v1 * 0.70710678118654752f));
                }
                if (RES) {
                    float2 rv = *(const float2*)(res + (size_t)m * Ntot + n);
                    v0 += rv.x; v1 += rv.y;
                }
                if (OUTF16) {
                    __half2 h2 = __floats2half2_rn(v0, v1);
                    *(__half2*)(Ch + (size_t)m * Ntot + n) = h2;
                } else {
                    *(float2*)(Cf + (size_t)m * Ntot + n) = make_float2(v0, v1);
                }
            }
        }
    }
}

// ---------------- conv GEMM: h = (xh+xl) @ Wh^T + bias + pos (fused assemble) ----------------
// A split in hi/lo (2-product), W fp16. M = CROWS (85*128 exact), K = 640, N = 768.
#define CSTG (3 * TILEB)
#define CNST 3
#define CSMTOT (CNST * CSTG)     // 92160 B/CTA

__global__ void __launch_bounds__(256, 2)
conv_gemm(const __half* __restrict__ Ah, const __half* __restrict__ Al,
          const __half* __restrict__ Wh, const float* __restrict__ bias,
          const float* __restrict__ pos, float* __restrict__ hout) {
    extern __shared__ char dsm[];
    const uint32_t sb = smem_u32(dsm);
    const int K = KCPAD, KT = KCPAD / 32;  // 20

    const int tid = threadIdx.x;
    const int lane = tid & 31, wid = tid >> 5;
    const int wm = wid & 1, wn = wid >> 1;
    const int group = lane >> 2, tq = lane & 3;
    const int m0 = blockIdx.y * 128;
    const int n0 = blockIdx.x * 128;

    const __half* gAh = Ah + (size_t)m0 * K;
    const __half* gAl = Al + (size_t)m0 * K;
    const __half* gWh = Wh + (size_t)n0 * K;

    float acc[4][4][4];
#pragma unroll
    for (int mi = 0; mi < 4; mi++)
#pragma unroll
        for (int ni = 0; ni < 4; ni++)
#pragma unroll
            for (int q = 0; q < 4; q++) acc[mi][ni][q] = 0.f;

    const int lr = tid >> 2;
    const int lc = tid & 3;

    auto load_stage = [&](int kt, int st) {
        const size_t koff = (size_t)kt * 32;
        uint32_t base = sb + st * CSTG;
#pragma unroll
        for (int i = 0; i < 2; i++) {
            int r = lr + i * 64;
            uint32_t so = (r * GSTR + lc * 8) * 2;
            size_t go = (size_t)r * K + koff + lc * 8;
            cp_async16(base + 0 * TILEB + so, gAh + go);
            cp_async16(base + 1 * TILEB + so, gAl + go);
            cp_async16(base + 2 * TILEB + so, gWh + go);
        }
        cp_commit();
    };

    const uint32_t arow = wm * 64 + (lane & 7) + ((lane >> 3) & 1) * 8;
    const uint32_t acol = (lane >> 4) * 8;
    const uint32_t aoff = (arow * GSTR + acol) * 2;
    const uint32_t brow = wn * 32 + (lane & 7) + (lane >> 4) * 8;
    const uint32_t bcol = ((lane >> 3) & 1) * 8;
    const uint32_t boff = (brow * GSTR + bcol) * 2;

    load_stage(0, 0);
    load_stage(1, 1);

#pragma unroll 1
    for (int kt = 0; kt < KT; kt++) {
        if (kt + 1 < KT) cp_wait<1>();
        else             cp_wait<0>();
        __syncthreads();

        const uint32_t stbase = sb + (kt % 3) * CSTG;
        const uint32_t aH = stbase + aoff;
        const uint32_t aL = stbase + TILEB + aoff;
        const uint32_t bH = stbase + 2 * TILEB + boff;

#pragma unroll
        for (int ks = 0; ks < 2; ks++) {
            const uint32_t kadd = ks * 32;
            uint32_t afh[16], afl[16], bh[8];
#pragma unroll
            for (int mi = 0; mi < 4; mi++) {
                ldsm4(afh + mi * 4, aH + mi * (16 * GSTR * 2) + kadd);
                ldsm4(afl + mi * 4, aL + mi * (16 * GSTR * 2) + kadd);
            }
#pragma unroll
            for (int nj = 0; nj < 2; nj++)
                ldsm4(bh + nj * 4, bH + nj * (16 * GSTR * 2) + kadd);
#pragma unroll
            for (int mi = 0; mi < 4; mi++)
#pragma unroll
                for (int ni = 0; ni < 4; ni++)
                    mma_f16(acc[mi][ni], afh + mi * 4, bh + ni * 2);
#pragma unroll
            for (int mi = 0; mi < 4; mi++)
#pragma unroll
                for (int ni = 0; ni < 4; ni++)
                    mma_f16(acc[mi][ni], afl + mi * 4, bh + ni * 2);
        }

        if (kt + 2 < KT) load_stage(kt + 2, (kt + 2) % 3);
    }

    // epilogue: remap conv row (b,p) -> token row b*171+p+1, add bias+pos
#pragma unroll
    for (int mi = 0; mi < 4; mi++) {
#pragma unroll
        for (int rr = 0; rr < 2; rr++) {
            int m = m0 + wm * 64 + mi * 16 + group + rr * 8;   // < CROWS always
            int b = m / NPATCH, p = m % NPATCH;
            size_t row = (size_t)b * NTOK + p + 1;
            const float* pr = pos + (size_t)(p + 1) * DD;
#pragma unroll
            for (int ni = 0; ni < 4; ni++) {
                int n = n0 + wn * 32 + ni * 8 + tq * 2;
                float v0 = acc[mi][ni][rr * 2 + 0] + bias[n] + pr[n];
                float v1 = acc[mi][ni][rr * 2 + 1] + bias[n + 1] + pr[n + 1];
                *(float2*)(hout + row * DD + n) = make_float2(v0, v1);
            }
        }
    }
}

// ---------------- im2col -> split fp16 (padded K=640) ----------------
__global__ void im2col_split(const float* __restrict__ x,
                             __half* __restrict__ colh, __half* __restrict__ coll) {
    int idx = blockIdx.x * blockDim.x + threadIdx.x;
    if (idx >= CROWS * KCPAD) return;
    int r = idx / KCPAD, c = idx % KCPAD;
    float v = 0.f;
    if (c < KCONV) {
        int b = r / NPATCH, p = r % NPATCH;
        int chn = c / 100, rem = c % 100;
        int kh = rem / 10, kw = rem % 10;
        int phh = p / 34, pw = p % 34;
        v = x[((b * 6 + chn) * 50 + phh * 10 + kh) * 345 + pw * 10 + kw];
    }
    __half hi, lo;
    splith(v, hi, lo);
    colh[idx] = hi;
    coll[idx] = lo;
}

// ---------------- conv weight -> fp16 (padded K=640; already [N,K] layout) ----------------
__global__ void convw_prep(const float* __restrict__ w, __half* __restrict__ wh) {
    int idx = blockIdx.x * blockDim.x + threadIdx.x;
    if (idx >= DD * KCPAD) return;
    int d = idx / KCPAD, k = idx % KCPAD;
    wh[idx] = __float2half(k < KCONV ? w[d * KCONV + k] : 0.f);
}

// ---------------- cls token rows: h[b*171] = cls + pos[0] ----------------
__global__ void cls_fill(const float* __restrict__ cls, const float* __restrict__ pos,
                         float* __restrict__ h) {
    int idx = blockIdx.x * blockDim.x + threadIdx.x;
    if (idx >= BATCH * DD) return;
    int b = idx / DD, d = idx % DD;
    h[(size_t)b * NTOK * DD + d] = cls[d] + pos[d];
}

// ---------------- weight transpose -> fp16 (hi only) ----------------
__global__ void transpose_hi(const float* __restrict__ W, __half* __restrict__ Wh,
                             int R, int C) {
    __shared__ float t[32][33];
    int z = blockIdx.z;
    const float* Wz = W + (size_t)z * R * C;
    __half* Whz = Wh + (size_t)z * R * C;
    int c0 = blockIdx.x * 32, r0 = blockIdx.y * 32;
    int x = threadIdx.x, y = threadIdx.y;
#pragma unroll
    for (int i = 0; i < 32; i += 8)
        t[y + i][x] = Wz[(size_t)(r0 + y + i) * C + c0 + x];
    __syncthreads();
#pragma unroll
    for (int i = 0; i < 32; i += 8)
        Whz[(size_t)(c0 + y + i) * R + r0 + x] = __float2half(t[x][y + i]);
}

// ---------------- LayerNorm fp32 -> fp16 ----------------
__global__ void ln_f16_kernel(const float* __restrict__ X, const float* __restrict__ w,
                              const float* __restrict__ b, __half* __restrict__ Y) {
    int row = blockIdx.x;
    int tid = threadIdx.x;
    const float* xr = X + (size_t)row * DD;
    float v0 = xr[tid], v1 = xr[tid + 256], v2 = xr[tid + 512];
    float s = v0 + v1 + v2;
    float q = v0 * v0 + v1 * v1 + v2 * v2;
    int lane = tid & 31, warp = tid >> 5;
#pragma unroll
    for (int off = 16; off; off >>= 1) {
        s += __shfl_down_sync(0xffffffffu, s, off);
        q += __shfl_down_sync(0xffffffffu, q, off);
    }
    __shared__ float sa[8], sbm[8];
    if (lane == 0) { sa[warp] = s; sbm[warp] = q; }
    __syncthreads();
    if (warp == 0) {
        s = (lane < 8) ? sa[lane] : 0.f;
        q = (lane < 8) ? sbm[lane] : 0.f;
#pragma unroll
        for (int off = 4; off; off >>= 1) {
            s += __shfl_down_sync(0xffffffffu, s, off);
            q += __shfl_down_sync(0xffffffffu, q, off);
        }
        if (lane == 0) { sa[0] = s; sbm[0] = q; }
    }
    __syncthreads();
    float mean = sa[0] * (1.f / DD);
    float var = sbm[0] * (1.f / DD) - mean * mean;
    float inv = rsqrtf(var + EPS);
    __half* yr = Y + (size_t)row * DD;
    yr[tid]       = __float2half((v0 - mean) * inv * w[tid]       + b[tid]);
    yr[tid + 256] = __float2half((v1 - mean) * inv * w[tid + 256] + b[tid + 256]);
    yr[tid + 512] = __float2half((v2 - mean) * inv * w[tid + 512] + b[tid + 512]);
}

// ---------------- LayerNorm fp32 -> fp32 (final, cls rows) ----------------
__global__ void ln_kernel(const float* __restrict__ X, const float* __restrict__ w,
                          const float* __restrict__ b, float* __restrict__ Y, int row_mul) {
    int row_in = blockIdx.x * row_mul;
    int row_out = blockIdx.x;
    int tid = threadIdx.x;
    const float* xr = X + (size_t)row_in * DD;
    float v0 = xr[tid], v1 = xr[tid + 256], v2 = xr[tid + 512];
    float s = v0 + v1 + v2;
    float q = v0 * v0 + v1 * v1 + v2 * v2;
    int lane = tid & 31, warp = tid >> 5;
#pragma unroll
    for (int off = 16; off; off >>= 1) {
        s += __shfl_down_sync(0xffffffffu, s, off);
        q += __shfl_down_sync(0xffffffffu, q, off);
    }
    __shared__ float sa[8], sbm[8];
    if (lane == 0) { sa[warp] = s; sbm[warp] = q; }
    __syncthreads();
    if (warp == 0) {
        s = (lane < 8) ? sa[lane] : 0.f;
        q = (lane < 8) ? sbm[lane] : 0.f;
#pragma unroll
        for (int off = 4; off; off >>= 1) {
            s += __shfl_down_sync(0xffffffffu, s, off);
            q += __shfl_down_sync(0xffffffffu, q, off);
        }
        if (lane == 0) { sa[0] = s; sbm[0] = q; }
    }
    __syncthreads();
    float mean = sa[0] * (1.f / DD);
    float var = sbm[0] * (1.f / DD) - mean * mean;
    float inv = rsqrtf(var + EPS);
    float* yr = Y + (size_t)row_out * DD;
    yr[tid]       = (v0 - mean) * inv * w[tid]       + b[tid];
    yr[tid + 256] = (v1 - mean) * inv * w[tid + 256] + b[tid + 256];
    yr[tid + 512] = (v2 - mean) * inv * w[tid + 512] + b[tid + 512];
}

// ---------------- MMA attention (split fp16, ~fp32 exact) ----------------
#define NTOKP 176
#define ASTR 72
#define VSTR 184
#define SA_QH 0
#define SA_QL (SA_QH + NTOKP*ASTR*2)
#define SA_KH (SA_QL + NTOKP*ASTR*2)
#define SA_KL (SA_KH + NTOKP*ASTR*2)
#define SA_VH (SA_KL + NTOKP*ASTR*2)
#define SA_VL (SA_VH + 64*VSTR*2)
#define ATTN_SMEM (SA_VL + 64*VSTR*2)

__global__ void __launch_bounds__(256, 1)
attn_mma_kernel(const float* __restrict__ qkv, __half* __restrict__ out) {
    extern __shared__ char asmem[];
    const uint32_t sb = smem_u32(asmem);
    __half* QH = (__half*)(asmem + SA_QH);
    __half* QL = (__half*)(asmem + SA_QL);
    __half* KH = (__half*)(asmem + SA_KH);
    __half* KL = (__half*)(asmem + SA_KL);
    __half* VH = (__half*)(asmem + SA_VH);
    __half* VL = (__half*)(asmem + SA_VL);

    const int bh = blockIdx.x;
    const int b = bh / NHEAD, hh = bh % NHEAD;
    const int tid = threadIdx.x;
    const int lane = tid & 31, wid = tid >> 5;
    const int group = lane >> 2, tq = lane & 3;
    const size_t base = (size_t)b * NTOK * (3 * DD) + hh * HDIM;

    for (int idx = tid; idx < NTOKP * 64; idx += 256) {
        int row = idx >> 6, d = idx & 63;
        float qv = 0.f, kv = 0.f, vv = 0.f;
        if (row < NTOK) {
            size_t o = base + (size_t)row * (3 * DD) + d;
            qv = qkv[o]; kv = qkv[o + DD]; vv = qkv[o + 2 * DD];
        }
        __half h, l;
        splith(qv, h, l); QH[row * ASTR + d] = h; QL[row * ASTR + d] = l;
        splith(kv, h, l); KH[row * ASTR + d] = h; KL[row * ASTR + d] = l;
        splith(vv, h, l); VH[d * VSTR + row] = h; VL[d * VSTR + row] = l;
    }
    __syncthreads();

    const uint32_t a_r = (lane & 7) + ((lane >> 3) & 1) * 8;
    const uint32_t a_c = (lane >> 4) * 8;
    const uint32_t b_r = (lane & 7) + (lane >> 4) * 8;
    const uint32_t b_c = ((lane >> 3) & 1) * 8;

    for (int t = wid; t < 11; t += 8) {
        const int m0 = t * 16;

        uint32_t aq[4][4], aql[4][4];
#pragma unroll
        for (int k = 0; k < 4; k++) {
            uint32_t off = ((m0 + a_r) * ASTR + a_c + k * 16) * 2;
            ldsm4(aq[k], sb + SA_QH + off);
            ldsm4(aql[k], sb + SA_QL + off);
        }

        float s[22][4];
#pragma unroll
        for (int j = 0; j < 22; j++)
#pragma unroll
            for (int q = 0; q < 4; q++) s[j][q] = 0.f;

#pragma unroll
        for (int nj = 0; nj < 11; nj++) {
            const int n0 = nj * 16;
#pragma unroll
            for (int k = 0; k < 4; k++) {
                uint32_t bkh[4], bkl[4];
                uint32_t off = ((n0 + b_r) * ASTR + b_c + k * 16) * 2;
                ldsm4(bkh, sb + SA_KH + off);
                ldsm4(bkl, sb + SA_KL + off);
                mma_f16(s[2 * nj],     aq[k],  bkh);
                mma_f16(s[2 * nj + 1], aq[k],  bkh + 2);
                mma_f16(s[2 * nj],     aql[k], bkh);
                mma_f16(s[2 * nj + 1], aql[k], bkh + 2);
                mma_f16(s[2 * nj],     aq[k],  bkl);
                mma_f16(s[2 * nj + 1], aq[k],  bkl + 2);
            }
        }

        {
            int c0 = 168 + tq * 2;
            if (c0 >= NTOK)     { s[21][0] = -1e30f; s[21][2] = -1e30f; }
            if (c0 + 1 >= NTOK) { s[21][1] = -1e30f; s[21][3] = -1e30f; }
        }

        float mx0 = -1e30f, mx1 = -1e30f;
#pragma unroll
        for (int j = 0; j < 22; j++) {
            mx0 = fmaxf(mx0, fmaxf(s[j][0], s[j][1]));
            mx1 = fmaxf(mx1, fmaxf(s[j][2], s[j][3]));
        }
        mx0 = fmaxf(mx0, __shfl_xor_sync(0xffffffffu, mx0, 1));
        mx0 = fmaxf(mx0, __shfl_xor_sync(0xffffffffu, mx0, 2));
        mx1 = fmaxf(mx1, __shfl_xor_sync(0xffffffffu, mx1, 1));
        mx1 = fmaxf(mx1, __shfl_xor_sync(0xffffffffu, mx1, 2));

        float rs0 = 0.f, rs1 = 0.f;
#pragma unroll
        for (int j = 0; j < 22; j++) {
            s[j][0] = __expf((s[j][0] - mx0) * 0.125f);
            s[j][1] = __expf((s[j][1] - mx0) * 0.125f);
            s[j][2] = __expf((s[j][2] - mx1) * 0.125f);
            s[j][3] = __expf((s[j][3] - mx1) * 0.125f);
            rs0 += s[j][0] + s[j][1];
            rs1 += s[j][2] + s[j][3];
        }
        rs0 += __shfl_xor_sync(0xffffffffu, rs0, 1);
        rs0 += __shfl_xor_sync(0xffffffffu, rs0, 2);
        rs1 += __shfl_xor_sync(0xffffffffu, rs1, 1);
        rs1 += __shfl_xor_sync(0xffffffffu, rs1, 2);

        float o[8][4];
#pragma unroll
        for (int j = 0; j < 8; j++)
#pragma unroll
            for (int q = 0; q < 4; q++) o[j][q] = 0.f;

#pragma unroll
        for (int kt = 0; kt < 11; kt++) {
            uint32_t ap[4], apl[4];
#pragma unroll
            for (int half = 0; half < 2; half++) {
                const float* sv = s[2 * kt + half];
                __half h0 = __float2half(sv[0]), h1 = __float2half(sv[1]);
                __half h2v = __float2half(sv[2]), h3 = __float2half(sv[3]);
                ap[2 * half]     = pack_h2(__half2float(h0), __half2float(h1));
                ap[2 * half + 1] = pack_h2(__half2float(h2v), __half2float(h3));
                apl[2 * half]     = pack_h2(sv[0] - __half2float(h0), sv[1] - __half2float(h1));
                apl[2 * half + 1] = pack_h2(sv[2] - __half2float(h2v), sv[3] - __half2float(h3));
            }
#pragma unroll
            for (int dj = 0; dj < 4; dj++) {
                const int d0 = dj * 16;
                uint32_t bvh[4], bvl[4];
                uint32_t off = ((d0 + b_r) * VSTR + b_c + kt * 16) * 2;
                ldsm4(bvh, sb + SA_VH + off);
                ldsm4(bvl, sb + SA_VL + off);
                mma_f16(o[2 * dj],     ap,  bvh);
                mma_f16(o[2 * dj + 1], ap,  bvh + 2);
                mma_f16(o[2 * dj],     apl, bvh);
                mma_f16(o[2 * dj + 1], apl, bvh + 2);
                mma_f16(o[2 * dj],     ap,  bvl);
                mma_f16(o[2 * dj + 1], ap,  bvl + 2);
            }
        }

        const float i0 = 1.f / rs0, i1 = 1.f / rs1;
        const int r0 = m0 + group, r1 = r0 + 8;
#pragma unroll
        for (int j = 0; j < 8; j++) {
            int d = 8 * j + tq * 2;
            if (r0 < NTOK) {
                __half2 hv = __floats2half2_rn(o[j][0] * i0, o[j][1] * i0);
                *(__half2*)(out + (size_t)(b * NTOK + r0) * DD + hh * HDIM + d) = hv;
            }
            if (r1 < NTOK) {
                __half2 hv = __floats2half2_rn(o[j][2] * i1, o[j][3] * i1);
                *(__half2*)(out + (size_t)(b * NTOK + r1) * DD + hh * HDIM + d) = hv;
            }
        }
    }
}

// ---------------- head ----------------
__global__ void head_kernel(const float* __restrict__ cls, const float* __restrict__ hw,
                            const float* __restrict__ hb, float* __restrict__ out) {
    int b = blockIdx.x;
    int tid = threadIdx.x;
    float a0 = 0.f, a1 = 0.f, a2 = 0.f;
    for (int d = tid; d < DD; d += 256) {
        float v = cls[b * DD + d];
        a0 += v * hw[d * 3 + 0];
        a1 += v * hw[d * 3 + 1];
        a2 += v * hw[d * 3 + 2];
    }
    int lane = tid & 31, warp = tid >> 5;
#pragma unroll
    for (int off = 16; off; off >>= 1) {
        a0 += __shfl_down_sync(0xffffffffu, a0, off);
        a1 += __shfl_down_sync(0xffffffffu, a1, off);
        a2 += __shfl_down_sync(0xffffffffu, a2, off);
    }
    __shared__ float s0[8], s1[8], s2[8];
    if (lane == 0) { s0[warp] = a0; s1[warp] = a1; s2[warp] = a2; }
    __syncthreads();
    if (warp == 0 && lane < 8) {
        a0 = s0[lane]; a1 = s1[lane]; a2 = s2[lane];
#pragma unroll
        for (int off = 4; off; off >>= 1) {
            a0 += __shfl_down_sync(0x000000ffu, a0, off);
            a1 += __shfl_down_sync(0x000000ffu, a1, off);
            a2 += __shfl_down_sync(0x000000ffu, a2, off);
        }
        if (lane == 0) {
            out[b * 3 + 0] = a0 + hb[0];
            out[b * 3 + 1] = a1 + hb[1];
            out[b * 3 + 2] = a2 + hb[2];
        }
    }
}

// ---------------- launcher ----------------
extern "C" void kernel_launch(void* const* d_in, const int* in_sizes, int n_in,
                              void* d_out, int out_size) {
    const float* x        = (const float*)d_in[0];
    const float* conv_w   = (const float*)d_in[1];
    const float* conv_b   = (const float*)d_in[2];
    const float* cls_tok  = (const float*)d_in[3];
    const float* pos      = (const float*)d_in[4];
    const float* ln1_w    = (const float*)d_in[5];
    const float* ln1_b    = (const float*)d_in[6];
    const float* qkv_w    = (const float*)d_in[7];
    const float* qkv_b    = (const float*)d_in[8];
    const float* proj_w   = (const float*)d_in[9];
    const float* proj_b   = (const float*)d_in[10];
    const float* ln2_w    = (const float*)d_in[11];
    const float* ln2_b    = (const float*)d_in[12];
    const float* fc1_w    = (const float*)d_in[13];
    const float* fc1_b    = (const float*)d_in[14];
    const float* fc2_w    = (const float*)d_in[15];
    const float* fc2_b    = (const float*)d_in[16];
    const float* norm_w   = (const float*)d_in[17];
    const float* norm_b   = (const float*)d_in[18];
    const float* head_w   = (const float*)d_in[19];
    const float* head_b   = (const float*)d_in[20];
    float* out = (float*)d_out;

    float *h, *clsb, *qkvf;
    __half *colh, *coll, *convWh, *yf, *af, *bigf;
    __half *qkvWh, *projWh, *fc1Wh, *fc2Wh;
    cudaGetSymbolAddress((void**)&colh, g_colh);
    cudaGetSymbolAddress((void**)&coll, g_coll);
    cudaGetSymbolAddress((void**)&convWh, g_convWh);
    cudaGetSymbolAddress((void**)&h, g_h);
    cudaGetSymbolAddress((void**)&clsb, g_cls);
    cudaGetSymbolAddress((void**)&qkvf, g_qkvf);
    cudaGetSymbolAddress((void**)&yf, g_yf);
    cudaGetSymbolAddress((void**)&af, g_af);
    cudaGetSymbolAddress((void**)&bigf, g_bigf);
    cudaGetSymbolAddress((void**)&qkvWh, g_qkvWh);
    cudaGetSymbolAddress((void**)&projWh, g_projWh);
    cudaGetSymbolAddress((void**)&fc1Wh, g_fc1Wh);
    cudaGetSymbolAddress((void**)&fc2Wh, g_fc2Wh);

    cudaFuncSetAttribute(attn_mma_kernel, cudaFuncAttributeMaxDynamicSharedMemorySize, ATTN_SMEM);
    cudaFuncSetAttribute(hmma_gemm<false, false, false>, cudaFuncAttributeMaxDynamicSharedMemorySize, SMTOT1);
    cudaFuncSetAttribute(hmma_gemm<false, false, true>, cudaFuncAttributeMaxDynamicSharedMemorySize, SMTOT1);
    cudaFuncSetAttribute(hmma_gemm<true, true, false>, cudaFuncAttributeMaxDynamicSharedMemorySize, SMTOT1);
    cudaFuncSetAttribute(conv_gemm, cudaFuncAttributeMaxDynamicSharedMemorySize, CSMTOT);

    // weight prep
    transpose_hi<<<dim3(3 * DD / 32, DD / 32, DEPTH), dim3(32, 8)>>>(qkv_w, qkvWh, DD, 3 * DD);
    transpose_hi<<<dim3(DD / 32, DD / 32, DEPTH), dim3(32, 8)>>>(proj_w, projWh, DD, DD);
    transpose_hi<<<dim3(4 * DD / 32, DD / 32, DEPTH), dim3(32, 8)>>>(fc1_w, fc1Wh, DD, 4 * DD);
    transpose_hi<<<dim3(DD / 32, 4 * DD / 32, DEPTH), dim3(32, 8)>>>(fc2_w, fc2Wh, 4 * DD, DD);
    convw_prep<<<(DD * KCPAD + 255) / 256, 256>>>(conv_w, convWh);

    // patch embed (fp16 2-product, fused pos-embed + assemble)
    im2col_split<<<(CROWS * KCPAD + 255) / 256, 256>>>(x, colh, coll);
    cls_fill<<<(BATCH * DD + 255) / 256, 256>>>(cls_tok, pos, h);
    conv_gemm<<<dim3(DD / 128, CROWS / 128), 256, CSMTOT>>>(colh, coll, convWh, conv_b, pos, h);

    const int MT = MPAD / 128;  // 86
    for (int i = 0; i < DEPTH; i++) {
        ln_f16_kernel<<<MROWS, 256>>>(h, ln1_w + (size_t)i * DD, ln1_b + (size_t)i * DD, yf);
        hmma_gemm<false, false, false><<<dim3(3 * DD / 128, MT), 256, SMTOT1>>>(
            yf, qkvWh + (size_t)i * 3 * DD * DD,
            qkv_b + (size_t)i * 3 * DD, nullptr, qkvf, nullptr, MROWS, 3 * DD, DD);
        attn_mma_kernel<<<BATCH * NHEAD, 256, ATTN_SMEM>>>(qkvf, af);
        hmma_gemm<false, false, true><<<dim3(DD / 128, MT), 256, SMTOT1>>>(
            af, projWh + (size_t)i * DD * DD,
            proj_b + (size_t)i * DD, h, h, nullptr, MROWS, DD, DD);
        ln_f16_kernel<<<MROWS, 256>>>(h, ln2_w + (size_t)i * DD, ln2_b + (size_t)i * DD, yf);
        hmma_gemm<true, true, false><<<dim3(4 * DD / 128, MT), 256, SMTOT1>>>(
            yf, fc1Wh + (size_t)i * 4 * DD * DD,
            fc1_b + (size_t)i * 4 * DD, nullptr, nullptr, bigf, MROWS, 4 * DD, DD);
        hmma_gemm<false, false, true><<<dim3(DD / 128, MT), 256, SMTOT1>>>(
            bigf, fc2Wh + (size_t)i * 4 * DD * DD,
            fc2_b + (size_t)i * DD, h, h, nullptr, MROWS, DD, 4 * DD);
    }

    ln_kernel<<<BATCH, 256>>>(h, norm_w, norm_b, clsb, NTOK);
    head_kernel<<<BATCH, 256>>>(clsb, head_w, head_b, out);
}

// round 12
// speedup vs baseline: 6.9006x; 1.0373x over previous
#include <cuda_runtime.h>
#include <cuda_fp16.h>
#include <math.h>
#include <stdint.h>

// ---------------- problem constants ----------------
#define DD     768
#define NTOK   171
#define BATCH  64
#define MROWS  (BATCH*NTOK)      // 10944
#define MPAD   11008             // 86*128
#define NPATCH 170
#define CROWS  (BATCH*NPATCH)    // 10880 = 85*128
#define KCONV  600
#define KCPAD  640
#define NHEAD  12
#define HDIM   64
#define DEPTH  12
#define EPS    1e-5f

// ---------------- scratch (device globals) ----------------
__device__ __half g_colh[CROWS * KCPAD];
__device__ __half g_coll[CROWS * KCPAD];
__device__ __half g_convWh[DD * KCPAD];
__device__ float g_h   [MROWS * DD];
__device__ float g_cls [BATCH * DD];
__device__ float g_qkvf[MPAD * 3 * DD];
__device__ __half g_yf   [MPAD * DD];
__device__ __half g_af   [MPAD * DD];
__device__ __half g_bigf [MPAD * 4 * DD];
__device__ __half g_qkvWh[DEPTH * 3 * DD * DD];
__device__ __half g_projWh[DEPTH * DD * DD];
__device__ __half g_fc1Wh[DEPTH * 4 * DD * DD];
__device__ __half g_fc2Wh[DEPTH * 4 * DD * DD];

// ---------------- helpers ----------------
__device__ __forceinline__ uint32_t smem_u32(const void* p) {
    uint32_t a;
    asm("{ .reg .u64 t; cvta.to.shared.u64 t, %1; cvt.u32.u64 %0, t; }" : "=r"(a) : "l"(p));
    return a;
}
__device__ __forceinline__ void cp_async16(uint32_t dst, const void* src) {
    asm volatile("cp.async.cg.shared.global [%0], [%1], 16;"
                 :: "r"(dst), "l"(src) : "memory");
}
__device__ __forceinline__ void cp_commit() {
    asm volatile("cp.async.commit_group;" ::: "memory");
}
template <int N>
__device__ __forceinline__ void cp_wait() {
    asm volatile("cp.async.wait_group %0;" :: "n"(N) : "memory");
}
__device__ __forceinline__ void ldsm4(uint32_t* r, uint32_t addr) {
    asm volatile("ldmatrix.sync.aligned.m8n8.x4.shared.b16 {%0,%1,%2,%3}, [%4];"
                 : "=r"(r[0]), "=r"(r[1]), "=r"(r[2]), "=r"(r[3]) : "r"(addr));
}
__device__ __forceinline__ void mma_f16(float* c, const uint32_t* a, const uint32_t* b) {
    asm volatile(
        "mma.sync.aligned.m16n8k16.row.col.f32.f16.f16.f32 "
        "{%0,%1,%2,%3}, {%4,%5,%6,%7}, {%8,%9}, {%0,%1,%2,%3};"
        : "+f"(c[0]), "+f"(c[1]), "+f"(c[2]), "+f"(c[3])
        : "r"(a[0]), "r"(a[1]), "r"(a[2]), "r"(a[3]), "r"(b[0]), "r"(b[1]));
}
__device__ __forceinline__ void splith(float v, __half& hi, __half& lo) {
    hi = __float2half(v);
    lo = __float2half(v - __half2float(hi));
}
__device__ __forceinline__ uint32_t pack_h2(float a, float b) {
    __half2 h = __floats2half2_rn(a, b);
    return *(uint32_t*)&h;
}

// ---------------- fp16 GEMM: C = A @ Wh^T (single product, 2 CTAs/SM, 1 sync/kt) ----------------
#define GSTR 40
#define TILEB (128 * GSTR * 2)
#define STG (2 * TILEB)
#define NST 4
#define SMTOT1 (NST * STG)       // 81920 B/CTA

template <bool OUTF16, bool GELU_, bool RES>
__global__ void __launch_bounds__(256, 2)
hmma_gemm(const __half* __restrict__ A, const __half* __restrict__ Wh,
          const float* __restrict__ bias, const float* __restrict__ res,
          float* __restrict__ Cf, __half* __restrict__ Ch,
          int Mvalid, int Ntot, int K) {
    extern __shared__ char dsm[];
    const uint32_t sb = smem_u32(dsm);

    const int tid = threadIdx.x;
    const int lane = tid & 31, wid = tid >> 5;
    const int wm = wid & 1, wn = wid >> 1;
    const int group = lane >> 2, tq = lane & 3;
    const int m0 = blockIdx.y * 128;
    const int n0 = blockIdx.x * 128;
    const int KT = K >> 5;

    const __half* gA = A + (size_t)m0 * K;
    const __half* gWh = Wh + (size_t)n0 * K;

    float acc[4][4][4];
#pragma unroll
    for (int mi = 0; mi < 4; mi++)
#pragma unroll
        for (int ni = 0; ni < 4; ni++)
#pragma unroll
            for (int q = 0; q < 4; q++) acc[mi][ni][q] = 0.f;

    const int lr = tid >> 2;
    const int lc = tid & 3;

    auto load_stage = [&](int kt, int st) {
        const size_t koff = (size_t)kt * 32;
        uint32_t base = sb + st * STG;
#pragma unroll
        for (int i = 0; i < 2; i++) {
            int r = lr + i * 64;
            uint32_t so = (r * GSTR + lc * 8) * 2;
            size_t go = (size_t)r * K + koff + lc * 8;
            cp_async16(base + 0 * TILEB + so, gA + go);
            cp_async16(base + 1 * TILEB + so, gWh + go);
        }
        cp_commit();
    };

    const uint32_t arow = wm * 64 + (lane & 7) + ((lane >> 3) & 1) * 8;
    const uint32_t acol = (lane >> 4) * 8;
    const uint32_t aoff = (arow * GSTR + acol) * 2;
    const uint32_t brow = wn * 32 + (lane & 7) + (lane >> 4) * 8;
    const uint32_t bcol = ((lane >> 3) & 1) * 8;
    const uint32_t boff = (brow * GSTR + bcol) * 2;

    load_stage(0, 0);
    load_stage(1, 1);
    load_stage(2, 2);

#pragma unroll 1
    for (int kt = 0; kt < KT; kt++) {
        if (kt + 2 < KT)      cp_wait<2>();
        else if (kt + 1 < KT) cp_wait<1>();
        else                  cp_wait<0>();
        __syncthreads();

        const uint32_t stbase = sb + (kt & 3) * STG;
        const uint32_t aA = stbase + aoff;
        const uint32_t bH = stbase + TILEB + boff;

#pragma unroll
        for (int ks = 0; ks < 2; ks++) {
            const uint32_t kadd = ks * 32;
            uint32_t af[16], bh[8];
#pragma unroll
            for (int mi = 0; mi < 4; mi++)
                ldsm4(af + mi * 4, aA + mi * (16 * GSTR * 2) + kadd);
#pragma unroll
            for (int nj = 0; nj < 2; nj++)
                ldsm4(bh + nj * 4, bH + nj * (16 * GSTR * 2) + kadd);
#pragma unroll
            for (int mi = 0; mi < 4; mi++)
#pragma unroll
                for (int ni = 0; ni < 4; ni++)
                    mma_f16(acc[mi][ni], af + mi * 4, bh + ni * 2);
        }

        if (kt + 3 < KT) load_stage(kt + 3, (kt + 3) & 3);
    }

#pragma unroll
    for (int mi = 0; mi < 4; mi++) {
#pragma unroll
        for (int rr = 0; rr < 2; rr++) {
            int m = m0 + wm * 64 + mi * 16 + group + rr * 8;
            if (m >= Mvalid) continue;
#pragma unroll
            for (int ni = 0; ni < 4; ni++) {
                int n = n0 + wn * 32 + ni * 8 + tq * 2;
                float v0 = acc[mi][ni][rr * 2 + 0] + bias[n];
                float v1 = acc[mi][ni][rr * 2 + 1] + bias[n + 1];
                if (GELU_) {
                    v0 = 0.5f * v0 * (1.f + erff(v0 * 0.70710678118654752f));
                    v1 = 0.5f * v1 * (1.f + erff(v1 * 0.70710678118654752f));
                }
                if (RES) {
                    float2 rv = *(const float2*)(res + (size_t)m * Ntot + n);
                    v0 += rv.x; v1 += rv.y;
                }
                if (OUTF16) {
                    __half2 h2 = __floats2half2_rn(v0, v1);
                    *(__half2*)(Ch + (size_t)m * Ntot + n) = h2;
                } else {
                    *(float2*)(Cf + (size_t)m * Ntot + n) = make_float2(v0, v1);
                }
            }
        }
    }
}

// ---------------- conv GEMM: h = (xh+xl) @ Wh^T + bias + pos (fused assemble) ----------------
#define CSTG (3 * TILEB)
#define CNST 3
#define CSMTOT (CNST * CSTG)     // 92160 B/CTA

__global__ void __launch_bounds__(256, 2)
conv_gemm(const __half* __restrict__ Ah, const __half* __restrict__ Al,
          const __half* __restrict__ Wh, const float* __restrict__ bias,
          const float* __restrict__ pos, float* __restrict__ hout) {
    extern __shared__ char dsm[];
    const uint32_t sb = smem_u32(dsm);
    const int K = KCPAD, KT = KCPAD / 32;  // 20

    const int tid = threadIdx.x;
    const int lane = tid & 31, wid = tid >> 5;
    const int wm = wid & 1, wn = wid >> 1;
    const int group = lane >> 2, tq = lane & 3;
    const int m0 = blockIdx.y * 128;
    const int n0 = blockIdx.x * 128;

    const __half* gAh = Ah + (size_t)m0 * K;
    const __half* gAl = Al + (size_t)m0 * K;
    const __half* gWh = Wh + (size_t)n0 * K;

    float acc[4][4][4];
#pragma unroll
    for (int mi = 0; mi < 4; mi++)
#pragma unroll
        for (int ni = 0; ni < 4; ni++)
#pragma unroll
            for (int q = 0; q < 4; q++) acc[mi][ni][q] = 0.f;

    const int lr = tid >> 2;
    const int lc = tid & 3;

    auto load_stage = [&](int kt, int st) {
        const size_t koff = (size_t)kt * 32;
        uint32_t base = sb + st * CSTG;
#pragma unroll
        for (int i = 0; i < 2; i++) {
            int r = lr + i * 64;
            uint32_t so = (r * GSTR + lc * 8) * 2;
            size_t go = (size_t)r * K + koff + lc * 8;
            cp_async16(base + 0 * TILEB + so, gAh + go);
            cp_async16(base + 1 * TILEB + so, gAl + go);
            cp_async16(base + 2 * TILEB + so, gWh + go);
        }
        cp_commit();
    };

    const uint32_t arow = wm * 64 + (lane & 7) + ((lane >> 3) & 1) * 8;
    const uint32_t acol = (lane >> 4) * 8;
    const uint32_t aoff = (arow * GSTR + acol) * 2;
    const uint32_t brow = wn * 32 + (lane & 7) + (lane >> 4) * 8;
    const uint32_t bcol = ((lane >> 3) & 1) * 8;
    const uint32_t boff = (brow * GSTR + bcol) * 2;

    load_stage(0, 0);
    load_stage(1, 1);

#pragma unroll 1
    for (int kt = 0; kt < KT; kt++) {
        if (kt + 1 < KT) cp_wait<1>();
        else             cp_wait<0>();
        __syncthreads();

        const uint32_t stbase = sb + (kt % 3) * CSTG;
        const uint32_t aH = stbase + aoff;
        const uint32_t aL = stbase + TILEB + aoff;
        const uint32_t bH = stbase + 2 * TILEB + boff;

#pragma unroll
        for (int ks = 0; ks < 2; ks++) {
            const uint32_t kadd = ks * 32;
            uint32_t afh[16], afl[16], bh[8];
#pragma unroll
            for (int mi = 0; mi < 4; mi++) {
                ldsm4(afh + mi * 4, aH + mi * (16 * GSTR * 2) + kadd);
                ldsm4(afl + mi * 4, aL + mi * (16 * GSTR * 2) + kadd);
            }
#pragma unroll
            for (int nj = 0; nj < 2; nj++)
                ldsm4(bh + nj * 4, bH + nj * (16 * GSTR * 2) + kadd);
#pragma unroll
            for (int mi = 0; mi < 4; mi++)
#pragma unroll
                for (int ni = 0; ni < 4; ni++)
                    mma_f16(acc[mi][ni], afh + mi * 4, bh + ni * 2);
#pragma unroll
            for (int mi = 0; mi < 4; mi++)
#pragma unroll
                for (int ni = 0; ni < 4; ni++)
                    mma_f16(acc[mi][ni], afl + mi * 4, bh + ni * 2);
        }

        if (kt + 2 < KT) load_stage(kt + 2, (kt + 2) % 3);
    }

#pragma unroll
    for (int mi = 0; mi < 4; mi++) {
#pragma unroll
        for (int rr = 0; rr < 2; rr++) {
            int m = m0 + wm * 64 + mi * 16 + group + rr * 8;
            int b = m / NPATCH, p = m % NPATCH;
            size_t row = (size_t)b * NTOK + p + 1;
            const float* pr = pos + (size_t)(p + 1) * DD;
#pragma unroll
            for (int ni = 0; ni < 4; ni++) {
                int n = n0 + wn * 32 + ni * 8 + tq * 2;
                float v0 = acc[mi][ni][rr * 2 + 0] + bias[n] + pr[n];
                float v1 = acc[mi][ni][rr * 2 + 1] + bias[n + 1] + pr[n + 1];
                *(float2*)(hout + row * DD + n) = make_float2(v0, v1);
            }
        }
    }
}

// ---------------- im2col -> split fp16 (padded K=640) ----------------
__global__ void im2col_split(const float* __restrict__ x,
                             __half* __restrict__ colh, __half* __restrict__ coll) {
    int idx = blockIdx.x * blockDim.x + threadIdx.x;
    if (idx >= CROWS * KCPAD) return;
    int r = idx / KCPAD, c = idx % KCPAD;
    float v = 0.f;
    if (c < KCONV) {
        int b = r / NPATCH, p = r % NPATCH;
        int chn = c / 100, rem = c % 100;
        int kh = rem / 10, kw = rem % 10;
        int phh = p / 34, pw = p % 34;
        v = x[((b * 6 + chn) * 50 + phh * 10 + kh) * 345 + pw * 10 + kw];
    }
    __half hi, lo;
    splith(v, hi, lo);
    colh[idx] = hi;
    coll[idx] = lo;
}

// ---------------- conv weight -> fp16 (padded K=640) ----------------
__global__ void convw_prep(const float* __restrict__ w, __half* __restrict__ wh) {
    int idx = blockIdx.x * blockDim.x + threadIdx.x;
    if (idx >= DD * KCPAD) return;
    int d = idx / KCPAD, k = idx % KCPAD;
    wh[idx] = __float2half(k < KCONV ? w[d * KCONV + k] : 0.f);
}

// ---------------- cls token rows ----------------
__global__ void cls_fill(const float* __restrict__ cls, const float* __restrict__ pos,
                         float* __restrict__ h) {
    int idx = blockIdx.x * blockDim.x + threadIdx.x;
    if (idx >= BATCH * DD) return;
    int b = idx / DD, d = idx % DD;
    h[(size_t)b * NTOK * DD + d] = cls[d] + pos[d];
}

// ---------------- weight transpose -> fp16 (hi only) ----------------
__global__ void transpose_hi(const float* __restrict__ W, __half* __restrict__ Wh,
                             int R, int C) {
    __shared__ float t[32][33];
    int z = blockIdx.z;
    const float* Wz = W + (size_t)z * R * C;
    __half* Whz = Wh + (size_t)z * R * C;
    int c0 = blockIdx.x * 32, r0 = blockIdx.y * 32;
    int x = threadIdx.x, y = threadIdx.y;
#pragma unroll
    for (int i = 0; i < 32; i += 8)
        t[y + i][x] = Wz[(size_t)(r0 + y + i) * C + c0 + x];
    __syncthreads();
#pragma unroll
    for (int i = 0; i < 32; i += 8)
        Whz[(size_t)(c0 + y + i) * R + r0 + x] = __float2half(t[x][y + i]);
}

// ---------------- LayerNorm fp32 -> fp16 ----------------
__global__ void ln_f16_kernel(const float* __restrict__ X, const float* __restrict__ w,
                              const float* __restrict__ b, __half* __restrict__ Y) {
    int row = blockIdx.x;
    int tid = threadIdx.x;
    const float* xr = X + (size_t)row * DD;
    float v0 = xr[tid], v1 = xr[tid + 256], v2 = xr[tid + 512];
    float s = v0 + v1 + v2;
    float q = v0 * v0 + v1 * v1 + v2 * v2;
    int lane = tid & 31, warp = tid >> 5;
#pragma unroll
    for (int off = 16; off; off >>= 1) {
        s += __shfl_down_sync(0xffffffffu, s, off);
        q += __shfl_down_sync(0xffffffffu, q, off);
    }
    __shared__ float sa[8], sbm[8];
    if (lane == 0) { sa[warp] = s; sbm[warp] = q; }
    __syncthreads();
    if (warp == 0) {
        s = (lane < 8) ? sa[lane] : 0.f;
        q = (lane < 8) ? sbm[lane] : 0.f;
#pragma unroll
        for (int off = 4; off; off >>= 1) {
            s += __shfl_down_sync(0xffffffffu, s, off);
            q += __shfl_down_sync(0xffffffffu, q, off);
        }
        if (lane == 0) { sa[0] = s; sbm[0] = q; }
    }
    __syncthreads();
    float mean = sa[0] * (1.f / DD);
    float var = sbm[0] * (1.f / DD) - mean * mean;
    float inv = rsqrtf(var + EPS);
    __half* yr = Y + (size_t)row * DD;
    yr[tid]       = __float2half((v0 - mean) * inv * w[tid]       + b[tid]);
    yr[tid + 256] = __float2half((v1 - mean) * inv * w[tid + 256] + b[tid + 256]);
    yr[tid + 512] = __float2half((v2 - mean) * inv * w[tid + 512] + b[tid + 512]);
}

// ---------------- LayerNorm fp32 -> fp32 (final, cls rows) ----------------
__global__ void ln_kernel(const float* __restrict__ X, const float* __restrict__ w,
                          const float* __restrict__ b, float* __restrict__ Y, int row_mul) {
    int row_in = blockIdx.x * row_mul;
    int row_out = blockIdx.x;
    int tid = threadIdx.x;
    const float* xr = X + (size_t)row_in * DD;
    float v0 = xr[tid], v1 = xr[tid + 256], v2 = xr[tid + 512];
    float s = v0 + v1 + v2;
    float q = v0 * v0 + v1 * v1 + v2 * v2;
    int lane = tid & 31, warp = tid >> 5;
#pragma unroll
    for (int off = 16; off; off >>= 1) {
        s += __shfl_down_sync(0xffffffffu, s, off);
        q += __shfl_down_sync(0xffffffffu, q, off);
    }
    __shared__ float sa[8], sbm[8];
    if (lane == 0) { sa[warp] = s; sbm[warp] = q; }
    __syncthreads();
    if (warp == 0) {
        s = (lane < 8) ? sa[lane] : 0.f;
        q = (lane < 8) ? sbm[lane] : 0.f;
#pragma unroll
        for (int off = 4; off; off >>= 1) {
            s += __shfl_down_sync(0xffffffffu, s, off);
            q += __shfl_down_sync(0xffffffffu, q, off);
        }
        if (lane == 0) { sa[0] = s; sbm[0] = q; }
    }
    __syncthreads();
    float mean = sa[0] * (1.f / DD);
    float var = sbm[0] * (1.f / DD) - mean * mean;
    float inv = rsqrtf(var + EPS);
    float* yr = Y + (size_t)row_out * DD;
    yr[tid]       = (v0 - mean) * inv * w[tid]       + b[tid];
    yr[tid + 256] = (v1 - mean) * inv * w[tid + 256] + b[tid + 256];
    yr[tid + 512] = (v2 - mean) * inv * w[tid + 512] + b[tid + 512];
}

// ---------------- MMA attention (Q,P split; K,V single fp16; 11 warps) ----------------
#define NTOKP 176
#define ASTR 72
#define VSTR 184
#define SA_QH 0
#define SA_QL (SA_QH + NTOKP*ASTR*2)
#define SA_KH (SA_QL + NTOKP*ASTR*2)
#define SA_VH (SA_KH + NTOKP*ASTR*2)
#define ATTN_SMEM (SA_VH + 64*VSTR*2)   // 99584 B
#define ATHREADS 352

__global__ void __launch_bounds__(ATHREADS, 1)
attn_mma_kernel(const float* __restrict__ qkv, __half* __restrict__ out) {
    extern __shared__ char asmem[];
    const uint32_t sb = smem_u32(asmem);
    __half* QH = (__half*)(asmem + SA_QH);
    __half* QL = (__half*)(asmem + SA_QL);
    __half* KH = (__half*)(asmem + SA_KH);
    __half* VH = (__half*)(asmem + SA_VH);

    const int bh = blockIdx.x;
    const int b = bh / NHEAD, hh = bh % NHEAD;
    const int tid = threadIdx.x;
    const int lane = tid & 31, wid = tid >> 5;
    const int group = lane >> 2, tq = lane & 3;
    const size_t base = (size_t)b * NTOK * (3 * DD) + hh * HDIM;

    for (int idx = tid; idx < NTOKP * 64; idx += ATHREADS) {
        int row = idx >> 6, d = idx & 63;
        float qv = 0.f, kv = 0.f, vv = 0.f;
        if (row < NTOK) {
            size_t o = base + (size_t)row * (3 * DD) + d;
            qv = qkv[o]; kv = qkv[o + DD]; vv = qkv[o + 2 * DD];
        }
        __half h, l;
        splith(qv, h, l);
        QH[row * ASTR + d] = h;
        QL[row * ASTR + d] = l;
        KH[row * ASTR + d] = __float2half(kv);
        VH[d * VSTR + row] = __float2half(vv);
    }
    __syncthreads();

    const uint32_t a_r = (lane & 7) + ((lane >> 3) & 1) * 8;
    const uint32_t a_c = (lane >> 4) * 8;
    const uint32_t b_r = (lane & 7) + (lane >> 4) * 8;
    const uint32_t b_c = ((lane >> 3) & 1) * 8;

    if (wid < 11) {
        const int m0 = wid * 16;

        uint32_t aq[4][4], aql[4][4];
#pragma unroll
        for (int k = 0; k < 4; k++) {
            uint32_t off = ((m0 + a_r) * ASTR + a_c + k * 16) * 2;
            ldsm4(aq[k], sb + SA_QH + off);
            ldsm4(aql[k], sb + SA_QL + off);
        }

        float s[22][4];
#pragma unroll
        for (int j = 0; j < 22; j++)
#pragma unroll
            for (int q = 0; q < 4; q++) s[j][q] = 0.f;

#pragma unroll
        for (int nj = 0; nj < 11; nj++) {
            const int n0 = nj * 16;
#pragma unroll
            for (int k = 0; k < 4; k++) {
                uint32_t bkh[4];
                uint32_t off = ((n0 + b_r) * ASTR + b_c + k * 16) * 2;
                ldsm4(bkh, sb + SA_KH + off);
                mma_f16(s[2 * nj],     aq[k],  bkh);
                mma_f16(s[2 * nj + 1], aq[k],  bkh + 2);
                mma_f16(s[2 * nj],     aql[k], bkh);
                mma_f16(s[2 * nj + 1], aql[k], bkh + 2);
            }
        }

        {
            int c0 = 168 + tq * 2;
            if (c0 >= NTOK)     { s[21][0] = -1e30f; s[21][2] = -1e30f; }
            if (c0 + 1 >= NTOK) { s[21][1] = -1e30f; s[21][3] = -1e30f; }
        }

        float mx0 = -1e30f, mx1 = -1e30f;
#pragma unroll
        for (int j = 0; j < 22; j++) {
            mx0 = fmaxf(mx0, fmaxf(s[j][0], s[j][1]));
            mx1 = fmaxf(mx1, fmaxf(s[j][2], s[j][3]));
        }
        mx0 = fmaxf(mx0, __shfl_xor_sync(0xffffffffu, mx0, 1));
        mx0 = fmaxf(mx0, __shfl_xor_sync(0xffffffffu, mx0, 2));
        mx1 = fmaxf(mx1, __shfl_xor_sync(0xffffffffu, mx1, 1));
        mx1 = fmaxf(mx1, __shfl_xor_sync(0xffffffffu, mx1, 2));

        float rs0 = 0.f, rs1 = 0.f;
#pragma unroll
        for (int j = 0; j < 22; j++) {
            s[j][0] = __expf((s[j][0] - mx0) * 0.125f);
            s[j][1] = __expf((s[j][1] - mx0) * 0.125f);
            s[j][2] = __expf((s[j][2] - mx1) * 0.125f);
            s[j][3] = __expf((s[j][3] - mx1) * 0.125f);
            rs0 += s[j][0] + s[j][1];
            rs1 += s[j][2] + s[j][3];
        }
        rs0 += __shfl_xor_sync(0xffffffffu, rs0, 1);
        rs0 += __shfl_xor_sync(0xffffffffu, rs0, 2);
        rs1 += __shfl_xor_sync(0xffffffffu, rs1, 1);
        rs1 += __shfl_xor_sync(0xffffffffu, rs1, 2);

        float o[8][4];
#pragma unroll
        for (int j = 0; j < 8; j++)
#pragma unroll
            for (int q = 0; q < 4; q++) o[j][q] = 0.f;

#pragma unroll
        for (int kt = 0; kt < 11; kt++) {
            uint32_t ap[4], apl[4];
#pragma unroll
            for (int half = 0; half < 2; half++) {
                const float* sv = s[2 * kt + half];
                __half h0 = __float2half(sv[0]), h1 = __float2half(sv[1]);
                __half h2v = __float2half(sv[2]), h3 = __float2half(sv[3]);
                ap[2 * half]     = pack_h2(__half2float(h0), __half2float(h1));
                ap[2 * half + 1] = pack_h2(__half2float(h2v), __half2float(h3));
                apl[2 * half]     = pack_h2(sv[0] - __half2float(h0), sv[1] - __half2float(h1));
                apl[2 * half + 1] = pack_h2(sv[2] - __half2float(h2v), sv[3] - __half2float(h3));
            }
#pragma unroll
            for (int dj = 0; dj < 4; dj++) {
                const int d0 = dj * 16;
                uint32_t bvh[4];
                uint32_t off = ((d0 + b_r) * VSTR + b_c + kt * 16) * 2;
                ldsm4(bvh, sb + SA_VH + off);
                mma_f16(o[2 * dj],     ap,  bvh);
                mma_f16(o[2 * dj + 1], ap,  bvh + 2);
                mma_f16(o[2 * dj],     apl, bvh);
                mma_f16(o[2 * dj + 1], apl, bvh + 2);
            }
        }

        const float i0 = 1.f / rs0, i1 = 1.f / rs1;
        const int r0 = m0 + group, r1 = r0 + 8;
#pragma unroll
        for (int j = 0; j < 8; j++) {
            int d = 8 * j + tq * 2;
            if (r0 < NTOK) {
                __half2 hv = __floats2half2_rn(o[j][0] * i0, o[j][1] * i0);
                *(__half2*)(out + (size_t)(b * NTOK + r0) * DD + hh * HDIM + d) = hv;
            }
            if (r1 < NTOK) {
                __half2 hv = __floats2half2_rn(o[j][2] * i1, o[j][3] * i1);
                *(__half2*)(out + (size_t)(b * NTOK + r1) * DD + hh * HDIM + d) = hv;
            }
        }
    }
}

// ---------------- head ----------------
__global__ void head_kernel(const float* __restrict__ cls, const float* __restrict__ hw,
                            const float* __restrict__ hb, float* __restrict__ out) {
    int b = blockIdx.x;
    int tid = threadIdx.x;
    float a0 = 0.f, a1 = 0.f, a2 = 0.f;
    for (int d = tid; d < DD; d += 256) {
        float v = cls[b * DD + d];
        a0 += v * hw[d * 3 + 0];
        a1 += v * hw[d * 3 + 1];
        a2 += v * hw[d * 3 + 2];
    }
    int lane = tid & 31, warp = tid >> 5;
#pragma unroll
    for (int off = 16; off; off >>= 1) {
        a0 += __shfl_down_sync(0xffffffffu, a0, off);
        a1 += __shfl_down_sync(0xffffffffu, a1, off);
        a2 += __shfl_down_sync(0xffffffffu, a2, off);
    }
    __shared__ float s0[8], s1[8], s2[8];
    if (lane == 0) { s0[warp] = a0; s1[warp] = a1; s2[warp] = a2; }
    __syncthreads();
    if (warp == 0 && lane < 8) {
        a0 = s0[lane]; a1 = s1[lane]; a2 = s2[lane];
#pragma unroll
        for (int off = 4; off; off >>= 1) {
            a0 += __shfl_down_sync(0x000000ffu, a0, off);
            a1 += __shfl_down_sync(0x000000ffu, a1, off);
            a2 += __shfl_down_sync(0x000000ffu, a2, off);
        }
        if (lane == 0) {
            out[b * 3 + 0] = a0 + hb[0];
            out[b * 3 + 1] = a1 + hb[1];
            out[b * 3 + 2] = a2 + hb[2];
        }
    }
}

// ---------------- launcher ----------------
extern "C" void kernel_launch(void* const* d_in, const int* in_sizes, int n_in,
                              void* d_out, int out_size) {
    const float* x        = (const float*)d_in[0];
    const float* conv_w   = (const float*)d_in[1];
    const float* conv_b   = (const float*)d_in[2];
    const float* cls_tok  = (const float*)d_in[3];
    const float* pos      = (const float*)d_in[4];
    const float* ln1_w    = (const float*)d_in[5];
    const float* ln1_b    = (const float*)d_in[6];
    const float* qkv_w    = (const float*)d_in[7];
    const float* qkv_b    = (const float*)d_in[8];
    const float* proj_w   = (const float*)d_in[9];
    const float* proj_b   = (const float*)d_in[10];
    const float* ln2_w    = (const float*)d_in[11];
    const float* ln2_b    = (const float*)d_in[12];
    const float* fc1_w    = (const float*)d_in[13];
    const float* fc1_b    = (const float*)d_in[14];
    const float* fc2_w    = (const float*)d_in[15];
    const float* fc2_b    = (const float*)d_in[16];
    const float* norm_w   = (const float*)d_in[17];
    const float* norm_b   = (const float*)d_in[18];
    const float* head_w   = (const float*)d_in[19];
    const float* head_b   = (const float*)d_in[20];
    float* out = (float*)d_out;

    float *h, *clsb, *qkvf;
    __half *colh, *coll, *convWh, *yf, *af, *bigf;
    __half *qkvWh, *projWh, *fc1Wh, *fc2Wh;
    cudaGetSymbolAddress((void**)&colh, g_colh);
    cudaGetSymbolAddress((void**)&coll, g_coll);
    cudaGetSymbolAddress((void**)&convWh, g_convWh);
    cudaGetSymbolAddress((void**)&h, g_h);
    cudaGetSymbolAddress((void**)&clsb, g_cls);
    cudaGetSymbolAddress((void**)&qkvf, g_qkvf);
    cudaGetSymbolAddress((void**)&yf, g_yf);
    cudaGetSymbolAddress((void**)&af, g_af);
    cudaGetSymbolAddress((void**)&bigf, g_bigf);
    cudaGetSymbolAddress((void**)&qkvWh, g_qkvWh);
    cudaGetSymbolAddress((void**)&projWh, g_projWh);
    cudaGetSymbolAddress((void**)&fc1Wh, g_fc1Wh);
    cudaGetSymbolAddress((void**)&fc2Wh, g_fc2Wh);

    cudaFuncSetAttribute(attn_mma_kernel, cudaFuncAttributeMaxDynamicSharedMemorySize, ATTN_SMEM);
    cudaFuncSetAttribute(hmma_gemm<false, false, false>, cudaFuncAttributeMaxDynamicSharedMemorySize, SMTOT1);
    cudaFuncSetAttribute(hmma_gemm<false, false, true>, cudaFuncAttributeMaxDynamicSharedMemorySize, SMTOT1);
    cudaFuncSetAttribute(hmma_gemm<true, true, false>, cudaFuncAttributeMaxDynamicSharedMemorySize, SMTOT1);
    cudaFuncSetAttribute(conv_gemm, cudaFuncAttributeMaxDynamicSharedMemorySize, CSMTOT);

    // weight prep
    transpose_hi<<<dim3(3 * DD / 32, DD / 32, DEPTH), dim3(32, 8)>>>(qkv_w, qkvWh, DD, 3 * DD);
    transpose_hi<<<dim3(DD / 32, DD / 32, DEPTH), dim3(32, 8)>>>(proj_w, projWh, DD, DD);
    transpose_hi<<<dim3(4 * DD / 32, DD / 32, DEPTH), dim3(32, 8)>>>(fc1_w, fc1Wh, DD, 4 * DD);
    transpose_hi<<<dim3(DD / 32, 4 * DD / 32, DEPTH), dim3(32, 8)>>>(fc2_w, fc2Wh, 4 * DD, DD);
    convw_prep<<<(DD * KCPAD + 255) / 256, 256>>>(conv_w, convWh);

    // patch embed (fp16 2-product, fused pos-embed + assemble)
    im2col_split<<<(CROWS * KCPAD + 255) / 256, 256>>>(x, colh, coll);
    cls_fill<<<(BATCH * DD + 255) / 256, 256>>>(cls_tok, pos, h);
    conv_gemm<<<dim3(DD / 128, CROWS / 128), 256, CSMTOT>>>(colh, coll, convWh, conv_b, pos, h);

    const int MT = MPAD / 128;  // 86
    for (int i = 0; i < DEPTH; i++) {
        ln_f16_kernel<<<MROWS, 256>>>(h, ln1_w + (size_t)i * DD, ln1_b + (size_t)i * DD, yf);
        hmma_gemm<false, false, false><<<dim3(3 * DD / 128, MT), 256, SMTOT1>>>(
            yf, qkvWh + (size_t)i * 3 * DD * DD,
            qkv_b + (size_t)i * 3 * DD, nullptr, qkvf, nullptr, MROWS, 3 * DD, DD);
        attn_mma_kernel<<<BATCH * NHEAD, ATHREADS, ATTN_SMEM>>>(qkvf, af);
        hmma_gemm<false, false, true><<<dim3(DD / 128, MT), 256, SMTOT1>>>(
            af, projWh + (size_t)i * DD * DD,
            proj_b + (size_t)i * DD, h, h, nullptr, MROWS, DD, DD);
        ln_f16_kernel<<<MROWS, 256>>>(h, ln2_w + (size_t)i * DD, ln2_b + (size_t)i * DD, yf);
        hmma_gemm<true, true, false><<<dim3(4 * DD / 128, MT), 256, SMTOT1>>>(
            yf, fc1Wh + (size_t)i * 4 * DD * DD,
            fc1_b + (size_t)i * 4 * DD, nullptr, nullptr, bigf, MROWS, 4 * DD, DD);
        hmma_gemm<false, false, true><<<dim3(DD / 128, MT), 256, SMTOT1>>>(
            bigf, fc2Wh + (size_t)i * 4 * DD * DD,
            fc2_b + (size_t)i * DD, h, h, nullptr, MROWS, DD, 4 * DD);
    }

    ln_kernel<<<BATCH, 256>>>(h, norm_w, norm_b, clsb, NTOK);
    head_kernel<<<BATCH, 256>>>(clsb, head_w, head_b, out);
}

// round 13
// speedup vs baseline: 7.2642x; 1.0527x over previous
#include <cuda_runtime.h>
#include <cuda_fp16.h>
#include <math.h>
#include <stdint.h>

// ---------------- problem constants ----------------
#define DD     768
#define NTOK   171
#define BATCH  64
#define MROWS  (BATCH*NTOK)      // 10944
#define MPAD   11008             // 86*128
#define NPATCH 170
#define CROWS  (BATCH*NPATCH)    // 10880 = 85*128
#define KCONV  600
#define KCPAD  640
#define NHEAD  12
#define HDIM   64
#define DEPTH  12
#define EPS    1e-5f

// ---------------- scratch (device globals) ----------------
__device__ __half g_colh[CROWS * KCPAD];
__device__ __half g_coll[CROWS * KCPAD];
__device__ __half g_convWh[DD * KCPAD];
__device__ float g_h   [MROWS * DD];
__device__ float g_cls [BATCH * DD];
__device__ __half g_qkvh [MPAD * 3 * DD];
__device__ __half g_yf   [MPAD * DD];
__device__ __half g_af   [MPAD * DD];
__device__ __half g_bigf [MPAD * 4 * DD];
__device__ __half g_qkvWh[DEPTH * 3 * DD * DD];
__device__ __half g_projWh[DEPTH * DD * DD];
__device__ __half g_fc1Wh[DEPTH * 4 * DD * DD];
__device__ __half g_fc2Wh[DEPTH * 4 * DD * DD];

// ---------------- helpers ----------------
__device__ __forceinline__ uint32_t smem_u32(const void* p) {
    uint32_t a;
    asm("{ .reg .u64 t; cvta.to.shared.u64 t, %1; cvt.u32.u64 %0, t; }" : "=r"(a) : "l"(p));
    return a;
}
__device__ __forceinline__ void cp_async16(uint32_t dst, const void* src) {
    asm volatile("cp.async.cg.shared.global [%0], [%1], 16;"
                 :: "r"(dst), "l"(src) : "memory");
}
__device__ __forceinline__ void cp_commit() {
    asm volatile("cp.async.commit_group;" ::: "memory");
}
template <int N>
__device__ __forceinline__ void cp_wait() {
    asm volatile("cp.async.wait_group %0;" :: "n"(N) : "memory");
}
__device__ __forceinline__ void ldsm4(uint32_t* r, uint32_t addr) {
    asm volatile("ldmatrix.sync.aligned.m8n8.x4.shared.b16 {%0,%1,%2,%3}, [%4];"
                 : "=r"(r[0]), "=r"(r[1]), "=r"(r[2]), "=r"(r[3]) : "r"(addr));
}
__device__ __forceinline__ void mma_f16(float* c, const uint32_t* a, const uint32_t* b) {
    asm volatile(
        "mma.sync.aligned.m16n8k16.row.col.f32.f16.f16.f32 "
        "{%0,%1,%2,%3}, {%4,%5,%6,%7}, {%8,%9}, {%0,%1,%2,%3};"
        : "+f"(c[0]), "+f"(c[1]), "+f"(c[2]), "+f"(c[3])
        : "r"(a[0]), "r"(a[1]), "r"(a[2]), "r"(a[3]), "r"(b[0]), "r"(b[1]));
}
__device__ __forceinline__ void splith(float v, __half& hi, __half& lo) {
    hi = __float2half(v);
    lo = __float2half(v - __half2float(hi));
}
__device__ __forceinline__ uint32_t pack_h2(float a, float b) {
    __half2 h = __floats2half2_rn(a, b);
    return *(uint32_t*)&h;
}

// ---------------- fp16 GEMM: C = A @ Wh^T (single product, 2 CTAs/SM, 1 sync/kt) ----------------
#define GSTR 40
#define TILEB (128 * GSTR * 2)
#define STG (2 * TILEB)
#define NST 4
#define SMTOT1 (NST * STG)       // 81920 B/CTA

template <bool OUTF16, bool GELU_, bool RES>
__global__ void __launch_bounds__(256, 2)
hmma_gemm(const __half* __restrict__ A, const __half* __restrict__ Wh,
          const float* __restrict__ bias, const float* __restrict__ res,
          float* __restrict__ Cf, __half* __restrict__ Ch,
          int Mvalid, int Ntot, int K) {
    extern __shared__ char dsm[];
    const uint32_t sb = smem_u32(dsm);

    const int tid = threadIdx.x;
    const int lane = tid & 31, wid = tid >> 5;
    const int wm = wid & 1, wn = wid >> 1;
    const int group = lane >> 2, tq = lane & 3;
    const int m0 = blockIdx.y * 128;
    const int n0 = blockIdx.x * 128;
    const int KT = K >> 5;

    const __half* gA = A + (size_t)m0 * K;
    const __half* gWh = Wh + (size_t)n0 * K;

    float acc[4][4][4];
#pragma unroll
    for (int mi = 0; mi < 4; mi++)
#pragma unroll
        for (int ni = 0; ni < 4; ni++)
#pragma unroll
            for (int q = 0; q < 4; q++) acc[mi][ni][q] = 0.f;

    const int lr = tid >> 2;
    const int lc = tid & 3;

    auto load_stage = [&](int kt, int st) {
        const size_t koff = (size_t)kt * 32;
        uint32_t base = sb + st * STG;
#pragma unroll
        for (int i = 0; i < 2; i++) {
            int r = lr + i * 64;
            uint32_t so = (r * GSTR + lc * 8) * 2;
            size_t go = (size_t)r * K + koff + lc * 8;
            cp_async16(base + 0 * TILEB + so, gA + go);
            cp_async16(base + 1 * TILEB + so, gWh + go);
        }
        cp_commit();
    };

    const uint32_t arow = wm * 64 + (lane & 7) + ((lane >> 3) & 1) * 8;
    const uint32_t acol = (lane >> 4) * 8;
    const uint32_t aoff = (arow * GSTR + acol) * 2;
    const uint32_t brow = wn * 32 + (lane & 7) + (lane >> 4) * 8;
    const uint32_t bcol = ((lane >> 3) & 1) * 8;
    const uint32_t boff = (brow * GSTR + bcol) * 2;

    load_stage(0, 0);
    load_stage(1, 1);
    load_stage(2, 2);

#pragma unroll 1
    for (int kt = 0; kt < KT; kt++) {
        if (kt + 2 < KT)      cp_wait<2>();
        else if (kt + 1 < KT) cp_wait<1>();
        else                  cp_wait<0>();
        __syncthreads();

        const uint32_t stbase = sb + (kt & 3) * STG;
        const uint32_t aA = stbase + aoff;
        const uint32_t bH = stbase + TILEB + boff;

#pragma unroll
        for (int ks = 0; ks < 2; ks++) {
            const uint32_t kadd = ks * 32;
            uint32_t af[16], bh[8];
#pragma unroll
            for (int mi = 0; mi < 4; mi++)
                ldsm4(af + mi * 4, aA + mi * (16 * GSTR * 2) + kadd);
#pragma unroll
            for (int nj = 0; nj < 2; nj++)
                ldsm4(bh + nj * 4, bH + nj * (16 * GSTR * 2) + kadd);
#pragma unroll
            for (int mi = 0; mi < 4; mi++)
#pragma unroll
                for (int ni = 0; ni < 4; ni++)
                    mma_f16(acc[mi][ni], af + mi * 4, bh + ni * 2);
        }

        if (kt + 3 < KT) load_stage(kt + 3, (kt + 3) & 3);
    }

#pragma unroll
    for (int mi = 0; mi < 4; mi++) {
#pragma unroll
        for (int rr = 0; rr < 2; rr++) {
            int m = m0 + wm * 64 + mi * 16 + group + rr * 8;
            if (m >= Mvalid) continue;
#pragma unroll
            for (int ni = 0; ni < 4; ni++) {
                int n = n0 + wn * 32 + ni * 8 + tq * 2;
                float v0 = acc[mi][ni][rr * 2 + 0] + bias[n];
                float v1 = acc[mi][ni][rr * 2 + 1] + bias[n + 1];
                if (GELU_) {
                    v0 = 0.5f * v0 * (1.f + erff(v0 * 0.70710678118654752f));
                    v1 = 0.5f * v1 * (1.f + erff(v1 * 0.70710678118654752f));
                }
                if (RES) {
                    float2 rv = *(const float2*)(res + (size_t)m * Ntot + n);
                    v0 += rv.x; v1 += rv.y;
                }
                if (OUTF16) {
                    __half2 h2 = __floats2half2_rn(v0, v1);
                    *(__half2*)(Ch + (size_t)m * Ntot + n) = h2;
                } else {
                    *(float2*)(Cf + (size_t)m * Ntot + n) = make_float2(v0, v1);
                }
            }
        }
    }
}

// ---------------- conv GEMM: h = (xh+xl) @ Wh^T + bias + pos (fused assemble) ----------------
#define CSTG (3 * TILEB)
#define CNST 3
#define CSMTOT (CNST * CSTG)     // 92160 B/CTA

__global__ void __launch_bounds__(256, 2)
conv_gemm(const __half* __restrict__ Ah, const __half* __restrict__ Al,
          const __half* __restrict__ Wh, const float* __restrict__ bias,
          const float* __restrict__ pos, float* __restrict__ hout) {
    extern __shared__ char dsm[];
    const uint32_t sb = smem_u32(dsm);
    const int K = KCPAD, KT = KCPAD / 32;  // 20

    const int tid = threadIdx.x;
    const int lane = tid & 31, wid = tid >> 5;
    const int wm = wid & 1, wn = wid >> 1;
    const int group = lane >> 2, tq = lane & 3;
    const int m0 = blockIdx.y * 128;
    const int n0 = blockIdx.x * 128;

    const __half* gAh = Ah + (size_t)m0 * K;
    const __half* gAl = Al + (size_t)m0 * K;
    const __half* gWh = Wh + (size_t)n0 * K;

    float acc[4][4][4];
#pragma unroll
    for (int mi = 0; mi < 4; mi++)
#pragma unroll
        for (int ni = 0; ni < 4; ni++)
#pragma unroll
            for (int q = 0; q < 4; q++) acc[mi][ni][q] = 0.f;

    const int lr = tid >> 2;
    const int lc = tid & 3;

    auto load_stage = [&](int kt, int st) {
        const size_t koff = (size_t)kt * 32;
        uint32_t base = sb + st * CSTG;
#pragma unroll
        for (int i = 0; i < 2; i++) {
            int r = lr + i * 64;
            uint32_t so = (r * GSTR + lc * 8) * 2;
            size_t go = (size_t)r * K + koff + lc * 8;
            cp_async16(base + 0 * TILEB + so, gAh + go);
            cp_async16(base + 1 * TILEB + so, gAl + go);
            cp_async16(base + 2 * TILEB + so, gWh + go);
        }
        cp_commit();
    };

    const uint32_t arow = wm * 64 + (lane & 7) + ((lane >> 3) & 1) * 8;
    const uint32_t acol = (lane >> 4) * 8;
    const uint32_t aoff = (arow * GSTR + acol) * 2;
    const uint32_t brow = wn * 32 + (lane & 7) + (lane >> 4) * 8;
    const uint32_t bcol = ((lane >> 3) & 1) * 8;
    const uint32_t boff = (brow * GSTR + bcol) * 2;

    load_stage(0, 0);
    load_stage(1, 1);

#pragma unroll 1
    for (int kt = 0; kt < KT; kt++) {
        if (kt + 1 < KT) cp_wait<1>();
        else             cp_wait<0>();
        __syncthreads();

        const uint32_t stbase = sb + (kt % 3) * CSTG;
        const uint32_t aH = stbase + aoff;
        const uint32_t aL = stbase + TILEB + aoff;
        const uint32_t bH = stbase + 2 * TILEB + boff;

#pragma unroll
        for (int ks = 0; ks < 2; ks++) {
            const uint32_t kadd = ks * 32;
            uint32_t afh[16], afl[16], bh[8];
#pragma unroll
            for (int mi = 0; mi < 4; mi++) {
                ldsm4(afh + mi * 4, aH + mi * (16 * GSTR * 2) + kadd);
                ldsm4(afl + mi * 4, aL + mi * (16 * GSTR * 2) + kadd);
            }
#pragma unroll
            for (int nj = 0; nj < 2; nj++)
                ldsm4(bh + nj * 4, bH + nj * (16 * GSTR * 2) + kadd);
#pragma unroll
            for (int mi = 0; mi < 4; mi++)
#pragma unroll
                for (int ni = 0; ni < 4; ni++)
                    mma_f16(acc[mi][ni], afh + mi * 4, bh + ni * 2);
#pragma unroll
            for (int mi = 0; mi < 4; mi++)
#pragma unroll
                for (int ni = 0; ni < 4; ni++)
                    mma_f16(acc[mi][ni], afl + mi * 4, bh + ni * 2);
        }

        if (kt + 2 < KT) load_stage(kt + 2, (kt + 2) % 3);
    }

#pragma unroll
    for (int mi = 0; mi < 4; mi++) {
#pragma unroll
        for (int rr = 0; rr < 2; rr++) {
            int m = m0 + wm * 64 + mi * 16 + group + rr * 8;
            int b = m / NPATCH, p = m % NPATCH;
            size_t row = (size_t)b * NTOK + p + 1;
            const float* pr = pos + (size_t)(p + 1) * DD;
#pragma unroll
            for (int ni = 0; ni < 4; ni++) {
                int n = n0 + wn * 32 + ni * 8 + tq * 2;
                float v0 = acc[mi][ni][rr * 2 + 0] + bias[n] + pr[n];
                float v1 = acc[mi][ni][rr * 2 + 1] + bias[n + 1] + pr[n + 1];
                *(float2*)(hout + row * DD + n) = make_float2(v0, v1);
            }
        }
    }
}

// ---------------- im2col -> split fp16 (padded K=640) ----------------
__global__ void im2col_split(const float* __restrict__ x,
                             __half* __restrict__ colh, __half* __restrict__ coll) {
    int idx = blockIdx.x * blockDim.x + threadIdx.x;
    if (idx >= CROWS * KCPAD) return;
    int r = idx / KCPAD, c = idx % KCPAD;
    float v = 0.f;
    if (c < KCONV) {
        int b = r / NPATCH, p = r % NPATCH;
        int chn = c / 100, rem = c % 100;
        int kh = rem / 10, kw = rem % 10;
        int phh = p / 34, pw = p % 34;
        v = x[((b * 6 + chn) * 50 + phh * 10 + kh) * 345 + pw * 10 + kw];
    }
    __half hi, lo;
    splith(v, hi, lo);
    colh[idx] = hi;
    coll[idx] = lo;
}

// ---------------- conv weight -> fp16 (padded K=640) ----------------
__global__ void convw_prep(const float* __restrict__ w, __half* __restrict__ wh) {
    int idx = blockIdx.x * blockDim.x + threadIdx.x;
    if (idx >= DD * KCPAD) return;
    int d = idx / KCPAD, k = idx % KCPAD;
    wh[idx] = __float2half(k < KCONV ? w[d * KCONV + k] : 0.f);
}

// ---------------- cls token rows ----------------
__global__ void cls_fill(const float* __restrict__ cls, const float* __restrict__ pos,
                         float* __restrict__ h) {
    int idx = blockIdx.x * blockDim.x + threadIdx.x;
    if (idx >= BATCH * DD) return;
    int b = idx / DD, d = idx % DD;
    h[(size_t)b * NTOK * DD + d] = cls[d] + pos[d];
}

// ---------------- weight transpose -> fp16 (hi only) ----------------
__global__ void transpose_hi(const float* __restrict__ W, __half* __restrict__ Wh,
                             int R, int C) {
    __shared__ float t[32][33];
    int z = blockIdx.z;
    const float* Wz = W + (size_t)z * R * C;
    __half* Whz = Wh + (size_t)z * R * C;
    int c0 = blockIdx.x * 32, r0 = blockIdx.y * 32;
    int x = threadIdx.x, y = threadIdx.y;
#pragma unroll
    for (int i = 0; i < 32; i += 8)
        t[y + i][x] = Wz[(size_t)(r0 + y + i) * C + c0 + x];
    __syncthreads();
#pragma unroll
    for (int i = 0; i < 32; i += 8)
        Whz[(size_t)(c0 + y + i) * R + r0 + x] = __float2half(t[x][y + i]);
}

// ---------------- LayerNorm fp32 -> fp16 ----------------
__global__ void ln_f16_kernel(const float* __restrict__ X, const float* __restrict__ w,
                              const float* __restrict__ b, __half* __restrict__ Y) {
    int row = blockIdx.x;
    int tid = threadIdx.x;
    const float* xr = X + (size_t)row * DD;
    float v0 = xr[tid], v1 = xr[tid + 256], v2 = xr[tid + 512];
    float s = v0 + v1 + v2;
    float q = v0 * v0 + v1 * v1 + v2 * v2;
    int lane = tid & 31, warp = tid >> 5;
#pragma unroll
    for (int off = 16; off; off >>= 1) {
        s += __shfl_down_sync(0xffffffffu, s, off);
        q += __shfl_down_sync(0xffffffffu, q, off);
    }
    __shared__ float sa[8], sbm[8];
    if (lane == 0) { sa[warp] = s; sbm[warp] = q; }
    __syncthreads();
    if (warp == 0) {
        s = (lane < 8) ? sa[lane] : 0.f;
        q = (lane < 8) ? sbm[lane] : 0.f;
#pragma unroll
        for (int off = 4; off; off >>= 1) {
            s += __shfl_down_sync(0xffffffffu, s, off);
            q += __shfl_down_sync(0xffffffffu, q, off);
        }
        if (lane == 0) { sa[0] = s; sbm[0] = q; }
    }
    __syncthreads();
    float mean = sa[0] * (1.f / DD);
    float var = sbm[0] * (1.f / DD) - mean * mean;
    float inv = rsqrtf(var + EPS);
    __half* yr = Y + (size_t)row * DD;
    yr[tid]       = __float2half((v0 - mean) * inv * w[tid]       + b[tid]);
    yr[tid + 256] = __float2half((v1 - mean) * inv * w[tid + 256] + b[tid + 256]);
    yr[tid + 512] = __float2half((v2 - mean) * inv * w[tid + 512] + b[tid + 512]);
}

// ---------------- LayerNorm fp32 -> fp32 (final, cls rows) ----------------
__global__ void ln_kernel(const float* __restrict__ X, const float* __restrict__ w,
                          const float* __restrict__ b, float* __restrict__ Y, int row_mul) {
    int row_in = blockIdx.x * row_mul;
    int row_out = blockIdx.x;
    int tid = threadIdx.x;
    const float* xr = X + (size_t)row_in * DD;
    float v0 = xr[tid], v1 = xr[tid + 256], v2 = xr[tid + 512];
    float s = v0 + v1 + v2;
    float q = v0 * v0 + v1 * v1 + v2 * v2;
    int lane = tid & 31, warp = tid >> 5;
#pragma unroll
    for (int off = 16; off; off >>= 1) {
        s += __shfl_down_sync(0xffffffffu, s, off);
        q += __shfl_down_sync(0xffffffffu, q, off);
    }
    __shared__ float sa[8], sbm[8];
    if (lane == 0) { sa[warp] = s; sbm[warp] = q; }
    __syncthreads();
    if (warp == 0) {
        s = (lane < 8) ? sa[lane] : 0.f;
        q = (lane < 8) ? sbm[lane] : 0.f;
#pragma unroll
        for (int off = 4; off; off >>= 1) {
            s += __shfl_down_sync(0xffffffffu, s, off);
            q += __shfl_down_sync(0xffffffffu, q, off);
        }
        if (lane == 0) { sa[0] = s; sbm[0] = q; }
    }
    __syncthreads();
    float mean = sa[0] * (1.f / DD);
    float var = sbm[0] * (1.f / DD) - mean * mean;
    float inv = rsqrtf(var + EPS);
    float* yr = Y + (size_t)row_out * DD;
    yr[tid]       = (v0 - mean) * inv * w[tid]       + b[tid];
    yr[tid + 256] = (v1 - mean) * inv * w[tid + 256] + b[tid + 256];
    yr[tid + 512] = (v2 - mean) * inv * w[tid + 512] + b[tid + 512];
}

// ---------------- MMA attention (fp16 qkv in, single product, 11 warps) ----------------
#define NTOKP 176
#define ASTR 72
#define VSTR 184
#define SA_QH 0
#define SA_KH (SA_QH + NTOKP*ASTR*2)
#define SA_VH (SA_KH + NTOKP*ASTR*2)
#define ATTN_SMEM (SA_VH + 64*VSTR*2)   // 74240 B
#define ATHREADS 352

__global__ void __launch_bounds__(ATHREADS, 1)
attn_mma_kernel(const __half* __restrict__ qkv, __half* __restrict__ out) {
    extern __shared__ char asmem[];
    const uint32_t sb = smem_u32(asmem);
    __half* QH = (__half*)(asmem + SA_QH);
    __half* KH = (__half*)(asmem + SA_KH);
    __half* VH = (__half*)(asmem + SA_VH);

    const int bh = blockIdx.x;
    const int b = bh / NHEAD, hh = bh % NHEAD;
    const int tid = threadIdx.x;
    const int lane = tid & 31, wid = tid >> 5;
    const int group = lane >> 2, tq = lane & 3;
    const size_t base = (size_t)b * NTOK * (3 * DD) + hh * HDIM;

    for (int idx = tid; idx < NTOKP * 64; idx += ATHREADS) {
        int row = idx >> 6, d = idx & 63;
        __half qv = __float2half(0.f), kv = qv, vv = qv;
        if (row < NTOK) {
            size_t o = base + (size_t)row * (3 * DD) + d;
            qv = qkv[o]; kv = qkv[o + DD]; vv = qkv[o + 2 * DD];
        }
        QH[row * ASTR + d] = qv;
        KH[row * ASTR + d] = kv;
        VH[d * VSTR + row] = vv;
    }
    __syncthreads();

    const uint32_t a_r = (lane & 7) + ((lane >> 3) & 1) * 8;
    const uint32_t a_c = (lane >> 4) * 8;
    const uint32_t b_r = (lane & 7) + (lane >> 4) * 8;
    const uint32_t b_c = ((lane >> 3) & 1) * 8;

    if (wid < 11) {
        const int m0 = wid * 16;

        uint32_t aq[4][4];
#pragma unroll
        for (int k = 0; k < 4; k++) {
            uint32_t off = ((m0 + a_r) * ASTR + a_c + k * 16) * 2;
            ldsm4(aq[k], sb + SA_QH + off);
        }

        float s[22][4];
#pragma unroll
        for (int j = 0; j < 22; j++)
#pragma unroll
            for (int q = 0; q < 4; q++) s[j][q] = 0.f;

#pragma unroll
        for (int nj = 0; nj < 11; nj++) {
            const int n0 = nj * 16;
#pragma unroll
            for (int k = 0; k < 4; k++) {
                uint32_t bkh[4];
                uint32_t off = ((n0 + b_r) * ASTR + b_c + k * 16) * 2;
                ldsm4(bkh, sb + SA_KH + off);
                mma_f16(s[2 * nj],     aq[k], bkh);
                mma_f16(s[2 * nj + 1], aq[k], bkh + 2);
            }
        }

        {
            int c0 = 168 + tq * 2;
            if (c0 >= NTOK)     { s[21][0] = -1e30f; s[21][2] = -1e30f; }
            if (c0 + 1 >= NTOK) { s[21][1] = -1e30f; s[21][3] = -1e30f; }
        }

        float mx0 = -1e30f, mx1 = -1e30f;
#pragma unroll
        for (int j = 0; j < 22; j++) {
            mx0 = fmaxf(mx0, fmaxf(s[j][0], s[j][1]));
            mx1 = fmaxf(mx1, fmaxf(s[j][2], s[j][3]));
        }
        mx0 = fmaxf(mx0, __shfl_xor_sync(0xffffffffu, mx0, 1));
        mx0 = fmaxf(mx0, __shfl_xor_sync(0xffffffffu, mx0, 2));
        mx1 = fmaxf(mx1, __shfl_xor_sync(0xffffffffu, mx1, 1));
        mx1 = fmaxf(mx1, __shfl_xor_sync(0xffffffffu, mx1, 2));

        float rs0 = 0.f, rs1 = 0.f;
#pragma unroll
        for (int j = 0; j < 22; j++) {
            s[j][0] = __expf((s[j][0] - mx0) * 0.125f);
            s[j][1] = __expf((s[j][1] - mx0) * 0.125f);
            s[j][2] = __expf((s[j][2] - mx1) * 0.125f);
            s[j][3] = __expf((s[j][3] - mx1) * 0.125f);
            rs0 += s[j][0] + s[j][1];
            rs1 += s[j][2] + s[j][3];
        }
        rs0 += __shfl_xor_sync(0xffffffffu, rs0, 1);
        rs0 += __shfl_xor_sync(0xffffffffu, rs0, 2);
        rs1 += __shfl_xor_sync(0xffffffffu, rs1, 1);
        rs1 += __shfl_xor_sync(0xffffffffu, rs1, 2);

        float o[8][4];
#pragma unroll
        for (int j = 0; j < 8; j++)
#pragma unroll
            for (int q = 0; q < 4; q++) o[j][q] = 0.f;

#pragma unroll
        for (int kt = 0; kt < 11; kt++) {
            uint32_t ap[4];
#pragma unroll
            for (int half = 0; half < 2; half++) {
                const float* sv = s[2 * kt + half];
                ap[2 * half]     = pack_h2(sv[0], sv[1]);
                ap[2 * half + 1] = pack_h2(sv[2], sv[3]);
            }
#pragma unroll
            for (int dj = 0; dj < 4; dj++) {
                const int d0 = dj * 16;
                uint32_t bvh[4];
                uint32_t off = ((d0 + b_r) * VSTR + b_c + kt * 16) * 2;
                ldsm4(bvh, sb + SA_VH + off);
                mma_f16(o[2 * dj],     ap, bvh);
                mma_f16(o[2 * dj + 1], ap, bvh + 2);
            }
        }

        const float i0 = 1.f / rs0, i1 = 1.f / rs1;
        const int r0 = m0 + group, r1 = r0 + 8;
#pragma unroll
        for (int j = 0; j < 8; j++) {
            int d = 8 * j + tq * 2;
            if (r0 < NTOK) {
                __half2 hv = __floats2half2_rn(o[j][0] * i0, o[j][1] * i0);
                *(__half2*)(out + (size_t)(b * NTOK + r0) * DD + hh * HDIM + d) = hv;
            }
            if (r1 < NTOK) {
                __half2 hv = __floats2half2_rn(o[j][2] * i1, o[j][3] * i1);
                *(__half2*)(out + (size_t)(b * NTOK + r1) * DD + hh * HDIM + d) = hv;
            }
        }
    }
}

// ---------------- head ----------------
__global__ void head_kernel(const float* __restrict__ cls, const float* __restrict__ hw,
                            const float* __restrict__ hb, float* __restrict__ out) {
    int b = blockIdx.x;
    int tid = threadIdx.x;
    float a0 = 0.f, a1 = 0.f, a2 = 0.f;
    for (int d = tid; d < DD; d += 256) {
        float v = cls[b * DD + d];
        a0 += v * hw[d * 3 + 0];
        a1 += v * hw[d * 3 + 1];
        a2 += v * hw[d * 3 + 2];
    }
    int lane = tid & 31, warp = tid >> 5;
#pragma unroll
    for (int off = 16; off; off >>= 1) {
        a0 += __shfl_down_sync(0xffffffffu, a0, off);
        a1 += __shfl_down_sync(0xffffffffu, a1, off);
        a2 += __shfl_down_sync(0xffffffffu, a2, off);
    }
    __shared__ float s0[8], s1[8], s2[8];
    if (lane == 0) { s0[warp] = a0; s1[warp] = a1; s2[warp] = a2; }
    __syncthreads();
    if (warp == 0 && lane < 8) {
        a0 = s0[lane]; a1 = s1[lane]; a2 = s2[lane];
#pragma unroll
        for (int off = 4; off; off >>= 1) {
            a0 += __shfl_down_sync(0x000000ffu, a0, off);
            a1 += __shfl_down_sync(0x000000ffu, a1, off);
            a2 += __shfl_down_sync(0x000000ffu, a2, off);
        }
        if (lane == 0) {
            out[b * 3 + 0] = a0 + hb[0];
            out[b * 3 + 1] = a1 + hb[1];
            out[b * 3 + 2] = a2 + hb[2];
        }
    }
}

// ---------------- launcher ----------------
extern "C" void kernel_launch(void* const* d_in, const int* in_sizes, int n_in,
                              void* d_out, int out_size) {
    const float* x        = (const float*)d_in[0];
    const float* conv_w   = (const float*)d_in[1];
    const float* conv_b   = (const float*)d_in[2];
    const float* cls_tok  = (const float*)d_in[3];
    const float* pos      = (const float*)d_in[4];
    const float* ln1_w    = (const float*)d_in[5];
    const float* ln1_b    = (const float*)d_in[6];
    const float* qkv_w    = (const float*)d_in[7];
    const float* qkv_b    = (const float*)d_in[8];
    const float* proj_w   = (const float*)d_in[9];
    const float* proj_b   = (const float*)d_in[10];
    const float* ln2_w    = (const float*)d_in[11];
    const float* ln2_b    = (const float*)d_in[12];
    const float* fc1_w    = (const float*)d_in[13];
    const float* fc1_b    = (const float*)d_in[14];
    const float* fc2_w    = (const float*)d_in[15];
    const float* fc2_b    = (const float*)d_in[16];
    const float* norm_w   = (const float*)d_in[17];
    const float* norm_b   = (const float*)d_in[18];
    const float* head_w   = (const float*)d_in[19];
    const float* head_b   = (const float*)d_in[20];
    float* out = (float*)d_out;

    float *h, *clsb;
    __half *colh, *coll, *convWh, *qkvh, *yf, *af, *bigf;
    __half *qkvWh, *projWh, *fc1Wh, *fc2Wh;
    cudaGetSymbolAddress((void**)&colh, g_colh);
    cudaGetSymbolAddress((void**)&coll, g_coll);
    cudaGetSymbolAddress((void**)&convWh, g_convWh);
    cudaGetSymbolAddress((void**)&h, g_h);
    cudaGetSymbolAddress((void**)&clsb, g_cls);
    cudaGetSymbolAddress((void**)&qkvh, g_qkvh);
    cudaGetSymbolAddress((void**)&yf, g_yf);
    cudaGetSymbolAddress((void**)&af, g_af);
    cudaGetSymbolAddress((void**)&bigf, g_bigf);
    cudaGetSymbolAddress((void**)&qkvWh, g_qkvWh);
    cudaGetSymbolAddress((void**)&projWh, g_projWh);
    cudaGetSymbolAddress((void**)&fc1Wh, g_fc1Wh);
    cudaGetSymbolAddress((void**)&fc2Wh, g_fc2Wh);

    cudaFuncSetAttribute(attn_mma_kernel, cudaFuncAttributeMaxDynamicSharedMemorySize, ATTN_SMEM);
    cudaFuncSetAttribute(hmma_gemm<true, false, false>, cudaFuncAttributeMaxDynamicSharedMemorySize, SMTOT1);
    cudaFuncSetAttribute(hmma_gemm<false, false, true>, cudaFuncAttributeMaxDynamicSharedMemorySize, SMTOT1);
    cudaFuncSetAttribute(hmma_gemm<true, true, false>, cudaFuncAttributeMaxDynamicSharedMemorySize, SMTOT1);
    cudaFuncSetAttribute(conv_gemm, cudaFuncAttributeMaxDynamicSharedMemorySize, CSMTOT);

    // weight prep
    transpose_hi<<<dim3(3 * DD / 32, DD / 32, DEPTH), dim3(32, 8)>>>(qkv_w, qkvWh, DD, 3 * DD);
    transpose_hi<<<dim3(DD / 32, DD / 32, DEPTH), dim3(32, 8)>>>(proj_w, projWh, DD, DD);
    transpose_hi<<<dim3(4 * DD / 32, DD / 32, DEPTH), dim3(32, 8)>>>(fc1_w, fc1Wh, DD, 4 * DD);
    transpose_hi<<<dim3(DD / 32, 4 * DD / 32, DEPTH), dim3(32, 8)>>>(fc2_w, fc2Wh, 4 * DD, DD);
    convw_prep<<<(DD * KCPAD + 255) / 256, 256>>>(conv_w, convWh);

    // patch embed (fp16 2-product, fused pos-embed + assemble)
    im2col_split<<<(CROWS * KCPAD + 255) / 256, 256>>>(x, colh, coll);
    cls_fill<<<(BATCH * DD + 255) / 256, 256>>>(cls_tok, pos, h);
    conv_gemm<<<dim3(DD / 128, CROWS / 128), 256, CSMTOT>>>(colh, coll, convWh, conv_b, pos, h);

    const int MT = MPAD / 128;  // 86
    for (int i = 0; i < DEPTH; i++) {
        ln_f16_kernel<<<MROWS, 256>>>(h, ln1_w + (size_t)i * DD, ln1_b + (size_t)i * DD, yf);
        hmma_gemm<true, false, false><<<dim3(3 * DD / 128, MT), 256, SMTOT1>>>(
            yf, qkvWh + (size_t)i * 3 * DD * DD,
            qkv_b + (size_t)i * 3 * DD, nullptr, nullptr, qkvh, MROWS, 3 * DD, DD);
        attn_mma_kernel<<<BATCH * NHEAD, ATHREADS, ATTN_SMEM>>>(qkvh, af);
        hmma_gemm<false, false, true><<<dim3(DD / 128, MT), 256, SMTOT1>>>(
            af, projWh + (size_t)i * DD * DD,
            proj_b + (size_t)i * DD, h, h, nullptr, MROWS, DD, DD);
        ln_f16_kernel<<<MROWS, 256>>>(h, ln2_w + (size_t)i * DD, ln2_b + (size_t)i * DD, yf);
        hmma_gemm<true, true, false><<<dim3(4 * DD / 128, MT), 256, SMTOT1>>>(
            yf, fc1Wh + (size_t)i * 4 * DD * DD,
            fc1_b + (size_t)i * 4 * DD, nullptr, nullptr, bigf, MROWS, 4 * DD, DD);
        hmma_gemm<false, false, true><<<dim3(DD / 128, MT), 256, SMTOT1>>>(
            bigf, fc2Wh + (size_t)i * 4 * DD * DD,
            fc2_b + (size_t)i * DD, h, h, nullptr, MROWS, DD, 4 * DD);
    }

    ln_kernel<<<BATCH, 256>>>(h, norm_w, norm_b, clsb, NTOK);
    head_kernel<<<BATCH, 256>>>(clsb, head_w, head_b, out);
}

// round 14
// speedup vs baseline: 8.3616x; 1.1511x over previous
#include <cuda_runtime.h>
#include <cuda_fp16.h>
#include <math.h>
#include <stdint.h>

// ---------------- problem constants ----------------
#define DD     768
#define NTOK   171
#define BATCH  64
#define MROWS  (BATCH*NTOK)      // 10944
#define MPAD   11008             // 86*128
#define NPATCH 170
#define CROWS  (BATCH*NPATCH)    // 10880 = 85*128
#define KCONV  600
#define KCPAD  640
#define NHEAD  12
#define HDIM   64
#define DEPTH  12
#define EPS    1e-5f

// ---------------- scratch (device globals) ----------------
__device__ __half g_colh[CROWS * KCPAD];
__device__ __half g_coll[CROWS * KCPAD];
__device__ __half g_convWh[DD * KCPAD];
__device__ float g_h   [MROWS * DD];
__device__ float g_cls [BATCH * DD];
__device__ __half g_qkvh [MPAD * 3 * DD];
__device__ __half g_yf   [MPAD * DD];
__device__ __half g_af   [MPAD * DD];
__device__ __half g_bigf [MPAD * 4 * DD];
__device__ __half g_qkvWh[DEPTH * 3 * DD * DD];
__device__ __half g_projWh[DEPTH * DD * DD];
__device__ __half g_fc1Wh[DEPTH * 4 * DD * DD];
__device__ __half g_fc2Wh[DEPTH * 4 * DD * DD];

// ---------------- helpers ----------------
__device__ __forceinline__ uint32_t smem_u32(const void* p) {
    uint32_t a;
    asm("{ .reg .u64 t; cvta.to.shared.u64 t, %1; cvt.u32.u64 %0, t; }" : "=r"(a) : "l"(p));
    return a;
}
__device__ __forceinline__ void cp_async16(uint32_t dst, const void* src) {
    asm volatile("cp.async.cg.shared.global [%0], [%1], 16;"
                 :: "r"(dst), "l"(src) : "memory");
}
__device__ __forceinline__ void cp_commit() {
    asm volatile("cp.async.commit_group;" ::: "memory");
}
template <int N>
__device__ __forceinline__ void cp_wait() {
    asm volatile("cp.async.wait_group %0;" :: "n"(N) : "memory");
}
__device__ __forceinline__ void ldsm4(uint32_t* r, uint32_t addr) {
    asm volatile("ldmatrix.sync.aligned.m8n8.x4.shared.b16 {%0,%1,%2,%3}, [%4];"
                 : "=r"(r[0]), "=r"(r[1]), "=r"(r[2]), "=r"(r[3]) : "r"(addr));
}
__device__ __forceinline__ void mma_f16(float* c, const uint32_t* a, const uint32_t* b) {
    asm volatile(
        "mma.sync.aligned.m16n8k16.row.col.f32.f16.f16.f32 "
        "{%0,%1,%2,%3}, {%4,%5,%6,%7}, {%8,%9}, {%0,%1,%2,%3};"
        : "+f"(c[0]), "+f"(c[1]), "+f"(c[2]), "+f"(c[3])
        : "r"(a[0]), "r"(a[1]), "r"(a[2]), "r"(a[3]), "r"(b[0]), "r"(b[1]));
}
__device__ __forceinline__ void splith(float v, __half& hi, __half& lo) {
    hi = __float2half(v);
    lo = __float2half(v - __half2float(hi));
}
__device__ __forceinline__ uint32_t pack_h2(float a, float b) {
    __half2 h = __floats2half2_rn(a, b);
    return *(uint32_t*)&h;
}

// ---------------- fp16 GEMM: C = A @ Wh^T (BK=64, 3 stages, 2 CTAs/SM, 1 sync/kt) ----------------
#define GSTR2 72                         // row stride (halves) = 144B; ldsm conflict-free
#define TILE2B (128 * GSTR2 * 2)         // 18432 B
#define STG2 (2 * TILE2B)                // 36864 B per stage (A + W)
#define NST2 3
#define SMTOT1 (NST2 * STG2)             // 110592 B/CTA

template <bool OUTF16, bool GELU_, bool RES>
__global__ void __launch_bounds__(256, 2)
hmma_gemm(const __half* __restrict__ A, const __half* __restrict__ Wh,
          const float* __restrict__ bias, const float* __restrict__ res,
          float* __restrict__ Cf, __half* __restrict__ Ch,
          int Mvalid, int Ntot, int K) {
    extern __shared__ char dsm[];
    const uint32_t sb = smem_u32(dsm);

    const int tid = threadIdx.x;
    const int lane = tid & 31, wid = tid >> 5;
    const int wm = wid & 1, wn = wid >> 1;
    const int group = lane >> 2, tq = lane & 3;
    const int m0 = blockIdx.y * 128;
    const int n0 = blockIdx.x * 128;
    const int KT = K >> 6;               // K/64 chunks

    const __half* gA = A + (size_t)m0 * K;
    const __half* gWh = Wh + (size_t)n0 * K;

    float acc[4][4][4];
#pragma unroll
    for (int mi = 0; mi < 4; mi++)
#pragma unroll
        for (int ni = 0; ni < 4; ni++)
#pragma unroll
            for (int q = 0; q < 4; q++) acc[mi][ni][q] = 0.f;

    const int lr = tid >> 3;             // 0..31
    const int lc = tid & 7;              // 16B chunk 0..7

    auto load_stage = [&](int kt, int st) {
        const size_t koff = (size_t)kt * 64;
        uint32_t base = sb + st * STG2;
#pragma unroll
        for (int i = 0; i < 4; i++) {
            int r = lr + i * 32;
            uint32_t so = (r * GSTR2 + lc * 8) * 2;
            size_t go = (size_t)r * K + koff + lc * 8;
            cp_async16(base + 0 * TILE2B + so, gA + go);
            cp_async16(base + 1 * TILE2B + so, gWh + go);
        }
        cp_commit();
    };

    const uint32_t arow = wm * 64 + (lane & 7) + ((lane >> 3) & 1) * 8;
    const uint32_t acol = (lane >> 4) * 8;
    const uint32_t aoff = (arow * GSTR2 + acol) * 2;
    const uint32_t brow = wn * 32 + (lane & 7) + (lane >> 4) * 8;
    const uint32_t bcol = ((lane >> 3) & 1) * 8;
    const uint32_t boff = (brow * GSTR2 + bcol) * 2;

    load_stage(0, 0);
    if (KT > 1) load_stage(1, 1);

#pragma unroll 1
    for (int kt = 0; kt < KT; kt++) {
        if (kt + 1 < KT) cp_wait<1>();
        else             cp_wait<0>();
        __syncthreads();

        const uint32_t stbase = sb + (kt % 3) * STG2;
        const uint32_t aA = stbase + aoff;
        const uint32_t bH = stbase + TILE2B + boff;

#pragma unroll
        for (int ks = 0; ks < 4; ks++) {
            const uint32_t kadd = ks * 32;   // 16 halves
            uint32_t af[16], bh[8];
#pragma unroll
            for (int mi = 0; mi < 4; mi++)
                ldsm4(af + mi * 4, aA + mi * (16 * GSTR2 * 2) + kadd);
#pragma unroll
            for (int nj = 0; nj < 2; nj++)
                ldsm4(bh + nj * 4, bH + nj * (16 * GSTR2 * 2) + kadd);
#pragma unroll
            for (int mi = 0; mi < 4; mi++)
#pragma unroll
                for (int ni = 0; ni < 4; ni++)
                    mma_f16(acc[mi][ni], af + mi * 4, bh + ni * 2);
        }

        if (kt + 2 < KT) load_stage(kt + 2, (kt + 2) % 3);
    }

#pragma unroll
    for (int mi = 0; mi < 4; mi++) {
#pragma unroll
        for (int rr = 0; rr < 2; rr++) {
            int m = m0 + wm * 64 + mi * 16 + group + rr * 8;
            if (m >= Mvalid) continue;
#pragma unroll
            for (int ni = 0; ni < 4; ni++) {
                int n = n0 + wn * 32 + ni * 8 + tq * 2;
                float v0 = acc[mi][ni][rr * 2 + 0] + bias[n];
                float v1 = acc[mi][ni][rr * 2 + 1] + bias[n + 1];
                if (GELU_) {
                    v0 = 0.5f * v0 * (1.f + erff(v0 * 0.70710678118654752f));
                    v1 = 0.5f * v1 * (1.f + erff(v1 * 0.70710678118654752f));
                }
                if (RES) {
                    float2 rv = *(const float2*)(res + (size_t)m * Ntot + n);
                    v0 += rv.x; v1 += rv.y;
                }
                if (OUTF16) {
                    __half2 h2 = __floats2half2_rn(v0, v1);
                    *(__half2*)(Ch + (size_t)m * Ntot + n) = h2;
                } else {
                    *(float2*)(Cf + (size_t)m * Ntot + n) = make_float2(v0, v1);
                }
            }
        }
    }
}

// ---------------- conv GEMM (BK=32, split-A 2-product; unchanged from R13) ----------------
#define GSTR 40
#define TILEB (128 * GSTR * 2)
#define CSTG (3 * TILEB)
#define CSMTOT (3 * CSTG)     // 92160 B/CTA

__global__ void __launch_bounds__(256, 2)
conv_gemm(const __half* __restrict__ Ah, const __half* __restrict__ Al,
          const __half* __restrict__ Wh, const float* __restrict__ bias,
          const float* __restrict__ pos, float* __restrict__ hout) {
    extern __shared__ char dsm[];
    const uint32_t sb = smem_u32(dsm);
    const int K = KCPAD, KT = KCPAD / 32;  // 20

    const int tid = threadIdx.x;
    const int lane = tid & 31, wid = tid >> 5;
    const int wm = wid & 1, wn = wid >> 1;
    const int group = lane >> 2, tq = lane & 3;
    const int m0 = blockIdx.y * 128;
    const int n0 = blockIdx.x * 128;

    const __half* gAh = Ah + (size_t)m0 * K;
    const __half* gAl = Al + (size_t)m0 * K;
    const __half* gWh = Wh + (size_t)n0 * K;

    float acc[4][4][4];
#pragma unroll
    for (int mi = 0; mi < 4; mi++)
#pragma unroll
        for (int ni = 0; ni < 4; ni++)
#pragma unroll
            for (int q = 0; q < 4; q++) acc[mi][ni][q] = 0.f;

    const int lr = tid >> 2;
    const int lc = tid & 3;

    auto load_stage = [&](int kt, int st) {
        const size_t koff = (size_t)kt * 32;
        uint32_t base = sb + st * CSTG;
#pragma unroll
        for (int i = 0; i < 2; i++) {
            int r = lr + i * 64;
            uint32_t so = (r * GSTR + lc * 8) * 2;
            size_t go = (size_t)r * K + koff + lc * 8;
            cp_async16(base + 0 * TILEB + so, gAh + go);
            cp_async16(base + 1 * TILEB + so, gAl + go);
            cp_async16(base + 2 * TILEB + so, gWh + go);
        }
        cp_commit();
    };

    const uint32_t arow = wm * 64 + (lane & 7) + ((lane >> 3) & 1) * 8;
    const uint32_t acol = (lane >> 4) * 8;
    const uint32_t aoff = (arow * GSTR + acol) * 2;
    const uint32_t brow = wn * 32 + (lane & 7) + (lane >> 4) * 8;
    const uint32_t bcol = ((lane >> 3) & 1) * 8;
    const uint32_t boff = (brow * GSTR + bcol) * 2;

    load_stage(0, 0);
    load_stage(1, 1);

#pragma unroll 1
    for (int kt = 0; kt < KT; kt++) {
        if (kt + 1 < KT) cp_wait<1>();
        else             cp_wait<0>();
        __syncthreads();

        const uint32_t stbase = sb + (kt % 3) * CSTG;
        const uint32_t aH = stbase + aoff;
        const uint32_t aL = stbase + TILEB + aoff;
        const uint32_t bH = stbase + 2 * TILEB + boff;

#pragma unroll
        for (int ks = 0; ks < 2; ks++) {
            const uint32_t kadd = ks * 32;
            uint32_t afh[16], afl[16], bh[8];
#pragma unroll
            for (int mi = 0; mi < 4; mi++) {
                ldsm4(afh + mi * 4, aH + mi * (16 * GSTR * 2) + kadd);
                ldsm4(afl + mi * 4, aL + mi * (16 * GSTR * 2) + kadd);
            }
#pragma unroll
            for (int nj = 0; nj < 2; nj++)
                ldsm4(bh + nj * 4, bH + nj * (16 * GSTR * 2) + kadd);
#pragma unroll
            for (int mi = 0; mi < 4; mi++)
#pragma unroll
                for (int ni = 0; ni < 4; ni++)
                    mma_f16(acc[mi][ni], afh + mi * 4, bh + ni * 2);
#pragma unroll
            for (int mi = 0; mi < 4; mi++)
#pragma unroll
                for (int ni = 0; ni < 4; ni++)
                    mma_f16(acc[mi][ni], afl + mi * 4, bh + ni * 2);
        }

        if (kt + 2 < KT) load_stage(kt + 2, (kt + 2) % 3);
    }

#pragma unroll
    for (int mi = 0; mi < 4; mi++) {
#pragma unroll
        for (int rr = 0; rr < 2; rr++) {
            int m = m0 + wm * 64 + mi * 16 + group + rr * 8;
            int b = m / NPATCH, p = m % NPATCH;
            size_t row = (size_t)b * NTOK + p + 1;
            const float* pr = pos + (size_t)(p + 1) * DD;
#pragma unroll
            for (int ni = 0; ni < 4; ni++) {
                int n = n0 + wn * 32 + ni * 8 + tq * 2;
                float v0 = acc[mi][ni][rr * 2 + 0] + bias[n] + pr[n];
                float v1 = acc[mi][ni][rr * 2 + 1] + bias[n + 1] + pr[n + 1];
                *(float2*)(hout + row * DD + n) = make_float2(v0, v1);
            }
        }
    }
}

// ---------------- im2col -> split fp16 (padded K=640) ----------------
__global__ void im2col_split(const float* __restrict__ x,
                             __half* __restrict__ colh, __half* __restrict__ coll) {
    int idx = blockIdx.x * blockDim.x + threadIdx.x;
    if (idx >= CROWS * KCPAD) return;
    int r = idx / KCPAD, c = idx % KCPAD;
    float v = 0.f;
    if (c < KCONV) {
        int b = r / NPATCH, p = r % NPATCH;
        int chn = c / 100, rem = c % 100;
        int kh = rem / 10, kw = rem % 10;
        int phh = p / 34, pw = p % 34;
        v = x[((b * 6 + chn) * 50 + phh * 10 + kh) * 345 + pw * 10 + kw];
    }
    __half hi, lo;
    splith(v, hi, lo);
    colh[idx] = hi;
    coll[idx] = lo;
}

// ---------------- conv weight -> fp16 (padded K=640) ----------------
__global__ void convw_prep(const float* __restrict__ w, __half* __restrict__ wh) {
    int idx = blockIdx.x * blockDim.x + threadIdx.x;
    if (idx >= DD * KCPAD) return;
    int d = idx / KCPAD, k = idx % KCPAD;
    wh[idx] = __float2half(k < KCONV ? w[d * KCONV + k] : 0.f);
}

// ---------------- cls token rows ----------------
__global__ void cls_fill(const float* __restrict__ cls, const float* __restrict__ pos,
                         float* __restrict__ h) {
    int idx = blockIdx.x * blockDim.x + threadIdx.x;
    if (idx >= BATCH * DD) return;
    int b = idx / DD, d = idx % DD;
    h[(size_t)b * NTOK * DD + d] = cls[d] + pos[d];
}

// ---------------- weight transpose -> fp16 (hi only) ----------------
__global__ void transpose_hi(const float* __restrict__ W, __half* __restrict__ Wh,
                             int R, int C) {
    __shared__ float t[32][33];
    int z = blockIdx.z;
    const float* Wz = W + (size_t)z * R * C;
    __half* Whz = Wh + (size_t)z * R * C;
    int c0 = blockIdx.x * 32, r0 = blockIdx.y * 32;
    int x = threadIdx.x, y = threadIdx.y;
#pragma unroll
    for (int i = 0; i < 32; i += 8)
        t[y + i][x] = Wz[(size_t)(r0 + y + i) * C + c0 + x];
    __syncthreads();
#pragma unroll
    for (int i = 0; i < 32; i += 8)
        Whz[(size_t)(c0 + y + i) * R + r0 + x] = __float2half(t[x][y + i]);
}

// ---------------- LayerNorm fp32 -> fp16 ----------------
__global__ void ln_f16_kernel(const float* __restrict__ X, const float* __restrict__ w,
                              const float* __restrict__ b, __half* __restrict__ Y) {
    int row = blockIdx.x;
    int tid = threadIdx.x;
    const float* xr = X + (size_t)row * DD;
    float v0 = xr[tid], v1 = xr[tid + 256], v2 = xr[tid + 512];
    float s = v0 + v1 + v2;
    float q = v0 * v0 + v1 * v1 + v2 * v2;
    int lane = tid & 31, warp = tid >> 5;
#pragma unroll
    for (int off = 16; off; off >>= 1) {
        s += __shfl_down_sync(0xffffffffu, s, off);
        q += __shfl_down_sync(0xffffffffu, q, off);
    }
    __shared__ float sa[8], sbm[8];
    if (lane == 0) { sa[warp] = s; sbm[warp] = q; }
    __syncthreads();
    if (warp == 0) {
        s = (lane < 8) ? sa[lane] : 0.f;
        q = (lane < 8) ? sbm[lane] : 0.f;
#pragma unroll
        for (int off = 4; off; off >>= 1) {
            s += __shfl_down_sync(0xffffffffu, s, off);
            q += __shfl_down_sync(0xffffffffu, q, off);
        }
        if (lane == 0) { sa[0] = s; sbm[0] = q; }
    }
    __syncthreads();
    float mean = sa[0] * (1.f / DD);
    float var = sbm[0] * (1.f / DD) - mean * mean;
    float inv = rsqrtf(var + EPS);
    __half* yr = Y + (size_t)row * DD;
    yr[tid]       = __float2half((v0 - mean) * inv * w[tid]       + b[tid]);
    yr[tid + 256] = __float2half((v1 - mean) * inv * w[tid + 256] + b[tid + 256]);
    yr[tid + 512] = __float2half((v2 - mean) * inv * w[tid + 512] + b[tid + 512]);
}

// ---------------- LayerNorm fp32 -> fp32 (final, cls rows) ----------------
__global__ void ln_kernel(const float* __restrict__ X, const float* __restrict__ w,
                          const float* __restrict__ b, float* __restrict__ Y, int row_mul) {
    int row_in = blockIdx.x * row_mul;
    int row_out = blockIdx.x;
    int tid = threadIdx.x;
    const float* xr = X + (size_t)row_in * DD;
    float v0 = xr[tid], v1 = xr[tid + 256], v2 = xr[tid + 512];
    float s = v0 + v1 + v2;
    float q = v0 * v0 + v1 * v1 + v2 * v2;
    int lane = tid & 31, warp = tid >> 5;
#pragma unroll
    for (int off = 16; off; off >>= 1) {
        s += __shfl_down_sync(0xffffffffu, s, off);
        q += __shfl_down_sync(0xffffffffu, q, off);
    }
    __shared__ float sa[8], sbm[8];
    if (lane == 0) { sa[warp] = s; sbm[warp] = q; }
    __syncthreads();
    if (warp == 0) {
        s = (lane < 8) ? sa[lane] : 0.f;
        q = (lane < 8) ? sbm[lane] : 0.f;
#pragma unroll
        for (int off = 4; off; off >>= 1) {
            s += __shfl_down_sync(0xffffffffu, s, off);
            q += __shfl_down_sync(0xffffffffu, q, off);
        }
        if (lane == 0) { sa[0] = s; sbm[0] = q; }
    }
    __syncthreads();
    float mean = sa[0] * (1.f / DD);
    float var = sbm[0] * (1.f / DD) - mean * mean;
    float inv = rsqrtf(var + EPS);
    float* yr = Y + (size_t)row_out * DD;
    yr[tid]       = (v0 - mean) * inv * w[tid]       + b[tid];
    yr[tid + 256] = (v1 - mean) * inv * w[tid + 256] + b[tid + 256];
    yr[tid + 512] = (v2 - mean) * inv * w[tid + 512] + b[tid + 512];
}

// ---------------- MMA attention (fp16 qkv in, single product, 11 warps) ----------------
#define NTOKP 176
#define ASTR 72
#define VSTR 184
#define SA_QH 0
#define SA_KH (SA_QH + NTOKP*ASTR*2)
#define SA_VH (SA_KH + NTOKP*ASTR*2)
#define ATTN_SMEM (SA_VH + 64*VSTR*2)   // 74240 B
#define ATHREADS 352

__global__ void __launch_bounds__(ATHREADS, 1)
attn_mma_kernel(const __half* __restrict__ qkv, __half* __restrict__ out) {
    extern __shared__ char asmem[];
    const uint32_t sb = smem_u32(asmem);
    __half* QH = (__half*)(asmem + SA_QH);
    __half* KH = (__half*)(asmem + SA_KH);
    __half* VH = (__half*)(asmem + SA_VH);

    const int bh = blockIdx.x;
    const int b = bh / NHEAD, hh = bh % NHEAD;
    const int tid = threadIdx.x;
    const int lane = tid & 31, wid = tid >> 5;
    const int group = lane >> 2, tq = lane & 3;
    const size_t base = (size_t)b * NTOK * (3 * DD) + hh * HDIM;

    for (int idx = tid; idx < NTOKP * 64; idx += ATHREADS) {
        int row = idx >> 6, d = idx & 63;
        __half qv = __float2half(0.f), kv = qv, vv = qv;
        if (row < NTOK) {
            size_t o = base + (size_t)row * (3 * DD) + d;
            qv = qkv[o]; kv = qkv[o + DD]; vv = qkv[o + 2 * DD];
        }
        QH[row * ASTR + d] = qv;
        KH[row * ASTR + d] = kv;
        VH[d * VSTR + row] = vv;
    }
    __syncthreads();

    const uint32_t a_r = (lane & 7) + ((lane >> 3) & 1) * 8;
    const uint32_t a_c = (lane >> 4) * 8;
    const uint32_t b_r = (lane & 7) + (lane >> 4) * 8;
    const uint32_t b_c = ((lane >> 3) & 1) * 8;

    if (wid < 11) {
        const int m0 = wid * 16;

        uint32_t aq[4][4];
#pragma unroll
        for (int k = 0; k < 4; k++) {
            uint32_t off = ((m0 + a_r) * ASTR + a_c + k * 16) * 2;
            ldsm4(aq[k], sb + SA_QH + off);
        }

        float s[22][4];
#pragma unroll
        for (int j = 0; j < 22; j++)
#pragma unroll
            for (int q = 0; q < 4; q++) s[j][q] = 0.f;

#pragma unroll
        for (int nj = 0; nj < 11; nj++) {
            const int n0 = nj * 16;
#pragma unroll
            for (int k = 0; k < 4; k++) {
                uint32_t bkh[4];
                uint32_t off = ((n0 + b_r) * ASTR + b_c + k * 16) * 2;
                ldsm4(bkh, sb + SA_KH + off);
                mma_f16(s[2 * nj],     aq[k], bkh);
                mma_f16(s[2 * nj + 1], aq[k], bkh + 2);
            }
        }

        {
            int c0 = 168 + tq * 2;
            if (c0 >= NTOK)     { s[21][0] = -1e30f; s[21][2] = -1e30f; }
            if (c0 + 1 >= NTOK) { s[21][1] = -1e30f; s[21][3] = -1e30f; }
        }

        float mx0 = -1e30f, mx1 = -1e30f;
#pragma unroll
        for (int j = 0; j < 22; j++) {
            mx0 = fmaxf(mx0, fmaxf(s[j][0], s[j][1]));
            mx1 = fmaxf(mx1, fmaxf(s[j][2], s[j][3]));
        }
        mx0 = fmaxf(mx0, __shfl_xor_sync(0xffffffffu, mx0, 1));
        mx0 = fmaxf(mx0, __shfl_xor_sync(0xffffffffu, mx0, 2));
        mx1 = fmaxf(mx1, __shfl_xor_sync(0xffffffffu, mx1, 1));
        mx1 = fmaxf(mx1, __shfl_xor_sync(0xffffffffu, mx1, 2));

        float rs0 = 0.f, rs1 = 0.f;
#pragma unroll
        for (int j = 0; j < 22; j++) {
            s[j][0] = __expf((s[j][0] - mx0) * 0.125f);
            s[j][1] = __expf((s[j][1] - mx0) * 0.125f);
            s[j][2] = __expf((s[j][2] - mx1) * 0.125f);
            s[j][3] = __expf((s[j][3] - mx1) * 0.125f);
            rs0 += s[j][0] + s[j][1];
            rs1 += s[j][2] + s[j][3];
        }
        rs0 += __shfl_xor_sync(0xffffffffu, rs0, 1);
        rs0 += __shfl_xor_sync(0xffffffffu, rs0, 2);
        rs1 += __shfl_xor_sync(0xffffffffu, rs1, 1);
        rs1 += __shfl_xor_sync(0xffffffffu, rs1, 2);

        float o[8][4];
#pragma unroll
        for (int j = 0; j < 8; j++)
#pragma unroll
            for (int q = 0; q < 4; q++) o[j][q] = 0.f;

#pragma unroll
        for (int kt = 0; kt < 11; kt++) {
            uint32_t ap[4];
#pragma unroll
            for (int half = 0; half < 2; half++) {
                const float* sv = s[2 * kt + half];
                ap[2 * half]     = pack_h2(sv[0], sv[1]);
                ap[2 * half + 1] = pack_h2(sv[2], sv[3]);
            }
#pragma unroll
            for (int dj = 0; dj < 4; dj++) {
                const int d0 = dj * 16;
                uint32_t bvh[4];
                uint32_t off = ((d0 + b_r) * VSTR + b_c + kt * 16) * 2;
                ldsm4(bvh, sb + SA_VH + off);
                mma_f16(o[2 * dj],     ap, bvh);
                mma_f16(o[2 * dj + 1], ap, bvh + 2);
            }
        }

        const float i0 = 1.f / rs0, i1 = 1.f / rs1;
        const int r0 = m0 + group, r1 = r0 + 8;
#pragma unroll
        for (int j = 0; j < 8; j++) {
            int d = 8 * j + tq * 2;
            if (r0 < NTOK) {
                __half2 hv = __floats2half2_rn(o[j][0] * i0, o[j][1] * i0);
                *(__half2*)(out + (size_t)(b * NTOK + r0) * DD + hh * HDIM + d) = hv;
            }
            if (r1 < NTOK) {
                __half2 hv = __floats2half2_rn(o[j][2] * i1, o[j][3] * i1);
                *(__half2*)(out + (size_t)(b * NTOK + r1) * DD + hh * HDIM + d) = hv;
            }
        }
    }
}

// ---------------- head ----------------
__global__ void head_kernel(const float* __restrict__ cls, const float* __restrict__ hw,
                            const float* __restrict__ hb, float* __restrict__ out) {
    int b = blockIdx.x;
    int tid = threadIdx.x;
    float a0 = 0.f, a1 = 0.f, a2 = 0.f;
    for (int d = tid; d < DD; d += 256) {
        float v = cls[b * DD + d];
        a0 += v * hw[d * 3 + 0];
        a1 += v * hw[d * 3 + 1];
        a2 += v * hw[d * 3 + 2];
    }
    int lane = tid & 31, warp = tid >> 5;
#pragma unroll
    for (int off = 16; off; off >>= 1) {
        a0 += __shfl_down_sync(0xffffffffu, a0, off);
        a1 += __shfl_down_sync(0xffffffffu, a1, off);
        a2 += __shfl_down_sync(0xffffffffu, a2, off);
    }
    __shared__ float s0[8], s1[8], s2[8];
    if (lane == 0) { s0[warp] = a0; s1[warp] = a1; s2[warp] = a2; }
    __syncthreads();
    if (warp == 0 && lane < 8) {
        a0 = s0[lane]; a1 = s1[lane]; a2 = s2[lane];
#pragma unroll
        for (int off = 4; off; off >>= 1) {
            a0 += __shfl_down_sync(0x000000ffu, a0, off);
            a1 += __shfl_down_sync(0x000000ffu, a1, off);
            a2 += __shfl_down_sync(0x000000ffu, a2, off);
        }
        if (lane == 0) {
            out[b * 3 + 0] = a0 + hb[0];
            out[b * 3 + 1] = a1 + hb[1];
            out[b * 3 + 2] = a2 + hb[2];
        }
    }
}

// ---------------- launcher ----------------
extern "C" void kernel_launch(void* const* d_in, const int* in_sizes, int n_in,
                              void* d_out, int out_size) {
    const float* x        = (const float*)d_in[0];
    const float* conv_w   = (const float*)d_in[1];
    const float* conv_b   = (const float*)d_in[2];
    const float* cls_tok  = (const float*)d_in[3];
    const float* pos      = (const float*)d_in[4];
    const float* ln1_w    = (const float*)d_in[5];
    const float* ln1_b    = (const float*)d_in[6];
    const float* qkv_w    = (const float*)d_in[7];
    const float* qkv_b    = (const float*)d_in[8];
    const float* proj_w   = (const float*)d_in[9];
    const float* proj_b   = (const float*)d_in[10];
    const float* ln2_w    = (const float*)d_in[11];
    const float* ln2_b    = (const float*)d_in[12];
    const float* fc1_w    = (const float*)d_in[13];
    const float* fc1_b    = (const float*)d_in[14];
    const float* fc2_w    = (const float*)d_in[15];
    const float* fc2_b    = (const float*)d_in[16];
    const float* norm_w   = (const float*)d_in[17];
    const float* norm_b   = (const float*)d_in[18];
    const float* head_w   = (const float*)d_in[19];
    const float* head_b   = (const float*)d_in[20];
    float* out = (float*)d_out;

    float *h, *clsb;
    __half *colh, *coll, *convWh, *qkvh, *yf, *af, *bigf;
    __half *qkvWh, *projWh, *fc1Wh, *fc2Wh;
    cudaGetSymbolAddress((void**)&colh, g_colh);
    cudaGetSymbolAddress((void**)&coll, g_coll);
    cudaGetSymbolAddress((void**)&convWh, g_convWh);
    cudaGetSymbolAddress((void**)&h, g_h);
    cudaGetSymbolAddress((void**)&clsb, g_cls);
    cudaGetSymbolAddress((void**)&qkvh, g_qkvh);
    cudaGetSymbolAddress((void**)&yf, g_yf);
    cudaGetSymbolAddress((void**)&af, g_af);
    cudaGetSymbolAddress((void**)&bigf, g_bigf);
    cudaGetSymbolAddress((void**)&qkvWh, g_qkvWh);
    cudaGetSymbolAddress((void**)&projWh, g_projWh);
    cudaGetSymbolAddress((void**)&fc1Wh, g_fc1Wh);
    cudaGetSymbolAddress((void**)&fc2Wh, g_fc2Wh);

    cudaFuncSetAttribute(attn_mma_kernel, cudaFuncAttributeMaxDynamicSharedMemorySize, ATTN_SMEM);
    cudaFuncSetAttribute(hmma_gemm<true, false, false>, cudaFuncAttributeMaxDynamicSharedMemorySize, SMTOT1);
    cudaFuncSetAttribute(hmma_gemm<false, false, true>, cudaFuncAttributeMaxDynamicSharedMemorySize, SMTOT1);
    cudaFuncSetAttribute(hmma_gemm<true, true, false>, cudaFuncAttributeMaxDynamicSharedMemorySize, SMTOT1);
    cudaFuncSetAttribute(conv_gemm, cudaFuncAttributeMaxDynamicSharedMemorySize, CSMTOT);

    // weight prep
    transpose_hi<<<dim3(3 * DD / 32, DD / 32, DEPTH), dim3(32, 8)>>>(qkv_w, qkvWh, DD, 3 * DD);
    transpose_hi<<<dim3(DD / 32, DD / 32, DEPTH), dim3(32, 8)>>>(proj_w, projWh, DD, DD);
    transpose_hi<<<dim3(4 * DD / 32, DD / 32, DEPTH), dim3(32, 8)>>>(fc1_w, fc1Wh, DD, 4 * DD);
    transpose_hi<<<dim3(DD / 32, 4 * DD / 32, DEPTH), dim3(32, 8)>>>(fc2_w, fc2Wh, 4 * DD, DD);
    convw_prep<<<(DD * KCPAD + 255) / 256, 256>>>(conv_w, convWh);

    // patch embed (fp16 2-product, fused pos-embed + assemble)
    im2col_split<<<(CROWS * KCPAD + 255) / 256, 256>>>(x, colh, coll);
    cls_fill<<<(BATCH * DD + 255) / 256, 256>>>(cls_tok, pos, h);
    conv_gemm<<<dim3(DD / 128, CROWS / 128), 256, CSMTOT>>>(colh, coll, convWh, conv_b, pos, h);

    const int MT = MPAD / 128;  // 86
    for (int i = 0; i < DEPTH; i++) {
        ln_f16_kernel<<<MROWS, 256>>>(h, ln1_w + (size_t)i * DD, ln1_b + (size_t)i * DD, yf);
        hmma_gemm<true, false, false><<<dim3(3 * DD / 128, MT), 256, SMTOT1>>>(
            yf, qkvWh + (size_t)i * 3 * DD * DD,
            qkv_b + (size_t)i * 3 * DD, nullptr, nullptr, qkvh, MROWS, 3 * DD, DD);
        attn_mma_kernel<<<BATCH * NHEAD, ATHREADS, ATTN_SMEM>>>(qkvh, af);
        hmma_gemm<false, false, true><<<dim3(DD / 128, MT), 256, SMTOT1>>>(
            af, projWh + (size_t)i * DD * DD,
            proj_b + (size_t)i * DD, h, h, nullptr, MROWS, DD, DD);
        ln_f16_kernel<<<MROWS, 256>>>(h, ln2_w + (size_t)i * DD, ln2_b + (size_t)i * DD, yf);
        hmma_gemm<true, true, false><<<dim3(4 * DD / 128, MT), 256, SMTOT1>>>(
            yf, fc1Wh + (size_t)i * 4 * DD * DD,
            fc1_b + (size_t)i * 4 * DD, nullptr, nullptr, bigf, MROWS, 4 * DD, DD);
        hmma_gemm<false, false, true><<<dim3(DD / 128, MT), 256, SMTOT1>>>(
            bigf, fc2Wh + (size_t)i * 4 * DD * DD,
            fc2_b + (size_t)i * DD, h, h, nullptr, MROWS, DD, 4 * DD);
    }

    ln_kernel<<<BATCH, 256>>>(h, norm_w, norm_b, clsb, NTOK);
    head_kernel<<<BATCH, 256>>>(clsb, head_w, head_b, out);
}

// round 15
// speedup vs baseline: 8.3667x; 1.0006x over previous
#include <cuda_runtime.h>
#include <cuda_fp16.h>
#include <math.h>
#include <stdint.h>

// ---------------- problem constants ----------------
#define DD     768
#define NTOK   171
#define BATCH  64
#define MROWS  (BATCH*NTOK)      // 10944
#define MPAD   11008             // 86*128
#define NPATCH 170
#define CROWS  (BATCH*NPATCH)    // 10880 = 85*128
#define KCONV  600
#define KCPAD  640
#define NHEAD  12
#define HDIM   64
#define DEPTH  12
#define EPS    1e-5f

// ---------------- scratch (device globals) ----------------
__device__ __half g_colh[CROWS * KCPAD];
__device__ __half g_coll[CROWS * KCPAD];
__device__ __half g_convWh[DD * KCPAD];
__device__ float g_h   [MROWS * DD];
__device__ float g_cls [BATCH * DD];
__device__ __half g_qkvh [MPAD * 3 * DD];
__device__ __half g_yf   [MPAD * DD];
__device__ __half g_af   [MPAD * DD];
__device__ __half g_bigf [MPAD * 4 * DD];
__device__ __half g_qkvWh[DEPTH * 3 * DD * DD];
__device__ __half g_projWh[DEPTH * DD * DD];
__device__ __half g_fc1Wh[DEPTH * 4 * DD * DD];
__device__ __half g_fc2Wh[DEPTH * 4 * DD * DD];

// ---------------- helpers ----------------
__device__ __forceinline__ uint32_t smem_u32(const void* p) {
    uint32_t a;
    asm("{ .reg .u64 t; cvta.to.shared.u64 t, %1; cvt.u32.u64 %0, t; }" : "=r"(a) : "l"(p));
    return a;
}
__device__ __forceinline__ void cp_async16(uint32_t dst, const void* src) {
    asm volatile("cp.async.cg.shared.global [%0], [%1], 16;"
                 :: "r"(dst), "l"(src) : "memory");
}
__device__ __forceinline__ void cp_commit() {
    asm volatile("cp.async.commit_group;" ::: "memory");
}
template <int N>
__device__ __forceinline__ void cp_wait() {
    asm volatile("cp.async.wait_group %0;" :: "n"(N) : "memory");
}
__device__ __forceinline__ void ldsm4(uint32_t* r, uint32_t addr) {
    asm volatile("ldmatrix.sync.aligned.m8n8.x4.shared.b16 {%0,%1,%2,%3}, [%4];"
                 : "=r"(r[0]), "=r"(r[1]), "=r"(r[2]), "=r"(r[3]) : "r"(addr));
}
__device__ __forceinline__ void mma_f16(float* c, const uint32_t* a, const uint32_t* b) {
    asm volatile(
        "mma.sync.aligned.m16n8k16.row.col.f32.f16.f16.f32 "
        "{%0,%1,%2,%3}, {%4,%5,%6,%7}, {%8,%9}, {%0,%1,%2,%3};"
        : "+f"(c[0]), "+f"(c[1]), "+f"(c[2]), "+f"(c[3])
        : "r"(a[0]), "r"(a[1]), "r"(a[2]), "r"(a[3]), "r"(b[0]), "r"(b[1]));
}
__device__ __forceinline__ void splith(float v, __half& hi, __half& lo) {
    hi = __float2half(v);
    lo = __float2half(v - __half2float(hi));
}
__device__ __forceinline__ uint32_t pack_h2(float a, float b) {
    __half2 h = __floats2half2_rn(a, b);
    return *(uint32_t*)&h;
}

// ---------------- fp16 GEMM: C = A @ Wh^T (BK=64, 3 stages, unroll-3 ring) ----------------
#define GSTR2 72                         // row stride (halves) = 144B
#define TILE2B (128 * GSTR2 * 2)         // 18432 B
#define STG2 (2 * TILE2B)                // 36864 B per stage
#define NST2 3
#define SMTOT1 (NST2 * STG2)             // 110592 B/CTA

template <bool OUTF16, bool GELU_, bool RES>
__global__ void __launch_bounds__(256, 2)
hmma_gemm(const __half* __restrict__ A, const __half* __restrict__ Wh,
          const float* __restrict__ bias, const float* __restrict__ res,
          float* __restrict__ Cf, __half* __restrict__ Ch,
          int Mvalid, int Ntot, int K) {
    extern __shared__ char dsm[];
    const uint32_t sb = smem_u32(dsm);

    const int tid = threadIdx.x;
    const int lane = tid & 31, wid = tid >> 5;
    const int wm = wid & 1, wn = wid >> 1;
    const int group = lane >> 2, tq = lane & 3;
    const int m0 = blockIdx.y * 128;
    const int n0 = blockIdx.x * 128;
    const int KT = K >> 6;               // K/64 chunks (12 or 48; always %3==0)

    const __half* gA = A + (size_t)m0 * K;
    const __half* gWh = Wh + (size_t)n0 * K;

    float acc[4][4][4];
#pragma unroll
    for (int mi = 0; mi < 4; mi++)
#pragma unroll
        for (int ni = 0; ni < 4; ni++)
#pragma unroll
            for (int q = 0; q < 4; q++) acc[mi][ni][q] = 0.f;

    const int lr = tid >> 3;             // 0..31
    const int lc = tid & 7;              // 16B chunk 0..7

    auto load_stage = [&](int kt, int st) {
        const size_t koff = (size_t)kt * 64;
        uint32_t base = sb + st * STG2;
#pragma unroll
        for (int i = 0; i < 4; i++) {
            int r = lr + i * 32;
            uint32_t so = (r * GSTR2 + lc * 8) * 2;
            size_t go = (size_t)r * K + koff + lc * 8;
            cp_async16(base + 0 * TILE2B + so, gA + go);
            cp_async16(base + 1 * TILE2B + so, gWh + go);
        }
        cp_commit();
    };

    const uint32_t arow = wm * 64 + (lane & 7) + ((lane >> 3) & 1) * 8;
    const uint32_t acol = (lane >> 4) * 8;
    const uint32_t aoff = (arow * GSTR2 + acol) * 2;
    const uint32_t brow = wn * 32 + (lane & 7) + (lane >> 4) * 8;
    const uint32_t bcol = ((lane >> 3) & 1) * 8;
    const uint32_t boff = (brow * GSTR2 + bcol) * 2;

    load_stage(0, 0);
    if (KT > 1) load_stage(1, 1);

#pragma unroll 3
    for (int kt = 0; kt < KT; kt++) {
        if (kt + 1 < KT) cp_wait<1>();
        else             cp_wait<0>();
        __syncthreads();

        const uint32_t stbase = sb + (kt % 3) * STG2;   // constant under unroll-3
        const uint32_t aA = stbase + aoff;
        const uint32_t bH = stbase + TILE2B + boff;

#pragma unroll
        for (int ks = 0; ks < 4; ks++) {
            const uint32_t kadd = ks * 32;
            uint32_t af[16], bh[8];
#pragma unroll
            for (int mi = 0; mi < 4; mi++)
                ldsm4(af + mi * 4, aA + mi * (16 * GSTR2 * 2) + kadd);
#pragma unroll
            for (int nj = 0; nj < 2; nj++)
                ldsm4(bh + nj * 4, bH + nj * (16 * GSTR2 * 2) + kadd);
#pragma unroll
            for (int mi = 0; mi < 4; mi++)
#pragma unroll
                for (int ni = 0; ni < 4; ni++)
                    mma_f16(acc[mi][ni], af + mi * 4, bh + ni * 2);
        }

        if (kt + 2 < KT) load_stage(kt + 2, (kt + 2) % 3);
    }

#pragma unroll
    for (int mi = 0; mi < 4; mi++) {
#pragma unroll
        for (int rr = 0; rr < 2; rr++) {
            int m = m0 + wm * 64 + mi * 16 + group + rr * 8;
            if (m >= Mvalid) continue;
#pragma unroll
            for (int ni = 0; ni < 4; ni++) {
                int n = n0 + wn * 32 + ni * 8 + tq * 2;
                float v0 = acc[mi][ni][rr * 2 + 0] + __ldg(bias + n);
                float v1 = acc[mi][ni][rr * 2 + 1] + __ldg(bias + n + 1);
                if (GELU_) {
                    v0 = 0.5f * v0 * (1.f + erff(v0 * 0.70710678118654752f));
                    v1 = 0.5f * v1 * (1.f + erff(v1 * 0.70710678118654752f));
                }
                if (RES) {
                    float2 rv = *(const float2*)(res + (size_t)m * Ntot + n);
                    v0 += rv.x; v1 += rv.y;
                }
                if (OUTF16) {
                    __half2 h2 = __floats2half2_rn(v0, v1);
                    *(__half2*)(Ch + (size_t)m * Ntot + n) = h2;
                } else {
                    *(float2*)(Cf + (size_t)m * Ntot + n) = make_float2(v0, v1);
                }
            }
        }
    }
}

// ---------------- conv GEMM (BK=32, split-A 2-product) ----------------
#define GSTR 40
#define TILEB (128 * GSTR * 2)
#define CSTG (3 * TILEB)
#define CSMTOT (3 * CSTG)     // 92160 B/CTA

__global__ void __launch_bounds__(256, 2)
conv_gemm(const __half* __restrict__ Ah, const __half* __restrict__ Al,
          const __half* __restrict__ Wh, const float* __restrict__ bias,
          const float* __restrict__ pos, float* __restrict__ hout) {
    extern __shared__ char dsm[];
    const uint32_t sb = smem_u32(dsm);
    const int K = KCPAD, KT = KCPAD / 32;  // 20

    const int tid = threadIdx.x;
    const int lane = tid & 31, wid = tid >> 5;
    const int wm = wid & 1, wn = wid >> 1;
    const int group = lane >> 2, tq = lane & 3;
    const int m0 = blockIdx.y * 128;
    const int n0 = blockIdx.x * 128;

    const __half* gAh = Ah + (size_t)m0 * K;
    const __half* gAl = Al + (size_t)m0 * K;
    const __half* gWh = Wh + (size_t)n0 * K;

    float acc[4][4][4];
#pragma unroll
    for (int mi = 0; mi < 4; mi++)
#pragma unroll
        for (int ni = 0; ni < 4; ni++)
#pragma unroll
            for (int q = 0; q < 4; q++) acc[mi][ni][q] = 0.f;

    const int lr = tid >> 2;
    const int lc = tid & 3;

    auto load_stage = [&](int kt, int st) {
        const size_t koff = (size_t)kt * 32;
        uint32_t base = sb + st * CSTG;
#pragma unroll
        for (int i = 0; i < 2; i++) {
            int r = lr + i * 64;
            uint32_t so = (r * GSTR + lc * 8) * 2;
            size_t go = (size_t)r * K + koff + lc * 8;
            cp_async16(base + 0 * TILEB + so, gAh + go);
            cp_async16(base + 1 * TILEB + so, gAl + go);
            cp_async16(base + 2 * TILEB + so, gWh + go);
        }
        cp_commit();
    };

    const uint32_t arow = wm * 64 + (lane & 7) + ((lane >> 3) & 1) * 8;
    const uint32_t acol = (lane >> 4) * 8;
    const uint32_t aoff = (arow * GSTR + acol) * 2;
    const uint32_t brow = wn * 32 + (lane & 7) + (lane >> 4) * 8;
    const uint32_t bcol = ((lane >> 3) & 1) * 8;
    const uint32_t boff = (brow * GSTR + bcol) * 2;

    load_stage(0, 0);
    load_stage(1, 1);

#pragma unroll 1
    for (int kt = 0; kt < KT; kt++) {
        if (kt + 1 < KT) cp_wait<1>();
        else             cp_wait<0>();
        __syncthreads();

        const uint32_t stbase = sb + (kt % 3) * CSTG;
        const uint32_t aH = stbase + aoff;
        const uint32_t aL = stbase + TILEB + aoff;
        const uint32_t bH = stbase + 2 * TILEB + boff;

#pragma unroll
        for (int ks = 0; ks < 2; ks++) {
            const uint32_t kadd = ks * 32;
            uint32_t afh[16], afl[16], bh[8];
#pragma unroll
            for (int mi = 0; mi < 4; mi++) {
                ldsm4(afh + mi * 4, aH + mi * (16 * GSTR * 2) + kadd);
                ldsm4(afl + mi * 4, aL + mi * (16 * GSTR * 2) + kadd);
            }
#pragma unroll
            for (int nj = 0; nj < 2; nj++)
                ldsm4(bh + nj * 4, bH + nj * (16 * GSTR * 2) + kadd);
#pragma unroll
            for (int mi = 0; mi < 4; mi++)
#pragma unroll
                for (int ni = 0; ni < 4; ni++)
                    mma_f16(acc[mi][ni], afh + mi * 4, bh + ni * 2);
#pragma unroll
            for (int mi = 0; mi < 4; mi++)
#pragma unroll
                for (int ni = 0; ni < 4; ni++)
                    mma_f16(acc[mi][ni], afl + mi * 4, bh + ni * 2);
        }

        if (kt + 2 < KT) load_stage(kt + 2, (kt + 2) % 3);
    }

#pragma unroll
    for (int mi = 0; mi < 4; mi++) {
#pragma unroll
        for (int rr = 0; rr < 2; rr++) {
            int m = m0 + wm * 64 + mi * 16 + group + rr * 8;
            int b = m / NPATCH, p = m % NPATCH;
            size_t row = (size_t)b * NTOK + p + 1;
            const float* pr = pos + (size_t)(p + 1) * DD;
#pragma unroll
            for (int ni = 0; ni < 4; ni++) {
                int n = n0 + wn * 32 + ni * 8 + tq * 2;
                float v0 = acc[mi][ni][rr * 2 + 0] + bias[n] + pr[n];
                float v1 = acc[mi][ni][rr * 2 + 1] + bias[n + 1] + pr[n + 1];
                *(float2*)(hout + row * DD + n) = make_float2(v0, v1);
            }
        }
    }
}

// ---------------- im2col -> split fp16 (padded K=640) ----------------
__global__ void im2col_split(const float* __restrict__ x,
                             __half* __restrict__ colh, __half* __restrict__ coll) {
    int idx = blockIdx.x * blockDim.x + threadIdx.x;
    if (idx >= CROWS * KCPAD) return;
    int r = idx / KCPAD, c = idx % KCPAD;
    float v = 0.f;
    if (c < KCONV) {
        int b = r / NPATCH, p = r % NPATCH;
        int chn = c / 100, rem = c % 100;
        int kh = rem / 10, kw = rem % 10;
        int phh = p / 34, pw = p % 34;
        v = x[((b * 6 + chn) * 50 + phh * 10 + kh) * 345 + pw * 10 + kw];
    }
    __half hi, lo;
    splith(v, hi, lo);
    colh[idx] = hi;
    coll[idx] = lo;
}

// ---------------- conv weight -> fp16 (padded K=640) ----------------
__global__ void convw_prep(const float* __restrict__ w, __half* __restrict__ wh) {
    int idx = blockIdx.x * blockDim.x + threadIdx.x;
    if (idx >= DD * KCPAD) return;
    int d = idx / KCPAD, k = idx % KCPAD;
    wh[idx] = __float2half(k < KCONV ? w[d * KCONV + k] : 0.f);
}

// ---------------- cls token rows ----------------
__global__ void cls_fill(const float* __restrict__ cls, const float* __restrict__ pos,
                         float* __restrict__ h) {
    int idx = blockIdx.x * blockDim.x + threadIdx.x;
    if (idx >= BATCH * DD) return;
    int b = idx / DD, d = idx % DD;
    h[(size_t)b * NTOK * DD + d] = cls[d] + pos[d];
}

// ---------------- weight transpose -> fp16 (hi only) ----------------
__global__ void transpose_hi(const float* __restrict__ W, __half* __restrict__ Wh,
                             int R, int C) {
    __shared__ float t[32][33];
    int z = blockIdx.z;
    const float* Wz = W + (size_t)z * R * C;
    __half* Whz = Wh + (size_t)z * R * C;
    int c0 = blockIdx.x * 32, r0 = blockIdx.y * 32;
    int x = threadIdx.x, y = threadIdx.y;
#pragma unroll
    for (int i = 0; i < 32; i += 8)
        t[y + i][x] = Wz[(size_t)(r0 + y + i) * C + c0 + x];
    __syncthreads();
#pragma unroll
    for (int i = 0; i < 32; i += 8)
        Whz[(size_t)(c0 + y + i) * R + r0 + x] = __float2half(t[x][y + i]);
}

// ---------------- LayerNorm fp32 -> fp16 ----------------
__global__ void ln_f16_kernel(const float* __restrict__ X, const float* __restrict__ w,
                              const float* __restrict__ b, __half* __restrict__ Y) {
    int row = blockIdx.x;
    int tid = threadIdx.x;
    const float* xr = X + (size_t)row * DD;
    float v0 = xr[tid], v1 = xr[tid + 256], v2 = xr[tid + 512];
    float s = v0 + v1 + v2;
    float q = v0 * v0 + v1 * v1 + v2 * v2;
    int lane = tid & 31, warp = tid >> 5;
#pragma unroll
    for (int off = 16; off; off >>= 1) {
        s += __shfl_down_sync(0xffffffffu, s, off);
        q += __shfl_down_sync(0xffffffffu, q, off);
    }
    __shared__ float sa[8], sbm[8];
    if (lane == 0) { sa[warp] = s; sbm[warp] = q; }
    __syncthreads();
    if (warp == 0) {
        s = (lane < 8) ? sa[lane] : 0.f;
        q = (lane < 8) ? sbm[lane] : 0.f;
#pragma unroll
        for (int off = 4; off; off >>= 1) {
            s += __shfl_down_sync(0xffffffffu, s, off);
            q += __shfl_down_sync(0xffffffffu, q, off);
        }
        if (lane == 0) { sa[0] = s; sbm[0] = q; }
    }
    __syncthreads();
    float mean = sa[0] * (1.f / DD);
    float var = sbm[0] * (1.f / DD) - mean * mean;
    float inv = rsqrtf(var + EPS);
    __half* yr = Y + (size_t)row * DD;
    yr[tid]       = __float2half((v0 - mean) * inv * w[tid]       + b[tid]);
    yr[tid + 256] = __float2half((v1 - mean) * inv * w[tid + 256] + b[tid + 256]);
    yr[tid + 512] = __float2half((v2 - mean) * inv * w[tid + 512] + b[tid + 512]);
}

// ---------------- LayerNorm fp32 -> fp32 (final, cls rows) ----------------
__global__ void ln_kernel(const float* __restrict__ X, const float* __restrict__ w,
                          const float* __restrict__ b, float* __restrict__ Y, int row_mul) {
    int row_in = blockIdx.x * row_mul;
    int row_out = blockIdx.x;
    int tid = threadIdx.x;
    const float* xr = X + (size_t)row_in * DD;
    float v0 = xr[tid], v1 = xr[tid + 256], v2 = xr[tid + 512];
    float s = v0 + v1 + v2;
    float q = v0 * v0 + v1 * v1 + v2 * v2;
    int lane = tid & 31, warp = tid >> 5;
#pragma unroll
    for (int off = 16; off; off >>= 1) {
        s += __shfl_down_sync(0xffffffffu, s, off);
        q += __shfl_down_sync(0xffffffffu, q, off);
    }
    __shared__ float sa[8], sbm[8];
    if (lane == 0) { sa[warp] = s; sbm[warp] = q; }
    __syncthreads();
    if (warp == 0) {
        s = (lane < 8) ? sa[lane] : 0.f;
        q = (lane < 8) ? sbm[lane] : 0.f;
#pragma unroll
        for (int off = 4; off; off >>= 1) {
            s += __shfl_down_sync(0xffffffffu, s, off);
            q += __shfl_down_sync(0xffffffffu, q, off);
        }
        if (lane == 0) { sa[0] = s; sbm[0] = q; }
    }
    __syncthreads();
    float mean = sa[0] * (1.f / DD);
    float var = sbm[0] * (1.f / DD) - mean * mean;
    float inv = rsqrtf(var + EPS);
    float* yr = Y + (size_t)row_out * DD;
    yr[tid]       = (v0 - mean) * inv * w[tid]       + b[tid];
    yr[tid + 256] = (v1 - mean) * inv * w[tid + 256] + b[tid + 256];
    yr[tid + 512] = (v2 - mean) * inv * w[tid + 512] + b[tid + 512];
}

// ---------------- MMA attention (fp16 qkv in, single product, 11 warps) ----------------
#define NTOKP 176
#define ASTR 72
#define VSTR 184
#define SA_QH 0
#define SA_KH (SA_QH + NTOKP*ASTR*2)
#define SA_VH (SA_KH + NTOKP*ASTR*2)
#define ATTN_SMEM (SA_VH + 64*VSTR*2)   // 74240 B
#define ATHREADS 352

__global__ void __launch_bounds__(ATHREADS, 1)
attn_mma_kernel(const __half* __restrict__ qkv, __half* __restrict__ out) {
    extern __shared__ char asmem[];
    const uint32_t sb = smem_u32(asmem);
    __half* QH = (__half*)(asmem + SA_QH);
    __half* KH = (__half*)(asmem + SA_KH);
    __half* VH = (__half*)(asmem + SA_VH);

    const int bh = blockIdx.x;
    const int b = bh / NHEAD, hh = bh % NHEAD;
    const int tid = threadIdx.x;
    const int lane = tid & 31, wid = tid >> 5;
    const int group = lane >> 2, tq = lane & 3;
    const size_t base = (size_t)b * NTOK * (3 * DD) + hh * HDIM;

    for (int idx = tid; idx < NTOKP * 64; idx += ATHREADS) {
        int row = idx >> 6, d = idx & 63;
        __half qv = __float2half(0.f), kv = qv, vv = qv;
        if (row < NTOK) {
            size_t o = base + (size_t)row * (3 * DD) + d;
            qv = qkv[o]; kv = qkv[o + DD]; vv = qkv[o + 2 * DD];
        }
        QH[row * ASTR + d] = qv;
        KH[row * ASTR + d] = kv;
        VH[d * VSTR + row] = vv;
    }
    __syncthreads();

    const uint32_t a_r = (lane & 7) + ((lane >> 3) & 1) * 8;
    const uint32_t a_c = (lane >> 4) * 8;
    const uint32_t b_r = (lane & 7) + (lane >> 4) * 8;
    const uint32_t b_c = ((lane >> 3) & 1) * 8;

    if (wid < 11) {
        const int m0 = wid * 16;

        uint32_t aq[4][4];
#pragma unroll
        for (int k = 0; k < 4; k++) {
            uint32_t off = ((m0 + a_r) * ASTR + a_c + k * 16) * 2;
            ldsm4(aq[k], sb + SA_QH + off);
        }

        float s[22][4];
#pragma unroll
        for (int j = 0; j < 22; j++)
#pragma unroll
            for (int q = 0; q < 4; q++) s[j][q] = 0.f;

#pragma unroll
        for (int nj = 0; nj < 11; nj++) {
            const int n0 = nj * 16;
#pragma unroll
            for (int k = 0; k < 4; k++) {
                uint32_t bkh[4];
                uint32_t off = ((n0 + b_r) * ASTR + b_c + k * 16) * 2;
                ldsm4(bkh, sb + SA_KH + off);
                mma_f16(s[2 * nj],     aq[k], bkh);
                mma_f16(s[2 * nj + 1], aq[k], bkh + 2);
            }
        }

        {
            int c0 = 168 + tq * 2;
            if (c0 >= NTOK)     { s[21][0] = -1e30f; s[21][2] = -1e30f; }
            if (c0 + 1 >= NTOK) { s[21][1] = -1e30f; s[21][3] = -1e30f; }
        }

        float mx0 = -1e30f, mx1 = -1e30f;
#pragma unroll
        for (int j = 0; j < 22; j++) {
            mx0 = fmaxf(mx0, fmaxf(s[j][0], s[j][1]));
            mx1 = fmaxf(mx1, fmaxf(s[j][2], s[j][3]));
        }
        mx0 = fmaxf(mx0, __shfl_xor_sync(0xffffffffu, mx0, 1));
        mx0 = fmaxf(mx0, __shfl_xor_sync(0xffffffffu, mx0, 2));
        mx1 = fmaxf(mx1, __shfl_xor_sync(0xffffffffu, mx1, 1));
        mx1 = fmaxf(mx1, __shfl_xor_sync(0xffffffffu, mx1, 2));

        float rs0 = 0.f, rs1 = 0.f;
#pragma unroll
        for (int j = 0; j < 22; j++) {
            s[j][0] = __expf((s[j][0] - mx0) * 0.125f);
            s[j][1] = __expf((s[j][1] - mx0) * 0.125f);
            s[j][2] = __expf((s[j][2] - mx1) * 0.125f);
            s[j][3] = __expf((s[j][3] - mx1) * 0.125f);
            rs0 += s[j][0] + s[j][1];
            rs1 += s[j][2] + s[j][3];
        }
        rs0 += __shfl_xor_sync(0xffffffffu, rs0, 1);
        rs0 += __shfl_xor_sync(0xffffffffu, rs0, 2);
        rs1 += __shfl_xor_sync(0xffffffffu, rs1, 1);
        rs1 += __shfl_xor_sync(0xffffffffu, rs1, 2);

        float o[8][4];
#pragma unroll
        for (int j = 0; j < 8; j++)
#pragma unroll
            for (int q = 0; q < 4; q++) o[j][q] = 0.f;

#pragma unroll
        for (int kt = 0; kt < 11; kt++) {
            uint32_t ap[4];
#pragma unroll
            for (int half = 0; half < 2; half++) {
                const float* sv = s[2 * kt + half];
                ap[2 * half]     = pack_h2(sv[0], sv[1]);
                ap[2 * half + 1] = pack_h2(sv[2], sv[3]);
            }
#pragma unroll
            for (int dj = 0; dj < 4; dj++) {
                const int d0 = dj * 16;
                uint32_t bvh[4];
                uint32_t off = ((d0 + b_r) * VSTR + b_c + kt * 16) * 2;
                ldsm4(bvh, sb + SA_VH + off);
                mma_f16(o[2 * dj],     ap, bvh);
                mma_f16(o[2 * dj + 1], ap, bvh + 2);
            }
        }

        const float i0 = 1.f / rs0, i1 = 1.f / rs1;
        const int r0 = m0 + group, r1 = r0 + 8;
#pragma unroll
        for (int j = 0; j < 8; j++) {
            int d = 8 * j + tq * 2;
            if (r0 < NTOK) {
                __half2 hv = __floats2half2_rn(o[j][0] * i0, o[j][1] * i0);
                *(__half2*)(out + (size_t)(b * NTOK + r0) * DD + hh * HDIM + d) = hv;
            }
            if (r1 < NTOK) {
                __half2 hv = __floats2half2_rn(o[j][2] * i1, o[j][3] * i1);
                *(__half2*)(out + (size_t)(b * NTOK + r1) * DD + hh * HDIM + d) = hv;
            }
        }
    }
}

// ---------------- head ----------------
__global__ void head_kernel(const float* __restrict__ cls, const float* __restrict__ hw,
                            const float* __restrict__ hb, float* __restrict__ out) {
    int b = blockIdx.x;
    int tid = threadIdx.x;
    float a0 = 0.f, a1 = 0.f, a2 = 0.f;
    for (int d = tid; d < DD; d += 256) {
        float v = cls[b * DD + d];
        a0 += v * hw[d * 3 + 0];
        a1 += v * hw[d * 3 + 1];
        a2 += v * hw[d * 3 + 2];
    }
    int lane = tid & 31, warp = tid >> 5;
#pragma unroll
    for (int off = 16; off; off >>= 1) {
        a0 += __shfl_down_sync(0xffffffffu, a0, off);
        a1 += __shfl_down_sync(0xffffffffu, a1, off);
        a2 += __shfl_down_sync(0xffffffffu, a2, off);
    }
    __shared__ float s0[8], s1[8], s2[8];
    if (lane == 0) { s0[warp] = a0; s1[warp] = a1; s2[warp] = a2; }
    __syncthreads();
    if (warp == 0 && lane < 8) {
        a0 = s0[lane]; a1 = s1[lane]; a2 = s2[lane];
#pragma unroll
        for (int off = 4; off; off >>= 1) {
            a0 += __shfl_down_sync(0x000000ffu, a0, off);
            a1 += __shfl_down_sync(0x000000ffu, a1, off);
            a2 += __shfl_down_sync(0x000000ffu, a2, off);
        }
        if (lane == 0) {
            out[b * 3 + 0] = a0 + hb[0];
            out[b * 3 + 1] = a1 + hb[1];
            out[b * 3 + 2] = a2 + hb[2];
        }
    }
}

// ---------------- launcher ----------------
extern "C" void kernel_launch(void* const* d_in, const int* in_sizes, int n_in,
                              void* d_out, int out_size) {
    const float* x        = (const float*)d_in[0];
    const float* conv_w   = (const float*)d_in[1];
    const float* conv_b   = (const float*)d_in[2];
    const float* cls_tok  = (const float*)d_in[3];
    const float* pos      = (const float*)d_in[4];
    const float* ln1_w    = (const float*)d_in[5];
    const float* ln1_b    = (const float*)d_in[6];
    const float* qkv_w    = (const float*)d_in[7];
    const float* qkv_b    = (const float*)d_in[8];
    const float* proj_w   = (const float*)d_in[9];
    const float* proj_b   = (const float*)d_in[10];
    const float* ln2_w    = (const float*)d_in[11];
    const float* ln2_b    = (const float*)d_in[12];
    const float* fc1_w    = (const float*)d_in[13];
    const float* fc1_b    = (const float*)d_in[14];
    const float* fc2_w    = (const float*)d_in[15];
    const float* fc2_b    = (const float*)d_in[16];
    const float* norm_w   = (const float*)d_in[17];
    const float* norm_b   = (const float*)d_in[18];
    const float* head_w   = (const float*)d_in[19];
    const float* head_b   = (const float*)d_in[20];
    float* out = (float*)d_out;

    float *h, *clsb;
    __half *colh, *coll, *convWh, *qkvh, *yf, *af, *bigf;
    __half *qkvWh, *projWh, *fc1Wh, *fc2Wh;
    cudaGetSymbolAddress((void**)&colh, g_colh);
    cudaGetSymbolAddress((void**)&coll, g_coll);
    cudaGetSymbolAddress((void**)&convWh, g_convWh);
    cudaGetSymbolAddress((void**)&h, g_h);
    cudaGetSymbolAddress((void**)&clsb, g_cls);
    cudaGetSymbolAddress((void**)&qkvh, g_qkvh);
    cudaGetSymbolAddress((void**)&yf, g_yf);
    cudaGetSymbolAddress((void**)&af, g_af);
    cudaGetSymbolAddress((void**)&bigf, g_bigf);
    cudaGetSymbolAddress((void**)&qkvWh, g_qkvWh);
    cudaGetSymbolAddress((void**)&projWh, g_projWh);
    cudaGetSymbolAddress((void**)&fc1Wh, g_fc1Wh);
    cudaGetSymbolAddress((void**)&fc2Wh, g_fc2Wh);

    cudaFuncSetAttribute(attn_mma_kernel, cudaFuncAttributeMaxDynamicSharedMemorySize, ATTN_SMEM);
    cudaFuncSetAttribute(hmma_gemm<true, false, false>, cudaFuncAttributeMaxDynamicSharedMemorySize, SMTOT1);
    cudaFuncSetAttribute(hmma_gemm<false, false, true>, cudaFuncAttributeMaxDynamicSharedMemorySize, SMTOT1);
    cudaFuncSetAttribute(hmma_gemm<true, true, false>, cudaFuncAttributeMaxDynamicSharedMemorySize, SMTOT1);
    cudaFuncSetAttribute(conv_gemm, cudaFuncAttributeMaxDynamicSharedMemorySize, CSMTOT);

    // weight prep
    transpose_hi<<<dim3(3 * DD / 32, DD / 32, DEPTH), dim3(32, 8)>>>(qkv_w, qkvWh, DD, 3 * DD);
    transpose_hi<<<dim3(DD / 32, DD / 32, DEPTH), dim3(32, 8)>>>(proj_w, projWh, DD, DD);
    transpose_hi<<<dim3(4 * DD / 32, DD / 32, DEPTH), dim3(32, 8)>>>(fc1_w, fc1Wh, DD, 4 * DD);
    transpose_hi<<<dim3(DD / 32, 4 * DD / 32, DEPTH), dim3(32, 8)>>>(fc2_w, fc2Wh, 4 * DD, DD);
    convw_prep<<<(DD * KCPAD + 255) / 256, 256>>>(conv_w, convWh);

    // patch embed (fp16 2-product, fused pos-embed + assemble)
    im2col_split<<<(CROWS * KCPAD + 255) / 256, 256>>>(x, colh, coll);
    cls_fill<<<(BATCH * DD + 255) / 256, 256>>>(cls_tok, pos, h);
    conv_gemm<<<dim3(DD / 128, CROWS / 128), 256, CSMTOT>>>(colh, coll, convWh, conv_b, pos, h);

    const int MT = MPAD / 128;  // 86
    for (int i = 0; i < DEPTH; i++) {
        ln_f16_kernel<<<MROWS, 256>>>(h, ln1_w + (size_t)i * DD, ln1_b + (size_t)i * DD, yf);
        hmma_gemm<true, false, false><<<dim3(3 * DD / 128, MT), 256, SMTOT1>>>(
            yf, qkvWh + (size_t)i * 3 * DD * DD,
            qkv_b + (size_t)i * 3 * DD, nullptr, nullptr, qkvh, MROWS, 3 * DD, DD);
        attn_mma_kernel<<<BATCH * NHEAD, ATHREADS, ATTN_SMEM>>>(qkvh, af);
        hmma_gemm<false, false, true><<<dim3(DD / 128, MT), 256, SMTOT1>>>(
            af, projWh + (size_t)i * DD * DD,
            proj_b + (size_t)i * DD, h, h, nullptr, MROWS, DD, DD);
        ln_f16_kernel<<<MROWS, 256>>>(h, ln2_w + (size_t)i * DD, ln2_b + (size_t)i * DD, yf);
        hmma_gemm<true, true, false><<<dim3(4 * DD / 128, MT), 256, SMTOT1>>>(
            yf, fc1Wh + (size_t)i * 4 * DD * DD,
            fc1_b + (size_t)i * 4 * DD, nullptr, nullptr, bigf, MROWS, 4 * DD, DD);
        hmma_gemm<false, false, true><<<dim3(DD / 128, MT), 256, SMTOT1>>>(
            bigf, fc2Wh + (size_t)i * 4 * DD * DD,
            fc2_b + (size_t)i * DD, h, h, nullptr, MROWS, DD, 4 * DD);
    }

    ln_kernel<<<BATCH, 256>>>(h, norm_w, norm_b, clsb, NTOK);
    head_kernel<<<BATCH, 256>>>(clsb, head_w, head_b, out);
}